// round 2
// baseline (speedup 1.0000x reference)
#include <cuda_runtime.h>
#include <math.h>

#define HW 65536
#define WIMG 256
#define CH 128
#define BB 4
#define ELT (BB*CH*HW)

// ---------------- scratch (static device globals; no runtime alloc) ----------------
__device__ float g_V[ELT];
__device__ float g_XW[ELT];
__device__ float g_Qb[ELT];
__device__ float g_Kb[ELT];
__device__ float g_OUT[ELT];
__device__ float g_T1[ELT];
__device__ float g_T2[ELT];
__device__ float g_T3[ELT];
__device__ float g_F[BB*32*HW];
__device__ float g_OFF[BB*2*HW];
__device__ float g_FMC[BB*HW];
__device__ float g_SA[BB*HW];
__device__ float g_FSUM[BB*32];
__device__ float g_CA[BB*CH];
__device__ float g_MASK[BB*256];

__device__ __forceinline__ float leakyf(float x) { return x > 0.f ? x : 0.2f * x; }

// ---------------- zero FSUM (graph replays must re-zero) ----------------
__global__ void zero_fsum_kernel() {
    g_FSUM[threadIdx.x] = 0.f;
}

// ---------------- generic 128->128 conv1x1 (GEMM) ----------------
// out[b][oc][p] = sum_ci w[oc*128+ci] * x[b][ci][p] + bias[oc]
__global__ void conv1x1_128(const float* __restrict__ x, const float* __restrict__ w,
                            const float* __restrict__ bias, float* __restrict__ y) {
    __shared__ float Xs[16][128];
    __shared__ float Ws[16][132];
    int b = blockIdx.y;
    int p0 = blockIdx.x * 128;
    int t = threadIdx.x;
    const float* xb = x + (size_t)b * CH * HW;
    float acc[4][16];
#pragma unroll
    for (int j = 0; j < 4; j++)
#pragma unroll
        for (int c = 0; c < 16; c++) acc[j][c] = 0.f;
    int lane = t & 31;
    int ocb = (t >> 5) * 16;
    for (int ci0 = 0; ci0 < 128; ci0 += 16) {
#pragma unroll
        for (int i = 0; i < 8; i++) {
            int idx = t + i * 256;
            int kk = idx >> 7, pp = idx & 127;
            Xs[kk][pp] = xb[(size_t)(ci0 + kk) * HW + p0 + pp];
        }
#pragma unroll
        for (int i = 0; i < 8; i++) {
            int idx = t + i * 256;
            int kk = idx & 15, oc = idx >> 4;
            Ws[kk][oc] = w[oc * 128 + ci0 + kk];
        }
        __syncthreads();
#pragma unroll
        for (int kk = 0; kk < 16; kk++) {
            float xr[4];
#pragma unroll
            for (int j = 0; j < 4; j++) xr[j] = Xs[kk][lane + 32 * j];
#pragma unroll
            for (int c = 0; c < 16; c++) {
                float wv = Ws[kk][ocb + c];
#pragma unroll
                for (int j = 0; j < 4; j++) acc[j][c] = fmaf(wv, xr[j], acc[j][c]);
            }
        }
        __syncthreads();
    }
    float* yb = y + (size_t)b * CH * HW;
#pragma unroll
    for (int c = 0; c < 16; c++) {
        float bv = __ldg(&bias[ocb + c]);
#pragma unroll
        for (int j = 0; j < 4; j++)
            yb[(size_t)(ocb + c) * HW + p0 + lane + 32 * j] = acc[j][c] + bv;
    }
}

// ---------------- predictor input conv (131->32) + offsets (32->16->2) + fmean_c + fsum ----------------
__global__ void predictor_kernel(const float* __restrict__ cond_g,
                                 const float* __restrict__ rin_w, const float* __restrict__ rin_b,
                                 const float* __restrict__ r1w, const float* __restrict__ r1b,
                                 const float* __restrict__ r2w, const float* __restrict__ r2b) {
    __shared__ float wr[32 * 131];
    __shared__ float wr1[16 * 32];
    __shared__ float wr2[32];
    __shared__ float partial[8][32];
    int t = threadIdx.x;
    int b = blockIdx.y;
    for (int i = t; i < 32 * 131; i += 256) wr[i] = rin_w[i];
    for (int i = t; i < 16 * 32; i += 256) wr1[i] = r1w[i];
    if (t < 32) wr2[t] = r2w[t];
    __syncthreads();

    int p0 = blockIdx.x * 512 + t;
    int p1 = p0 + 256;
    float a0[32], a1[32];
#pragma unroll
    for (int o = 0; o < 32; o++) {
        float bv = __ldg(&rin_b[o]);
        a0[o] = bv; a1[o] = bv;
    }
    const float* vb = g_V + (size_t)b * CH * HW;
#pragma unroll 2
    for (int ci = 0; ci < 128; ci++) {
        float x0 = vb[(size_t)ci * HW + p0];
        float x1 = vb[(size_t)ci * HW + p1];
#pragma unroll
        for (int o = 0; o < 32; o++) {
            float wv = wr[o * 131 + ci];
            a0[o] = fmaf(wv, x0, a0[o]);
            a1[o] = fmaf(wv, x1, a1[o]);
        }
    }
    float cg0 = __ldg(&cond_g[b * HW + p0]);
    float cg1 = __ldg(&cond_g[b * HW + p1]);
    int y0 = p0 >> 8, x0p = p0 & 255;
    int y1 = p1 >> 8, x1p = p1 & 255;
    float ly0 = -1.f + (float)(y0 & 15) * (2.f / 15.f);
    float lx0 = -1.f + (float)(x0p & 15) * (2.f / 15.f);
    float ly1 = -1.f + (float)(y1 & 15) * (2.f / 15.f);
    float lx1 = -1.f + (float)(x1p & 15) * (2.f / 15.f);
    float fm0 = 0.f, fm1 = 0.f;
    float* Fb = g_F + (size_t)b * 32 * HW;
#pragma unroll
    for (int o = 0; o < 32; o++) {
        float v0 = a0[o] + wr[o * 131 + 128] * cg0 + wr[o * 131 + 129] * ly0 + wr[o * 131 + 130] * lx0;
        float v1 = a1[o] + wr[o * 131 + 128] * cg1 + wr[o * 131 + 129] * ly1 + wr[o * 131 + 130] * lx1;
        v0 = leakyf(v0); v1 = leakyf(v1);
        a0[o] = v0; a1[o] = v1;
        Fb[(size_t)o * HW + p0] = v0;
        Fb[(size_t)o * HW + p1] = v1;
        fm0 += v0; fm1 += v1;
    }
    g_FMC[b * HW + p0] = fm0 * (1.f / 32.f);
    g_FMC[b * HW + p1] = fm1 * (1.f / 32.f);

    // offsets: 32 -> 16 (leaky) -> 2
    float h0[16], h1v[16];
#pragma unroll
    for (int o2 = 0; o2 < 16; o2++) {
        float bv = __ldg(&r1b[o2]);
        float s0 = bv, s1 = bv;
#pragma unroll
        for (int o = 0; o < 32; o++) {
            float wv = wr1[o2 * 32 + o];
            s0 = fmaf(wv, a0[o], s0);
            s1 = fmaf(wv, a1[o], s1);
        }
        h0[o2] = leakyf(s0);
        h1v[o2] = leakyf(s1);
    }
    float ox0 = __ldg(&r2b[0]), oy0 = __ldg(&r2b[1]);
    float ox1 = ox0, oy1 = oy0;
#pragma unroll
    for (int o2 = 0; o2 < 16; o2++) {
        ox0 = fmaf(wr2[o2], h0[o2], ox0);
        oy0 = fmaf(wr2[16 + o2], h0[o2], oy0);
        ox1 = fmaf(wr2[o2], h1v[o2], ox1);
        oy1 = fmaf(wr2[16 + o2], h1v[o2], oy1);
    }
    float* OFb = g_OFF + (size_t)b * 2 * HW;
    OFb[p0] = ox0; OFb[p1] = ox1;
    OFb[HW + p0] = oy0; OFb[HW + p1] = oy1;

    // fsum reduction
    int lane = t & 31, wid = t >> 5;
#pragma unroll
    for (int o = 0; o < 32; o++) {
        float v = a0[o] + a1[o];
        v += __shfl_xor_sync(0xffffffff, v, 16);
        v += __shfl_xor_sync(0xffffffff, v, 8);
        v += __shfl_xor_sync(0xffffffff, v, 4);
        v += __shfl_xor_sync(0xffffffff, v, 2);
        v += __shfl_xor_sync(0xffffffff, v, 1);
        if (lane == 0) partial[wid][o] = v;
    }
    __syncthreads();
    if (t < 32) {
        float s = 0.f;
#pragma unroll
        for (int w2 = 0; w2 < 8; w2++) s += partial[w2][t];
        atomicAdd(&g_FSUM[b * 32 + t], s);
    }
}

// ---------------- channel attention ca ----------------
__global__ void ca_kernel(const float* __restrict__ rca_w, const float* __restrict__ rca_b) {
    int c = threadIdx.x;
    int b = blockIdx.x;
    float s = __ldg(&rca_b[c]);
#pragma unroll
    for (int ci = 0; ci < 32; ci++)
        s = fmaf(__ldg(&rca_w[c * 32 + ci]), g_FSUM[b * 32 + ci] * (1.f / 65536.f), s);
    g_CA[b * CH + c] = 1.f / (1.f + expf(-s));
}

// ---------------- spatial attention sa: conv3x3 32->1 pad1 + sigmoid ----------------
__global__ void sa_kernel(const float* __restrict__ rsa_w, const float* __restrict__ rsa_b) {
    __shared__ float ws[288];
    int t = threadIdx.x;
    for (int i = t; i < 288; i += 256) ws[i] = rsa_w[i];   // FIX: 288 > 256 threads
    __syncthreads();
    int b = blockIdx.y;
    int p = blockIdx.x * 256 + t;
    int y = p >> 8, x = p & 255;
    float acc = __ldg(&rsa_b[0]);
    const float* Fb = g_F + (size_t)b * 32 * HW;
    for (int ci = 0; ci < 32; ci++) {
        const float* fp = Fb + (size_t)ci * HW;
#pragma unroll
        for (int ky = 0; ky < 3; ky++) {
            int yy = y + ky - 1;
            if ((unsigned)yy >= 256u) continue;
#pragma unroll
            for (int kx = 0; kx < 3; kx++) {
                int xx = x + kx - 1;
                if ((unsigned)xx >= 256u) continue;
                acc = fmaf(ws[ci * 9 + ky * 3 + kx], __ldg(&fp[yy * 256 + xx]), acc);
            }
        }
    }
    g_SA[b * HW + p] = 1.f / (1.f + expf(-acc));
}

// ---------------- window MLP + gumbel hard mask ----------------
__global__ void mask_kernel(const float* __restrict__ gu,
                            const float* __restrict__ rm1_w, const float* __restrict__ rm1_b,
                            const float* __restrict__ rm2_w, const float* __restrict__ rm2_b) {
    __shared__ float m[256];
    __shared__ float h1s[16];
    int n = blockIdx.x, b = blockIdx.y;
    int t = threadIdx.x;
    int dh = t >> 4, dw = t & 15;
    int pix = ((n >> 4) * 16 + dh) * 256 + (n & 15) * 16 + dw;
    m[t] = g_FMC[b * HW + pix];
    __syncthreads();
    if (t < 16) {
        float s = __ldg(&rm1_b[t]);
        for (int e = 0; e < 256; e++) s = fmaf(__ldg(&rm1_w[t * 256 + e]), m[e], s);
        h1s[t] = leakyf(s);
    }
    __syncthreads();
    if (t == 0) {
        float z0 = __ldg(&rm2_b[0]), z1 = __ldg(&rm2_b[1]);
#pragma unroll
        for (int o = 0; o < 16; o++) {
            z0 = fmaf(__ldg(&rm2_w[o]), h1s[o], z0);
            z1 = fmaf(__ldg(&rm2_w[16 + o]), h1s[o], z1);
        }
        float mx = fmaxf(z0, z1);
        float e0 = expf(z0 - mx), e1 = expf(z1 - mx);
        float inv = 1.f / (e0 + e1);
        float p0 = e0 * inv, p1 = e1 * inv;
        float u0 = __ldg(&gu[(b * 256 + n) * 2 + 0]);
        float u1 = __ldg(&gu[(b * 256 + n) * 2 + 1]);
        float g0 = -logf(-logf(u0 + 1e-10f) + 1e-10f);
        float g1 = -logf(-logf(u1 + 1e-10f) + 1e-10f);
        g_MASK[b * 256 + n] = (p0 + g0 >= p1 + g1) ? 1.f : 0.f;
    }
}

// ---------------- bilinear flow warp ----------------
__global__ void warp_kernel(const float* __restrict__ x) {
    int b = blockIdx.y;
    int p = blockIdx.x * 256 + threadIdx.x;
    int yy = p >> 8, xx = p & 255;
    const float* OFb = g_OFF + (size_t)b * 2 * HW;
    float fx = OFb[p];
    float fy = OFb[HW + p];
    float sx = fminf(fmaxf((float)xx + fx, 0.f), 255.f);
    float sy = fminf(fmaxf((float)yy + fy, 0.f), 255.f);
    float x0f = floorf(sx), y0f = floorf(sy);
    float x1f = fminf(x0f + 1.f, 255.f), y1f = fminf(y0f + 1.f, 255.f);
    float wx = sx - x0f, wy = sy - y0f;
    int x0 = (int)x0f, x1 = (int)x1f, y0 = (int)y0f, y1 = (int)y1f;
    int iA = y0 * 256 + x0, iB = y0 * 256 + x1, iC = y1 * 256 + x0, iD = y1 * 256 + x1;
    float w00 = (1.f - wx) * (1.f - wy), w01 = wx * (1.f - wy);
    float w10 = (1.f - wx) * wy, w11 = wx * wy;
    const float* xb = x + (size_t)b * CH * HW;
    float* ob = g_XW + (size_t)b * CH * HW;
#pragma unroll 4
    for (int c = 0; c < 128; c++) {
        const float* xc = xb + (size_t)c * HW;
        ob[(size_t)c * HW + p] =
            __ldg(&xc[iA]) * w00 + __ldg(&xc[iB]) * w01 +
            __ldg(&xc[iC]) * w10 + __ldg(&xc[iD]) * w11;
    }
}

// ---------------- window attention (masked) / v*sa (unmasked) ----------------
#define SMEM_ATTN (33344 * 4)
__global__ void attn_kernel() {
    int n = blockIdx.x, b = blockIdx.y;
    int t = threadIdx.x;
    int py0 = (n >> 4) * 16, px0 = (n & 15) * 16;
    int cbase = b * CH * HW;
    float mval = g_MASK[b * 256 + n];
    if (mval == 0.f) {
        for (int i = t; i < 256 * 128; i += 256) {
            int r = i & 255, c = i >> 8;
            int pix = (py0 + (r >> 4)) * 256 + px0 + (r & 15);
            g_OUT[cbase + c * HW + pix] = g_V[cbase + c * HW + pix] * g_SA[b * HW + pix];
        }
        return;
    }
    extern __shared__ float sm[];
    float* Qs = sm;                 // 64*129
    float* Ss = Qs + 64 * 129;      // 64*257
    float* KVs = Ss + 64 * 257;     // 64*129
    float* red = KVs + 64 * 129;    // 256
    float* rmax = red + 256;        // 64
    float* rsum = rmax + 64;        // 64

    int rr = t & 15;
    int cc = (t >> 4) * 4;
    int cc8 = (t >> 4) * 8;

    for (int rc = 0; rc < 4; rc++) {
        int r0 = rc * 64;
        __syncthreads();
        // load 64 Q rows
#pragma unroll
        for (int j = 0; j < 32; j++) {
            int i = t + j * 256;
            int r = i & 63, c = i >> 6;
            int row = r0 + r;
            int pix = (py0 + (row >> 4)) * 256 + px0 + (row & 15);
            Qs[r * 129 + c] = g_Qb[cbase + c * HW + pix];
        }
        // S = Q K^T
        for (int kvt = 0; kvt < 4; kvt++) {
            __syncthreads();
#pragma unroll
            for (int j = 0; j < 32; j++) {
                int i = t + j * 256;
                int r = i & 63, c = i >> 6;
                int row = kvt * 64 + r;
                int pix = (py0 + (row >> 4)) * 256 + px0 + (row & 15);
                KVs[r * 129 + c] = g_Kb[cbase + c * HW + pix];
            }
            __syncthreads();
            float acc[4][4];
#pragma unroll
            for (int i = 0; i < 4; i++)
#pragma unroll
                for (int j = 0; j < 4; j++) acc[i][j] = 0.f;
#pragma unroll 4
            for (int kk = 0; kk < 128; kk++) {
                float a[4], bv[4];
#pragma unroll
                for (int i = 0; i < 4; i++) a[i] = Qs[(rr + 16 * i) * 129 + kk];
#pragma unroll
                for (int j = 0; j < 4; j++) bv[j] = KVs[(cc + j) * 129 + kk];
#pragma unroll
                for (int i = 0; i < 4; i++)
#pragma unroll
                    for (int j = 0; j < 4; j++) acc[i][j] = fmaf(a[i], bv[j], acc[i][j]);
            }
#pragma unroll
            for (int i = 0; i < 4; i++)
#pragma unroll
                for (int j = 0; j < 4; j++)
                    Ss[(rr + 16 * i) * 257 + kvt * 64 + cc + j] = acc[i][j];
        }
        __syncthreads();
        // softmax over 256 cols (4 segments of 64)
        {
            int r = t & 63, seg = t >> 6;
            float* srow = &Ss[r * 257 + seg * 64];
            float mx = -1e30f;
#pragma unroll 8
            for (int k = 0; k < 64; k++) mx = fmaxf(mx, srow[k]);
            red[seg * 64 + r] = mx;
            __syncthreads();
            if (t < 64)
                rmax[t] = fmaxf(fmaxf(red[t], red[64 + t]), fmaxf(red[128 + t], red[192 + t]));
            __syncthreads();
            float rm_ = rmax[r];
            float s = 0.f;
#pragma unroll 8
            for (int k = 0; k < 64; k++) {
                float e = __expf(srow[k] - rm_);
                srow[k] = e;
                s += e;
            }
            red[seg * 64 + r] = s;
            __syncthreads();
            if (t < 64) rsum[t] = red[t] + red[64 + t] + red[128 + t] + red[192 + t];
            __syncthreads();
        }
        // O = S V
        float acc2[4][8];
#pragma unroll
        for (int i = 0; i < 4; i++)
#pragma unroll
            for (int j = 0; j < 8; j++) acc2[i][j] = 0.f;
        for (int kvt = 0; kvt < 4; kvt++) {
            __syncthreads();
#pragma unroll
            for (int j = 0; j < 32; j++) {
                int i = t + j * 256;
                int r = i & 63, c = i >> 6;
                int row = kvt * 64 + r;
                int pix = (py0 + (row >> 4)) * 256 + px0 + (row & 15);
                KVs[r * 129 + c] = g_V[cbase + c * HW + pix];
            }
            __syncthreads();
#pragma unroll 2
            for (int kk = 0; kk < 64; kk++) {
                float sreg[4], vreg[8];
#pragma unroll
                for (int i = 0; i < 4; i++) sreg[i] = Ss[(rr + 16 * i) * 257 + kvt * 64 + kk];
#pragma unroll
                for (int j = 0; j < 8; j++) vreg[j] = KVs[kk * 129 + cc8 + j];
#pragma unroll
                for (int i = 0; i < 4; i++)
#pragma unroll
                    for (int j = 0; j < 8; j++) acc2[i][j] = fmaf(sreg[i], vreg[j], acc2[i][j]);
            }
        }
        // epilogue
#pragma unroll
        for (int i = 0; i < 4; i++) {
            int row = r0 + rr + 16 * i;
            int pix = (py0 + (row >> 4)) * 256 + px0 + (row & 15);
            float inv = 1.f / rsum[rr + 16 * i];
#pragma unroll
            for (int j = 0; j < 8; j++)
                g_OUT[cbase + (cc8 + j) * HW + pix] = acc2[i][j] * inv;
        }
    }
}

// ---------------- depthwise 5x5 (dilation param) ----------------
__global__ void dw5_kernel(const float* __restrict__ in, const float* __restrict__ w,
                           const float* __restrict__ bias, float* __restrict__ out, int dil) {
    __shared__ float ws[25];
    int c = blockIdx.z & 127, b = blockIdx.z >> 7;
    int t = threadIdx.y * 32 + threadIdx.x;
    if (t < 25) ws[t] = w[c * 25 + t];
    __syncthreads();
    int x = blockIdx.x * 32 + threadIdx.x;
    int y = blockIdx.y * 8 + threadIdx.y;
    const float* ip = in + (size_t)(b * CH + c) * HW;
    float acc = __ldg(&bias[c]);
#pragma unroll
    for (int ky = 0; ky < 5; ky++) {
        int yy = y + (ky - 2) * dil;
        if ((unsigned)yy >= 256u) continue;
#pragma unroll
        for (int kx = 0; kx < 5; kx++) {
            int xx = x + (kx - 2) * dil;
            if ((unsigned)xx >= 256u) continue;
            acc = fmaf(ws[ky * 5 + kx], __ldg(&ip[yy * 256 + xx]), acc);
        }
    }
    out[(size_t)(b * CH + c) * HW + y * 256 + x] = acc;
}

// ---------------- gelu(cs)*ca + out -> T1 ----------------
__global__ void gelu_ca_add_kernel() {
    int i = blockIdx.x * 256 + threadIdx.x;
    int chw = i >> 16;
    int c = chw & 127, b = chw >> 7;
    float xv = g_T3[i];
    float g = 0.5f * xv * (1.f + erff(xv * 0.7071067811865475f));
    g_T1[i] = g * g_CA[b * CH + c] + g_OUT[i];
}

// ---------------- launch ----------------
extern "C" void kernel_launch(void* const* d_in, const int* in_sizes, int n_in,
                              void* d_out, int out_size) {
    const float* x      = (const float*)d_in[0];
    const float* cond_g = (const float*)d_in[1];
    const float* gu     = (const float*)d_in[2];
    const float* pv_w   = (const float*)d_in[3];
    const float* pv_b   = (const float*)d_in[4];
    const float* pq_w   = (const float*)d_in[5];
    const float* pq_b   = (const float*)d_in[6];
    const float* pk_w   = (const float*)d_in[7];
    const float* pk_b   = (const float*)d_in[8];
    const float* cs1_w  = (const float*)d_in[9];
    const float* cs1_b  = (const float*)d_in[10];
    const float* cs2_w  = (const float*)d_in[11];
    const float* cs2_b  = (const float*)d_in[12];
    const float* cs3_w  = (const float*)d_in[13];
    const float* cs3_b  = (const float*)d_in[14];
    const float* po_w   = (const float*)d_in[15];
    const float* po_b   = (const float*)d_in[16];
    const float* rin_w  = (const float*)d_in[17];
    const float* rin_b  = (const float*)d_in[18];
    const float* r1w    = (const float*)d_in[19];
    const float* r1b    = (const float*)d_in[20];
    const float* r2w    = (const float*)d_in[21];
    const float* r2b    = (const float*)d_in[22];
    const float* rm1_w  = (const float*)d_in[23];
    const float* rm1_b  = (const float*)d_in[24];
    const float* rm2_w  = (const float*)d_in[25];
    const float* rm2_b  = (const float*)d_in[26];
    const float* rca_w  = (const float*)d_in[27];
    const float* rca_b  = (const float*)d_in[28];
    const float* rsa_w  = (const float*)d_in[29];
    const float* rsa_b  = (const float*)d_in[30];

    float *pV, *pXW, *pQ, *pK, *pOUT, *pT1, *pT2, *pT3;
    cudaGetSymbolAddress((void**)&pV, g_V);
    cudaGetSymbolAddress((void**)&pXW, g_XW);
    cudaGetSymbolAddress((void**)&pQ, g_Qb);
    cudaGetSymbolAddress((void**)&pK, g_Kb);
    cudaGetSymbolAddress((void**)&pOUT, g_OUT);
    cudaGetSymbolAddress((void**)&pT1, g_T1);
    cudaGetSymbolAddress((void**)&pT2, g_T2);
    cudaGetSymbolAddress((void**)&pT3, g_T3);

    cudaFuncSetAttribute(attn_kernel, cudaFuncAttributeMaxDynamicSharedMemorySize, SMEM_ATTN);

    zero_fsum_kernel<<<1, 128>>>();
    // v = pv(x)
    conv1x1_128<<<dim3(HW / 128, BB), 256>>>(x, pv_w, pv_b, pV);
    // f, offsets, fmean_c, fsum
    predictor_kernel<<<dim3(HW / 512, BB), 256>>>(cond_g, rin_w, rin_b, r1w, r1b, r2w, r2b);
    ca_kernel<<<BB, 128>>>(rca_w, rca_b);
    sa_kernel<<<dim3(HW / 256, BB), 256>>>(rsa_w, rsa_b);
    mask_kernel<<<dim3(256, BB), 256>>>(gu, rm1_w, rm1_b, rm2_w, rm2_b);
    // flow warp
    warp_kernel<<<dim3(HW / 256, BB), 256>>>(x);
    // q / k projections
    conv1x1_128<<<dim3(HW / 128, BB), 256>>>(pXW, pq_w, pq_b, pQ);
    conv1x1_128<<<dim3(HW / 128, BB), 256>>>(pXW, pk_w, pk_b, pK);
    // window attention / sparse bypass
    attn_kernel<<<dim3(256, BB), 256, SMEM_ATTN>>>();
    // conv spatial chain
    conv1x1_128<<<dim3(HW / 128, BB), 256>>>(pOUT, cs1_w, cs1_b, pT1);
    dw5_kernel<<<dim3(8, 32, BB * CH), dim3(32, 8)>>>(pT1, cs2_w, cs2_b, pT2, 1);
    dw5_kernel<<<dim3(8, 32, BB * CH), dim3(32, 8)>>>(pT2, cs3_w, cs3_b, pT3, 3);
    gelu_ca_add_kernel<<<ELT / 256, 256>>>();
    // final projection -> d_out
    conv1x1_128<<<dim3(HW / 128, BB), 256>>>(pT1, po_w, po_b, (float*)d_out);
}

// round 4
// speedup vs baseline: 1.3249x; 1.3249x over previous
#include <cuda_runtime.h>
#include <cuda_bf16.h>
#include <stdint.h>
#include <math.h>

#define HW 65536
#define WIMG 256
#define CH 128
#define BB 4
#define ELT (BB*CH*HW)

// ---------------- scratch (static device globals; no runtime alloc) ----------------
__device__ float g_V[ELT];
__device__ float g_XW[ELT];
__device__ float g_Qb[ELT];
__device__ float g_Kb[ELT];
__device__ float g_OUT[ELT];
__device__ float g_T1[ELT];
__device__ float g_T2[ELT];
__device__ float g_T3[ELT];
__device__ float g_F[BB*32*HW];
__device__ float g_OFF[BB*2*HW];
__device__ float g_FMC[BB*HW];
__device__ float g_SA[BB*HW];
__device__ float g_FSUM[BB*32];
__device__ float g_CA[BB*CH];
__device__ float g_MASK[BB*256];
// hi/lo bf16 weights, row-padded to 136 (stride-68-word smem => conflict-free frags)
__device__ __align__(16) __nv_bfloat16 g_WT[5][2][128*136];

__device__ __forceinline__ float leakyf(float x) { return x > 0.f ? x : 0.2f * x; }

// ---------------- zero FSUM (graph replays must re-zero) ----------------
__global__ void zero_fsum_kernel() {
    g_FSUM[threadIdx.x] = 0.f;
}

// ---------------- weight prep: fp32 -> bf16 hi/lo, padded rows ----------------
__global__ void prep_w_kernel(const float* __restrict__ w, int set) {
    int i = blockIdx.x * 256 + threadIdx.x;   // 16384 elements
    int oc = i >> 7, ci = i & 127;
    float v = w[i];
    __nv_bfloat16 h = __float2bfloat16_rn(v);
    __nv_bfloat16 l = __float2bfloat16_rn(v - __bfloat162float(h));
    g_WT[set][0][oc * 136 + ci] = h;
    g_WT[set][1][oc * 136 + ci] = l;
}

// ---------------- HMMA m16n8k16 bf16 ----------------
#define MMA_BF16(d, a, b) \
    asm volatile("mma.sync.aligned.m16n8k16.row.col.f32.bf16.bf16.f32 " \
        "{%0,%1,%2,%3}, {%4,%5,%6,%7}, {%8,%9}, {%0,%1,%2,%3};" \
        : "+f"((d)[0]), "+f"((d)[1]), "+f"((d)[2]), "+f"((d)[3]) \
        : "r"((a)[0]), "r"((a)[1]), "r"((a)[2]), "r"((a)[3]), "r"((b)[0]), "r"((b)[1]))

// smem: Wh[128*136] | Wl | Xh[128*136] | Xl   (bf16; 34816B each; total 139264B)
#define CV_SMEM (4 * 128 * 136 * 2)

// ---------------- conv1x1 GEMM via mma.sync: one block = one half-window ----------------
// out[b][oc][pix] = sum_ci W[oc][ci] * X[ci][pix] + bias[oc]
__global__ void __launch_bounds__(256, 1)
conv1x1_mma(const float* __restrict__ xin, const __nv_bfloat16* __restrict__ wsp,
            const float* __restrict__ bias, float* __restrict__ yout, int useMask) {
    int hw = blockIdx.x, b = blockIdx.y;
    int n = hw >> 1, half = hw & 1;
    if (useMask && g_MASK[b * 256 + n] == 0.f) return;
    extern __shared__ __nv_bfloat16 smb[];
    __nv_bfloat16* Wh = smb;
    __nv_bfloat16* Wl = Wh + 128 * 136;
    __nv_bfloat16* Xh = Wl + 128 * 136;
    __nv_bfloat16* Xl = Xh + 128 * 136;
    int t = threadIdx.x;

    // ---- copy padded W hi+lo (69632 B = 4352 uint4; pad cols never used in math) ----
    {
        const uint4* src = (const uint4*)wsp;
        uint4* dst = (uint4*)smb;
#pragma unroll
        for (int i = 0; i < 17; i++) dst[t + i * 256] = src[t + i * 256];
    }

    // ---- stage X half-window transposed: Xs[px][ci] hi/lo (pack ci pairs) ----
    int py0 = (n >> 4) * 16, px0 = (n & 15) * 16;
    const float* xb = xin + (size_t)b * CH * HW;
#pragma unroll
    for (int j = 0; j < 32; j++) {
        int i = t + j * 256;
        int px = i & 127;        // consecutive threads -> consecutive px (coalesced-ish)
        int cp = i >> 7;         // ci pair 0..63
        int p = half * 128 + px;
        int pix = (py0 + (p >> 4)) * 256 + px0 + (p & 15);
        float v0 = xb[(size_t)(2 * cp) * HW + pix];
        float v1 = xb[(size_t)(2 * cp + 1) * HW + pix];
        __nv_bfloat16 h0 = __float2bfloat16_rn(v0);
        __nv_bfloat16 h1 = __float2bfloat16_rn(v1);
        __nv_bfloat16 l0 = __float2bfloat16_rn(v0 - __bfloat162float(h0));
        __nv_bfloat16 l1 = __float2bfloat16_rn(v1 - __bfloat162float(h1));
        ((__nv_bfloat162*)(Xh + px * 136))[cp] = __nv_bfloat162(h0, h1);
        ((__nv_bfloat162*)(Xl + px * 136))[cp] = __nv_bfloat162(l0, l1);
    }
    __syncthreads();

    // ---- warp tiling: 8 warps = 4(oc) x 2(px); warp tile 32 oc x 64 px ----
    int w = t >> 5, lane = t & 31;
    int oc0 = (w & 3) * 32;
    int n0 = (w >> 2) * 64;
    int gid = lane >> 2, tig = lane & 3;

    float acc[16][4];
#pragma unroll
    for (int i = 0; i < 16; i++)
#pragma unroll
        for (int j = 0; j < 4; j++) acc[i][j] = 0.f;

    const uint32_t* WhW = (const uint32_t*)Wh;
    const uint32_t* WlW = (const uint32_t*)Wl;
    const uint32_t* XhW = (const uint32_t*)Xh;
    const uint32_t* XlW = (const uint32_t*)Xl;

#pragma unroll 1
    for (int ks = 0; ks < 8; ks++) {
        int kw = ks * 8;   // word offset of k-step (16 bf16 = 8 words)
        uint32_t Ah[2][4], Al[2][4], Bh[8][2], Bl[8][2];
#pragma unroll
        for (int mt = 0; mt < 2; mt++) {
            int r0 = (oc0 + mt * 16 + gid) * 68 + kw + tig;
            int r8 = r0 + 8 * 68;
            Ah[mt][0] = WhW[r0];     Ah[mt][1] = WhW[r8];
            Ah[mt][2] = WhW[r0 + 4]; Ah[mt][3] = WhW[r8 + 4];
            Al[mt][0] = WlW[r0];     Al[mt][1] = WlW[r8];
            Al[mt][2] = WlW[r0 + 4]; Al[mt][3] = WlW[r8 + 4];
        }
#pragma unroll
        for (int nt = 0; nt < 8; nt++) {
            int rr = (n0 + nt * 8 + gid) * 68 + kw + tig;
            Bh[nt][0] = XhW[rr]; Bh[nt][1] = XhW[rr + 4];
            Bl[nt][0] = XlW[rr]; Bl[nt][1] = XlW[rr + 4];
        }
#pragma unroll
        for (int mt = 0; mt < 2; mt++)
#pragma unroll
            for (int nt = 0; nt < 8; nt++) {
                MMA_BF16(acc[mt * 8 + nt], Ah[mt], Bh[nt]);
                MMA_BF16(acc[mt * 8 + nt], Ah[mt], Bl[nt]);
                MMA_BF16(acc[mt * 8 + nt], Al[mt], Bh[nt]);
            }
    }

    // ---- epilogue: +bias, float2 stores into window layout ----
    float* yb = yout + (size_t)b * CH * HW;
#pragma unroll
    for (int mt = 0; mt < 2; mt++) {
        int ocA = oc0 + mt * 16 + gid;
        int ocB = ocA + 8;
        float bvA = __ldg(&bias[ocA]);
        float bvB = __ldg(&bias[ocB]);
#pragma unroll
        for (int nt = 0; nt < 8; nt++) {
            int col = n0 + nt * 8 + tig * 2;
            int p = half * 128 + col;
            int pix = (py0 + (p >> 4)) * 256 + px0 + (p & 15);
            float2 v0 = make_float2(acc[mt * 8 + nt][0] + bvA, acc[mt * 8 + nt][1] + bvA);
            float2 v1 = make_float2(acc[mt * 8 + nt][2] + bvB, acc[mt * 8 + nt][3] + bvB);
            *(float2*)(yb + (size_t)ocA * HW + pix) = v0;
            *(float2*)(yb + (size_t)ocB * HW + pix) = v1;
        }
    }
}

// ---------------- predictor input conv (131->32) + offsets (32->16->2) + fmean_c + fsum ----------------
__global__ void predictor_kernel(const float* __restrict__ cond_g,
                                 const float* __restrict__ rin_w, const float* __restrict__ rin_b,
                                 const float* __restrict__ r1w, const float* __restrict__ r1b,
                                 const float* __restrict__ r2w, const float* __restrict__ r2b) {
    __shared__ float wr[32 * 131];
    __shared__ float wr1[16 * 32];
    __shared__ float wr2[32];
    __shared__ float partial[8][32];
    int t = threadIdx.x;
    int b = blockIdx.y;
    for (int i = t; i < 32 * 131; i += 256) wr[i] = rin_w[i];
    for (int i = t; i < 16 * 32; i += 256) wr1[i] = r1w[i];
    if (t < 32) wr2[t] = r2w[t];
    __syncthreads();

    int p0 = blockIdx.x * 512 + t;
    int p1 = p0 + 256;
    float a0[32], a1[32];
#pragma unroll
    for (int o = 0; o < 32; o++) {
        float bv = __ldg(&rin_b[o]);
        a0[o] = bv; a1[o] = bv;
    }
    const float* vb = g_V + (size_t)b * CH * HW;
#pragma unroll 2
    for (int ci = 0; ci < 128; ci++) {
        float x0 = vb[(size_t)ci * HW + p0];
        float x1 = vb[(size_t)ci * HW + p1];
#pragma unroll
        for (int o = 0; o < 32; o++) {
            float wv = wr[o * 131 + ci];
            a0[o] = fmaf(wv, x0, a0[o]);
            a1[o] = fmaf(wv, x1, a1[o]);
        }
    }
    float cg0 = __ldg(&cond_g[b * HW + p0]);
    float cg1 = __ldg(&cond_g[b * HW + p1]);
    int y0 = p0 >> 8, x0p = p0 & 255;
    int y1 = p1 >> 8, x1p = p1 & 255;
    float ly0 = -1.f + (float)(y0 & 15) * (2.f / 15.f);
    float lx0 = -1.f + (float)(x0p & 15) * (2.f / 15.f);
    float ly1 = -1.f + (float)(y1 & 15) * (2.f / 15.f);
    float lx1 = -1.f + (float)(x1p & 15) * (2.f / 15.f);
    float fm0 = 0.f, fm1 = 0.f;
    float* Fb = g_F + (size_t)b * 32 * HW;
#pragma unroll
    for (int o = 0; o < 32; o++) {
        float v0 = a0[o] + wr[o * 131 + 128] * cg0 + wr[o * 131 + 129] * ly0 + wr[o * 131 + 130] * lx0;
        float v1 = a1[o] + wr[o * 131 + 128] * cg1 + wr[o * 131 + 129] * ly1 + wr[o * 131 + 130] * lx1;
        v0 = leakyf(v0); v1 = leakyf(v1);
        a0[o] = v0; a1[o] = v1;
        Fb[(size_t)o * HW + p0] = v0;
        Fb[(size_t)o * HW + p1] = v1;
        fm0 += v0; fm1 += v1;
    }
    g_FMC[b * HW + p0] = fm0 * (1.f / 32.f);
    g_FMC[b * HW + p1] = fm1 * (1.f / 32.f);

    float h0[16], h1v[16];
#pragma unroll
    for (int o2 = 0; o2 < 16; o2++) {
        float bv = __ldg(&r1b[o2]);
        float s0 = bv, s1 = bv;
#pragma unroll
        for (int o = 0; o < 32; o++) {
            float wv = wr1[o2 * 32 + o];
            s0 = fmaf(wv, a0[o], s0);
            s1 = fmaf(wv, a1[o], s1);
        }
        h0[o2] = leakyf(s0);
        h1v[o2] = leakyf(s1);
    }
    float ox0 = __ldg(&r2b[0]), oy0 = __ldg(&r2b[1]);
    float ox1 = ox0, oy1 = oy0;
#pragma unroll
    for (int o2 = 0; o2 < 16; o2++) {
        ox0 = fmaf(wr2[o2], h0[o2], ox0);
        oy0 = fmaf(wr2[16 + o2], h0[o2], oy0);
        ox1 = fmaf(wr2[o2], h1v[o2], ox1);
        oy1 = fmaf(wr2[16 + o2], h1v[o2], oy1);
    }
    float* OFb = g_OFF + (size_t)b * 2 * HW;
    OFb[p0] = ox0; OFb[p1] = ox1;
    OFb[HW + p0] = oy0; OFb[HW + p1] = oy1;

    int lane = t & 31, wid = t >> 5;
#pragma unroll
    for (int o = 0; o < 32; o++) {
        float v = a0[o] + a1[o];
        v += __shfl_xor_sync(0xffffffff, v, 16);
        v += __shfl_xor_sync(0xffffffff, v, 8);
        v += __shfl_xor_sync(0xffffffff, v, 4);
        v += __shfl_xor_sync(0xffffffff, v, 2);
        v += __shfl_xor_sync(0xffffffff, v, 1);
        if (lane == 0) partial[wid][o] = v;
    }
    __syncthreads();
    if (t < 32) {
        float s = 0.f;
#pragma unroll
        for (int w2 = 0; w2 < 8; w2++) s += partial[w2][t];
        atomicAdd(&g_FSUM[b * 32 + t], s);
    }
}

// ---------------- channel attention ca ----------------
__global__ void ca_kernel(const float* __restrict__ rca_w, const float* __restrict__ rca_b) {
    int c = threadIdx.x;
    int b = blockIdx.x;
    float s = __ldg(&rca_b[c]);
#pragma unroll
    for (int ci = 0; ci < 32; ci++)
        s = fmaf(__ldg(&rca_w[c * 32 + ci]), g_FSUM[b * 32 + ci] * (1.f / 65536.f), s);
    g_CA[b * CH + c] = 1.f / (1.f + expf(-s));
}

// ---------------- spatial attention sa: conv3x3 32->1 pad1 + sigmoid ----------------
__global__ void sa_kernel(const float* __restrict__ rsa_w, const float* __restrict__ rsa_b) {
    __shared__ float ws[288];
    int t = threadIdx.x;
    for (int i = t; i < 288; i += 256) ws[i] = rsa_w[i];
    __syncthreads();
    int b = blockIdx.y;
    int p = blockIdx.x * 256 + t;
    int y = p >> 8, x = p & 255;
    float acc = __ldg(&rsa_b[0]);
    const float* Fb = g_F + (size_t)b * 32 * HW;
    for (int ci = 0; ci < 32; ci++) {
        const float* fp = Fb + (size_t)ci * HW;
#pragma unroll
        for (int ky = 0; ky < 3; ky++) {
            int yy = y + ky - 1;
            if ((unsigned)yy >= 256u) continue;
#pragma unroll
            for (int kx = 0; kx < 3; kx++) {
                int xx = x + kx - 1;
                if ((unsigned)xx >= 256u) continue;
                acc = fmaf(ws[ci * 9 + ky * 3 + kx], __ldg(&fp[yy * 256 + xx]), acc);
            }
        }
    }
    g_SA[b * HW + p] = 1.f / (1.f + expf(-acc));
}

// ---------------- window MLP + gumbel hard mask ----------------
__global__ void mask_kernel(const float* __restrict__ gu,
                            const float* __restrict__ rm1_w, const float* __restrict__ rm1_b,
                            const float* __restrict__ rm2_w, const float* __restrict__ rm2_b) {
    __shared__ float m[256];
    __shared__ float h1s[16];
    int n = blockIdx.x, b = blockIdx.y;
    int t = threadIdx.x;
    int dh = t >> 4, dw = t & 15;
    int pix = ((n >> 4) * 16 + dh) * 256 + (n & 15) * 16 + dw;
    m[t] = g_FMC[b * HW + pix];
    __syncthreads();
    if (t < 16) {
        float s = __ldg(&rm1_b[t]);
        for (int e = 0; e < 256; e++) s = fmaf(__ldg(&rm1_w[t * 256 + e]), m[e], s);
        h1s[t] = leakyf(s);
    }
    __syncthreads();
    if (t == 0) {
        float z0 = __ldg(&rm2_b[0]), z1 = __ldg(&rm2_b[1]);
#pragma unroll
        for (int o = 0; o < 16; o++) {
            z0 = fmaf(__ldg(&rm2_w[o]), h1s[o], z0);
            z1 = fmaf(__ldg(&rm2_w[16 + o]), h1s[o], z1);
        }
        float mx = fmaxf(z0, z1);
        float e0 = expf(z0 - mx), e1 = expf(z1 - mx);
        float inv = 1.f / (e0 + e1);
        float p0 = e0 * inv, p1 = e1 * inv;
        float u0 = __ldg(&gu[(b * 256 + n) * 2 + 0]);
        float u1 = __ldg(&gu[(b * 256 + n) * 2 + 1]);
        float g0 = -logf(-logf(u0 + 1e-10f) + 1e-10f);
        float g1 = -logf(-logf(u1 + 1e-10f) + 1e-10f);
        g_MASK[b * 256 + n] = (p0 + g0 >= p1 + g1) ? 1.f : 0.f;
    }
}

// ---------------- bilinear flow warp (mask-skipped) ----------------
__global__ void warp_kernel(const float* __restrict__ x) {
    int b = blockIdx.y;
    int p = blockIdx.x * 256 + threadIdx.x;
    int yy = p >> 8, xx = p & 255;
    int wn = (yy >> 4) * 16 + (xx >> 4);
    if (g_MASK[b * 256 + wn] == 0.f) return;
    const float* OFb = g_OFF + (size_t)b * 2 * HW;
    float fx = OFb[p];
    float fy = OFb[HW + p];
    float sx = fminf(fmaxf((float)xx + fx, 0.f), 255.f);
    float sy = fminf(fmaxf((float)yy + fy, 0.f), 255.f);
    float x0f = floorf(sx), y0f = floorf(sy);
    float x1f = fminf(x0f + 1.f, 255.f), y1f = fminf(y0f + 1.f, 255.f);
    float wx = sx - x0f, wy = sy - y0f;
    int x0 = (int)x0f, x1 = (int)x1f, y0 = (int)y0f, y1 = (int)y1f;
    int iA = y0 * 256 + x0, iB = y0 * 256 + x1, iC = y1 * 256 + x0, iD = y1 * 256 + x1;
    float w00 = (1.f - wx) * (1.f - wy), w01 = wx * (1.f - wy);
    float w10 = (1.f - wx) * wy, w11 = wx * wy;
    const float* xb = x + (size_t)b * CH * HW;
    float* ob = g_XW + (size_t)b * CH * HW;
#pragma unroll 4
    for (int c = 0; c < 128; c++) {
        const float* xc = xb + (size_t)c * HW;
        ob[(size_t)c * HW + p] =
            __ldg(&xc[iA]) * w00 + __ldg(&xc[iB]) * w01 +
            __ldg(&xc[iC]) * w10 + __ldg(&xc[iD]) * w11;
    }
}

// ---------------- window attention (masked) / v*sa (unmasked) ----------------
#define SMEM_ATTN (33344 * 4)
__global__ void attn_kernel() {
    int n = blockIdx.x, b = blockIdx.y;
    int t = threadIdx.x;
    int py0 = (n >> 4) * 16, px0 = (n & 15) * 16;
    int cbase = b * CH * HW;
    float mval = g_MASK[b * 256 + n];
    if (mval == 0.f) {
        for (int i = t; i < 256 * 128; i += 256) {
            int r = i & 255, c = i >> 8;
            int pix = (py0 + (r >> 4)) * 256 + px0 + (r & 15);
            g_OUT[cbase + c * HW + pix] = g_V[cbase + c * HW + pix] * g_SA[b * HW + pix];
        }
        return;
    }
    extern __shared__ float smf[];
    float* Qs = smf;                // 64*129
    float* Ss = Qs + 64 * 129;      // 64*257
    float* KVs = Ss + 64 * 257;     // 64*129
    float* red = KVs + 64 * 129;    // 256
    float* rmax = red + 256;        // 64
    float* rsum = rmax + 64;        // 64

    int rr = t & 15;
    int cc = (t >> 4) * 4;
    int cc8 = (t >> 4) * 8;

    for (int rc = 0; rc < 4; rc++) {
        int r0 = rc * 64;
        __syncthreads();
#pragma unroll
        for (int j = 0; j < 32; j++) {
            int i = t + j * 256;
            int r = i & 63, c = i >> 6;
            int row = r0 + r;
            int pix = (py0 + (row >> 4)) * 256 + px0 + (row & 15);
            Qs[r * 129 + c] = g_Qb[cbase + c * HW + pix];
        }
        for (int kvt = 0; kvt < 4; kvt++) {
            __syncthreads();
#pragma unroll
            for (int j = 0; j < 32; j++) {
                int i = t + j * 256;
                int r = i & 63, c = i >> 6;
                int row = kvt * 64 + r;
                int pix = (py0 + (row >> 4)) * 256 + px0 + (row & 15);
                KVs[r * 129 + c] = g_Kb[cbase + c * HW + pix];
            }
            __syncthreads();
            float acc[4][4];
#pragma unroll
            for (int i = 0; i < 4; i++)
#pragma unroll
                for (int j = 0; j < 4; j++) acc[i][j] = 0.f;
#pragma unroll 4
            for (int kk = 0; kk < 128; kk++) {
                float a[4], bv[4];
#pragma unroll
                for (int i = 0; i < 4; i++) a[i] = Qs[(rr + 16 * i) * 129 + kk];
#pragma unroll
                for (int j = 0; j < 4; j++) bv[j] = KVs[(cc + j) * 129 + kk];
#pragma unroll
                for (int i = 0; i < 4; i++)
#pragma unroll
                    for (int j = 0; j < 4; j++) acc[i][j] = fmaf(a[i], bv[j], acc[i][j]);
            }
#pragma unroll
            for (int i = 0; i < 4; i++)
#pragma unroll
                for (int j = 0; j < 4; j++)
                    Ss[(rr + 16 * i) * 257 + kvt * 64 + cc + j] = acc[i][j];
        }
        __syncthreads();
        {
            int r = t & 63, seg = t >> 6;
            float* srow = &Ss[r * 257 + seg * 64];
            float mx = -1e30f;
#pragma unroll 8
            for (int k = 0; k < 64; k++) mx = fmaxf(mx, srow[k]);
            red[seg * 64 + r] = mx;
            __syncthreads();
            if (t < 64)
                rmax[t] = fmaxf(fmaxf(red[t], red[64 + t]), fmaxf(red[128 + t], red[192 + t]));
            __syncthreads();
            float rm_ = rmax[r];
            float s = 0.f;
#pragma unroll 8
            for (int k = 0; k < 64; k++) {
                float e = __expf(srow[k] - rm_);
                srow[k] = e;
                s += e;
            }
            red[seg * 64 + r] = s;
            __syncthreads();
            if (t < 64) rsum[t] = red[t] + red[64 + t] + red[128 + t] + red[192 + t];
            __syncthreads();
        }
        float acc2[4][8];
#pragma unroll
        for (int i = 0; i < 4; i++)
#pragma unroll
            for (int j = 0; j < 8; j++) acc2[i][j] = 0.f;
        for (int kvt = 0; kvt < 4; kvt++) {
            __syncthreads();
#pragma unroll
            for (int j = 0; j < 32; j++) {
                int i = t + j * 256;
                int r = i & 63, c = i >> 6;
                int row = kvt * 64 + r;
                int pix = (py0 + (row >> 4)) * 256 + px0 + (row & 15);
                KVs[r * 129 + c] = g_V[cbase + c * HW + pix];
            }
            __syncthreads();
#pragma unroll 2
            for (int kk = 0; kk < 64; kk++) {
                float sreg[4], vreg[8];
#pragma unroll
                for (int i = 0; i < 4; i++) sreg[i] = Ss[(rr + 16 * i) * 257 + kvt * 64 + kk];
#pragma unroll
                for (int j = 0; j < 8; j++) vreg[j] = KVs[kk * 129 + cc8 + j];
#pragma unroll
                for (int i = 0; i < 4; i++)
#pragma unroll
                    for (int j = 0; j < 8; j++) acc2[i][j] = fmaf(sreg[i], vreg[j], acc2[i][j]);
            }
        }
#pragma unroll
        for (int i = 0; i < 4; i++) {
            int row = r0 + rr + 16 * i;
            int pix = (py0 + (row >> 4)) * 256 + px0 + (row & 15);
            float inv = 1.f / rsum[rr + 16 * i];
#pragma unroll
            for (int j = 0; j < 8; j++)
                g_OUT[cbase + (cc8 + j) * HW + pix] = acc2[i][j] * inv;
        }
    }
}

// ---------------- depthwise 5x5 (dilation param) ----------------
__global__ void dw5_kernel(const float* __restrict__ in, const float* __restrict__ w,
                           const float* __restrict__ bias, float* __restrict__ out, int dil) {
    __shared__ float ws[25];
    int c = blockIdx.z & 127, b = blockIdx.z >> 7;
    int t = threadIdx.y * 32 + threadIdx.x;
    if (t < 25) ws[t] = w[c * 25 + t];
    __syncthreads();
    int x = blockIdx.x * 32 + threadIdx.x;
    int y = blockIdx.y * 8 + threadIdx.y;
    const float* ip = in + (size_t)(b * CH + c) * HW;
    float acc = __ldg(&bias[c]);
#pragma unroll
    for (int ky = 0; ky < 5; ky++) {
        int yy = y + (ky - 2) * dil;
        if ((unsigned)yy >= 256u) continue;
#pragma unroll
        for (int kx = 0; kx < 5; kx++) {
            int xx = x + (kx - 2) * dil;
            if ((unsigned)xx >= 256u) continue;
            acc = fmaf(ws[ky * 5 + kx], __ldg(&ip[yy * 256 + xx]), acc);
        }
    }
    out[(size_t)(b * CH + c) * HW + y * 256 + x] = acc;
}

// ---------------- gelu(cs)*ca + out -> T1 ----------------
__global__ void gelu_ca_add_kernel() {
    int i = blockIdx.x * 256 + threadIdx.x;
    int chw = i >> 16;
    int c = chw & 127, b = chw >> 7;
    float xv = g_T3[i];
    float g = 0.5f * xv * (1.f + erff(xv * 0.7071067811865475f));
    g_T1[i] = g * g_CA[b * CH + c] + g_OUT[i];
}

// ---------------- launch ----------------
extern "C" void kernel_launch(void* const* d_in, const int* in_sizes, int n_in,
                              void* d_out, int out_size) {
    const float* x      = (const float*)d_in[0];
    const float* cond_g = (const float*)d_in[1];
    const float* gu     = (const float*)d_in[2];
    const float* pv_w   = (const float*)d_in[3];
    const float* pv_b   = (const float*)d_in[4];
    const float* pq_w   = (const float*)d_in[5];
    const float* pq_b   = (const float*)d_in[6];
    const float* pk_w   = (const float*)d_in[7];
    const float* pk_b   = (const float*)d_in[8];
    const float* cs1_w  = (const float*)d_in[9];
    const float* cs1_b  = (const float*)d_in[10];
    const float* cs2_w  = (const float*)d_in[11];
    const float* cs2_b  = (const float*)d_in[12];
    const float* cs3_w  = (const float*)d_in[13];
    const float* cs3_b  = (const float*)d_in[14];
    const float* po_w   = (const float*)d_in[15];
    const float* po_b   = (const float*)d_in[16];
    const float* rin_w  = (const float*)d_in[17];
    const float* rin_b  = (const float*)d_in[18];
    const float* r1w    = (const float*)d_in[19];
    const float* r1b    = (const float*)d_in[20];
    const float* r2w    = (const float*)d_in[21];
    const float* r2b    = (const float*)d_in[22];
    const float* rm1_w  = (const float*)d_in[23];
    const float* rm1_b  = (const float*)d_in[24];
    const float* rm2_w  = (const float*)d_in[25];
    const float* rm2_b  = (const float*)d_in[26];
    const float* rca_w  = (const float*)d_in[27];
    const float* rca_b  = (const float*)d_in[28];
    const float* rsa_w  = (const float*)d_in[29];
    const float* rsa_b  = (const float*)d_in[30];

    float *pV, *pXW, *pQ, *pK, *pOUT, *pT1, *pT2, *pT3;
    __nv_bfloat16* pWT;
    cudaGetSymbolAddress((void**)&pV, g_V);
    cudaGetSymbolAddress((void**)&pXW, g_XW);
    cudaGetSymbolAddress((void**)&pQ, g_Qb);
    cudaGetSymbolAddress((void**)&pK, g_Kb);
    cudaGetSymbolAddress((void**)&pOUT, g_OUT);
    cudaGetSymbolAddress((void**)&pT1, g_T1);
    cudaGetSymbolAddress((void**)&pT2, g_T2);
    cudaGetSymbolAddress((void**)&pT3, g_T3);
    cudaGetSymbolAddress((void**)&pWT, g_WT);

    cudaFuncSetAttribute(attn_kernel, cudaFuncAttributeMaxDynamicSharedMemorySize, SMEM_ATTN);
    cudaFuncSetAttribute(conv1x1_mma, cudaFuncAttributeMaxDynamicSharedMemorySize, CV_SMEM);

    const int WSET = 2 * 128 * 136;   // elements per weight set

    zero_fsum_kernel<<<1, 128>>>();
    prep_w_kernel<<<64, 256>>>(pv_w, 0);
    prep_w_kernel<<<64, 256>>>(pq_w, 1);
    prep_w_kernel<<<64, 256>>>(pk_w, 2);
    prep_w_kernel<<<64, 256>>>(cs1_w, 3);
    prep_w_kernel<<<64, 256>>>(po_w, 4);

    dim3 ghw(512, BB);
    // v = pv(x)
    conv1x1_mma<<<ghw, 256, CV_SMEM>>>(x, pWT + 0 * WSET, pv_b, pV, 0);
    // f, offsets, fmean_c, fsum
    predictor_kernel<<<dim3(HW / 512, BB), 256>>>(cond_g, rin_w, rin_b, r1w, r1b, r2w, r2b);
    ca_kernel<<<BB, 128>>>(rca_w, rca_b);
    sa_kernel<<<dim3(HW / 256, BB), 256>>>(rsa_w, rsa_b);
    mask_kernel<<<dim3(256, BB), 256>>>(gu, rm1_w, rm1_b, rm2_w, rm2_b);
    // flow warp (masked windows only)
    warp_kernel<<<dim3(HW / 256, BB), 256>>>(x);
    // q / k projections (masked windows only)
    conv1x1_mma<<<ghw, 256, CV_SMEM>>>(pXW, pWT + 1 * WSET, pq_b, pQ, 1);
    conv1x1_mma<<<ghw, 256, CV_SMEM>>>(pXW, pWT + 2 * WSET, pk_b, pK, 1);
    // window attention / sparse bypass
    attn_kernel<<<dim3(256, BB), 256, SMEM_ATTN>>>();
    // conv spatial chain
    conv1x1_mma<<<ghw, 256, CV_SMEM>>>(pOUT, pWT + 3 * WSET, cs1_b, pT1, 0);
    dw5_kernel<<<dim3(8, 32, BB * CH), dim3(32, 8)>>>(pT1, cs2_w, cs2_b, pT2, 1);
    dw5_kernel<<<dim3(8, 32, BB * CH), dim3(32, 8)>>>(pT2, cs3_w, cs3_b, pT3, 3);
    gelu_ca_add_kernel<<<ELT / 256, 256>>>();
    // final projection -> d_out
    conv1x1_mma<<<ghw, 256, CV_SMEM>>>(pT1, pWT + 4 * WSET, po_b, (float*)d_out, 0);
}

// round 5
// speedup vs baseline: 1.6035x; 1.2102x over previous
#include <cuda_runtime.h>
#include <cuda_bf16.h>
#include <stdint.h>
#include <math.h>

#define HW 65536
#define WIMG 256
#define CH 128
#define BB 4
#define ELT (BB*CH*HW)

// ---------------- scratch (static device globals; no runtime alloc) ----------------
__device__ float g_V[ELT];
__device__ float g_XW[ELT];
__device__ float g_Qb[ELT];
__device__ float g_Kb[ELT];
__device__ float g_OUT[ELT];
__device__ float g_T1[ELT];
__device__ float g_T2[ELT];
__device__ float g_F[BB*32*HW];
__device__ float g_OFF[BB*2*HW];
__device__ float g_FMC[BB*HW];
__device__ float g_SA[BB*HW];
__device__ float g_FSUM[BB*32];
__device__ float g_CA[BB*CH];
__device__ float g_MASK[BB*256];
// hi/lo bf16 weights, row-padded to 136 (stride-68-word smem => conflict-free frags)
__device__ __align__(16) __nv_bfloat16 g_WT[5][2][128*136];

__device__ __forceinline__ float leakyf(float x) { return x > 0.f ? x : 0.2f * x; }

// ---------------- zero FSUM ----------------
__global__ void zero_fsum_kernel() {
    g_FSUM[threadIdx.x] = 0.f;
}

// ---------------- weight prep: fp32 -> bf16 hi/lo, padded rows ----------------
__global__ void prep_w_kernel(const float* __restrict__ w, int set) {
    int i = blockIdx.x * 256 + threadIdx.x;
    int oc = i >> 7, ci = i & 127;
    float v = w[i];
    __nv_bfloat16 h = __float2bfloat16_rn(v);
    __nv_bfloat16 l = __float2bfloat16_rn(v - __bfloat162float(h));
    g_WT[set][0][oc * 136 + ci] = h;
    g_WT[set][1][oc * 136 + ci] = l;
}

// ---------------- HMMA m16n8k16 bf16 ----------------
#define MMA_BF16(d, a, b) \
    asm volatile("mma.sync.aligned.m16n8k16.row.col.f32.bf16.bf16.f32 " \
        "{%0,%1,%2,%3}, {%4,%5,%6,%7}, {%8,%9}, {%0,%1,%2,%3};" \
        : "+f"((d)[0]), "+f"((d)[1]), "+f"((d)[2]), "+f"((d)[3]) \
        : "r"((a)[0]), "r"((a)[1]), "r"((a)[2]), "r"((a)[3]), "r"((b)[0]), "r"((b)[1]))

#define CV_SMEM (4 * 128 * 136 * 2)

// ---------------- conv1x1 GEMM via mma.sync (unchanged from R4, proven) ----------------
__global__ void __launch_bounds__(256, 1)
conv1x1_mma(const float* __restrict__ xin, const __nv_bfloat16* __restrict__ wsp,
            const float* __restrict__ bias, float* __restrict__ yout, int useMask) {
    int hw = blockIdx.x, b = blockIdx.y;
    int n = hw >> 1, half = hw & 1;
    if (useMask && g_MASK[b * 256 + n] == 0.f) return;
    extern __shared__ __nv_bfloat16 smb[];
    __nv_bfloat16* Wh = smb;
    __nv_bfloat16* Wl = Wh + 128 * 136;
    __nv_bfloat16* Xh = Wl + 128 * 136;
    __nv_bfloat16* Xl = Xh + 128 * 136;
    int t = threadIdx.x;

    {
        const uint4* src = (const uint4*)wsp;
        uint4* dst = (uint4*)smb;
#pragma unroll
        for (int i = 0; i < 17; i++) dst[t + i * 256] = src[t + i * 256];
    }

    int py0 = (n >> 4) * 16, px0 = (n & 15) * 16;
    const float* xb = xin + (size_t)b * CH * HW;
#pragma unroll
    for (int j = 0; j < 32; j++) {
        int i = t + j * 256;
        int px = i & 127;
        int cp = i >> 7;
        int p = half * 128 + px;
        int pix = (py0 + (p >> 4)) * 256 + px0 + (p & 15);
        float v0 = xb[(size_t)(2 * cp) * HW + pix];
        float v1 = xb[(size_t)(2 * cp + 1) * HW + pix];
        __nv_bfloat16 h0 = __float2bfloat16_rn(v0);
        __nv_bfloat16 h1 = __float2bfloat16_rn(v1);
        __nv_bfloat16 l0 = __float2bfloat16_rn(v0 - __bfloat162float(h0));
        __nv_bfloat16 l1 = __float2bfloat16_rn(v1 - __bfloat162float(h1));
        ((__nv_bfloat162*)(Xh + px * 136))[cp] = __nv_bfloat162(h0, h1);
        ((__nv_bfloat162*)(Xl + px * 136))[cp] = __nv_bfloat162(l0, l1);
    }
    __syncthreads();

    int w = t >> 5, lane = t & 31;
    int oc0 = (w & 3) * 32;
    int n0 = (w >> 2) * 64;
    int gid = lane >> 2, tig = lane & 3;

    float acc[16][4];
#pragma unroll
    for (int i = 0; i < 16; i++)
#pragma unroll
        for (int j = 0; j < 4; j++) acc[i][j] = 0.f;

    const uint32_t* WhW = (const uint32_t*)Wh;
    const uint32_t* WlW = (const uint32_t*)Wl;
    const uint32_t* XhW = (const uint32_t*)Xh;
    const uint32_t* XlW = (const uint32_t*)Xl;

#pragma unroll 1
    for (int ks = 0; ks < 8; ks++) {
        int kw = ks * 8;
        uint32_t Ah[2][4], Al[2][4], Bh[8][2], Bl[8][2];
#pragma unroll
        for (int mt = 0; mt < 2; mt++) {
            int r0 = (oc0 + mt * 16 + gid) * 68 + kw + tig;
            int r8 = r0 + 8 * 68;
            Ah[mt][0] = WhW[r0];     Ah[mt][1] = WhW[r8];
            Ah[mt][2] = WhW[r0 + 4]; Ah[mt][3] = WhW[r8 + 4];
            Al[mt][0] = WlW[r0];     Al[mt][1] = WlW[r8];
            Al[mt][2] = WlW[r0 + 4]; Al[mt][3] = WlW[r8 + 4];
        }
#pragma unroll
        for (int nt = 0; nt < 8; nt++) {
            int rr = (n0 + nt * 8 + gid) * 68 + kw + tig;
            Bh[nt][0] = XhW[rr]; Bh[nt][1] = XhW[rr + 4];
            Bl[nt][0] = XlW[rr]; Bl[nt][1] = XlW[rr + 4];
        }
#pragma unroll
        for (int mt = 0; mt < 2; mt++)
#pragma unroll
            for (int nt = 0; nt < 8; nt++) {
                MMA_BF16(acc[mt * 8 + nt], Ah[mt], Bh[nt]);
                MMA_BF16(acc[mt * 8 + nt], Ah[mt], Bl[nt]);
                MMA_BF16(acc[mt * 8 + nt], Al[mt], Bh[nt]);
            }
    }

    float* yb = yout + (size_t)b * CH * HW;
#pragma unroll
    for (int mt = 0; mt < 2; mt++) {
        int ocA = oc0 + mt * 16 + gid;
        int ocB = ocA + 8;
        float bvA = __ldg(&bias[ocA]);
        float bvB = __ldg(&bias[ocB]);
#pragma unroll
        for (int nt = 0; nt < 8; nt++) {
            int col = n0 + nt * 8 + tig * 2;
            int p = half * 128 + col;
            int pix = (py0 + (p >> 4)) * 256 + px0 + (p & 15);
            float2 v0 = make_float2(acc[mt * 8 + nt][0] + bvA, acc[mt * 8 + nt][1] + bvA);
            float2 v1 = make_float2(acc[mt * 8 + nt][2] + bvB, acc[mt * 8 + nt][3] + bvB);
            *(float2*)(yb + (size_t)ocA * HW + pix) = v0;
            *(float2*)(yb + (size_t)ocB * HW + pix) = v1;
        }
    }
}

// ---------------- predictor ----------------
__global__ void predictor_kernel(const float* __restrict__ cond_g,
                                 const float* __restrict__ rin_w, const float* __restrict__ rin_b,
                                 const float* __restrict__ r1w, const float* __restrict__ r1b,
                                 const float* __restrict__ r2w, const float* __restrict__ r2b) {
    __shared__ float wr[32 * 131];
    __shared__ float wr1[16 * 32];
    __shared__ float wr2[32];
    __shared__ float partial[8][32];
    int t = threadIdx.x;
    int b = blockIdx.y;
    for (int i = t; i < 32 * 131; i += 256) wr[i] = rin_w[i];
    for (int i = t; i < 16 * 32; i += 256) wr1[i] = r1w[i];
    if (t < 32) wr2[t] = r2w[t];
    __syncthreads();

    int p0 = blockIdx.x * 512 + t;
    int p1 = p0 + 256;
    float a0[32], a1[32];
#pragma unroll
    for (int o = 0; o < 32; o++) {
        float bv = __ldg(&rin_b[o]);
        a0[o] = bv; a1[o] = bv;
    }
    const float* vb = g_V + (size_t)b * CH * HW;
#pragma unroll 2
    for (int ci = 0; ci < 128; ci++) {
        float x0 = vb[(size_t)ci * HW + p0];
        float x1 = vb[(size_t)ci * HW + p1];
#pragma unroll
        for (int o = 0; o < 32; o++) {
            float wv = wr[o * 131 + ci];
            a0[o] = fmaf(wv, x0, a0[o]);
            a1[o] = fmaf(wv, x1, a1[o]);
        }
    }
    float cg0 = __ldg(&cond_g[b * HW + p0]);
    float cg1 = __ldg(&cond_g[b * HW + p1]);
    int y0 = p0 >> 8, x0p = p0 & 255;
    int y1 = p1 >> 8, x1p = p1 & 255;
    float ly0 = -1.f + (float)(y0 & 15) * (2.f / 15.f);
    float lx0 = -1.f + (float)(x0p & 15) * (2.f / 15.f);
    float ly1 = -1.f + (float)(y1 & 15) * (2.f / 15.f);
    float lx1 = -1.f + (float)(x1p & 15) * (2.f / 15.f);
    float fm0 = 0.f, fm1 = 0.f;
    float* Fb = g_F + (size_t)b * 32 * HW;
#pragma unroll
    for (int o = 0; o < 32; o++) {
        float v0 = a0[o] + wr[o * 131 + 128] * cg0 + wr[o * 131 + 129] * ly0 + wr[o * 131 + 130] * lx0;
        float v1 = a1[o] + wr[o * 131 + 128] * cg1 + wr[o * 131 + 129] * ly1 + wr[o * 131 + 130] * lx1;
        v0 = leakyf(v0); v1 = leakyf(v1);
        a0[o] = v0; a1[o] = v1;
        Fb[(size_t)o * HW + p0] = v0;
        Fb[(size_t)o * HW + p1] = v1;
        fm0 += v0; fm1 += v1;
    }
    g_FMC[b * HW + p0] = fm0 * (1.f / 32.f);
    g_FMC[b * HW + p1] = fm1 * (1.f / 32.f);

    float h0[16], h1v[16];
#pragma unroll
    for (int o2 = 0; o2 < 16; o2++) {
        float bv = __ldg(&r1b[o2]);
        float s0 = bv, s1 = bv;
#pragma unroll
        for (int o = 0; o < 32; o++) {
            float wv = wr1[o2 * 32 + o];
            s0 = fmaf(wv, a0[o], s0);
            s1 = fmaf(wv, a1[o], s1);
        }
        h0[o2] = leakyf(s0);
        h1v[o2] = leakyf(s1);
    }
    float ox0 = __ldg(&r2b[0]), oy0 = __ldg(&r2b[1]);
    float ox1 = ox0, oy1 = oy0;
#pragma unroll
    for (int o2 = 0; o2 < 16; o2++) {
        ox0 = fmaf(wr2[o2], h0[o2], ox0);
        oy0 = fmaf(wr2[16 + o2], h0[o2], oy0);
        ox1 = fmaf(wr2[o2], h1v[o2], ox1);
        oy1 = fmaf(wr2[16 + o2], h1v[o2], oy1);
    }
    float* OFb = g_OFF + (size_t)b * 2 * HW;
    OFb[p0] = ox0; OFb[p1] = ox1;
    OFb[HW + p0] = oy0; OFb[HW + p1] = oy1;

    int lane = t & 31, wid = t >> 5;
#pragma unroll
    for (int o = 0; o < 32; o++) {
        float v = a0[o] + a1[o];
        v += __shfl_xor_sync(0xffffffff, v, 16);
        v += __shfl_xor_sync(0xffffffff, v, 8);
        v += __shfl_xor_sync(0xffffffff, v, 4);
        v += __shfl_xor_sync(0xffffffff, v, 2);
        v += __shfl_xor_sync(0xffffffff, v, 1);
        if (lane == 0) partial[wid][o] = v;
    }
    __syncthreads();
    if (t < 32) {
        float s = 0.f;
#pragma unroll
        for (int w2 = 0; w2 < 8; w2++) s += partial[w2][t];
        atomicAdd(&g_FSUM[b * 32 + t], s);
    }
}

// ---------------- channel attention ca ----------------
__global__ void ca_kernel(const float* __restrict__ rca_w, const float* __restrict__ rca_b) {
    int c = threadIdx.x;
    int b = blockIdx.x;
    float s = __ldg(&rca_b[c]);
#pragma unroll
    for (int ci = 0; ci < 32; ci++)
        s = fmaf(__ldg(&rca_w[c * 32 + ci]), g_FSUM[b * 32 + ci] * (1.f / 65536.f), s);
    g_CA[b * CH + c] = 1.f / (1.f + expf(-s));
}

// ---------------- spatial attention sa ----------------
__global__ void sa_kernel(const float* __restrict__ rsa_w, const float* __restrict__ rsa_b) {
    __shared__ float ws[288];
    int t = threadIdx.x;
    for (int i = t; i < 288; i += 256) ws[i] = rsa_w[i];
    __syncthreads();
    int b = blockIdx.y;
    int p = blockIdx.x * 256 + t;
    int y = p >> 8, x = p & 255;
    float acc = __ldg(&rsa_b[0]);
    const float* Fb = g_F + (size_t)b * 32 * HW;
    for (int ci = 0; ci < 32; ci++) {
        const float* fp = Fb + (size_t)ci * HW;
#pragma unroll
        for (int ky = 0; ky < 3; ky++) {
            int yy = y + ky - 1;
            if ((unsigned)yy >= 256u) continue;
#pragma unroll
            for (int kx = 0; kx < 3; kx++) {
                int xx = x + kx - 1;
                if ((unsigned)xx >= 256u) continue;
                acc = fmaf(ws[ci * 9 + ky * 3 + kx], __ldg(&fp[yy * 256 + xx]), acc);
            }
        }
    }
    g_SA[b * HW + p] = 1.f / (1.f + expf(-acc));
}

// ---------------- window MLP + gumbel hard mask ----------------
__global__ void mask_kernel(const float* __restrict__ gu,
                            const float* __restrict__ rm1_w, const float* __restrict__ rm1_b,
                            const float* __restrict__ rm2_w, const float* __restrict__ rm2_b) {
    __shared__ float m[256];
    __shared__ float h1s[16];
    int n = blockIdx.x, b = blockIdx.y;
    int t = threadIdx.x;
    int dh = t >> 4, dw = t & 15;
    int pix = ((n >> 4) * 16 + dh) * 256 + (n & 15) * 16 + dw;
    m[t] = g_FMC[b * HW + pix];
    __syncthreads();
    if (t < 16) {
        float s = __ldg(&rm1_b[t]);
        for (int e = 0; e < 256; e++) s = fmaf(__ldg(&rm1_w[t * 256 + e]), m[e], s);
        h1s[t] = leakyf(s);
    }
    __syncthreads();
    if (t == 0) {
        float z0 = __ldg(&rm2_b[0]), z1 = __ldg(&rm2_b[1]);
#pragma unroll
        for (int o = 0; o < 16; o++) {
            z0 = fmaf(__ldg(&rm2_w[o]), h1s[o], z0);
            z1 = fmaf(__ldg(&rm2_w[16 + o]), h1s[o], z1);
        }
        float mx = fmaxf(z0, z1);
        float e0 = expf(z0 - mx), e1 = expf(z1 - mx);
        float inv = 1.f / (e0 + e1);
        float p0 = e0 * inv, p1 = e1 * inv;
        float u0 = __ldg(&gu[(b * 256 + n) * 2 + 0]);
        float u1 = __ldg(&gu[(b * 256 + n) * 2 + 1]);
        float g0 = -logf(-logf(u0 + 1e-10f) + 1e-10f);
        float g1 = -logf(-logf(u1 + 1e-10f) + 1e-10f);
        g_MASK[b * 256 + n] = (p0 + g0 >= p1 + g1) ? 1.f : 0.f;
    }
}

// ---------------- bilinear flow warp (mask-skipped) ----------------
__global__ void warp_kernel(const float* __restrict__ x) {
    int b = blockIdx.y;
    int p = blockIdx.x * 256 + threadIdx.x;
    int yy = p >> 8, xx = p & 255;
    int wn = (yy >> 4) * 16 + (xx >> 4);
    if (g_MASK[b * 256 + wn] == 0.f) return;
    const float* OFb = g_OFF + (size_t)b * 2 * HW;
    float fx = OFb[p];
    float fy = OFb[HW + p];
    float sx = fminf(fmaxf((float)xx + fx, 0.f), 255.f);
    float sy = fminf(fmaxf((float)yy + fy, 0.f), 255.f);
    float x0f = floorf(sx), y0f = floorf(sy);
    float x1f = fminf(x0f + 1.f, 255.f), y1f = fminf(y0f + 1.f, 255.f);
    float wx = sx - x0f, wy = sy - y0f;
    int x0 = (int)x0f, x1 = (int)x1f, y0 = (int)y0f, y1 = (int)y1f;
    int iA = y0 * 256 + x0, iB = y0 * 256 + x1, iC = y1 * 256 + x0, iD = y1 * 256 + x1;
    float w00 = (1.f - wx) * (1.f - wy), w01 = wx * (1.f - wy);
    float w10 = (1.f - wx) * wy, w11 = wx * wy;
    const float* xb = x + (size_t)b * CH * HW;
    float* ob = g_XW + (size_t)b * CH * HW;
#pragma unroll 4
    for (int c = 0; c < 128; c++) {
        const float* xc = xb + (size_t)c * HW;
        ob[(size_t)c * HW + p] =
            __ldg(&xc[iA]) * w00 + __ldg(&xc[iB]) * w01 +
            __ldg(&xc[iC]) * w10 + __ldg(&xc[iD]) * w11;
    }
}

// ---------------- window attention via mma.sync (masked) / v*sa (unmasked) ----------------
// smem: S fp32 [64][257] + red/rmax/rsum, then bf16: Qh/Ql [64*136], KVh/KVl [9216], Pth/Ptl [64*72]
#define SMEM_ATTN2 (67328 + 90112)
__global__ void __launch_bounds__(256, 1) attn_mma_kernel() {
    int n = blockIdx.x, b = blockIdx.y;
    int t = threadIdx.x;
    int py0 = (n >> 4) * 16, px0 = (n & 15) * 16;
    int cbase = b * CH * HW;
    if (g_MASK[b * 256 + n] == 0.f) {
        for (int i = t; i < 256 * 128; i += 256) {
            int r = i & 255, c = i >> 8;
            int pix = (py0 + (r >> 4)) * 256 + px0 + (r & 15);
            g_OUT[cbase + c * HW + pix] = g_V[cbase + c * HW + pix] * g_SA[b * HW + pix];
        }
        return;
    }
    extern __shared__ char smraw[];
    float* S = (float*)smraw;                      // 64*257
    float* red = S + 64 * 257;                     // 256
    float* rmax = red + 256;                       // 64
    float* rsum = rmax + 64;                       // 64
    __nv_bfloat16* Qh = (__nv_bfloat16*)(rsum + 64);
    __nv_bfloat16* Ql = Qh + 64 * 136;
    __nv_bfloat16* KVh = Ql + 64 * 136;            // 9216 (used as [64][136] for K, [128][72] for V)
    __nv_bfloat16* KVl = KVh + 9216;
    __nv_bfloat16* Pth = KVl + 9216;               // 64*72
    __nv_bfloat16* Ptl = Pth + 64 * 72;

    const uint32_t* QhW = (const uint32_t*)Qh;
    const uint32_t* QlW = (const uint32_t*)Ql;
    const uint32_t* KVhW = (const uint32_t*)KVh;
    const uint32_t* KVlW = (const uint32_t*)KVl;
    const uint32_t* PthW = (const uint32_t*)Pth;
    const uint32_t* PtlW = (const uint32_t*)Ptl;

    int w = t >> 5, lane = t & 31;
    int gid = lane >> 4 ? 0 : 0;  // placeholder (avoid unused warn)
    gid = lane >> 2;
    int tig = lane & 3;

#pragma unroll 1
    for (int rc = 0; rc < 4; rc++) {
        int r0 = rc * 64;
        __syncthreads();
        // ---- stage Q chunk transposed hi/lo: Q[qrow][ch] ----
#pragma unroll
        for (int j = 0; j < 16; j++) {
            int i = t + j * 256;
            int px = i & 63, cp = i >> 6;
            int p = r0 + px;
            int pix = (py0 + (p >> 4)) * 256 + px0 + (p & 15);
            float v0 = g_Qb[cbase + (2 * cp) * HW + pix];
            float v1 = g_Qb[cbase + (2 * cp + 1) * HW + pix];
            __nv_bfloat16 h0 = __float2bfloat16_rn(v0);
            __nv_bfloat16 h1 = __float2bfloat16_rn(v1);
            __nv_bfloat16 l0 = __float2bfloat16_rn(v0 - __bfloat162float(h0));
            __nv_bfloat16 l1 = __float2bfloat16_rn(v1 - __bfloat162float(h1));
            ((__nv_bfloat162*)(Qh + px * 136))[cp] = __nv_bfloat162(h0, h1);
            ((__nv_bfloat162*)(Ql + px * 136))[cp] = __nv_bfloat162(l0, l1);
        }

        // ---- S = Q K^T, per 64-col KV tile ----
        int mrowS = (w & 3) * 16, ncolS = (w >> 2) * 32;
#pragma unroll 1
        for (int kvt = 0; kvt < 4; kvt++) {
            __syncthreads();
#pragma unroll
            for (int j = 0; j < 16; j++) {
                int i = t + j * 256;
                int px = i & 63, cp = i >> 6;
                int p = kvt * 64 + px;
                int pix = (py0 + (p >> 4)) * 256 + px0 + (p & 15);
                float v0 = g_Kb[cbase + (2 * cp) * HW + pix];
                float v1 = g_Kb[cbase + (2 * cp + 1) * HW + pix];
                __nv_bfloat16 h0 = __float2bfloat16_rn(v0);
                __nv_bfloat16 h1 = __float2bfloat16_rn(v1);
                __nv_bfloat16 l0 = __float2bfloat16_rn(v0 - __bfloat162float(h0));
                __nv_bfloat16 l1 = __float2bfloat16_rn(v1 - __bfloat162float(h1));
                ((__nv_bfloat162*)(KVh + px * 136))[cp] = __nv_bfloat162(h0, h1);
                ((__nv_bfloat162*)(KVl + px * 136))[cp] = __nv_bfloat162(l0, l1);
            }
            __syncthreads();
            float acc[4][4];
#pragma unroll
            for (int i = 0; i < 4; i++)
#pragma unroll
                for (int j2 = 0; j2 < 4; j2++) acc[i][j2] = 0.f;
#pragma unroll
            for (int ks = 0; ks < 8; ks++) {
                int kw = ks * 8;
                uint32_t Ahf[4], Alf[4], Bhf[4][2], Blf[4][2];
                int ra = (mrowS + gid) * 68 + kw + tig;
                int ra8 = ra + 8 * 68;
                Ahf[0] = QhW[ra];     Ahf[1] = QhW[ra8];
                Ahf[2] = QhW[ra + 4]; Ahf[3] = QhW[ra8 + 4];
                Alf[0] = QlW[ra];     Alf[1] = QlW[ra8];
                Alf[2] = QlW[ra + 4]; Alf[3] = QlW[ra8 + 4];
#pragma unroll
                for (int nt = 0; nt < 4; nt++) {
                    int rr = (ncolS + nt * 8 + gid) * 68 + kw + tig;
                    Bhf[nt][0] = KVhW[rr]; Bhf[nt][1] = KVhW[rr + 4];
                    Blf[nt][0] = KVlW[rr]; Blf[nt][1] = KVlW[rr + 4];
                }
#pragma unroll
                for (int nt = 0; nt < 4; nt++) {
                    MMA_BF16(acc[nt], Ahf, Bhf[nt]);
                    MMA_BF16(acc[nt], Ahf, Blf[nt]);
                    MMA_BF16(acc[nt], Alf, Bhf[nt]);
                }
            }
#pragma unroll
            for (int nt = 0; nt < 4; nt++) {
                int col = kvt * 64 + ncolS + nt * 8 + tig * 2;
                S[(mrowS + gid) * 257 + col] = acc[nt][0];
                S[(mrowS + gid) * 257 + col + 1] = acc[nt][1];
                S[(mrowS + gid + 8) * 257 + col] = acc[nt][2];
                S[(mrowS + gid + 8) * 257 + col + 1] = acc[nt][3];
            }
        }
        __syncthreads();

        // ---- softmax over 256 cols (4 segments of 64) ----
        {
            int r = t & 63, seg = t >> 6;
            float* srow = &S[r * 257 + seg * 64];
            float mx = -1e30f;
#pragma unroll 8
            for (int k = 0; k < 64; k++) mx = fmaxf(mx, srow[k]);
            red[seg * 64 + r] = mx;
            __syncthreads();
            if (t < 64)
                rmax[t] = fmaxf(fmaxf(red[t], red[64 + t]), fmaxf(red[128 + t], red[192 + t]));
            __syncthreads();
            float rm_ = rmax[r];
            float s = 0.f;
#pragma unroll 8
            for (int k = 0; k < 64; k++) {
                float e = __expf(srow[k] - rm_);
                srow[k] = e;
                s += e;
            }
            red[seg * 64 + r] = s;
            __syncthreads();
            if (t < 64) rsum[t] = red[t] + red[64 + t] + red[128 + t] + red[192 + t];
            __syncthreads();
        }

        // ---- O = P V via mma (P unnormalized exp; normalize at store) ----
        int mrowO = (w & 3) * 16, ncolO = (w >> 2) * 64;
        float oacc[8][4];
#pragma unroll
        for (int i = 0; i < 8; i++)
#pragma unroll
            for (int j2 = 0; j2 < 4; j2++) oacc[i][j2] = 0.f;

#pragma unroll 1
        for (int kvt = 0; kvt < 4; kvt++) {
            __syncthreads();
            // convert P tile [64 rows][64 cols] -> bf16 hi/lo, stride 72
#pragma unroll
            for (int j = 0; j < 16; j++) {
                int i = t + j * 256;
                int col = i & 63, row = i >> 6;
                float v = S[row * 257 + kvt * 64 + col];
                __nv_bfloat16 h = __float2bfloat16_rn(v);
                Pth[row * 72 + col] = h;
                Ptl[row * 72 + col] = __float2bfloat16_rn(v - __bfloat162float(h));
            }
            // stage V tile transposed-natural: Vt[ch][px], stride 72
#pragma unroll
            for (int j = 0; j < 32; j++) {
                int i = t + j * 256;
                int px = i & 63, ch = i >> 6;
                int p = kvt * 64 + px;
                int pix = (py0 + (p >> 4)) * 256 + px0 + (p & 15);
                float v = g_V[cbase + ch * HW + pix];
                __nv_bfloat16 h = __float2bfloat16_rn(v);
                KVh[ch * 72 + px] = h;
                KVl[ch * 72 + px] = __float2bfloat16_rn(v - __bfloat162float(h));
            }
            __syncthreads();
#pragma unroll
            for (int ks = 0; ks < 4; ks++) {
                int kw = ks * 8;
                uint32_t Ahf[4], Alf[4], Bhf[8][2], Blf[8][2];
                int ra = (mrowO + gid) * 36 + kw + tig;
                int ra8 = ra + 8 * 36;
                Ahf[0] = PthW[ra];     Ahf[1] = PthW[ra8];
                Ahf[2] = PthW[ra + 4]; Ahf[3] = PthW[ra8 + 4];
                Alf[0] = PtlW[ra];     Alf[1] = PtlW[ra8];
                Alf[2] = PtlW[ra + 4]; Alf[3] = PtlW[ra8 + 4];
#pragma unroll
                for (int nt = 0; nt < 8; nt++) {
                    int rr = (ncolO + nt * 8 + gid) * 36 + kw + tig;
                    Bhf[nt][0] = KVhW[rr]; Bhf[nt][1] = KVhW[rr + 4];
                    Blf[nt][0] = KVlW[rr]; Blf[nt][1] = KVlW[rr + 4];
                }
#pragma unroll
                for (int nt = 0; nt < 8; nt++) {
                    MMA_BF16(oacc[nt], Ahf, Bhf[nt]);
                    MMA_BF16(oacc[nt], Ahf, Blf[nt]);
                    MMA_BF16(oacc[nt], Alf, Bhf[nt]);
                }
            }
        }

        // ---- epilogue: normalize + store ----
        {
            int rowA = mrowO + gid, rowB = rowA + 8;
            float invA = 1.f / rsum[rowA];
            float invB = 1.f / rsum[rowB];
            int pA = r0 + rowA, pB = r0 + rowB;
            int pixA = (py0 + (pA >> 4)) * 256 + px0 + (pA & 15);
            int pixB = (py0 + (pB >> 4)) * 256 + px0 + (pB & 15);
#pragma unroll
            for (int nt = 0; nt < 8; nt++) {
                int ch = ncolO + nt * 8 + tig * 2;
                g_OUT[cbase + ch * HW + pixA] = oacc[nt][0] * invA;
                g_OUT[cbase + (ch + 1) * HW + pixA] = oacc[nt][1] * invA;
                g_OUT[cbase + ch * HW + pixB] = oacc[nt][2] * invB;
                g_OUT[cbase + (ch + 1) * HW + pixB] = oacc[nt][3] * invB;
            }
        }
    }
}

// ---------------- depthwise 5x5 (dilation param; optional fused gelu*ca + residual) ----------------
__global__ void dw5_kernel(const float* __restrict__ in, const float* __restrict__ w,
                           const float* __restrict__ bias, float* __restrict__ out,
                           int dil, int fuse) {
    __shared__ float ws[25];
    int c = blockIdx.z & 127, b = blockIdx.z >> 7;
    int t = threadIdx.y * 32 + threadIdx.x;
    if (t < 25) ws[t] = w[c * 25 + t];
    __syncthreads();
    int x = blockIdx.x * 32 + threadIdx.x;
    int y = blockIdx.y * 8 + threadIdx.y;
    const float* ip = in + (size_t)(b * CH + c) * HW;
    float acc = __ldg(&bias[c]);
#pragma unroll
    for (int ky = 0; ky < 5; ky++) {
        int yy = y + (ky - 2) * dil;
        if ((unsigned)yy >= 256u) continue;
#pragma unroll
        for (int kx = 0; kx < 5; kx++) {
            int xx = x + (kx - 2) * dil;
            if ((unsigned)xx >= 256u) continue;
            acc = fmaf(ws[ky * 5 + kx], __ldg(&ip[yy * 256 + xx]), acc);
        }
    }
    size_t oidx = (size_t)(b * CH + c) * HW + y * 256 + x;
    if (fuse) {
        float g = 0.5f * acc * (1.f + erff(acc * 0.7071067811865475f));
        out[oidx] = g * g_CA[b * CH + c] + g_OUT[oidx];
    } else {
        out[oidx] = acc;
    }
}

// ---------------- launch ----------------
extern "C" void kernel_launch(void* const* d_in, const int* in_sizes, int n_in,
                              void* d_out, int out_size) {
    const float* x      = (const float*)d_in[0];
    const float* cond_g = (const float*)d_in[1];
    const float* gu     = (const float*)d_in[2];
    const float* pv_w   = (const float*)d_in[3];
    const float* pv_b   = (const float*)d_in[4];
    const float* pq_w   = (const float*)d_in[5];
    const float* pq_b   = (const float*)d_in[6];
    const float* pk_w   = (const float*)d_in[7];
    const float* pk_b   = (const float*)d_in[8];
    const float* cs1_w  = (const float*)d_in[9];
    const float* cs1_b  = (const float*)d_in[10];
    const float* cs2_w  = (const float*)d_in[11];
    const float* cs2_b  = (const float*)d_in[12];
    const float* cs3_w  = (const float*)d_in[13];
    const float* cs3_b  = (const float*)d_in[14];
    const float* po_w   = (const float*)d_in[15];
    const float* po_b   = (const float*)d_in[16];
    const float* rin_w  = (const float*)d_in[17];
    const float* rin_b  = (const float*)d_in[18];
    const float* r1w    = (const float*)d_in[19];
    const float* r1b    = (const float*)d_in[20];
    const float* r2w    = (const float*)d_in[21];
    const float* r2b    = (const float*)d_in[22];
    const float* rm1_w  = (const float*)d_in[23];
    const float* rm1_b  = (const float*)d_in[24];
    const float* rm2_w  = (const float*)d_in[25];
    const float* rm2_b  = (const float*)d_in[26];
    const float* rca_w  = (const float*)d_in[27];
    const float* rca_b  = (const float*)d_in[28];
    const float* rsa_w  = (const float*)d_in[29];
    const float* rsa_b  = (const float*)d_in[30];

    float *pV, *pXW, *pQ, *pK, *pOUT, *pT1, *pT2;
    __nv_bfloat16* pWT;
    cudaGetSymbolAddress((void**)&pV, g_V);
    cudaGetSymbolAddress((void**)&pXW, g_XW);
    cudaGetSymbolAddress((void**)&pQ, g_Qb);
    cudaGetSymbolAddress((void**)&pK, g_Kb);
    cudaGetSymbolAddress((void**)&pOUT, g_OUT);
    cudaGetSymbolAddress((void**)&pT1, g_T1);
    cudaGetSymbolAddress((void**)&pT2, g_T2);
    cudaGetSymbolAddress((void**)&pWT, g_WT);

    cudaFuncSetAttribute(attn_mma_kernel, cudaFuncAttributeMaxDynamicSharedMemorySize, SMEM_ATTN2);
    cudaFuncSetAttribute(conv1x1_mma, cudaFuncAttributeMaxDynamicSharedMemorySize, CV_SMEM);

    const int WSET = 2 * 128 * 136;

    zero_fsum_kernel<<<1, 128>>>();
    prep_w_kernel<<<64, 256>>>(pv_w, 0);
    prep_w_kernel<<<64, 256>>>(pq_w, 1);
    prep_w_kernel<<<64, 256>>>(pk_w, 2);
    prep_w_kernel<<<64, 256>>>(cs1_w, 3);
    prep_w_kernel<<<64, 256>>>(po_w, 4);

    dim3 ghw(512, BB);
    conv1x1_mma<<<ghw, 256, CV_SMEM>>>(x, pWT + 0 * WSET, pv_b, pV, 0);
    predictor_kernel<<<dim3(HW / 512, BB), 256>>>(cond_g, rin_w, rin_b, r1w, r1b, r2w, r2b);
    ca_kernel<<<BB, 128>>>(rca_w, rca_b);
    sa_kernel<<<dim3(HW / 256, BB), 256>>>(rsa_w, rsa_b);
    mask_kernel<<<dim3(256, BB), 256>>>(gu, rm1_w, rm1_b, rm2_w, rm2_b);
    warp_kernel<<<dim3(HW / 256, BB), 256>>>(x);
    conv1x1_mma<<<ghw, 256, CV_SMEM>>>(pXW, pWT + 1 * WSET, pq_b, pQ, 1);
    conv1x1_mma<<<ghw, 256, CV_SMEM>>>(pXW, pWT + 2 * WSET, pk_b, pK, 1);
    attn_mma_kernel<<<dim3(256, BB), 256, SMEM_ATTN2>>>();
    conv1x1_mma<<<ghw, 256, CV_SMEM>>>(pOUT, pWT + 3 * WSET, cs1_b, pT1, 0);
    dw5_kernel<<<dim3(8, 32, BB * CH), dim3(32, 8)>>>(pT1, cs2_w, cs2_b, pT2, 1, 0);
    dw5_kernel<<<dim3(8, 32, BB * CH), dim3(32, 8)>>>(pT2, cs3_w, cs3_b, pT1, 3, 1);
    conv1x1_mma<<<ghw, 256, CV_SMEM>>>(pT1, pWT + 4 * WSET, po_b, (float*)d_out, 0);
}

// round 6
// speedup vs baseline: 1.7102x; 1.0666x over previous
#include <cuda_runtime.h>
#include <cuda_bf16.h>
#include <stdint.h>
#include <math.h>

#define HW 65536
#define WIMG 256
#define CH 128
#define BB 4
#define ELT (BB*CH*HW)

// ---------------- scratch (static device globals; no runtime alloc) ----------------
__device__ float g_V[ELT];
__device__ float g_Qb[ELT];
__device__ float g_Kb[ELT];
__device__ float g_OUT[ELT];
__device__ float g_T1[ELT];
__device__ float g_T2[ELT];
__device__ float g_F[BB*32*HW];
__device__ float g_OFF[BB*2*HW];
__device__ float g_FMC[BB*HW];
__device__ float g_SA[BB*HW];
__device__ float g_FSUM[BB*32];
__device__ float g_CA[BB*CH];
__device__ float g_MASK[BB*256];
// hi/lo bf16 weights, row-padded to 136 (stride-68-word smem => conflict-free frags)
__device__ __align__(16) __nv_bfloat16 g_WT[5][2][128*136];

__device__ __forceinline__ float leakyf(float x) { return x > 0.f ? x : 0.2f * x; }

__global__ void zero_fsum_kernel() {
    g_FSUM[threadIdx.x] = 0.f;
}

// ---------------- weight prep: fp32 -> bf16 hi/lo, padded rows ----------------
__global__ void prep_w_kernel(const float* __restrict__ w, int set) {
    int i = blockIdx.x * 256 + threadIdx.x;
    int oc = i >> 7, ci = i & 127;
    float v = w[i];
    __nv_bfloat16 h = __float2bfloat16_rn(v);
    __nv_bfloat16 l = __float2bfloat16_rn(v - __bfloat162float(h));
    g_WT[set][0][oc * 136 + ci] = h;
    g_WT[set][1][oc * 136 + ci] = l;
}

// ---------------- HMMA m16n8k16 bf16 ----------------
#define MMA_BF16(d, a, b) \
    asm volatile("mma.sync.aligned.m16n8k16.row.col.f32.bf16.bf16.f32 " \
        "{%0,%1,%2,%3}, {%4,%5,%6,%7}, {%8,%9}, {%0,%1,%2,%3};" \
        : "+f"((d)[0]), "+f"((d)[1]), "+f"((d)[2]), "+f"((d)[3]) \
        : "r"((a)[0]), "r"((a)[1]), "r"((a)[2]), "r"((a)[3]), "r"((b)[0]), "r"((b)[1]))

#define CV_SMEM (4 * 128 * 136 * 2)

// ---- shared GEMM body: W(hi/lo smem) x X(hi/lo smem) -> y window half ----
__device__ __forceinline__ void gemm_body_128(
    const uint32_t* WhW, const uint32_t* WlW,
    const uint32_t* XhW, const uint32_t* XlW,
    const float* __restrict__ bias, float* __restrict__ yb,
    int py0, int px0, int half, int w, int gid, int tig) {
    int oc0 = (w & 3) * 32;
    int n0 = (w >> 2) * 64;
    float acc[16][4];
#pragma unroll
    for (int i = 0; i < 16; i++)
#pragma unroll
        for (int j = 0; j < 4; j++) acc[i][j] = 0.f;
#pragma unroll 1
    for (int ks = 0; ks < 8; ks++) {
        int kw = ks * 8;
        uint32_t Ah[2][4], Al[2][4], Bh[8][2], Bl[8][2];
#pragma unroll
        for (int mt = 0; mt < 2; mt++) {
            int r0 = (oc0 + mt * 16 + gid) * 68 + kw + tig;
            int r8 = r0 + 8 * 68;
            Ah[mt][0] = WhW[r0];     Ah[mt][1] = WhW[r8];
            Ah[mt][2] = WhW[r0 + 4]; Ah[mt][3] = WhW[r8 + 4];
            Al[mt][0] = WlW[r0];     Al[mt][1] = WlW[r8];
            Al[mt][2] = WlW[r0 + 4]; Al[mt][3] = WlW[r8 + 4];
        }
#pragma unroll
        for (int nt = 0; nt < 8; nt++) {
            int rr = (n0 + nt * 8 + gid) * 68 + kw + tig;
            Bh[nt][0] = XhW[rr]; Bh[nt][1] = XhW[rr + 4];
            Bl[nt][0] = XlW[rr]; Bl[nt][1] = XlW[rr + 4];
        }
#pragma unroll
        for (int mt = 0; mt < 2; mt++)
#pragma unroll
            for (int nt = 0; nt < 8; nt++) {
                MMA_BF16(acc[mt * 8 + nt], Ah[mt], Bh[nt]);
                MMA_BF16(acc[mt * 8 + nt], Ah[mt], Bl[nt]);
                MMA_BF16(acc[mt * 8 + nt], Al[mt], Bh[nt]);
            }
    }
#pragma unroll
    for (int mt = 0; mt < 2; mt++) {
        int ocA = oc0 + mt * 16 + gid;
        int ocB = ocA + 8;
        float bvA = __ldg(&bias[ocA]);
        float bvB = __ldg(&bias[ocB]);
#pragma unroll
        for (int nt = 0; nt < 8; nt++) {
            int col = n0 + nt * 8 + tig * 2;
            int p = half * 128 + col;
            int pix = (py0 + (p >> 4)) * 256 + px0 + (p & 15);
            float2 v0 = make_float2(acc[mt * 8 + nt][0] + bvA, acc[mt * 8 + nt][1] + bvA);
            float2 v1 = make_float2(acc[mt * 8 + nt][2] + bvB, acc[mt * 8 + nt][3] + bvB);
            *(float2*)(yb + (size_t)ocA * HW + pix) = v0;
            *(float2*)(yb + (size_t)ocB * HW + pix) = v1;
        }
    }
}

// ---------------- conv1x1 GEMM via mma.sync (proven) ----------------
__global__ void __launch_bounds__(256, 1)
conv1x1_mma(const float* __restrict__ xin, const __nv_bfloat16* __restrict__ wsp,
            const float* __restrict__ bias, float* __restrict__ yout, int useMask) {
    int hw = blockIdx.x, b = blockIdx.y;
    int n = hw >> 1, half = hw & 1;
    if (useMask && g_MASK[b * 256 + n] == 0.f) return;
    extern __shared__ __nv_bfloat16 smb[];
    __nv_bfloat16* Wh = smb;
    __nv_bfloat16* Wl = Wh + 128 * 136;
    __nv_bfloat16* Xh = Wl + 128 * 136;
    __nv_bfloat16* Xl = Xh + 128 * 136;
    int t = threadIdx.x;

    {
        const uint4* src = (const uint4*)wsp;
        uint4* dst = (uint4*)smb;
#pragma unroll
        for (int i = 0; i < 17; i++) dst[t + i * 256] = src[t + i * 256];
    }

    int py0 = (n >> 4) * 16, px0 = (n & 15) * 16;
    const float* xb = xin + (size_t)b * CH * HW;
    {
        int px = t & 127;
        int p = half * 128 + px;
        int pix = (py0 + (p >> 4)) * 256 + px0 + (p & 15);
        int cp0 = t >> 7;
#pragma unroll
        for (int j = 0; j < 32; j++) {
            int cp = cp0 + j * 2;
            float v0 = xb[(size_t)(2 * cp) * HW + pix];
            float v1 = xb[(size_t)(2 * cp + 1) * HW + pix];
            __nv_bfloat16 h0 = __float2bfloat16_rn(v0);
            __nv_bfloat16 h1 = __float2bfloat16_rn(v1);
            __nv_bfloat16 l0 = __float2bfloat16_rn(v0 - __bfloat162float(h0));
            __nv_bfloat16 l1 = __float2bfloat16_rn(v1 - __bfloat162float(h1));
            ((__nv_bfloat162*)(Xh + px * 136))[cp] = __nv_bfloat162(h0, h1);
            ((__nv_bfloat162*)(Xl + px * 136))[cp] = __nv_bfloat162(l0, l1);
        }
    }
    __syncthreads();

    int w = t >> 5, lane = t & 31;
    int gid = lane >> 2, tig = lane & 3;
    gemm_body_128((const uint32_t*)Wh, (const uint32_t*)Wl,
                  (const uint32_t*)Xh, (const uint32_t*)Xl,
                  bias, yout + (size_t)b * CH * HW, py0, px0, half, w, gid, tig);
}

// ---------------- fused flow-warp + q/k projections (masked windows only) ----------------
// smem: Wqh|Wql|Wkh|Wkl|Xh|Xl  (6 x 128*136 bf16 = 208896 B)
#define QK_SMEM (6 * 128 * 136 * 2)
__global__ void __launch_bounds__(256, 1)
convqk_mma(const float* __restrict__ xin,
           const __nv_bfloat16* __restrict__ wq, const __nv_bfloat16* __restrict__ wk,
           const float* __restrict__ qbias, const float* __restrict__ kbias) {
    int hw = blockIdx.x, b = blockIdx.y;
    int n = hw >> 1, half = hw & 1;
    if (g_MASK[b * 256 + n] == 0.f) return;
    extern __shared__ __nv_bfloat16 smb[];
    __nv_bfloat16* Wqh = smb;
    __nv_bfloat16* Wql = Wqh + 128 * 136;
    __nv_bfloat16* Wkh = Wql + 128 * 136;
    __nv_bfloat16* Wkl = Wkh + 128 * 136;
    __nv_bfloat16* Xh  = Wkl + 128 * 136;
    __nv_bfloat16* Xl  = Xh + 128 * 136;
    int t = threadIdx.x;

    // copy both weight sets (2 x 69632 B = 8704 uint4)
    {
        const uint4* srcq = (const uint4*)wq;
        const uint4* srck = (const uint4*)wk;
        uint4* dstq = (uint4*)Wqh;
        uint4* dstk = (uint4*)Wkh;
#pragma unroll
        for (int i = 0; i < 17; i++) {
            dstq[t + i * 256] = srcq[t + i * 256];
            dstk[t + i * 256] = srck[t + i * 256];
        }
    }

    // ---- stage X = flow_warp(x) window half, hi/lo bf16 (gather inline) ----
    int py0 = (n >> 4) * 16, px0 = (n & 15) * 16;
    {
        int px = t & 127;
        int p = half * 128 + px;
        int gy = py0 + (p >> 4), gx = px0 + (p & 15);
        int pp = gy * 256 + gx;
        const float* OFb = g_OFF + (size_t)b * 2 * HW;
        float fx = OFb[pp];
        float fy = OFb[HW + pp];
        float sx = fminf(fmaxf((float)gx + fx, 0.f), 255.f);
        float sy = fminf(fmaxf((float)gy + fy, 0.f), 255.f);
        float x0f = floorf(sx), y0f = floorf(sy);
        float x1f = fminf(x0f + 1.f, 255.f), y1f = fminf(y0f + 1.f, 255.f);
        float wx = sx - x0f, wy = sy - y0f;
        int x0 = (int)x0f, x1 = (int)x1f, y0 = (int)y0f, y1 = (int)y1f;
        int iA = y0 * 256 + x0, iB = y0 * 256 + x1, iC = y1 * 256 + x0, iD = y1 * 256 + x1;
        float w00 = (1.f - wx) * (1.f - wy), w01 = wx * (1.f - wy);
        float w10 = (1.f - wx) * wy, w11 = wx * wy;
        const float* xb = xin + (size_t)b * CH * HW;
        int cp0 = t >> 7;
#pragma unroll 4
        for (int j = 0; j < 32; j++) {
            int cp = cp0 + j * 2;
            const float* xc0 = xb + (size_t)(2 * cp) * HW;
            const float* xc1 = xc0 + HW;
            float v0 = __ldg(&xc0[iA]) * w00 + __ldg(&xc0[iB]) * w01 +
                       __ldg(&xc0[iC]) * w10 + __ldg(&xc0[iD]) * w11;
            float v1 = __ldg(&xc1[iA]) * w00 + __ldg(&xc1[iB]) * w01 +
                       __ldg(&xc1[iC]) * w10 + __ldg(&xc1[iD]) * w11;
            __nv_bfloat16 h0 = __float2bfloat16_rn(v0);
            __nv_bfloat16 h1 = __float2bfloat16_rn(v1);
            __nv_bfloat16 l0 = __float2bfloat16_rn(v0 - __bfloat162float(h0));
            __nv_bfloat16 l1 = __float2bfloat16_rn(v1 - __bfloat162float(h1));
            ((__nv_bfloat162*)(Xh + px * 136))[cp] = __nv_bfloat162(h0, h1);
            ((__nv_bfloat162*)(Xl + px * 136))[cp] = __nv_bfloat162(l0, l1);
        }
    }
    __syncthreads();

    int w = t >> 5, lane = t & 31;
    int gid = lane >> 2, tig = lane & 3;
    // Q = Wq . X
    gemm_body_128((const uint32_t*)Wqh, (const uint32_t*)Wql,
                  (const uint32_t*)Xh, (const uint32_t*)Xl,
                  qbias, g_Qb + (size_t)b * CH * HW, py0, px0, half, w, gid, tig);
    // K = Wk . X  (X unchanged; no sync needed, reads only)
    gemm_body_128((const uint32_t*)Wkh, (const uint32_t*)Wkl,
                  (const uint32_t*)Xh, (const uint32_t*)Xl,
                  kbias, g_Kb + (size_t)b * CH * HW, py0, px0, half, w, gid, tig);
}

// ---------------- predictor ----------------
__global__ void predictor_kernel(const float* __restrict__ cond_g,
                                 const float* __restrict__ rin_w, const float* __restrict__ rin_b,
                                 const float* __restrict__ r1w, const float* __restrict__ r1b,
                                 const float* __restrict__ r2w, const float* __restrict__ r2b) {
    __shared__ float wr[32 * 131];
    __shared__ float wr1[16 * 32];
    __shared__ float wr2[32];
    __shared__ float partial[8][32];
    int t = threadIdx.x;
    int b = blockIdx.y;
    for (int i = t; i < 32 * 131; i += 256) wr[i] = rin_w[i];
    for (int i = t; i < 16 * 32; i += 256) wr1[i] = r1w[i];
    if (t < 32) wr2[t] = r2w[t];
    __syncthreads();

    int p0 = blockIdx.x * 512 + t;
    int p1 = p0 + 256;
    float a0[32], a1[32];
#pragma unroll
    for (int o = 0; o < 32; o++) {
        float bv = __ldg(&rin_b[o]);
        a0[o] = bv; a1[o] = bv;
    }
    const float* vb = g_V + (size_t)b * CH * HW;
#pragma unroll 2
    for (int ci = 0; ci < 128; ci++) {
        float x0 = vb[(size_t)ci * HW + p0];
        float x1 = vb[(size_t)ci * HW + p1];
#pragma unroll
        for (int o = 0; o < 32; o++) {
            float wv = wr[o * 131 + ci];
            a0[o] = fmaf(wv, x0, a0[o]);
            a1[o] = fmaf(wv, x1, a1[o]);
        }
    }
    float cg0 = __ldg(&cond_g[b * HW + p0]);
    float cg1 = __ldg(&cond_g[b * HW + p1]);
    int y0 = p0 >> 8, x0p = p0 & 255;
    int y1 = p1 >> 8, x1p = p1 & 255;
    float ly0 = -1.f + (float)(y0 & 15) * (2.f / 15.f);
    float lx0 = -1.f + (float)(x0p & 15) * (2.f / 15.f);
    float ly1 = -1.f + (float)(y1 & 15) * (2.f / 15.f);
    float lx1 = -1.f + (float)(x1p & 15) * (2.f / 15.f);
    float fm0 = 0.f, fm1 = 0.f;
    float* Fb = g_F + (size_t)b * 32 * HW;
#pragma unroll
    for (int o = 0; o < 32; o++) {
        float v0 = a0[o] + wr[o * 131 + 128] * cg0 + wr[o * 131 + 129] * ly0 + wr[o * 131 + 130] * lx0;
        float v1 = a1[o] + wr[o * 131 + 128] * cg1 + wr[o * 131 + 129] * ly1 + wr[o * 131 + 130] * lx1;
        v0 = leakyf(v0); v1 = leakyf(v1);
        a0[o] = v0; a1[o] = v1;
        Fb[(size_t)o * HW + p0] = v0;
        Fb[(size_t)o * HW + p1] = v1;
        fm0 += v0; fm1 += v1;
    }
    g_FMC[b * HW + p0] = fm0 * (1.f / 32.f);
    g_FMC[b * HW + p1] = fm1 * (1.f / 32.f);

    float h0[16], h1v[16];
#pragma unroll
    for (int o2 = 0; o2 < 16; o2++) {
        float bv = __ldg(&r1b[o2]);
        float s0 = bv, s1 = bv;
#pragma unroll
        for (int o = 0; o < 32; o++) {
            float wv = wr1[o2 * 32 + o];
            s0 = fmaf(wv, a0[o], s0);
            s1 = fmaf(wv, a1[o], s1);
        }
        h0[o2] = leakyf(s0);
        h1v[o2] = leakyf(s1);
    }
    float ox0 = __ldg(&r2b[0]), oy0 = __ldg(&r2b[1]);
    float ox1 = ox0, oy1 = oy0;
#pragma unroll
    for (int o2 = 0; o2 < 16; o2++) {
        ox0 = fmaf(wr2[o2], h0[o2], ox0);
        oy0 = fmaf(wr2[16 + o2], h0[o2], oy0);
        ox1 = fmaf(wr2[o2], h1v[o2], ox1);
        oy1 = fmaf(wr2[16 + o2], h1v[o2], oy1);
    }
    float* OFb = g_OFF + (size_t)b * 2 * HW;
    OFb[p0] = ox0; OFb[p1] = ox1;
    OFb[HW + p0] = oy0; OFb[HW + p1] = oy1;

    int lane = t & 31, wid = t >> 5;
#pragma unroll
    for (int o = 0; o < 32; o++) {
        float v = a0[o] + a1[o];
        v += __shfl_xor_sync(0xffffffff, v, 16);
        v += __shfl_xor_sync(0xffffffff, v, 8);
        v += __shfl_xor_sync(0xffffffff, v, 4);
        v += __shfl_xor_sync(0xffffffff, v, 2);
        v += __shfl_xor_sync(0xffffffff, v, 1);
        if (lane == 0) partial[wid][o] = v;
    }
    __syncthreads();
    if (t < 32) {
        float s = 0.f;
#pragma unroll
        for (int w2 = 0; w2 < 8; w2++) s += partial[w2][t];
        atomicAdd(&g_FSUM[b * 32 + t], s);
    }
}

// ---------------- channel attention ca ----------------
__global__ void ca_kernel(const float* __restrict__ rca_w, const float* __restrict__ rca_b) {
    int c = threadIdx.x;
    int b = blockIdx.x;
    float s = __ldg(&rca_b[c]);
#pragma unroll
    for (int ci = 0; ci < 32; ci++)
        s = fmaf(__ldg(&rca_w[c * 32 + ci]), g_FSUM[b * 32 + ci] * (1.f / 65536.f), s);
    g_CA[b * CH + c] = 1.f / (1.f + expf(-s));
}

// ---------------- spatial attention sa ----------------
__global__ void sa_kernel(const float* __restrict__ rsa_w, const float* __restrict__ rsa_b) {
    __shared__ float ws[288];
    int t = threadIdx.x;
    for (int i = t; i < 288; i += 256) ws[i] = rsa_w[i];
    __syncthreads();
    int b = blockIdx.y;
    int p = blockIdx.x * 256 + t;
    int y = p >> 8, x = p & 255;
    float acc = __ldg(&rsa_b[0]);
    const float* Fb = g_F + (size_t)b * 32 * HW;
    for (int ci = 0; ci < 32; ci++) {
        const float* fp = Fb + (size_t)ci * HW;
#pragma unroll
        for (int ky = 0; ky < 3; ky++) {
            int yy = y + ky - 1;
            if ((unsigned)yy >= 256u) continue;
#pragma unroll
            for (int kx = 0; kx < 3; kx++) {
                int xx = x + kx - 1;
                if ((unsigned)xx >= 256u) continue;
                acc = fmaf(ws[ci * 9 + ky * 3 + kx], __ldg(&fp[yy * 256 + xx]), acc);
            }
        }
    }
    g_SA[b * HW + p] = 1.f / (1.f + expf(-acc));
}

// ---------------- window MLP + gumbel hard mask ----------------
__global__ void mask_kernel(const float* __restrict__ gu,
                            const float* __restrict__ rm1_w, const float* __restrict__ rm1_b,
                            const float* __restrict__ rm2_w, const float* __restrict__ rm2_b) {
    __shared__ float m[256];
    __shared__ float h1s[16];
    int n = blockIdx.x, b = blockIdx.y;
    int t = threadIdx.x;
    int dh = t >> 4, dw = t & 15;
    int pix = ((n >> 4) * 16 + dh) * 256 + (n & 15) * 16 + dw;
    m[t] = g_FMC[b * HW + pix];
    __syncthreads();
    if (t < 16) {
        float s = __ldg(&rm1_b[t]);
        for (int e = 0; e < 256; e++) s = fmaf(__ldg(&rm1_w[t * 256 + e]), m[e], s);
        h1s[t] = leakyf(s);
    }
    __syncthreads();
    if (t == 0) {
        float z0 = __ldg(&rm2_b[0]), z1 = __ldg(&rm2_b[1]);
#pragma unroll
        for (int o = 0; o < 16; o++) {
            z0 = fmaf(__ldg(&rm2_w[o]), h1s[o], z0);
            z1 = fmaf(__ldg(&rm2_w[16 + o]), h1s[o], z1);
        }
        float mx = fmaxf(z0, z1);
        float e0 = expf(z0 - mx), e1 = expf(z1 - mx);
        float inv = 1.f / (e0 + e1);
        float p0 = e0 * inv, p1 = e1 * inv;
        float u0 = __ldg(&gu[(b * 256 + n) * 2 + 0]);
        float u1 = __ldg(&gu[(b * 256 + n) * 2 + 1]);
        float g0 = -logf(-logf(u0 + 1e-10f) + 1e-10f);
        float g1 = -logf(-logf(u1 + 1e-10f) + 1e-10f);
        g_MASK[b * 256 + n] = (p0 + g0 >= p1 + g1) ? 1.f : 0.f;
    }
}

// ---------------- window attention via mma.sync (masked) / v*sa (unmasked) ----------------
#define SMEM_ATTN2 (67328 + 90112)
__global__ void __launch_bounds__(256, 1) attn_mma_kernel() {
    int n = blockIdx.x, b = blockIdx.y;
    int t = threadIdx.x;
    int py0 = (n >> 4) * 16, px0 = (n & 15) * 16;
    int cbase = b * CH * HW;
    if (g_MASK[b * 256 + n] == 0.f) {
        const float* sab = g_SA + (size_t)b * HW;
#pragma unroll 4
        for (int i = t; i < 8192; i += 256) {
            int ch = i >> 6, r4 = i & 63;
            int wrow = r4 >> 2, px4 = (r4 & 3) * 4;
            int pix = (py0 + wrow) * 256 + px0 + px4;
            float4 v = *(const float4*)(g_V + cbase + ch * HW + pix);
            float4 s = *(const float4*)(sab + pix);
            v.x *= s.x; v.y *= s.y; v.z *= s.z; v.w *= s.w;
            *(float4*)(g_OUT + cbase + ch * HW + pix) = v;
        }
        return;
    }
    extern __shared__ char smraw[];
    float* S = (float*)smraw;
    float* red = S + 64 * 257;
    float* rmax = red + 256;
    float* rsum = rmax + 64;
    __nv_bfloat16* Qh = (__nv_bfloat16*)(rsum + 64);
    __nv_bfloat16* Ql = Qh + 64 * 136;
    __nv_bfloat16* KVh = Ql + 64 * 136;
    __nv_bfloat16* KVl = KVh + 9216;
    __nv_bfloat16* Pth = KVl + 9216;
    __nv_bfloat16* Ptl = Pth + 64 * 72;

    const uint32_t* QhW = (const uint32_t*)Qh;
    const uint32_t* QlW = (const uint32_t*)Ql;
    const uint32_t* KVhW = (const uint32_t*)KVh;
    const uint32_t* KVlW = (const uint32_t*)KVl;
    const uint32_t* PthW = (const uint32_t*)Pth;
    const uint32_t* PtlW = (const uint32_t*)Ptl;

    int w = t >> 5, lane = t & 31;
    int gid = lane >> 2;
    int tig = lane & 3;

#pragma unroll 1
    for (int rc = 0; rc < 4; rc++) {
        int r0 = rc * 64;
        __syncthreads();
#pragma unroll
        for (int j = 0; j < 16; j++) {
            int i = t + j * 256;
            int px = i & 63, cp = i >> 6;
            int p = r0 + px;
            int pix = (py0 + (p >> 4)) * 256 + px0 + (p & 15);
            float v0 = g_Qb[cbase + (2 * cp) * HW + pix];
            float v1 = g_Qb[cbase + (2 * cp + 1) * HW + pix];
            __nv_bfloat16 h0 = __float2bfloat16_rn(v0);
            __nv_bfloat16 h1 = __float2bfloat16_rn(v1);
            __nv_bfloat16 l0 = __float2bfloat16_rn(v0 - __bfloat162float(h0));
            __nv_bfloat16 l1 = __float2bfloat16_rn(v1 - __bfloat162float(h1));
            ((__nv_bfloat162*)(Qh + px * 136))[cp] = __nv_bfloat162(h0, h1);
            ((__nv_bfloat162*)(Ql + px * 136))[cp] = __nv_bfloat162(l0, l1);
        }

        int mrowS = (w & 3) * 16, ncolS = (w >> 2) * 32;
#pragma unroll 1
        for (int kvt = 0; kvt < 4; kvt++) {
            __syncthreads();
#pragma unroll
            for (int j = 0; j < 16; j++) {
                int i = t + j * 256;
                int px = i & 63, cp = i >> 6;
                int p = kvt * 64 + px;
                int pix = (py0 + (p >> 4)) * 256 + px0 + (p & 15);
                float v0 = g_Kb[cbase + (2 * cp) * HW + pix];
                float v1 = g_Kb[cbase + (2 * cp + 1) * HW + pix];
                __nv_bfloat16 h0 = __float2bfloat16_rn(v0);
                __nv_bfloat16 h1 = __float2bfloat16_rn(v1);
                __nv_bfloat16 l0 = __float2bfloat16_rn(v0 - __bfloat162float(h0));
                __nv_bfloat16 l1 = __float2bfloat16_rn(v1 - __bfloat162float(h1));
                ((__nv_bfloat162*)(KVh + px * 136))[cp] = __nv_bfloat162(h0, h1);
                ((__nv_bfloat162*)(KVl + px * 136))[cp] = __nv_bfloat162(l0, l1);
            }
            __syncthreads();
            float acc[4][4];
#pragma unroll
            for (int i = 0; i < 4; i++)
#pragma unroll
                for (int j2 = 0; j2 < 4; j2++) acc[i][j2] = 0.f;
#pragma unroll
            for (int ks = 0; ks < 8; ks++) {
                int kw = ks * 8;
                uint32_t Ahf[4], Alf[4], Bhf[4][2], Blf[4][2];
                int ra = (mrowS + gid) * 68 + kw + tig;
                int ra8 = ra + 8 * 68;
                Ahf[0] = QhW[ra];     Ahf[1] = QhW[ra8];
                Ahf[2] = QhW[ra + 4]; Ahf[3] = QhW[ra8 + 4];
                Alf[0] = QlW[ra];     Alf[1] = QlW[ra8];
                Alf[2] = QlW[ra + 4]; Alf[3] = QlW[ra8 + 4];
#pragma unroll
                for (int nt = 0; nt < 4; nt++) {
                    int rr = (ncolS + nt * 8 + gid) * 68 + kw + tig;
                    Bhf[nt][0] = KVhW[rr]; Bhf[nt][1] = KVhW[rr + 4];
                    Blf[nt][0] = KVlW[rr]; Blf[nt][1] = KVlW[rr + 4];
                }
#pragma unroll
                for (int nt = 0; nt < 4; nt++) {
                    MMA_BF16(acc[nt], Ahf, Bhf[nt]);
                    MMA_BF16(acc[nt], Ahf, Blf[nt]);
                    MMA_BF16(acc[nt], Alf, Bhf[nt]);
                }
            }
#pragma unroll
            for (int nt = 0; nt < 4; nt++) {
                int col = kvt * 64 + ncolS + nt * 8 + tig * 2;
                S[(mrowS + gid) * 257 + col] = acc[nt][0];
                S[(mrowS + gid) * 257 + col + 1] = acc[nt][1];
                S[(mrowS + gid + 8) * 257 + col] = acc[nt][2];
                S[(mrowS + gid + 8) * 257 + col + 1] = acc[nt][3];
            }
        }
        __syncthreads();

        {
            int r = t & 63, seg = t >> 6;
            float* srow = &S[r * 257 + seg * 64];
            float mx = -1e30f;
#pragma unroll 8
            for (int k = 0; k < 64; k++) mx = fmaxf(mx, srow[k]);
            red[seg * 64 + r] = mx;
            __syncthreads();
            if (t < 64)
                rmax[t] = fmaxf(fmaxf(red[t], red[64 + t]), fmaxf(red[128 + t], red[192 + t]));
            __syncthreads();
            float rm_ = rmax[r];
            float s = 0.f;
#pragma unroll 8
            for (int k = 0; k < 64; k++) {
                float e = __expf(srow[k] - rm_);
                srow[k] = e;
                s += e;
            }
            red[seg * 64 + r] = s;
            __syncthreads();
            if (t < 64) rsum[t] = red[t] + red[64 + t] + red[128 + t] + red[192 + t];
            __syncthreads();
        }

        int mrowO = (w & 3) * 16, ncolO = (w >> 2) * 64;
        float oacc[8][4];
#pragma unroll
        for (int i = 0; i < 8; i++)
#pragma unroll
            for (int j2 = 0; j2 < 4; j2++) oacc[i][j2] = 0.f;

#pragma unroll 1
        for (int kvt = 0; kvt < 4; kvt++) {
            __syncthreads();
#pragma unroll
            for (int j = 0; j < 16; j++) {
                int i = t + j * 256;
                int col = i & 63, row = i >> 6;
                float v = S[row * 257 + kvt * 64 + col];
                __nv_bfloat16 h = __float2bfloat16_rn(v);
                Pth[row * 72 + col] = h;
                Ptl[row * 72 + col] = __float2bfloat16_rn(v - __bfloat162float(h));
            }
#pragma unroll
            for (int j = 0; j < 32; j++) {
                int i = t + j * 256;
                int px = i & 63, ch = i >> 6;
                int p = kvt * 64 + px;
                int pix = (py0 + (p >> 4)) * 256 + px0 + (p & 15);
                float v = g_V[cbase + ch * HW + pix];
                __nv_bfloat16 h = __float2bfloat16_rn(v);
                KVh[ch * 72 + px] = h;
                KVl[ch * 72 + px] = __float2bfloat16_rn(v - __bfloat162float(h));
            }
            __syncthreads();
#pragma unroll
            for (int ks = 0; ks < 4; ks++) {
                int kw = ks * 8;
                uint32_t Ahf[4], Alf[4], Bhf[8][2], Blf[8][2];
                int ra = (mrowO + gid) * 36 + kw + tig;
                int ra8 = ra + 8 * 36;
                Ahf[0] = PthW[ra];     Ahf[1] = PthW[ra8];
                Ahf[2] = PthW[ra + 4]; Ahf[3] = PthW[ra8 + 4];
                Alf[0] = PtlW[ra];     Alf[1] = PtlW[ra8];
                Alf[2] = PtlW[ra + 4]; Alf[3] = PtlW[ra8 + 4];
#pragma unroll
                for (int nt = 0; nt < 8; nt++) {
                    int rr = (ncolO + nt * 8 + gid) * 36 + kw + tig;
                    Bhf[nt][0] = KVhW[rr]; Bhf[nt][1] = KVhW[rr + 4];
                    Blf[nt][0] = KVlW[rr]; Blf[nt][1] = KVlW[rr + 4];
                }
#pragma unroll
                for (int nt = 0; nt < 8; nt++) {
                    MMA_BF16(oacc[nt], Ahf, Bhf[nt]);
                    MMA_BF16(oacc[nt], Ahf, Blf[nt]);
                    MMA_BF16(oacc[nt], Alf, Bhf[nt]);
                }
            }
        }

        {
            int rowA = mrowO + gid, rowB = rowA + 8;
            float invA = 1.f / rsum[rowA];
            float invB = 1.f / rsum[rowB];
            int pA = r0 + rowA, pB = r0 + rowB;
            int pixA = (py0 + (pA >> 4)) * 256 + px0 + (pA & 15);
            int pixB = (py0 + (pB >> 4)) * 256 + px0 + (pB & 15);
#pragma unroll
            for (int nt = 0; nt < 8; nt++) {
                int ch = ncolO + nt * 8 + tig * 2;
                g_OUT[cbase + ch * HW + pixA] = oacc[nt][0] * invA;
                g_OUT[cbase + (ch + 1) * HW + pixA] = oacc[nt][1] * invA;
                g_OUT[cbase + ch * HW + pixB] = oacc[nt][2] * invB;
                g_OUT[cbase + (ch + 1) * HW + pixB] = oacc[nt][3] * invB;
            }
        }
    }
}

// ---------------- depthwise 5x5 (dilation param; optional fused gelu*ca + residual) ----------------
__global__ void dw5_kernel(const float* __restrict__ in, const float* __restrict__ w,
                           const float* __restrict__ bias, float* __restrict__ out,
                           int dil, int fuse) {
    __shared__ float ws[25];
    int c = blockIdx.z & 127, b = blockIdx.z >> 7;
    int t = threadIdx.y * 32 + threadIdx.x;
    if (t < 25) ws[t] = w[c * 25 + t];
    __syncthreads();
    int x = blockIdx.x * 32 + threadIdx.x;
    int y = blockIdx.y * 8 + threadIdx.y;
    const float* ip = in + (size_t)(b * CH + c) * HW;
    float acc = __ldg(&bias[c]);
#pragma unroll
    for (int ky = 0; ky < 5; ky++) {
        int yy = y + (ky - 2) * dil;
        if ((unsigned)yy >= 256u) continue;
#pragma unroll
        for (int kx = 0; kx < 5; kx++) {
            int xx = x + (kx - 2) * dil;
            if ((unsigned)xx >= 256u) continue;
            acc = fmaf(ws[ky * 5 + kx], __ldg(&ip[yy * 256 + xx]), acc);
        }
    }
    size_t oidx = (size_t)(b * CH + c) * HW + y * 256 + x;
    if (fuse) {
        float g = 0.5f * acc * (1.f + erff(acc * 0.7071067811865475f));
        out[oidx] = g * g_CA[b * CH + c] + g_OUT[oidx];
    } else {
        out[oidx] = acc;
    }
}

// ---------------- launch ----------------
extern "C" void kernel_launch(void* const* d_in, const int* in_sizes, int n_in,
                              void* d_out, int out_size) {
    const float* x      = (const float*)d_in[0];
    const float* cond_g = (const float*)d_in[1];
    const float* gu     = (const float*)d_in[2];
    const float* pv_w   = (const float*)d_in[3];
    const float* pv_b   = (const float*)d_in[4];
    const float* pq_w   = (const float*)d_in[5];
    const float* pq_b   = (const float*)d_in[6];
    const float* pk_w   = (const float*)d_in[7];
    const float* pk_b   = (const float*)d_in[8];
    const float* cs1_w  = (const float*)d_in[9];
    const float* cs1_b  = (const float*)d_in[10];
    const float* cs2_w  = (const float*)d_in[11];
    const float* cs2_b  = (const float*)d_in[12];
    const float* cs3_w  = (const float*)d_in[13];
    const float* cs3_b  = (const float*)d_in[14];
    const float* po_w   = (const float*)d_in[15];
    const float* po_b   = (const float*)d_in[16];
    const float* rin_w  = (const float*)d_in[17];
    const float* rin_b  = (const float*)d_in[18];
    const float* r1w    = (const float*)d_in[19];
    const float* r1b    = (const float*)d_in[20];
    const float* r2w    = (const float*)d_in[21];
    const float* r2b    = (const float*)d_in[22];
    const float* rm1_w  = (const float*)d_in[23];
    const float* rm1_b  = (const float*)d_in[24];
    const float* rm2_w  = (const float*)d_in[25];
    const float* rm2_b  = (const float*)d_in[26];
    const float* rca_w  = (const float*)d_in[27];
    const float* rca_b  = (const float*)d_in[28];
    const float* rsa_w  = (const float*)d_in[29];
    const float* rsa_b  = (const float*)d_in[30];

    float *pV, *pOUT, *pT1, *pT2;
    __nv_bfloat16* pWT;
    cudaGetSymbolAddress((void**)&pV, g_V);
    cudaGetSymbolAddress((void**)&pOUT, g_OUT);
    cudaGetSymbolAddress((void**)&pT1, g_T1);
    cudaGetSymbolAddress((void**)&pT2, g_T2);
    cudaGetSymbolAddress((void**)&pWT, g_WT);

    cudaFuncSetAttribute(attn_mma_kernel, cudaFuncAttributeMaxDynamicSharedMemorySize, SMEM_ATTN2);
    cudaFuncSetAttribute(conv1x1_mma, cudaFuncAttributeMaxDynamicSharedMemorySize, CV_SMEM);
    cudaFuncSetAttribute(convqk_mma, cudaFuncAttributeMaxDynamicSharedMemorySize, QK_SMEM);

    const int WSET = 2 * 128 * 136;
    dim3 ghw(512, BB);

    // preps first so ncu -s 5 lands on conv1x1_mma (launch #5)
    prep_w_kernel<<<64, 256>>>(pv_w, 0);
    prep_w_kernel<<<64, 256>>>(pq_w, 1);
    prep_w_kernel<<<64, 256>>>(pk_w, 2);
    prep_w_kernel<<<64, 256>>>(cs1_w, 3);
    prep_w_kernel<<<64, 256>>>(po_w, 4);
    // v = pv(x)   <- launch #5, profiled
    conv1x1_mma<<<ghw, 256, CV_SMEM>>>(x, pWT + 0 * WSET, pv_b, pV, 0);
    zero_fsum_kernel<<<1, 128>>>();
    predictor_kernel<<<dim3(HW / 512, BB), 256>>>(cond_g, rin_w, rin_b, r1w, r1b, r2w, r2b);
    ca_kernel<<<BB, 128>>>(rca_w, rca_b);
    sa_kernel<<<dim3(HW / 256, BB), 256>>>(rsa_w, rsa_b);
    mask_kernel<<<dim3(256, BB), 256>>>(gu, rm1_w, rm1_b, rm2_w, rm2_b);
    // fused flow-warp + q/k projections (masked windows only)
    convqk_mma<<<ghw, 256, QK_SMEM>>>(x, pWT + 1 * WSET, pWT + 2 * WSET, pq_b, pk_b);
    attn_mma_kernel<<<dim3(256, BB), 256, SMEM_ATTN2>>>();
    conv1x1_mma<<<ghw, 256, CV_SMEM>>>(pOUT, pWT + 3 * WSET, cs1_b, pT1, 0);
    dw5_kernel<<<dim3(8, 32, BB * CH), dim3(32, 8)>>>(pT1, cs2_w, cs2_b, pT2, 1, 0);
    dw5_kernel<<<dim3(8, 32, BB * CH), dim3(32, 8)>>>(pT2, cs3_w, cs3_b, pT1, 3, 1);
    conv1x1_mma<<<ghw, 256, CV_SMEM>>>(pT1, pWT + 4 * WSET, po_b, (float*)d_out, 0);
}

// round 7
// speedup vs baseline: 1.7112x; 1.0006x over previous
#include <cuda_runtime.h>
#include <cuda_bf16.h>
#include <stdint.h>
#include <math.h>

#define HW 65536
#define WIMG 256
#define CH 128
#define BB 4
#define ELT (BB*CH*HW)

// ---------------- scratch (static device globals; no runtime alloc) ----------------
__device__ float g_V[ELT];
__device__ float g_Qb[ELT];
__device__ float g_Kb[ELT];
__device__ float g_OUT[ELT];
__device__ float g_T1[ELT];
__device__ float g_T2[ELT];
__device__ float g_F[BB*32*HW];
__device__ float g_OFF[BB*2*HW];
__device__ float g_FMC[BB*HW];
__device__ float g_SA[BB*HW];
__device__ float g_FSUM[BB*32];
__device__ float g_CA[BB*CH];
__device__ float g_MASK[BB*256];
// hi/lo bf16 weights, row-padded to 136 (stride-68-word smem => conflict-free frags)
__device__ __align__(16) __nv_bfloat16 g_WT[5][2][128*136];

__device__ __forceinline__ float leakyf(float x) { return x > 0.f ? x : 0.2f * x; }

__global__ void zero_fsum_kernel() {
    g_FSUM[threadIdx.x] = 0.f;
}

// ---------------- weight prep: fp32 -> bf16 hi/lo, padded rows ----------------
__global__ void prep_w_kernel(const float* __restrict__ w, int set) {
    int i = blockIdx.x * 256 + threadIdx.x;
    int oc = i >> 7, ci = i & 127;
    float v = w[i];
    __nv_bfloat16 h = __float2bfloat16_rn(v);
    __nv_bfloat16 l = __float2bfloat16_rn(v - __bfloat162float(h));
    g_WT[set][0][oc * 136 + ci] = h;
    g_WT[set][1][oc * 136 + ci] = l;
}

// ---------------- HMMA m16n8k16 bf16 ----------------
#define MMA_BF16(d, a, b) \
    asm volatile("mma.sync.aligned.m16n8k16.row.col.f32.bf16.bf16.f32 " \
        "{%0,%1,%2,%3}, {%4,%5,%6,%7}, {%8,%9}, {%0,%1,%2,%3};" \
        : "+f"((d)[0]), "+f"((d)[1]), "+f"((d)[2]), "+f"((d)[3]) \
        : "r"((a)[0]), "r"((a)[1]), "r"((a)[2]), "r"((a)[3]), "r"((b)[0]), "r"((b)[1]))

#define CV_SMEM (4 * 128 * 136 * 2)

// ---- shared GEMM body: W(hi/lo smem) x X(hi/lo smem) -> y window half ----
__device__ __forceinline__ void gemm_body_128(
    const uint32_t* WhW, const uint32_t* WlW,
    const uint32_t* XhW, const uint32_t* XlW,
    const float* __restrict__ bias, float* __restrict__ yb,
    int py0, int px0, int half, int w, int gid, int tig) {
    int oc0 = (w & 3) * 32;
    int n0 = (w >> 2) * 64;
    float acc[16][4];
#pragma unroll
    for (int i = 0; i < 16; i++)
#pragma unroll
        for (int j = 0; j < 4; j++) acc[i][j] = 0.f;
#pragma unroll 1
    for (int ks = 0; ks < 8; ks++) {
        int kw = ks * 8;
        uint32_t Ah[2][4], Al[2][4], Bh[8][2], Bl[8][2];
#pragma unroll
        for (int mt = 0; mt < 2; mt++) {
            int r0 = (oc0 + mt * 16 + gid) * 68 + kw + tig;
            int r8 = r0 + 8 * 68;
            Ah[mt][0] = WhW[r0];     Ah[mt][1] = WhW[r8];
            Ah[mt][2] = WhW[r0 + 4]; Ah[mt][3] = WhW[r8 + 4];
            Al[mt][0] = WlW[r0];     Al[mt][1] = WlW[r8];
            Al[mt][2] = WlW[r0 + 4]; Al[mt][3] = WlW[r8 + 4];
        }
#pragma unroll
        for (int nt = 0; nt < 8; nt++) {
            int rr = (n0 + nt * 8 + gid) * 68 + kw + tig;
            Bh[nt][0] = XhW[rr]; Bh[nt][1] = XhW[rr + 4];
            Bl[nt][0] = XlW[rr]; Bl[nt][1] = XlW[rr + 4];
        }
#pragma unroll
        for (int mt = 0; mt < 2; mt++)
#pragma unroll
            for (int nt = 0; nt < 8; nt++) {
                MMA_BF16(acc[mt * 8 + nt], Ah[mt], Bh[nt]);
                MMA_BF16(acc[mt * 8 + nt], Ah[mt], Bl[nt]);
                MMA_BF16(acc[mt * 8 + nt], Al[mt], Bh[nt]);
            }
    }
#pragma unroll
    for (int mt = 0; mt < 2; mt++) {
        int ocA = oc0 + mt * 16 + gid;
        int ocB = ocA + 8;
        float bvA = __ldg(&bias[ocA]);
        float bvB = __ldg(&bias[ocB]);
#pragma unroll
        for (int nt = 0; nt < 8; nt++) {
            int col = n0 + nt * 8 + tig * 2;
            int p = half * 128 + col;
            int pix = (py0 + (p >> 4)) * 256 + px0 + (p & 15);
            float2 v0 = make_float2(acc[mt * 8 + nt][0] + bvA, acc[mt * 8 + nt][1] + bvA);
            float2 v1 = make_float2(acc[mt * 8 + nt][2] + bvB, acc[mt * 8 + nt][3] + bvB);
            *(float2*)(yb + (size_t)ocA * HW + pix) = v0;
            *(float2*)(yb + (size_t)ocB * HW + pix) = v1;
        }
    }
}

// ---------------- conv1x1 GEMM via mma.sync (proven) ----------------
__global__ void __launch_bounds__(256, 1)
conv1x1_mma(const float* __restrict__ xin, const __nv_bfloat16* __restrict__ wsp,
            const float* __restrict__ bias, float* __restrict__ yout, int useMask) {
    int hw = blockIdx.x, b = blockIdx.y;
    int n = hw >> 1, half = hw & 1;
    if (useMask && g_MASK[b * 256 + n] == 0.f) return;
    extern __shared__ __nv_bfloat16 smb[];
    __nv_bfloat16* Wh = smb;
    __nv_bfloat16* Wl = Wh + 128 * 136;
    __nv_bfloat16* Xh = Wl + 128 * 136;
    __nv_bfloat16* Xl = Xh + 128 * 136;
    int t = threadIdx.x;

    {
        const uint4* src = (const uint4*)wsp;
        uint4* dst = (uint4*)smb;
#pragma unroll
        for (int i = 0; i < 17; i++) dst[t + i * 256] = src[t + i * 256];
    }

    int py0 = (n >> 4) * 16, px0 = (n & 15) * 16;
    const float* xb = xin + (size_t)b * CH * HW;
    {
        int px = t & 127;
        int p = half * 128 + px;
        int pix = (py0 + (p >> 4)) * 256 + px0 + (p & 15);
        int cp0 = t >> 7;
#pragma unroll
        for (int j = 0; j < 32; j++) {
            int cp = cp0 + j * 2;
            float v0 = xb[(size_t)(2 * cp) * HW + pix];
            float v1 = xb[(size_t)(2 * cp + 1) * HW + pix];
            __nv_bfloat16 h0 = __float2bfloat16_rn(v0);
            __nv_bfloat16 h1 = __float2bfloat16_rn(v1);
            __nv_bfloat16 l0 = __float2bfloat16_rn(v0 - __bfloat162float(h0));
            __nv_bfloat16 l1 = __float2bfloat16_rn(v1 - __bfloat162float(h1));
            ((__nv_bfloat162*)(Xh + px * 136))[cp] = __nv_bfloat162(h0, h1);
            ((__nv_bfloat162*)(Xl + px * 136))[cp] = __nv_bfloat162(l0, l1);
        }
    }
    __syncthreads();

    int w = t >> 5, lane = t & 31;
    int gid = lane >> 2, tig = lane & 3;
    gemm_body_128((const uint32_t*)Wh, (const uint32_t*)Wl,
                  (const uint32_t*)Xh, (const uint32_t*)Xl,
                  bias, yout + (size_t)b * CH * HW, py0, px0, half, w, gid, tig);
}

// ---------------- fused flow-warp + q/k projections (masked windows only) ----------------
// smem: Wqh|Wql|Wkh|Wkl|Xh|Xl  (6 x 128*136 bf16 = 208896 B)
#define QK_SMEM (6 * 128 * 136 * 2)
__global__ void __launch_bounds__(256, 1)
convqk_mma(const float* __restrict__ xin,
           const __nv_bfloat16* __restrict__ wq, const __nv_bfloat16* __restrict__ wk,
           const float* __restrict__ qbias, const float* __restrict__ kbias) {
    int hw = blockIdx.x, b = blockIdx.y;
    int n = hw >> 1, half = hw & 1;
    if (g_MASK[b * 256 + n] == 0.f) return;
    extern __shared__ __nv_bfloat16 smb[];
    __nv_bfloat16* Wqh = smb;
    __nv_bfloat16* Wql = Wqh + 128 * 136;
    __nv_bfloat16* Wkh = Wql + 128 * 136;
    __nv_bfloat16* Wkl = Wkh + 128 * 136;
    __nv_bfloat16* Xh  = Wkl + 128 * 136;
    __nv_bfloat16* Xl  = Xh + 128 * 136;
    int t = threadIdx.x;

    // copy both weight sets (2 x 69632 B = 8704 uint4)
    {
        const uint4* srcq = (const uint4*)wq;
        const uint4* srck = (const uint4*)wk;
        uint4* dstq = (uint4*)Wqh;
        uint4* dstk = (uint4*)Wkh;
#pragma unroll
        for (int i = 0; i < 17; i++) {
            dstq[t + i * 256] = srcq[t + i * 256];
            dstk[t + i * 256] = srck[t + i * 256];
        }
    }

    // ---- stage X = flow_warp(x) window half, hi/lo bf16 (gather inline) ----
    int py0 = (n >> 4) * 16, px0 = (n & 15) * 16;
    {
        int px = t & 127;
        int p = half * 128 + px;
        int gy = py0 + (p >> 4), gx = px0 + (p & 15);
        int pp = gy * 256 + gx;
        const float* OFb = g_OFF + (size_t)b * 2 * HW;
        float fx = OFb[pp];
        float fy = OFb[HW + pp];
        float sx = fminf(fmaxf((float)gx + fx, 0.f), 255.f);
        float sy = fminf(fmaxf((float)gy + fy, 0.f), 255.f);
        float x0f = floorf(sx), y0f = floorf(sy);
        float x1f = fminf(x0f + 1.f, 255.f), y1f = fminf(y0f + 1.f, 255.f);
        float wx = sx - x0f, wy = sy - y0f;
        int x0 = (int)x0f, x1 = (int)x1f, y0 = (int)y0f, y1 = (int)y1f;
        int iA = y0 * 256 + x0, iB = y0 * 256 + x1, iC = y1 * 256 + x0, iD = y1 * 256 + x1;
        float w00 = (1.f - wx) * (1.f - wy), w01 = wx * (1.f - wy);
        float w10 = (1.f - wx) * wy, w11 = wx * wy;
        const float* xb = xin + (size_t)b * CH * HW;
        int cp0 = t >> 7;
#pragma unroll 4
        for (int j = 0; j < 32; j++) {
            int cp = cp0 + j * 2;
            const float* xc0 = xb + (size_t)(2 * cp) * HW;
            const float* xc1 = xc0 + HW;
            float v0 = __ldg(&xc0[iA]) * w00 + __ldg(&xc0[iB]) * w01 +
                       __ldg(&xc0[iC]) * w10 + __ldg(&xc0[iD]) * w11;
            float v1 = __ldg(&xc1[iA]) * w00 + __ldg(&xc1[iB]) * w01 +
                       __ldg(&xc1[iC]) * w10 + __ldg(&xc1[iD]) * w11;
            __nv_bfloat16 h0 = __float2bfloat16_rn(v0);
            __nv_bfloat16 h1 = __float2bfloat16_rn(v1);
            __nv_bfloat16 l0 = __float2bfloat16_rn(v0 - __bfloat162float(h0));
            __nv_bfloat16 l1 = __float2bfloat16_rn(v1 - __bfloat162float(h1));
            ((__nv_bfloat162*)(Xh + px * 136))[cp] = __nv_bfloat162(h0, h1);
            ((__nv_bfloat162*)(Xl + px * 136))[cp] = __nv_bfloat162(l0, l1);
        }
    }
    __syncthreads();

    int w = t >> 5, lane = t & 31;
    int gid = lane >> 2, tig = lane & 3;
    // Q = Wq . X
    gemm_body_128((const uint32_t*)Wqh, (const uint32_t*)Wql,
                  (const uint32_t*)Xh, (const uint32_t*)Xl,
                  qbias, g_Qb + (size_t)b * CH * HW, py0, px0, half, w, gid, tig);
    // K = Wk . X  (X unchanged; no sync needed, reads only)
    gemm_body_128((const uint32_t*)Wkh, (const uint32_t*)Wkl,
                  (const uint32_t*)Xh, (const uint32_t*)Xl,
                  kbias, g_Kb + (size_t)b * CH * HW, py0, px0, half, w, gid, tig);
}

// ---------------- predictor ----------------
__global__ void predictor_kernel(const float* __restrict__ cond_g,
                                 const float* __restrict__ rin_w, const float* __restrict__ rin_b,
                                 const float* __restrict__ r1w, const float* __restrict__ r1b,
                                 const float* __restrict__ r2w, const float* __restrict__ r2b) {
    __shared__ float wr[32 * 131];
    __shared__ float wr1[16 * 32];
    __shared__ float wr2[32];
    __shared__ float partial[8][32];
    int t = threadIdx.x;
    int b = blockIdx.y;
    for (int i = t; i < 32 * 131; i += 256) wr[i] = rin_w[i];
    for (int i = t; i < 16 * 32; i += 256) wr1[i] = r1w[i];
    if (t < 32) wr2[t] = r2w[t];
    __syncthreads();

    int p0 = blockIdx.x * 512 + t;
    int p1 = p0 + 256;
    float a0[32], a1[32];
#pragma unroll
    for (int o = 0; o < 32; o++) {
        float bv = __ldg(&rin_b[o]);
        a0[o] = bv; a1[o] = bv;
    }
    const float* vb = g_V + (size_t)b * CH * HW;
#pragma unroll 2
    for (int ci = 0; ci < 128; ci++) {
        float x0 = vb[(size_t)ci * HW + p0];
        float x1 = vb[(size_t)ci * HW + p1];
#pragma unroll
        for (int o = 0; o < 32; o++) {
            float wv = wr[o * 131 + ci];
            a0[o] = fmaf(wv, x0, a0[o]);
            a1[o] = fmaf(wv, x1, a1[o]);
        }
    }
    float cg0 = __ldg(&cond_g[b * HW + p0]);
    float cg1 = __ldg(&cond_g[b * HW + p1]);
    int y0 = p0 >> 8, x0p = p0 & 255;
    int y1 = p1 >> 8, x1p = p1 & 255;
    float ly0 = -1.f + (float)(y0 & 15) * (2.f / 15.f);
    float lx0 = -1.f + (float)(x0p & 15) * (2.f / 15.f);
    float ly1 = -1.f + (float)(y1 & 15) * (2.f / 15.f);
    float lx1 = -1.f + (float)(x1p & 15) * (2.f / 15.f);
    float fm0 = 0.f, fm1 = 0.f;
    float* Fb = g_F + (size_t)b * 32 * HW;
#pragma unroll
    for (int o = 0; o < 32; o++) {
        float v0 = a0[o] + wr[o * 131 + 128] * cg0 + wr[o * 131 + 129] * ly0 + wr[o * 131 + 130] * lx0;
        float v1 = a1[o] + wr[o * 131 + 128] * cg1 + wr[o * 131 + 129] * ly1 + wr[o * 131 + 130] * lx1;
        v0 = leakyf(v0); v1 = leakyf(v1);
        a0[o] = v0; a1[o] = v1;
        Fb[(size_t)o * HW + p0] = v0;
        Fb[(size_t)o * HW + p1] = v1;
        fm0 += v0; fm1 += v1;
    }
    g_FMC[b * HW + p0] = fm0 * (1.f / 32.f);
    g_FMC[b * HW + p1] = fm1 * (1.f / 32.f);

    float h0[16], h1v[16];
#pragma unroll
    for (int o2 = 0; o2 < 16; o2++) {
        float bv = __ldg(&r1b[o2]);
        float s0 = bv, s1 = bv;
#pragma unroll
        for (int o = 0; o < 32; o++) {
            float wv = wr1[o2 * 32 + o];
            s0 = fmaf(wv, a0[o], s0);
            s1 = fmaf(wv, a1[o], s1);
        }
        h0[o2] = leakyf(s0);
        h1v[o2] = leakyf(s1);
    }
    float ox0 = __ldg(&r2b[0]), oy0 = __ldg(&r2b[1]);
    float ox1 = ox0, oy1 = oy0;
#pragma unroll
    for (int o2 = 0; o2 < 16; o2++) {
        ox0 = fmaf(wr2[o2], h0[o2], ox0);
        oy0 = fmaf(wr2[16 + o2], h0[o2], oy0);
        ox1 = fmaf(wr2[o2], h1v[o2], ox1);
        oy1 = fmaf(wr2[16 + o2], h1v[o2], oy1);
    }
    float* OFb = g_OFF + (size_t)b * 2 * HW;
    OFb[p0] = ox0; OFb[p1] = ox1;
    OFb[HW + p0] = oy0; OFb[HW + p1] = oy1;

    int lane = t & 31, wid = t >> 5;
#pragma unroll
    for (int o = 0; o < 32; o++) {
        float v = a0[o] + a1[o];
        v += __shfl_xor_sync(0xffffffff, v, 16);
        v += __shfl_xor_sync(0xffffffff, v, 8);
        v += __shfl_xor_sync(0xffffffff, v, 4);
        v += __shfl_xor_sync(0xffffffff, v, 2);
        v += __shfl_xor_sync(0xffffffff, v, 1);
        if (lane == 0) partial[wid][o] = v;
    }
    __syncthreads();
    if (t < 32) {
        float s = 0.f;
#pragma unroll
        for (int w2 = 0; w2 < 8; w2++) s += partial[w2][t];
        atomicAdd(&g_FSUM[b * 32 + t], s);
    }
}

// ---------------- channel attention ca ----------------
__global__ void ca_kernel(const float* __restrict__ rca_w, const float* __restrict__ rca_b) {
    int c = threadIdx.x;
    int b = blockIdx.x;
    float s = __ldg(&rca_b[c]);
#pragma unroll
    for (int ci = 0; ci < 32; ci++)
        s = fmaf(__ldg(&rca_w[c * 32 + ci]), g_FSUM[b * 32 + ci] * (1.f / 65536.f), s);
    g_CA[b * CH + c] = 1.f / (1.f + expf(-s));
}

// ---------------- spatial attention sa ----------------
__global__ void sa_kernel(const float* __restrict__ rsa_w, const float* __restrict__ rsa_b) {
    __shared__ float ws[288];
    int t = threadIdx.x;
    for (int i = t; i < 288; i += 256) ws[i] = rsa_w[i];
    __syncthreads();
    int b = blockIdx.y;
    int p = blockIdx.x * 256 + t;
    int y = p >> 8, x = p & 255;
    float acc = __ldg(&rsa_b[0]);
    const float* Fb = g_F + (size_t)b * 32 * HW;
    for (int ci = 0; ci < 32; ci++) {
        const float* fp = Fb + (size_t)ci * HW;
#pragma unroll
        for (int ky = 0; ky < 3; ky++) {
            int yy = y + ky - 1;
            if ((unsigned)yy >= 256u) continue;
#pragma unroll
            for (int kx = 0; kx < 3; kx++) {
                int xx = x + kx - 1;
                if ((unsigned)xx >= 256u) continue;
                acc = fmaf(ws[ci * 9 + ky * 3 + kx], __ldg(&fp[yy * 256 + xx]), acc);
            }
        }
    }
    g_SA[b * HW + p] = 1.f / (1.f + expf(-acc));
}

// ---------------- window MLP + gumbel hard mask ----------------
__global__ void mask_kernel(const float* __restrict__ gu,
                            const float* __restrict__ rm1_w, const float* __restrict__ rm1_b,
                            const float* __restrict__ rm2_w, const float* __restrict__ rm2_b) {
    __shared__ float m[256];
    __shared__ float h1s[16];
    int n = blockIdx.x, b = blockIdx.y;
    int t = threadIdx.x;
    int dh = t >> 4, dw = t & 15;
    int pix = ((n >> 4) * 16 + dh) * 256 + (n & 15) * 16 + dw;
    m[t] = g_FMC[b * HW + pix];
    __syncthreads();
    if (t < 16) {
        float s = __ldg(&rm1_b[t]);
        for (int e = 0; e < 256; e++) s = fmaf(__ldg(&rm1_w[t * 256 + e]), m[e], s);
        h1s[t] = leakyf(s);
    }
    __syncthreads();
    if (t == 0) {
        float z0 = __ldg(&rm2_b[0]), z1 = __ldg(&rm2_b[1]);
#pragma unroll
        for (int o = 0; o < 16; o++) {
            z0 = fmaf(__ldg(&rm2_w[o]), h1s[o], z0);
            z1 = fmaf(__ldg(&rm2_w[16 + o]), h1s[o], z1);
        }
        float mx = fmaxf(z0, z1);
        float e0 = expf(z0 - mx), e1 = expf(z1 - mx);
        float inv = 1.f / (e0 + e1);
        float p0 = e0 * inv, p1 = e1 * inv;
        float u0 = __ldg(&gu[(b * 256 + n) * 2 + 0]);
        float u1 = __ldg(&gu[(b * 256 + n) * 2 + 1]);
        float g0 = -logf(-logf(u0 + 1e-10f) + 1e-10f);
        float g1 = -logf(-logf(u1 + 1e-10f) + 1e-10f);
        g_MASK[b * 256 + n] = (p0 + g0 >= p1 + g1) ? 1.f : 0.f;
    }
}

// ---------------- window attention via mma.sync (masked) / v*sa (unmasked) ----------------
#define SMEM_ATTN2 (67328 + 90112)
__global__ void __launch_bounds__(256, 1) attn_mma_kernel() {
    int n = blockIdx.x, b = blockIdx.y;
    int t = threadIdx.x;
    int py0 = (n >> 4) * 16, px0 = (n & 15) * 16;
    int cbase = b * CH * HW;
    if (g_MASK[b * 256 + n] == 0.f) {
        const float* sab = g_SA + (size_t)b * HW;
#pragma unroll 4
        for (int i = t; i < 8192; i += 256) {
            int ch = i >> 6, r4 = i & 63;
            int wrow = r4 >> 2, px4 = (r4 & 3) * 4;
            int pix = (py0 + wrow) * 256 + px0 + px4;
            float4 v = *(const float4*)(g_V + cbase + ch * HW + pix);
            float4 s = *(const float4*)(sab + pix);
            v.x *= s.x; v.y *= s.y; v.z *= s.z; v.w *= s.w;
            *(float4*)(g_OUT + cbase + ch * HW + pix) = v;
        }
        return;
    }
    extern __shared__ char smraw[];
    float* S = (float*)smraw;
    float* red = S + 64 * 257;
    float* rmax = red + 256;
    float* rsum = rmax + 64;
    __nv_bfloat16* Qh = (__nv_bfloat16*)(rsum + 64);
    __nv_bfloat16* Ql = Qh + 64 * 136;
    __nv_bfloat16* KVh = Ql + 64 * 136;
    __nv_bfloat16* KVl = KVh + 9216;
    __nv_bfloat16* Pth = KVl + 9216;
    __nv_bfloat16* Ptl = Pth + 64 * 72;

    const uint32_t* QhW = (const uint32_t*)Qh;
    const uint32_t* QlW = (const uint32_t*)Ql;
    const uint32_t* KVhW = (const uint32_t*)KVh;
    const uint32_t* KVlW = (const uint32_t*)KVl;
    const uint32_t* PthW = (const uint32_t*)Pth;
    const uint32_t* PtlW = (const uint32_t*)Ptl;

    int w = t >> 5, lane = t & 31;
    int gid = lane >> 2;
    int tig = lane & 3;

#pragma unroll 1
    for (int rc = 0; rc < 4; rc++) {
        int r0 = rc * 64;
        __syncthreads();
#pragma unroll
        for (int j = 0; j < 16; j++) {
            int i = t + j * 256;
            int px = i & 63, cp = i >> 6;
            int p = r0 + px;
            int pix = (py0 + (p >> 4)) * 256 + px0 + (p & 15);
            float v0 = g_Qb[cbase + (2 * cp) * HW + pix];
            float v1 = g_Qb[cbase + (2 * cp + 1) * HW + pix];
            __nv_bfloat16 h0 = __float2bfloat16_rn(v0);
            __nv_bfloat16 h1 = __float2bfloat16_rn(v1);
            __nv_bfloat16 l0 = __float2bfloat16_rn(v0 - __bfloat162float(h0));
            __nv_bfloat16 l1 = __float2bfloat16_rn(v1 - __bfloat162float(h1));
            ((__nv_bfloat162*)(Qh + px * 136))[cp] = __nv_bfloat162(h0, h1);
            ((__nv_bfloat162*)(Ql + px * 136))[cp] = __nv_bfloat162(l0, l1);
        }

        int mrowS = (w & 3) * 16, ncolS = (w >> 2) * 32;
#pragma unroll 1
        for (int kvt = 0; kvt < 4; kvt++) {
            __syncthreads();
#pragma unroll
            for (int j = 0; j < 16; j++) {
                int i = t + j * 256;
                int px = i & 63, cp = i >> 6;
                int p = kvt * 64 + px;
                int pix = (py0 + (p >> 4)) * 256 + px0 + (p & 15);
                float v0 = g_Kb[cbase + (2 * cp) * HW + pix];
                float v1 = g_Kb[cbase + (2 * cp + 1) * HW + pix];
                __nv_bfloat16 h0 = __float2bfloat16_rn(v0);
                __nv_bfloat16 h1 = __float2bfloat16_rn(v1);
                __nv_bfloat16 l0 = __float2bfloat16_rn(v0 - __bfloat162float(h0));
                __nv_bfloat16 l1 = __float2bfloat16_rn(v1 - __bfloat162float(h1));
                ((__nv_bfloat162*)(KVh + px * 136))[cp] = __nv_bfloat162(h0, h1);
                ((__nv_bfloat162*)(KVl + px * 136))[cp] = __nv_bfloat162(l0, l1);
            }
            __syncthreads();
            float acc[4][4];
#pragma unroll
            for (int i = 0; i < 4; i++)
#pragma unroll
                for (int j2 = 0; j2 < 4; j2++) acc[i][j2] = 0.f;
#pragma unroll
            for (int ks = 0; ks < 8; ks++) {
                int kw = ks * 8;
                uint32_t Ahf[4], Alf[4], Bhf[4][2], Blf[4][2];
                int ra = (mrowS + gid) * 68 + kw + tig;
                int ra8 = ra + 8 * 68;
                Ahf[0] = QhW[ra];     Ahf[1] = QhW[ra8];
                Ahf[2] = QhW[ra + 4]; Ahf[3] = QhW[ra8 + 4];
                Alf[0] = QlW[ra];     Alf[1] = QlW[ra8];
                Alf[2] = QlW[ra + 4]; Alf[3] = QlW[ra8 + 4];
#pragma unroll
                for (int nt = 0; nt < 4; nt++) {
                    int rr = (ncolS + nt * 8 + gid) * 68 + kw + tig;
                    Bhf[nt][0] = KVhW[rr]; Bhf[nt][1] = KVhW[rr + 4];
                    Blf[nt][0] = KVlW[rr]; Blf[nt][1] = KVlW[rr + 4];
                }
#pragma unroll
                for (int nt = 0; nt < 4; nt++) {
                    MMA_BF16(acc[nt], Ahf, Bhf[nt]);
                    MMA_BF16(acc[nt], Ahf, Blf[nt]);
                    MMA_BF16(acc[nt], Alf, Bhf[nt]);
                }
            }
#pragma unroll
            for (int nt = 0; nt < 4; nt++) {
                int col = kvt * 64 + ncolS + nt * 8 + tig * 2;
                S[(mrowS + gid) * 257 + col] = acc[nt][0];
                S[(mrowS + gid) * 257 + col + 1] = acc[nt][1];
                S[(mrowS + gid + 8) * 257 + col] = acc[nt][2];
                S[(mrowS + gid + 8) * 257 + col + 1] = acc[nt][3];
            }
        }
        __syncthreads();

        {
            int r = t & 63, seg = t >> 6;
            float* srow = &S[r * 257 + seg * 64];
            float mx = -1e30f;
#pragma unroll 8
            for (int k = 0; k < 64; k++) mx = fmaxf(mx, srow[k]);
            red[seg * 64 + r] = mx;
            __syncthreads();
            if (t < 64)
                rmax[t] = fmaxf(fmaxf(red[t], red[64 + t]), fmaxf(red[128 + t], red[192 + t]));
            __syncthreads();
            float rm_ = rmax[r];
            float s = 0.f;
#pragma unroll 8
            for (int k = 0; k < 64; k++) {
                float e = __expf(srow[k] - rm_);
                srow[k] = e;
                s += e;
            }
            red[seg * 64 + r] = s;
            __syncthreads();
            if (t < 64) rsum[t] = red[t] + red[64 + t] + red[128 + t] + red[192 + t];
            __syncthreads();
        }

        int mrowO = (w & 3) * 16, ncolO = (w >> 2) * 64;
        float oacc[8][4];
#pragma unroll
        for (int i = 0; i < 8; i++)
#pragma unroll
            for (int j2 = 0; j2 < 4; j2++) oacc[i][j2] = 0.f;

#pragma unroll 1
        for (int kvt = 0; kvt < 4; kvt++) {
            __syncthreads();
#pragma unroll
            for (int j = 0; j < 16; j++) {
                int i = t + j * 256;
                int col = i & 63, row = i >> 6;
                float v = S[row * 257 + kvt * 64 + col];
                __nv_bfloat16 h = __float2bfloat16_rn(v);
                Pth[row * 72 + col] = h;
                Ptl[row * 72 + col] = __float2bfloat16_rn(v - __bfloat162float(h));
            }
#pragma unroll
            for (int j = 0; j < 32; j++) {
                int i = t + j * 256;
                int px = i & 63, ch = i >> 6;
                int p = kvt * 64 + px;
                int pix = (py0 + (p >> 4)) * 256 + px0 + (p & 15);
                float v = g_V[cbase + ch * HW + pix];
                __nv_bfloat16 h = __float2bfloat16_rn(v);
                KVh[ch * 72 + px] = h;
                KVl[ch * 72 + px] = __float2bfloat16_rn(v - __bfloat162float(h));
            }
            __syncthreads();
#pragma unroll
            for (int ks = 0; ks < 4; ks++) {
                int kw = ks * 8;
                uint32_t Ahf[4], Alf[4], Bhf[8][2], Blf[8][2];
                int ra = (mrowO + gid) * 36 + kw + tig;
                int ra8 = ra + 8 * 36;
                Ahf[0] = PthW[ra];     Ahf[1] = PthW[ra8];
                Ahf[2] = PthW[ra + 4]; Ahf[3] = PthW[ra8 + 4];
                Alf[0] = PtlW[ra];     Alf[1] = PtlW[ra8];
                Alf[2] = PtlW[ra + 4]; Alf[3] = PtlW[ra8 + 4];
#pragma unroll
                for (int nt = 0; nt < 8; nt++) {
                    int rr = (ncolO + nt * 8 + gid) * 36 + kw + tig;
                    Bhf[nt][0] = KVhW[rr]; Bhf[nt][1] = KVhW[rr + 4];
                    Blf[nt][0] = KVlW[rr]; Blf[nt][1] = KVlW[rr + 4];
                }
#pragma unroll
                for (int nt = 0; nt < 8; nt++) {
                    MMA_BF16(oacc[nt], Ahf, Bhf[nt]);
                    MMA_BF16(oacc[nt], Ahf, Blf[nt]);
                    MMA_BF16(oacc[nt], Alf, Bhf[nt]);
                }
            }
        }

        {
            int rowA = mrowO + gid, rowB = rowA + 8;
            float invA = 1.f / rsum[rowA];
            float invB = 1.f / rsum[rowB];
            int pA = r0 + rowA, pB = r0 + rowB;
            int pixA = (py0 + (pA >> 4)) * 256 + px0 + (pA & 15);
            int pixB = (py0 + (pB >> 4)) * 256 + px0 + (pB & 15);
#pragma unroll
            for (int nt = 0; nt < 8; nt++) {
                int ch = ncolO + nt * 8 + tig * 2;
                g_OUT[cbase + ch * HW + pixA] = oacc[nt][0] * invA;
                g_OUT[cbase + (ch + 1) * HW + pixA] = oacc[nt][1] * invA;
                g_OUT[cbase + ch * HW + pixB] = oacc[nt][2] * invB;
                g_OUT[cbase + (ch + 1) * HW + pixB] = oacc[nt][3] * invB;
            }
        }
    }
}

// ---------------- depthwise 5x5 (dilation param; optional fused gelu*ca + residual) ----------------
__global__ void dw5_kernel(const float* __restrict__ in, const float* __restrict__ w,
                           const float* __restrict__ bias, float* __restrict__ out,
                           int dil, int fuse) {
    __shared__ float ws[25];
    int c = blockIdx.z & 127, b = blockIdx.z >> 7;
    int t = threadIdx.y * 32 + threadIdx.x;
    if (t < 25) ws[t] = w[c * 25 + t];
    __syncthreads();
    int x = blockIdx.x * 32 + threadIdx.x;
    int y = blockIdx.y * 8 + threadIdx.y;
    const float* ip = in + (size_t)(b * CH + c) * HW;
    float acc = __ldg(&bias[c]);
#pragma unroll
    for (int ky = 0; ky < 5; ky++) {
        int yy = y + (ky - 2) * dil;
        if ((unsigned)yy >= 256u) continue;
#pragma unroll
        for (int kx = 0; kx < 5; kx++) {
            int xx = x + (kx - 2) * dil;
            if ((unsigned)xx >= 256u) continue;
            acc = fmaf(ws[ky * 5 + kx], __ldg(&ip[yy * 256 + xx]), acc);
        }
    }
    size_t oidx = (size_t)(b * CH + c) * HW + y * 256 + x;
    if (fuse) {
        float g = 0.5f * acc * (1.f + erff(acc * 0.7071067811865475f));
        out[oidx] = g * g_CA[b * CH + c] + g_OUT[oidx];
    } else {
        out[oidx] = acc;
    }
}

// ---------------- launch ----------------
extern "C" void kernel_launch(void* const* d_in, const int* in_sizes, int n_in,
                              void* d_out, int out_size) {
    const float* x      = (const float*)d_in[0];
    const float* cond_g = (const float*)d_in[1];
    const float* gu     = (const float*)d_in[2];
    const float* pv_w   = (const float*)d_in[3];
    const float* pv_b   = (const float*)d_in[4];
    const float* pq_w   = (const float*)d_in[5];
    const float* pq_b   = (const float*)d_in[6];
    const float* pk_w   = (const float*)d_in[7];
    const float* pk_b   = (const float*)d_in[8];
    const float* cs1_w  = (const float*)d_in[9];
    const float* cs1_b  = (const float*)d_in[10];
    const float* cs2_w  = (const float*)d_in[11];
    const float* cs2_b  = (const float*)d_in[12];
    const float* cs3_w  = (const float*)d_in[13];
    const float* cs3_b  = (const float*)d_in[14];
    const float* po_w   = (const float*)d_in[15];
    const float* po_b   = (const float*)d_in[16];
    const float* rin_w  = (const float*)d_in[17];
    const float* rin_b  = (const float*)d_in[18];
    const float* r1w    = (const float*)d_in[19];
    const float* r1b    = (const float*)d_in[20];
    const float* r2w    = (const float*)d_in[21];
    const float* r2b    = (const float*)d_in[22];
    const float* rm1_w  = (const float*)d_in[23];
    const float* rm1_b  = (const float*)d_in[24];
    const float* rm2_w  = (const float*)d_in[25];
    const float* rm2_b  = (const float*)d_in[26];
    const float* rca_w  = (const float*)d_in[27];
    const float* rca_b  = (const float*)d_in[28];
    const float* rsa_w  = (const float*)d_in[29];
    const float* rsa_b  = (const float*)d_in[30];

    float *pV, *pOUT, *pT1, *pT2;
    __nv_bfloat16* pWT;
    cudaGetSymbolAddress((void**)&pV, g_V);
    cudaGetSymbolAddress((void**)&pOUT, g_OUT);
    cudaGetSymbolAddress((void**)&pT1, g_T1);
    cudaGetSymbolAddress((void**)&pT2, g_T2);
    cudaGetSymbolAddress((void**)&pWT, g_WT);

    cudaFuncSetAttribute(attn_mma_kernel, cudaFuncAttributeMaxDynamicSharedMemorySize, SMEM_ATTN2);
    cudaFuncSetAttribute(conv1x1_mma, cudaFuncAttributeMaxDynamicSharedMemorySize, CV_SMEM);
    cudaFuncSetAttribute(convqk_mma, cudaFuncAttributeMaxDynamicSharedMemorySize, QK_SMEM);

    const int WSET = 2 * 128 * 136;
    dim3 ghw(512, BB);

    // preps first so ncu -s 5 lands on conv1x1_mma (launch #5)
    prep_w_kernel<<<64, 256>>>(pv_w, 0);
    prep_w_kernel<<<64, 256>>>(pq_w, 1);
    prep_w_kernel<<<64, 256>>>(pk_w, 2);
    prep_w_kernel<<<64, 256>>>(cs1_w, 3);
    prep_w_kernel<<<64, 256>>>(po_w, 4);
    // v = pv(x)   <- launch #5, profiled
    conv1x1_mma<<<ghw, 256, CV_SMEM>>>(x, pWT + 0 * WSET, pv_b, pV, 0);
    zero_fsum_kernel<<<1, 128>>>();
    predictor_kernel<<<dim3(HW / 512, BB), 256>>>(cond_g, rin_w, rin_b, r1w, r1b, r2w, r2b);
    ca_kernel<<<BB, 128>>>(rca_w, rca_b);
    sa_kernel<<<dim3(HW / 256, BB), 256>>>(rsa_w, rsa_b);
    mask_kernel<<<dim3(256, BB), 256>>>(gu, rm1_w, rm1_b, rm2_w, rm2_b);
    // fused flow-warp + q/k projections (masked windows only)
    convqk_mma<<<ghw, 256, QK_SMEM>>>(x, pWT + 1 * WSET, pWT + 2 * WSET, pq_b, pk_b);
    attn_mma_kernel<<<dim3(256, BB), 256, SMEM_ATTN2>>>();
    conv1x1_mma<<<ghw, 256, CV_SMEM>>>(pOUT, pWT + 3 * WSET, cs1_b, pT1, 0);
    dw5_kernel<<<dim3(8, 32, BB * CH), dim3(32, 8)>>>(pT1, cs2_w, cs2_b, pT2, 1, 0);
    dw5_kernel<<<dim3(8, 32, BB * CH), dim3(32, 8)>>>(pT2, cs3_w, cs3_b, pT1, 3, 1);
    conv1x1_mma<<<ghw, 256, CV_SMEM>>>(pT1, pWT + 4 * WSET, po_b, (float*)d_out, 0);
}

// round 9
// speedup vs baseline: 2.2123x; 1.2928x over previous
#include <cuda_runtime.h>
#include <cuda_bf16.h>
#include <stdint.h>
#include <math.h>

#define HW 65536
#define WIMG 256
#define CH 128
#define BB 4
#define ELT (BB*CH*HW)

// ---------------- scratch (static device globals; no runtime alloc) ----------------
__device__ float g_V[ELT];
__device__ float g_Qb[ELT];
__device__ float g_Kb[ELT];
__device__ float g_OUT[ELT];
__device__ float g_T1[ELT];
__device__ float g_T2[ELT];
__device__ float g_F[BB*32*HW];
__device__ float g_OFF[BB*2*HW];
__device__ float g_FMC[BB*HW];
__device__ float g_SA[BB*HW];
__device__ float g_FSUM[BB*32];
__device__ float g_CA[BB*CH];
__device__ float g_MASK[BB*256];
__device__ __align__(16) __nv_bfloat16 g_WT[5][2][128*136];

__device__ __forceinline__ float leakyf(float x) { return x > 0.f ? x : 0.2f * x; }

__global__ void zero_fsum_kernel() {
    g_FSUM[threadIdx.x] = 0.f;
}

__global__ void nop_kernel() {}

// ---------------- weight prep: fp32 -> bf16 hi/lo, padded rows (all 5 sets in one launch) ----------------
__global__ void prep_all_kernel(const float* __restrict__ w0, const float* __restrict__ w1,
                                const float* __restrict__ w2, const float* __restrict__ w3,
                                const float* __restrict__ w4) {
    int set = blockIdx.y;
    const float* w = (set == 0) ? w0 : (set == 1) ? w1 : (set == 2) ? w2 : (set == 3) ? w3 : w4;
    int i = blockIdx.x * 256 + threadIdx.x;
    int oc = i >> 7, ci = i & 127;
    float v = w[i];
    __nv_bfloat16 h = __float2bfloat16_rn(v);
    __nv_bfloat16 l = __float2bfloat16_rn(v - __bfloat162float(h));
    g_WT[set][0][oc * 136 + ci] = h;
    g_WT[set][1][oc * 136 + ci] = l;
}

// ---------------- HMMA m16n8k16 bf16 ----------------
#define MMA_BF16(d, a, b) \
    asm volatile("mma.sync.aligned.m16n8k16.row.col.f32.bf16.bf16.f32 " \
        "{%0,%1,%2,%3}, {%4,%5,%6,%7}, {%8,%9}, {%0,%1,%2,%3};" \
        : "+f"((d)[0]), "+f"((d)[1]), "+f"((d)[2]), "+f"((d)[3]) \
        : "r"((a)[0]), "r"((a)[1]), "r"((a)[2]), "r"((a)[3]), "r"((b)[0]), "r"((b)[1]))

// ---- shared GEMM body: W(hi/lo smem) x X(hi/lo smem) -> y window half ----
__device__ __forceinline__ void gemm_body_128(
    const uint32_t* WhW, const uint32_t* WlW,
    const uint32_t* XhW, const uint32_t* XlW,
    const float* __restrict__ bias, float* __restrict__ yb,
    int py0, int px0, int half, int w, int gid, int tig) {
    int oc0 = (w & 3) * 32;
    int n0 = (w >> 2) * 64;
    float acc[16][4];
#pragma unroll
    for (int i = 0; i < 16; i++)
#pragma unroll
        for (int j = 0; j < 4; j++) acc[i][j] = 0.f;
#pragma unroll 1
    for (int ks = 0; ks < 8; ks++) {
        int kw = ks * 8;
        uint32_t Ah[2][4], Al[2][4], Bh[8][2], Bl[8][2];
#pragma unroll
        for (int mt = 0; mt < 2; mt++) {
            int r0 = (oc0 + mt * 16 + gid) * 68 + kw + tig;
            int r8 = r0 + 8 * 68;
            Ah[mt][0] = WhW[r0];     Ah[mt][1] = WhW[r8];
            Ah[mt][2] = WhW[r0 + 4]; Ah[mt][3] = WhW[r8 + 4];
            Al[mt][0] = WlW[r0];     Al[mt][1] = WlW[r8];
            Al[mt][2] = WlW[r0 + 4]; Al[mt][3] = WlW[r8 + 4];
        }
#pragma unroll
        for (int nt = 0; nt < 8; nt++) {
            int rr = (n0 + nt * 8 + gid) * 68 + kw + tig;
            Bh[nt][0] = XhW[rr]; Bh[nt][1] = XhW[rr + 4];
            Bl[nt][0] = XlW[rr]; Bl[nt][1] = XlW[rr + 4];
        }
#pragma unroll
        for (int mt = 0; mt < 2; mt++)
#pragma unroll
            for (int nt = 0; nt < 8; nt++) {
                MMA_BF16(acc[mt * 8 + nt], Ah[mt], Bh[nt]);
                MMA_BF16(acc[mt * 8 + nt], Ah[mt], Bl[nt]);
                MMA_BF16(acc[mt * 8 + nt], Al[mt], Bh[nt]);
            }
    }
#pragma unroll
    for (int mt = 0; mt < 2; mt++) {
        int ocA = oc0 + mt * 16 + gid;
        int ocB = ocA + 8;
        float bvA = __ldg(&bias[ocA]);
        float bvB = __ldg(&bias[ocB]);
#pragma unroll
        for (int nt = 0; nt < 8; nt++) {
            int col = n0 + nt * 8 + tig * 2;
            int p = half * 128 + col;
            int pix = (py0 + (p >> 4)) * 256 + px0 + (p & 15);
            float2 v0 = make_float2(acc[mt * 8 + nt][0] + bvA, acc[mt * 8 + nt][1] + bvA);
            float2 v1 = make_float2(acc[mt * 8 + nt][2] + bvB, acc[mt * 8 + nt][3] + bvB);
            *(float2*)(yb + (size_t)ocA * HW + pix) = v0;
            *(float2*)(yb + (size_t)ocB * HW + pix) = v1;
        }
    }
}

// ---------------- conv1x1 GEMM, FULL window per block (512 thr, weights staged once) ----------------
// smem: Wh|Wl (2*128*136) + Xh|Xl (2*256*136) = 208896 B
#define CV_SMEM_FULL ((2 * 128 * 136 + 2 * 256 * 136) * 2)
__global__ void __launch_bounds__(512, 1)
conv1x1_mma(const float* __restrict__ xin, const __nv_bfloat16* __restrict__ wsp,
            const float* __restrict__ bias, float* __restrict__ yout, int bOff) {
    int n = blockIdx.x, b = blockIdx.y + bOff;
    extern __shared__ __nv_bfloat16 smb[];
    __nv_bfloat16* Wh = smb;
    __nv_bfloat16* Wl = Wh + 128 * 136;
    __nv_bfloat16* Xh = Wl + 128 * 136;   // 256 rows x 136
    __nv_bfloat16* Xl = Xh + 256 * 136;
    int t = threadIdx.x;

    // ---- copy padded W hi+lo (69632 B = 4352 uint4) ----
    {
        const uint4* src = (const uint4*)wsp;
        uint4* dst = (uint4*)smb;
#pragma unroll
        for (int i = 0; i < 9; i++) {
            int idx = t + i * 512;
            if (idx < 4352) dst[idx] = src[idx];
        }
    }

    // ---- stage full X window (256 px) hi/lo ----
    int py0 = (n >> 4) * 16, px0 = (n & 15) * 16;
    const float* xb = xin + (size_t)b * CH * HW;
    {
        int px = t & 255;
        int pix = (py0 + (px >> 4)) * 256 + px0 + (px & 15);
        int cp0 = t >> 8;   // 0..1
#pragma unroll
        for (int j = 0; j < 32; j++) {
            int cp = cp0 + j * 2;
            float v0 = xb[(size_t)(2 * cp) * HW + pix];
            float v1 = xb[(size_t)(2 * cp + 1) * HW + pix];
            __nv_bfloat16 h0 = __float2bfloat16_rn(v0);
            __nv_bfloat16 h1 = __float2bfloat16_rn(v1);
            __nv_bfloat16 l0 = __float2bfloat16_rn(v0 - __bfloat162float(h0));
            __nv_bfloat16 l1 = __float2bfloat16_rn(v1 - __bfloat162float(h1));
            ((__nv_bfloat162*)(Xh + px * 136))[cp] = __nv_bfloat162(h0, h1);
            ((__nv_bfloat162*)(Xl + px * 136))[cp] = __nv_bfloat162(l0, l1);
        }
    }
    __syncthreads();

    int wfull = t >> 5, lane = t & 31;
    int half = wfull >> 3;          // warps 0-7 -> half 0, 8-15 -> half 1
    int w = wfull & 7;
    int gid = lane >> 2, tig = lane & 3;
    gemm_body_128((const uint32_t*)Wh, (const uint32_t*)Wl,
                  (const uint32_t*)(Xh + half * 128 * 136), (const uint32_t*)(Xl + half * 128 * 136),
                  bias, yout + (size_t)b * CH * HW, py0, px0, half, w, gid, tig);
}

// ---------------- fused flow-warp + q/k projections (masked windows only) ----------------
#define QK_SMEM (6 * 128 * 136 * 2)
__global__ void __launch_bounds__(256, 1)
convqk_mma(const float* __restrict__ xin,
           const __nv_bfloat16* __restrict__ wq, const __nv_bfloat16* __restrict__ wk,
           const float* __restrict__ qbias, const float* __restrict__ kbias) {
    int hw = blockIdx.x, b = blockIdx.y;
    int n = hw >> 1, half = hw & 1;
    if (g_MASK[b * 256 + n] == 0.f) return;
    extern __shared__ __nv_bfloat16 smb[];
    __nv_bfloat16* Wqh = smb;
    __nv_bfloat16* Wql = Wqh + 128 * 136;
    __nv_bfloat16* Wkh = Wql + 128 * 136;
    __nv_bfloat16* Wkl = Wkh + 128 * 136;
    __nv_bfloat16* Xh  = Wkl + 128 * 136;
    __nv_bfloat16* Xl  = Xh + 128 * 136;
    int t = threadIdx.x;

    {
        const uint4* srcq = (const uint4*)wq;
        const uint4* srck = (const uint4*)wk;
        uint4* dstq = (uint4*)Wqh;
        uint4* dstk = (uint4*)Wkh;
#pragma unroll
        for (int i = 0; i < 17; i++) {
            dstq[t + i * 256] = srcq[t + i * 256];
            dstk[t + i * 256] = srck[t + i * 256];
        }
    }

    int py0 = (n >> 4) * 16, px0 = (n & 15) * 16;
    {
        int px = t & 127;
        int p = half * 128 + px;
        int gy = py0 + (p >> 4), gx = px0 + (p & 15);
        int pp = gy * 256 + gx;
        const float* OFb = g_OFF + (size_t)b * 2 * HW;
        float fx = OFb[pp];
        float fy = OFb[HW + pp];
        float sx = fminf(fmaxf((float)gx + fx, 0.f), 255.f);
        float sy = fminf(fmaxf((float)gy + fy, 0.f), 255.f);
        float x0f = floorf(sx), y0f = floorf(sy);
        float x1f = fminf(x0f + 1.f, 255.f), y1f = fminf(y0f + 1.f, 255.f);
        float wx = sx - x0f, wy = sy - y0f;
        int x0 = (int)x0f, x1 = (int)x1f, y0 = (int)y0f, y1 = (int)y1f;
        int iA = y0 * 256 + x0, iB = y0 * 256 + x1, iC = y1 * 256 + x0, iD = y1 * 256 + x1;
        float w00 = (1.f - wx) * (1.f - wy), w01 = wx * (1.f - wy);
        float w10 = (1.f - wx) * wy, w11 = wx * wy;
        const float* xb = xin + (size_t)b * CH * HW;
        int cp0 = t >> 7;
#pragma unroll 4
        for (int j = 0; j < 32; j++) {
            int cp = cp0 + j * 2;
            const float* xc0 = xb + (size_t)(2 * cp) * HW;
            const float* xc1 = xc0 + HW;
            float v0 = __ldg(&xc0[iA]) * w00 + __ldg(&xc0[iB]) * w01 +
                       __ldg(&xc0[iC]) * w10 + __ldg(&xc0[iD]) * w11;
            float v1 = __ldg(&xc1[iA]) * w00 + __ldg(&xc1[iB]) * w01 +
                       __ldg(&xc1[iC]) * w10 + __ldg(&xc1[iD]) * w11;
            __nv_bfloat16 h0 = __float2bfloat16_rn(v0);
            __nv_bfloat16 h1 = __float2bfloat16_rn(v1);
            __nv_bfloat16 l0 = __float2bfloat16_rn(v0 - __bfloat162float(h0));
            __nv_bfloat16 l1 = __float2bfloat16_rn(v1 - __bfloat162float(h1));
            ((__nv_bfloat162*)(Xh + px * 136))[cp] = __nv_bfloat162(h0, h1);
            ((__nv_bfloat162*)(Xl + px * 136))[cp] = __nv_bfloat162(l0, l1);
        }
    }
    __syncthreads();

    int w = t >> 5, lane = t & 31;
    int gid = lane >> 2, tig = lane & 3;
    gemm_body_128((const uint32_t*)Wqh, (const uint32_t*)Wql,
                  (const uint32_t*)Xh, (const uint32_t*)Xl,
                  qbias, g_Qb + (size_t)b * CH * HW, py0, px0, half, w, gid, tig);
    gemm_body_128((const uint32_t*)Wkh, (const uint32_t*)Wkl,
                  (const uint32_t*)Xh, (const uint32_t*)Xl,
                  kbias, g_Kb + (size_t)b * CH * HW, py0, px0, half, w, gid, tig);
}

// ---------------- predictor ----------------
__global__ void predictor_kernel(const float* __restrict__ cond_g,
                                 const float* __restrict__ rin_w, const float* __restrict__ rin_b,
                                 const float* __restrict__ r1w, const float* __restrict__ r1b,
                                 const float* __restrict__ r2w, const float* __restrict__ r2b) {
    __shared__ float wr[32 * 131];
    __shared__ float wr1[16 * 32];
    __shared__ float wr2[32];
    __shared__ float partial[8][32];
    int t = threadIdx.x;
    int b = blockIdx.y;
    for (int i = t; i < 32 * 131; i += 256) wr[i] = rin_w[i];
    for (int i = t; i < 16 * 32; i += 256) wr1[i] = r1w[i];
    if (t < 32) wr2[t] = r2w[t];
    __syncthreads();

    int p0 = blockIdx.x * 512 + t;
    int p1 = p0 + 256;
    float a0[32], a1[32];
#pragma unroll
    for (int o = 0; o < 32; o++) {
        float bv = __ldg(&rin_b[o]);
        a0[o] = bv; a1[o] = bv;
    }
    const float* vb = g_V + (size_t)b * CH * HW;
#pragma unroll 2
    for (int ci = 0; ci < 128; ci++) {
        float x0 = vb[(size_t)ci * HW + p0];
        float x1 = vb[(size_t)ci * HW + p1];
#pragma unroll
        for (int o = 0; o < 32; o++) {
            float wv = wr[o * 131 + ci];
            a0[o] = fmaf(wv, x0, a0[o]);
            a1[o] = fmaf(wv, x1, a1[o]);
        }
    }
    float cg0 = __ldg(&cond_g[b * HW + p0]);
    float cg1 = __ldg(&cond_g[b * HW + p1]);
    int y0 = p0 >> 8, x0p = p0 & 255;
    int y1 = p1 >> 8, x1p = p1 & 255;
    float ly0 = -1.f + (float)(y0 & 15) * (2.f / 15.f);
    float lx0 = -1.f + (float)(x0p & 15) * (2.f / 15.f);
    float ly1 = -1.f + (float)(y1 & 15) * (2.f / 15.f);
    float lx1 = -1.f + (float)(x1p & 15) * (2.f / 15.f);
    float fm0 = 0.f, fm1 = 0.f;
    float* Fb = g_F + (size_t)b * 32 * HW;
#pragma unroll
    for (int o = 0; o < 32; o++) {
        float v0 = a0[o] + wr[o * 131 + 128] * cg0 + wr[o * 131 + 129] * ly0 + wr[o * 131 + 130] * lx0;
        float v1 = a1[o] + wr[o * 131 + 128] * cg1 + wr[o * 131 + 129] * ly1 + wr[o * 131 + 130] * lx1;
        v0 = leakyf(v0); v1 = leakyf(v1);
        a0[o] = v0; a1[o] = v1;
        Fb[(size_t)o * HW + p0] = v0;
        Fb[(size_t)o * HW + p1] = v1;
        fm0 += v0; fm1 += v1;
    }
    g_FMC[b * HW + p0] = fm0 * (1.f / 32.f);
    g_FMC[b * HW + p1] = fm1 * (1.f / 32.f);

    float h0[16], h1v[16];
#pragma unroll
    for (int o2 = 0; o2 < 16; o2++) {
        float bv = __ldg(&r1b[o2]);
        float s0 = bv, s1 = bv;
#pragma unroll
        for (int o = 0; o < 32; o++) {
            float wv = wr1[o2 * 32 + o];
            s0 = fmaf(wv, a0[o], s0);
            s1 = fmaf(wv, a1[o], s1);
        }
        h0[o2] = leakyf(s0);
        h1v[o2] = leakyf(s1);
    }
    float ox0 = __ldg(&r2b[0]), oy0 = __ldg(&r2b[1]);
    float ox1 = ox0, oy1 = oy0;
#pragma unroll
    for (int o2 = 0; o2 < 16; o2++) {
        ox0 = fmaf(wr2[o2], h0[o2], ox0);
        oy0 = fmaf(wr2[16 + o2], h0[o2], oy0);
        ox1 = fmaf(wr2[o2], h1v[o2], ox1);
        oy1 = fmaf(wr2[16 + o2], h1v[o2], oy1);
    }
    float* OFb = g_OFF + (size_t)b * 2 * HW;
    OFb[p0] = ox0; OFb[p1] = ox1;
    OFb[HW + p0] = oy0; OFb[HW + p1] = oy1;

    int lane = t & 31, wid = t >> 5;
#pragma unroll
    for (int o = 0; o < 32; o++) {
        float v = a0[o] + a1[o];
        v += __shfl_xor_sync(0xffffffff, v, 16);
        v += __shfl_xor_sync(0xffffffff, v, 8);
        v += __shfl_xor_sync(0xffffffff, v, 4);
        v += __shfl_xor_sync(0xffffffff, v, 2);
        v += __shfl_xor_sync(0xffffffff, v, 1);
        if (lane == 0) partial[wid][o] = v;
    }
    __syncthreads();
    if (t < 32) {
        float s = 0.f;
#pragma unroll
        for (int w2 = 0; w2 < 8; w2++) s += partial[w2][t];
        atomicAdd(&g_FSUM[b * 32 + t], s);
    }
}

// ---------------- channel attention ca ----------------
__global__ void ca_kernel(const float* __restrict__ rca_w, const float* __restrict__ rca_b) {
    int c = threadIdx.x;
    int b = blockIdx.x;
    float s = __ldg(&rca_b[c]);
#pragma unroll
    for (int ci = 0; ci < 32; ci++)
        s = fmaf(__ldg(&rca_w[c * 32 + ci]), g_FSUM[b * 32 + ci] * (1.f / 65536.f), s);
    g_CA[b * CH + c] = 1.f / (1.f + expf(-s));
}

// ---------------- spatial attention sa ----------------
__global__ void sa_kernel(const float* __restrict__ rsa_w, const float* __restrict__ rsa_b) {
    __shared__ float ws[288];
    int t = threadIdx.x;
    for (int i = t; i < 288; i += 256) ws[i] = rsa_w[i];
    __syncthreads();
    int b = blockIdx.y;
    int p = blockIdx.x * 256 + t;
    int y = p >> 8, x = p & 255;
    float acc = __ldg(&rsa_b[0]);
    const float* Fb = g_F + (size_t)b * 32 * HW;
    for (int ci = 0; ci < 32; ci++) {
        const float* fp = Fb + (size_t)ci * HW;
#pragma unroll
        for (int ky = 0; ky < 3; ky++) {
            int yy = y + ky - 1;
            if ((unsigned)yy >= 256u) continue;
#pragma unroll
            for (int kx = 0; kx < 3; kx++) {
                int xx = x + kx - 1;
                if ((unsigned)xx >= 256u) continue;
                acc = fmaf(ws[ci * 9 + ky * 3 + kx], __ldg(&fp[yy * 256 + xx]), acc);
            }
        }
    }
    g_SA[b * HW + p] = 1.f / (1.f + expf(-acc));
}

// ---------------- window MLP + gumbel hard mask ----------------
__global__ void mask_kernel(const float* __restrict__ gu,
                            const float* __restrict__ rm1_w, const float* __restrict__ rm1_b,
                            const float* __restrict__ rm2_w, const float* __restrict__ rm2_b) {
    __shared__ float m[256];
    __shared__ float h1s[16];
    int n = blockIdx.x, b = blockIdx.y;
    int t = threadIdx.x;
    int dh = t >> 4, dw = t & 15;
    int pix = ((n >> 4) * 16 + dh) * 256 + (n & 15) * 16 + dw;
    m[t] = g_FMC[b * HW + pix];
    __syncthreads();
    if (t < 16) {
        float s = __ldg(&rm1_b[t]);
        for (int e = 0; e < 256; e++) s = fmaf(__ldg(&rm1_w[t * 256 + e]), m[e], s);
        h1s[t] = leakyf(s);
    }
    __syncthreads();
    if (t == 0) {
        float z0 = __ldg(&rm2_b[0]), z1 = __ldg(&rm2_b[1]);
#pragma unroll
        for (int o = 0; o < 16; o++) {
            z0 = fmaf(__ldg(&rm2_w[o]), h1s[o], z0);
            z1 = fmaf(__ldg(&rm2_w[16 + o]), h1s[o], z1);
        }
        float mx = fmaxf(z0, z1);
        float e0 = expf(z0 - mx), e1 = expf(z1 - mx);
        float inv = 1.f / (e0 + e1);
        float p0 = e0 * inv, p1 = e1 * inv;
        float u0 = __ldg(&gu[(b * 256 + n) * 2 + 0]);
        float u1 = __ldg(&gu[(b * 256 + n) * 2 + 1]);
        float g0 = -logf(-logf(u0 + 1e-10f) + 1e-10f);
        float g1 = -logf(-logf(u1 + 1e-10f) + 1e-10f);
        g_MASK[b * 256 + n] = (p0 + g0 >= p1 + g1) ? 1.f : 0.f;
    }
}

// ---------------- window attention via mma.sync (masked) / v*sa (unmasked) ----------------
#define SMEM_ATTN2 (67328 + 90112)
__global__ void __launch_bounds__(256, 1) attn_mma_kernel() {
    int n = blockIdx.x, b = blockIdx.y;
    int t = threadIdx.x;
    int py0 = (n >> 4) * 16, px0 = (n & 15) * 16;
    int cbase = b * CH * HW;
    if (g_MASK[b * 256 + n] == 0.f) {
        const float* sab = g_SA + (size_t)b * HW;
#pragma unroll 4
        for (int i = t; i < 8192; i += 256) {
            int ch = i >> 6, r4 = i & 63;
            int wrow = r4 >> 2, px4 = (r4 & 3) * 4;
            int pix = (py0 + wrow) * 256 + px0 + px4;
            float4 v = *(const float4*)(g_V + cbase + ch * HW + pix);
            float4 s = *(const float4*)(sab + pix);
            v.x *= s.x; v.y *= s.y; v.z *= s.z; v.w *= s.w;
            *(float4*)(g_OUT + cbase + ch * HW + pix) = v;
        }
        return;
    }
    extern __shared__ char smraw[];
    float* S = (float*)smraw;
    float* red = S + 64 * 257;
    float* rmax = red + 256;
    float* rsum = rmax + 64;
    __nv_bfloat16* Qh = (__nv_bfloat16*)(rsum + 64);
    __nv_bfloat16* Ql = Qh + 64 * 136;
    __nv_bfloat16* KVh = Ql + 64 * 136;
    __nv_bfloat16* KVl = KVh + 9216;
    __nv_bfloat16* Pth = KVl + 9216;
    __nv_bfloat16* Ptl = Pth + 64 * 72;

    const uint32_t* QhW = (const uint32_t*)Qh;
    const uint32_t* QlW = (const uint32_t*)Ql;
    const uint32_t* KVhW = (const uint32_t*)KVh;
    const uint32_t* KVlW = (const uint32_t*)KVl;
    const uint32_t* PthW = (const uint32_t*)Pth;
    const uint32_t* PtlW = (const uint32_t*)Ptl;

    int w = t >> 5, lane = t & 31;
    int gid = lane >> 2;
    int tig = lane & 3;

#pragma unroll 1
    for (int rc = 0; rc < 4; rc++) {
        int r0 = rc * 64;
        __syncthreads();
#pragma unroll
        for (int j = 0; j < 16; j++) {
            int i = t + j * 256;
            int px = i & 63, cp = i >> 6;
            int p = r0 + px;
            int pix = (py0 + (p >> 4)) * 256 + px0 + (p & 15);
            float v0 = g_Qb[cbase + (2 * cp) * HW + pix];
            float v1 = g_Qb[cbase + (2 * cp + 1) * HW + pix];
            __nv_bfloat16 h0 = __float2bfloat16_rn(v0);
            __nv_bfloat16 h1 = __float2bfloat16_rn(v1);
            __nv_bfloat16 l0 = __float2bfloat16_rn(v0 - __bfloat162float(h0));
            __nv_bfloat16 l1 = __float2bfloat16_rn(v1 - __bfloat162float(h1));
            ((__nv_bfloat162*)(Qh + px * 136))[cp] = __nv_bfloat162(h0, h1);
            ((__nv_bfloat162*)(Ql + px * 136))[cp] = __nv_bfloat162(l0, l1);
        }

        int mrowS = (w & 3) * 16, ncolS = (w >> 2) * 32;
#pragma unroll 1
        for (int kvt = 0; kvt < 4; kvt++) {
            __syncthreads();
#pragma unroll
            for (int j = 0; j < 16; j++) {
                int i = t + j * 256;
                int px = i & 63, cp = i >> 6;
                int p = kvt * 64 + px;
                int pix = (py0 + (p >> 4)) * 256 + px0 + (p & 15);
                float v0 = g_Kb[cbase + (2 * cp) * HW + pix];
                float v1 = g_Kb[cbase + (2 * cp + 1) * HW + pix];
                __nv_bfloat16 h0 = __float2bfloat16_rn(v0);
                __nv_bfloat16 h1 = __float2bfloat16_rn(v1);
                __nv_bfloat16 l0 = __float2bfloat16_rn(v0 - __bfloat162float(h0));
                __nv_bfloat16 l1 = __float2bfloat16_rn(v1 - __bfloat162float(h1));
                ((__nv_bfloat162*)(KVh + px * 136))[cp] = __nv_bfloat162(h0, h1);
                ((__nv_bfloat162*)(KVl + px * 136))[cp] = __nv_bfloat162(l0, l1);
            }
            __syncthreads();
            float acc[4][4];
#pragma unroll
            for (int i = 0; i < 4; i++)
#pragma unroll
                for (int j2 = 0; j2 < 4; j2++) acc[i][j2] = 0.f;
#pragma unroll
            for (int ks = 0; ks < 8; ks++) {
                int kw = ks * 8;
                uint32_t Ahf[4], Alf[4], Bhf[4][2], Blf[4][2];
                int ra = (mrowS + gid) * 68 + kw + tig;
                int ra8 = ra + 8 * 68;
                Ahf[0] = QhW[ra];     Ahf[1] = QhW[ra8];
                Ahf[2] = QhW[ra + 4]; Ahf[3] = QhW[ra8 + 4];
                Alf[0] = QlW[ra];     Alf[1] = QlW[ra8];
                Alf[2] = QlW[ra + 4]; Alf[3] = QlW[ra8 + 4];
#pragma unroll
                for (int nt = 0; nt < 4; nt++) {
                    int rr = (ncolS + nt * 8 + gid) * 68 + kw + tig;
                    Bhf[nt][0] = KVhW[rr]; Bhf[nt][1] = KVhW[rr + 4];
                    Blf[nt][0] = KVlW[rr]; Blf[nt][1] = KVlW[rr + 4];
                }
#pragma unroll
                for (int nt = 0; nt < 4; nt++) {
                    MMA_BF16(acc[nt], Ahf, Bhf[nt]);
                    MMA_BF16(acc[nt], Ahf, Blf[nt]);
                    MMA_BF16(acc[nt], Alf, Bhf[nt]);
                }
            }
#pragma unroll
            for (int nt = 0; nt < 4; nt++) {
                int col = kvt * 64 + ncolS + nt * 8 + tig * 2;
                S[(mrowS + gid) * 257 + col] = acc[nt][0];
                S[(mrowS + gid) * 257 + col + 1] = acc[nt][1];
                S[(mrowS + gid + 8) * 257 + col] = acc[nt][2];
                S[(mrowS + gid + 8) * 257 + col + 1] = acc[nt][3];
            }
        }
        __syncthreads();

        {
            int r = t & 63, seg = t >> 6;
            float* srow = &S[r * 257 + seg * 64];
            float mx = -1e30f;
#pragma unroll 8
            for (int k = 0; k < 64; k++) mx = fmaxf(mx, srow[k]);
            red[seg * 64 + r] = mx;
            __syncthreads();
            if (t < 64)
                rmax[t] = fmaxf(fmaxf(red[t], red[64 + t]), fmaxf(red[128 + t], red[192 + t]));
            __syncthreads();
            float rm_ = rmax[r];
            float s = 0.f;
#pragma unroll 8
            for (int k = 0; k < 64; k++) {
                float e = __expf(srow[k] - rm_);
                srow[k] = e;
                s += e;
            }
            red[seg * 64 + r] = s;
            __syncthreads();
            if (t < 64) rsum[t] = red[t] + red[64 + t] + red[128 + t] + red[192 + t];
            __syncthreads();
        }

        int mrowO = (w & 3) * 16, ncolO = (w >> 2) * 64;
        float oacc[8][4];
#pragma unroll
        for (int i = 0; i < 8; i++)
#pragma unroll
            for (int j2 = 0; j2 < 4; j2++) oacc[i][j2] = 0.f;

#pragma unroll 1
        for (int kvt = 0; kvt < 4; kvt++) {
            __syncthreads();
#pragma unroll
            for (int j = 0; j < 16; j++) {
                int i = t + j * 256;
                int col = i & 63, row = i >> 6;
                float v = S[row * 257 + kvt * 64 + col];
                __nv_bfloat16 h = __float2bfloat16_rn(v);
                Pth[row * 72 + col] = h;
                Ptl[row * 72 + col] = __float2bfloat16_rn(v - __bfloat162float(h));
            }
#pragma unroll
            for (int j = 0; j < 32; j++) {
                int i = t + j * 256;
                int px = i & 63, ch = i >> 6;
                int p = kvt * 64 + px;
                int pix = (py0 + (p >> 4)) * 256 + px0 + (p & 15);
                float v = g_V[cbase + ch * HW + pix];
                __nv_bfloat16 h = __float2bfloat16_rn(v);
                KVh[ch * 72 + px] = h;
                KVl[ch * 72 + px] = __float2bfloat16_rn(v - __bfloat162float(h));
            }
            __syncthreads();
#pragma unroll
            for (int ks = 0; ks < 4; ks++) {
                int kw = ks * 8;
                uint32_t Ahf[4], Alf[4], Bhf[8][2], Blf[8][2];
                int ra = (mrowO + gid) * 36 + kw + tig;
                int ra8 = ra + 8 * 36;
                Ahf[0] = PthW[ra];     Ahf[1] = PthW[ra8];
                Ahf[2] = PthW[ra + 4]; Ahf[3] = PthW[ra8 + 4];
                Alf[0] = PtlW[ra];     Alf[1] = PtlW[ra8];
                Alf[2] = PtlW[ra + 4]; Alf[3] = PtlW[ra8 + 4];
#pragma unroll
                for (int nt = 0; nt < 8; nt++) {
                    int rr = (ncolO + nt * 8 + gid) * 36 + kw + tig;
                    Bhf[nt][0] = KVhW[rr]; Bhf[nt][1] = KVhW[rr + 4];
                    Blf[nt][0] = KVlW[rr]; Blf[nt][1] = KVlW[rr + 4];
                }
#pragma unroll
                for (int nt = 0; nt < 8; nt++) {
                    MMA_BF16(oacc[nt], Ahf, Bhf[nt]);
                    MMA_BF16(oacc[nt], Ahf, Blf[nt]);
                    MMA_BF16(oacc[nt], Alf, Bhf[nt]);
                }
            }
        }

        {
            int rowA = mrowO + gid, rowB = rowA + 8;
            float invA = 1.f / rsum[rowA];
            float invB = 1.f / rsum[rowB];
            int pA = r0 + rowA, pB = r0 + rowB;
            int pixA = (py0 + (pA >> 4)) * 256 + px0 + (pA & 15);
            int pixB = (py0 + (pB >> 4)) * 256 + px0 + (pB & 15);
#pragma unroll
            for (int nt = 0; nt < 8; nt++) {
                int ch = ncolO + nt * 8 + tig * 2;
                g_OUT[cbase + ch * HW + pixA] = oacc[nt][0] * invA;
                g_OUT[cbase + (ch + 1) * HW + pixA] = oacc[nt][1] * invA;
                g_OUT[cbase + ch * HW + pixB] = oacc[nt][2] * invB;
                g_OUT[cbase + (ch + 1) * HW + pixB] = oacc[nt][3] * invB;
            }
        }
    }
}

// ---------------- fused depthwise 5x5 (dil1) -> 5x5 (dil3) + gelu*ca + residual ----------------
// one block: 64x32 output tile of one (b, c) plane
__global__ void __launch_bounds__(256) dw5x2_kernel(
    const float* __restrict__ in, const float* __restrict__ w2, const float* __restrict__ b2,
    const float* __restrict__ w3, const float* __restrict__ b3, float* __restrict__ out) {
    __shared__ float sIn[48][81];
    __shared__ float sMid[44][77];
    __shared__ float wA[25], wB[25];
    int c = blockIdx.z & 127, b = blockIdx.z >> 7;
    int t = threadIdx.x;
    if (t < 25) wA[t] = w2[c * 25 + t];
    else if (t < 50) wB[t - 25] = w3[c * 25 + (t - 25)];
    int ox0 = blockIdx.x * 64, oy0 = blockIdx.y * 32;
    const float* ip = in + (size_t)(b * CH + c) * HW;

    // load input region [oy0-8, +48) x [ox0-8, +80), zero-padded
    for (int i = t; i < 48 * 80; i += 256) {
        int lx = i % 80, ly = i / 80;
        int gx = ox0 - 8 + lx, gy = oy0 - 8 + ly;
        float v = 0.f;
        if ((unsigned)gx < 256u && (unsigned)gy < 256u) v = __ldg(&ip[gy * 256 + gx]);
        sIn[ly][lx] = v;
    }
    __syncthreads();

    // intermediate = dw5 dil1 over [oy0-6, +44) x [ox0-6, +76); zero outside image
    float b2v = __ldg(&b2[c]);
    for (int i = t; i < 44 * 76; i += 256) {
        int mx = i % 76, my = i / 76;
        int gx = ox0 - 6 + mx, gy = oy0 - 6 + my;
        float acc = 0.f;
        if ((unsigned)gx < 256u && (unsigned)gy < 256u) {
            acc = b2v;
#pragma unroll
            for (int ky = 0; ky < 5; ky++)
#pragma unroll
                for (int kx = 0; kx < 5; kx++)
                    acc = fmaf(wA[ky * 5 + kx], sIn[my + ky][mx + kx], acc);
        }
        sMid[my][mx] = acc;
    }
    __syncthreads();

    // output = dw5 dil3 over intermediate, then gelu*ca + OUT
    float b3v = __ldg(&b3[c]);
    float cav = g_CA[b * CH + c];
    size_t obase = (size_t)(b * CH + c) * HW;
    for (int i = t; i < 32 * 64; i += 256) {
        int x = i % 64, y = i / 64;
        float acc = b3v;
#pragma unroll
        for (int ky = 0; ky < 5; ky++)
#pragma unroll
            for (int kx = 0; kx < 5; kx++)
                acc = fmaf(wB[ky * 5 + kx], sMid[y + 3 * ky][x + 3 * kx], acc);
        float g = 0.5f * acc * (1.f + erff(acc * 0.7071067811865475f));
        size_t oidx = obase + (size_t)(oy0 + y) * 256 + ox0 + x;
        out[oidx] = g * cav + g_OUT[oidx];
    }
}

// ---------------- launch ----------------
extern "C" void kernel_launch(void* const* d_in, const int* in_sizes, int n_in,
                              void* d_out, int out_size) {
    const float* x      = (const float*)d_in[0];
    const float* cond_g = (const float*)d_in[1];
    const float* gu     = (const float*)d_in[2];
    const float* pv_w   = (const float*)d_in[3];
    const float* pv_b   = (const float*)d_in[4];
    const float* pq_w   = (const float*)d_in[5];
    const float* pq_b   = (const float*)d_in[6];
    const float* pk_w   = (const float*)d_in[7];
    const float* pk_b   = (const float*)d_in[8];
    const float* cs1_w  = (const float*)d_in[9];
    const float* cs1_b  = (const float*)d_in[10];
    const float* cs2_w  = (const float*)d_in[11];
    const float* cs2_b  = (const float*)d_in[12];
    const float* cs3_w  = (const float*)d_in[13];
    const float* cs3_b  = (const float*)d_in[14];
    const float* po_w   = (const float*)d_in[15];
    const float* po_b   = (const float*)d_in[16];
    const float* rin_w  = (const float*)d_in[17];
    const float* rin_b  = (const float*)d_in[18];
    const float* r1w    = (const float*)d_in[19];
    const float* r1b    = (const float*)d_in[20];
    const float* r2w    = (const float*)d_in[21];
    const float* r2b    = (const float*)d_in[22];
    const float* rm1_w  = (const float*)d_in[23];
    const float* rm1_b  = (const float*)d_in[24];
    const float* rm2_w  = (const float*)d_in[25];
    const float* rm2_b  = (const float*)d_in[26];
    const float* rca_w  = (const float*)d_in[27];
    const float* rca_b  = (const float*)d_in[28];
    const float* rsa_w  = (const float*)d_in[29];
    const float* rsa_b  = (const float*)d_in[30];

    float *pV, *pOUT, *pT1, *pT2;
    __nv_bfloat16* pWT;
    cudaGetSymbolAddress((void**)&pV, g_V);
    cudaGetSymbolAddress((void**)&pOUT, g_OUT);
    cudaGetSymbolAddress((void**)&pT1, g_T1);
    cudaGetSymbolAddress((void**)&pT2, g_T2);
    cudaGetSymbolAddress((void**)&pWT, g_WT);

    cudaFuncSetAttribute(attn_mma_kernel, cudaFuncAttributeMaxDynamicSharedMemorySize, SMEM_ATTN2);
    cudaFuncSetAttribute(conv1x1_mma, cudaFuncAttributeMaxDynamicSharedMemorySize, CV_SMEM_FULL);
    cudaFuncSetAttribute(convqk_mma, cudaFuncAttributeMaxDynamicSharedMemorySize, QK_SMEM);

    const int WSET = 2 * 128 * 136;

    // launches #1-#4: prep/zero/nops ; #5 and #6 are BOTH conv1x1_mma (pv) for ncu
    prep_all_kernel<<<dim3(64, 5), 256>>>(pv_w, pq_w, pk_w, cs1_w, po_w);
    zero_fsum_kernel<<<1, 128>>>();
    nop_kernel<<<1, 32>>>();
    nop_kernel<<<1, 32>>>();
    conv1x1_mma<<<dim3(256, 2), 512, CV_SMEM_FULL>>>(x, pWT + 0 * WSET, pv_b, pV, 0);   // b = 0,1
    conv1x1_mma<<<dim3(256, 2), 512, CV_SMEM_FULL>>>(x, pWT + 0 * WSET, pv_b, pV, 2);   // b = 2,3
    predictor_kernel<<<dim3(HW / 512, BB), 256>>>(cond_g, rin_w, rin_b, r1w, r1b, r2w, r2b);
    ca_kernel<<<BB, 128>>>(rca_w, rca_b);
    sa_kernel<<<dim3(HW / 256, BB), 256>>>(rsa_w, rsa_b);
    mask_kernel<<<dim3(256, BB), 256>>>(gu, rm1_w, rm1_b, rm2_w, rm2_b);
    convqk_mma<<<dim3(512, BB), 256, QK_SMEM>>>(x, pWT + 1 * WSET, pWT + 2 * WSET, pq_b, pk_b);
    attn_mma_kernel<<<dim3(256, BB), 256, SMEM_ATTN2>>>();
    conv1x1_mma<<<dim3(256, BB), 512, CV_SMEM_FULL>>>(pOUT, pWT + 3 * WSET, cs1_b, pT1, 0);
    dw5x2_kernel<<<dim3(4, 8, BB * CH), 256>>>(pT1, cs2_w, cs2_b, cs3_w, cs3_b, pT2);
    conv1x1_mma<<<dim3(256, BB), 512, CV_SMEM_FULL>>>(pT2, pWT + 4 * WSET, po_b, (float*)d_out, 0);
}

// round 11
// speedup vs baseline: 2.2924x; 1.0362x over previous
#include <cuda_runtime.h>
#include <cuda_bf16.h>
#include <stdint.h>
#include <math.h>

#define HW 65536
#define WIMG 256
#define CH 128
#define BB 4
#define ELT (BB*CH*HW)

// ---------------- scratch ----------------
__device__ float g_V[ELT];
__device__ float g_Qb[ELT];
__device__ float g_Kb[ELT];
__device__ float g_OUT[ELT];
__device__ float g_T1[ELT];
__device__ float g_T2[ELT];
__device__ float g_F[BB*32*HW];
__device__ float g_OFF[BB*2*HW];
__device__ float g_FMC[BB*HW];
__device__ float g_SA[BB*HW];
__device__ float g_FSUM[BB*32];
__device__ float g_CA[BB*CH];
__device__ float g_MASK[BB*256];
__device__ __align__(16) __nv_bfloat16 g_WT[5][2][128*136];

__device__ __forceinline__ float leakyf(float x) { return x > 0.f ? x : 0.2f * x; }

__global__ void zero_fsum_kernel() {
    g_FSUM[threadIdx.x] = 0.f;
}

// ---------------- weight prep ----------------
__global__ void prep_all_kernel(const float* __restrict__ w0, const float* __restrict__ w1,
                                const float* __restrict__ w2, const float* __restrict__ w3,
                                const float* __restrict__ w4) {
    int set = blockIdx.y;
    const float* w = (set == 0) ? w0 : (set == 1) ? w1 : (set == 2) ? w2 : (set == 3) ? w3 : w4;
    int i = blockIdx.x * 256 + threadIdx.x;
    int oc = i >> 7, ci = i & 127;
    float v = w[i];
    __nv_bfloat16 h = __float2bfloat16_rn(v);
    __nv_bfloat16 l = __float2bfloat16_rn(v - __bfloat162float(h));
    g_WT[set][0][oc * 136 + ci] = h;
    g_WT[set][1][oc * 136 + ci] = l;
}

// ---------------- HMMA m16n8k16 bf16 ----------------
#define MMA_BF16(d, a, b) \
    asm volatile("mma.sync.aligned.m16n8k16.row.col.f32.bf16.bf16.f32 " \
        "{%0,%1,%2,%3}, {%4,%5,%6,%7}, {%8,%9}, {%0,%1,%2,%3};" \
        : "+f"((d)[0]), "+f"((d)[1]), "+f"((d)[2]), "+f"((d)[3]) \
        : "r"((a)[0]), "r"((a)[1]), "r"((a)[2]), "r"((a)[3]), "r"((b)[0]), "r"((b)[1]))

// ---- shared GEMM body (proven): 8-warp slice over one 128px half ----
__device__ __forceinline__ void gemm_body_128(
    const uint32_t* WhW, const uint32_t* WlW,
    const uint32_t* XhW, const uint32_t* XlW,
    const float* __restrict__ bias, float* __restrict__ yb,
    int py0, int px0, int half, int w, int gid, int tig) {
    int oc0 = (w & 3) * 32;
    int n0 = (w >> 2) * 64;
    float acc[16][4];
#pragma unroll
    for (int i = 0; i < 16; i++)
#pragma unroll
        for (int j = 0; j < 4; j++) acc[i][j] = 0.f;
#pragma unroll 1
    for (int ks = 0; ks < 8; ks++) {
        int kw = ks * 8;
        uint32_t Ah[2][4], Al[2][4], Bh[8][2], Bl[8][2];
#pragma unroll
        for (int mt = 0; mt < 2; mt++) {
            int r0 = (oc0 + mt * 16 + gid) * 68 + kw + tig;
            int r8 = r0 + 8 * 68;
            Ah[mt][0] = WhW[r0];     Ah[mt][1] = WhW[r8];
            Ah[mt][2] = WhW[r0 + 4]; Ah[mt][3] = WhW[r8 + 4];
            Al[mt][0] = WlW[r0];     Al[mt][1] = WlW[r8];
            Al[mt][2] = WlW[r0 + 4]; Al[mt][3] = WlW[r8 + 4];
        }
#pragma unroll
        for (int nt = 0; nt < 8; nt++) {
            int rr = (n0 + nt * 8 + gid) * 68 + kw + tig;
            Bh[nt][0] = XhW[rr]; Bh[nt][1] = XhW[rr + 4];
            Bl[nt][0] = XlW[rr]; Bl[nt][1] = XlW[rr + 4];
        }
#pragma unroll
        for (int mt = 0; mt < 2; mt++)
#pragma unroll
            for (int nt = 0; nt < 8; nt++) {
                MMA_BF16(acc[mt * 8 + nt], Ah[mt], Bh[nt]);
                MMA_BF16(acc[mt * 8 + nt], Ah[mt], Bl[nt]);
                MMA_BF16(acc[mt * 8 + nt], Al[mt], Bh[nt]);
            }
    }
#pragma unroll
    for (int mt = 0; mt < 2; mt++) {
        int ocA = oc0 + mt * 16 + gid;
        int ocB = ocA + 8;
        float bvA = __ldg(&bias[ocA]);
        float bvB = __ldg(&bias[ocB]);
#pragma unroll
        for (int nt = 0; nt < 8; nt++) {
            int col = n0 + nt * 8 + tig * 2;
            int p = half * 128 + col;
            int pix = (py0 + (p >> 4)) * 256 + px0 + (p & 15);
            float2 v0 = make_float2(acc[mt * 8 + nt][0] + bvA, acc[mt * 8 + nt][1] + bvA);
            float2 v1 = make_float2(acc[mt * 8 + nt][2] + bvB, acc[mt * 8 + nt][3] + bvB);
            *(float2*)(yb + (size_t)ocA * HW + pix) = v0;
            *(float2*)(yb + (size_t)ocB * HW + pix) = v1;
        }
    }
}

// ---------------- conv1x1 GEMM, FULL window per block (512 thr) ----------------
#define CV_SMEM_FULL ((2 * 128 * 136 + 2 * 256 * 136) * 2)
__global__ void __launch_bounds__(512, 1)
conv1x1_mma(const float* __restrict__ xin, const __nv_bfloat16* __restrict__ wsp,
            const float* __restrict__ bias, float* __restrict__ yout, int bOff) {
    int n = blockIdx.x, b = blockIdx.y + bOff;
    extern __shared__ __nv_bfloat16 smb[];
    __nv_bfloat16* Wh = smb;
    __nv_bfloat16* Wl = Wh + 128 * 136;
    __nv_bfloat16* Xh = Wl + 128 * 136;   // 256 rows x 136
    __nv_bfloat16* Xl = Xh + 256 * 136;
    int t = threadIdx.x;

    {
        const uint4* src = (const uint4*)wsp;
        uint4* dst = (uint4*)smb;
#pragma unroll
        for (int i = 0; i < 9; i++) {
            int idx = t + i * 512;
            if (idx < 4352) dst[idx] = src[idx];
        }
    }

    int py0 = (n >> 4) * 16, px0 = (n & 15) * 16;
    const float* xb = xin + (size_t)b * CH * HW;
    {
        int px = t & 255;
        int pix = (py0 + (px >> 4)) * 256 + px0 + (px & 15);
        int cp0 = t >> 8;
#pragma unroll
        for (int j = 0; j < 32; j++) {
            int cp = cp0 + j * 2;
            float v0 = xb[(size_t)(2 * cp) * HW + pix];
            float v1 = xb[(size_t)(2 * cp + 1) * HW + pix];
            __nv_bfloat16 h0 = __float2bfloat16_rn(v0);
            __nv_bfloat16 h1 = __float2bfloat16_rn(v1);
            __nv_bfloat16 l0 = __float2bfloat16_rn(v0 - __bfloat162float(h0));
            __nv_bfloat16 l1 = __float2bfloat16_rn(v1 - __bfloat162float(h1));
            ((__nv_bfloat162*)(Xh + px * 136))[cp] = __nv_bfloat162(h0, h1);
            ((__nv_bfloat162*)(Xl + px * 136))[cp] = __nv_bfloat162(l0, l1);
        }
    }
    __syncthreads();

    int wfull = t >> 5, lane = t & 31;
    int half = wfull >> 3;
    int w = wfull & 7;
    int gid = lane >> 2, tig = lane & 3;
    gemm_body_128((const uint32_t*)Wh, (const uint32_t*)Wl,
                  (const uint32_t*)(Xh + half * 128 * 136), (const uint32_t*)(Xl + half * 128 * 136),
                  bias, yout + (size_t)b * CH * HW, py0, px0, half, w, gid, tig);
}

// ---------------- fused flow-warp + q/k projections, FULL window (512 thr) ----------------
// smem: Wh|Wl (staged Wq then Wk) + Xh|Xl full window = CV_SMEM_FULL
__global__ void __launch_bounds__(512, 1)
convqk_mma(const float* __restrict__ xin,
           const __nv_bfloat16* __restrict__ wq, const __nv_bfloat16* __restrict__ wk,
           const float* __restrict__ qbias, const float* __restrict__ kbias) {
    int n = blockIdx.x, b = blockIdx.y;
    if (g_MASK[b * 256 + n] == 0.f) return;
    extern __shared__ __nv_bfloat16 smb[];
    __nv_bfloat16* Wh = smb;
    __nv_bfloat16* Wl = Wh + 128 * 136;
    __nv_bfloat16* Xh = Wl + 128 * 136;
    __nv_bfloat16* Xl = Xh + 256 * 136;
    int t = threadIdx.x;

    // stage Wq
    {
        const uint4* src = (const uint4*)wq;
        uint4* dst = (uint4*)smb;
#pragma unroll
        for (int i = 0; i < 9; i++) {
            int idx = t + i * 512;
            if (idx < 4352) dst[idx] = src[idx];
        }
    }

    // stage X = flow_warp(x), full window, gather computed once per thread
    int py0 = (n >> 4) * 16, px0 = (n & 15) * 16;
    {
        int px = t & 255;
        int gy = py0 + (px >> 4), gx = px0 + (px & 15);
        int pp = gy * 256 + gx;
        const float* OFb = g_OFF + (size_t)b * 2 * HW;
        float fx = OFb[pp];
        float fy = OFb[HW + pp];
        float sx = fminf(fmaxf((float)gx + fx, 0.f), 255.f);
        float sy = fminf(fmaxf((float)gy + fy, 0.f), 255.f);
        float x0f = floorf(sx), y0f = floorf(sy);
        float x1f = fminf(x0f + 1.f, 255.f), y1f = fminf(y0f + 1.f, 255.f);
        float wx = sx - x0f, wy = sy - y0f;
        int x0 = (int)x0f, x1 = (int)x1f, y0 = (int)y0f, y1 = (int)y1f;
        int iA = y0 * 256 + x0, iB = y0 * 256 + x1, iC = y1 * 256 + x0, iD = y1 * 256 + x1;
        float w00 = (1.f - wx) * (1.f - wy), w01 = wx * (1.f - wy);
        float w10 = (1.f - wx) * wy, w11 = wx * wy;
        const float* xb = xin + (size_t)b * CH * HW;
        int cp0 = t >> 8;
#pragma unroll 4
        for (int j = 0; j < 32; j++) {
            int cp = cp0 + j * 2;
            const float* xc0 = xb + (size_t)(2 * cp) * HW;
            const float* xc1 = xc0 + HW;
            float v0 = __ldg(&xc0[iA]) * w00 + __ldg(&xc0[iB]) * w01 +
                       __ldg(&xc0[iC]) * w10 + __ldg(&xc0[iD]) * w11;
            float v1 = __ldg(&xc1[iA]) * w00 + __ldg(&xc1[iB]) * w01 +
                       __ldg(&xc1[iC]) * w10 + __ldg(&xc1[iD]) * w11;
            __nv_bfloat16 h0 = __float2bfloat16_rn(v0);
            __nv_bfloat16 h1 = __float2bfloat16_rn(v1);
            __nv_bfloat16 l0 = __float2bfloat16_rn(v0 - __bfloat162float(h0));
            __nv_bfloat16 l1 = __float2bfloat16_rn(v1 - __bfloat162float(h1));
            ((__nv_bfloat162*)(Xh + px * 136))[cp] = __nv_bfloat162(h0, h1);
            ((__nv_bfloat162*)(Xl + px * 136))[cp] = __nv_bfloat162(l0, l1);
        }
    }
    __syncthreads();

    int wfull = t >> 5, lane = t & 31;
    int half = wfull >> 3;
    int w = wfull & 7;
    int gid = lane >> 2, tig = lane & 3;
    const uint32_t* XhW = (const uint32_t*)(Xh + half * 128 * 136);
    const uint32_t* XlW = (const uint32_t*)(Xl + half * 128 * 136);

    // Q = Wq . X
    gemm_body_128((const uint32_t*)Wh, (const uint32_t*)Wl, XhW, XlW,
                  qbias, g_Qb + (size_t)b * CH * HW, py0, px0, half, w, gid, tig);
    __syncthreads();   // all reads of Wq done before overwrite
    // stage Wk over Wq
    {
        const uint4* src = (const uint4*)wk;
        uint4* dst = (uint4*)smb;
#pragma unroll
        for (int i = 0; i < 9; i++) {
            int idx = t + i * 512;
            if (idx < 4352) dst[idx] = src[idx];
        }
    }
    __syncthreads();
    // K = Wk . X
    gemm_body_128((const uint32_t*)Wh, (const uint32_t*)Wl, XhW, XlW,
                  kbias, g_Kb + (size_t)b * CH * HW, py0, px0, half, w, gid, tig);
}

// ---------------- predictor ----------------
__global__ void predictor_kernel(const float* __restrict__ cond_g,
                                 const float* __restrict__ rin_w, const float* __restrict__ rin_b,
                                 const float* __restrict__ r1w, const float* __restrict__ r1b,
                                 const float* __restrict__ r2w, const float* __restrict__ r2b) {
    __shared__ float wr[32 * 131];
    __shared__ float wr1[16 * 32];
    __shared__ float wr2[32];
    __shared__ float partial[8][32];
    int t = threadIdx.x;
    int b = blockIdx.y;
    for (int i = t; i < 32 * 131; i += 256) wr[i] = rin_w[i];
    for (int i = t; i < 16 * 32; i += 256) wr1[i] = r1w[i];
    if (t < 32) wr2[t] = r2w[t];
    __syncthreads();

    int p0 = blockIdx.x * 512 + t;
    int p1 = p0 + 256;
    float a0[32], a1[32];
#pragma unroll
    for (int o = 0; o < 32; o++) {
        float bv = __ldg(&rin_b[o]);
        a0[o] = bv; a1[o] = bv;
    }
    const float* vb = g_V + (size_t)b * CH * HW;
#pragma unroll 2
    for (int ci = 0; ci < 128; ci++) {
        float x0 = vb[(size_t)ci * HW + p0];
        float x1 = vb[(size_t)ci * HW + p1];
#pragma unroll
        for (int o = 0; o < 32; o++) {
            float wv = wr[o * 131 + ci];
            a0[o] = fmaf(wv, x0, a0[o]);
            a1[o] = fmaf(wv, x1, a1[o]);
        }
    }
    float cg0 = __ldg(&cond_g[b * HW + p0]);
    float cg1 = __ldg(&cond_g[b * HW + p1]);
    int y0 = p0 >> 8, x0p = p0 & 255;
    int y1 = p1 >> 8, x1p = p1 & 255;
    float ly0 = -1.f + (float)(y0 & 15) * (2.f / 15.f);
    float lx0 = -1.f + (float)(x0p & 15) * (2.f / 15.f);
    float ly1 = -1.f + (float)(y1 & 15) * (2.f / 15.f);
    float lx1 = -1.f + (float)(x1p & 15) * (2.f / 15.f);
    float fm0 = 0.f, fm1 = 0.f;
    float* Fb = g_F + (size_t)b * 32 * HW;
#pragma unroll
    for (int o = 0; o < 32; o++) {
        float v0 = a0[o] + wr[o * 131 + 128] * cg0 + wr[o * 131 + 129] * ly0 + wr[o * 131 + 130] * lx0;
        float v1 = a1[o] + wr[o * 131 + 128] * cg1 + wr[o * 131 + 129] * ly1 + wr[o * 131 + 130] * lx1;
        v0 = leakyf(v0); v1 = leakyf(v1);
        a0[o] = v0; a1[o] = v1;
        Fb[(size_t)o * HW + p0] = v0;
        Fb[(size_t)o * HW + p1] = v1;
        fm0 += v0; fm1 += v1;
    }
    g_FMC[b * HW + p0] = fm0 * (1.f / 32.f);
    g_FMC[b * HW + p1] = fm1 * (1.f / 32.f);

    float h0[16], h1v[16];
#pragma unroll
    for (int o2 = 0; o2 < 16; o2++) {
        float bv = __ldg(&r1b[o2]);
        float s0 = bv, s1 = bv;
#pragma unroll
        for (int o = 0; o < 32; o++) {
            float wv = wr1[o2 * 32 + o];
            s0 = fmaf(wv, a0[o], s0);
            s1 = fmaf(wv, a1[o], s1);
        }
        h0[o2] = leakyf(s0);
        h1v[o2] = leakyf(s1);
    }
    float ox0 = __ldg(&r2b[0]), oy0 = __ldg(&r2b[1]);
    float ox1 = ox0, oy1 = oy0;
#pragma unroll
    for (int o2 = 0; o2 < 16; o2++) {
        ox0 = fmaf(wr2[o2], h0[o2], ox0);
        oy0 = fmaf(wr2[16 + o2], h0[o2], oy0);
        ox1 = fmaf(wr2[o2], h1v[o2], ox1);
        oy1 = fmaf(wr2[16 + o2], h1v[o2], oy1);
    }
    float* OFb = g_OFF + (size_t)b * 2 * HW;
    OFb[p0] = ox0; OFb[p1] = ox1;
    OFb[HW + p0] = oy0; OFb[HW + p1] = oy1;

    int lane = t & 31, wid = t >> 5;
#pragma unroll
    for (int o = 0; o < 32; o++) {
        float v = a0[o] + a1[o];
        v += __shfl_xor_sync(0xffffffff, v, 16);
        v += __shfl_xor_sync(0xffffffff, v, 8);
        v += __shfl_xor_sync(0xffffffff, v, 4);
        v += __shfl_xor_sync(0xffffffff, v, 2);
        v += __shfl_xor_sync(0xffffffff, v, 1);
        if (lane == 0) partial[wid][o] = v;
    }
    __syncthreads();
    if (t < 32) {
        float s = 0.f;
#pragma unroll
        for (int w2 = 0; w2 < 8; w2++) s += partial[w2][t];
        atomicAdd(&g_FSUM[b * 32 + t], s);
    }
}

// ---------------- channel attention ca ----------------
__global__ void ca_kernel(const float* __restrict__ rca_w, const float* __restrict__ rca_b) {
    int c = threadIdx.x;
    int b = blockIdx.x;
    float s = __ldg(&rca_b[c]);
#pragma unroll
    for (int ci = 0; ci < 32; ci++)
        s = fmaf(__ldg(&rca_w[c * 32 + ci]), g_FSUM[b * 32 + ci] * (1.f / 65536.f), s);
    g_CA[b * CH + c] = 1.f / (1.f + expf(-s));
}

// ---------------- spatial attention sa ----------------
__global__ void sa_kernel(const float* __restrict__ rsa_w, const float* __restrict__ rsa_b) {
    __shared__ float ws[288];
    int t = threadIdx.x;
    for (int i = t; i < 288; i += 256) ws[i] = rsa_w[i];
    __syncthreads();
    int b = blockIdx.y;
    int p = blockIdx.x * 256 + t;
    int y = p >> 8, x = p & 255;
    float acc = __ldg(&rsa_b[0]);
    const float* Fb = g_F + (size_t)b * 32 * HW;
    for (int ci = 0; ci < 32; ci++) {
        const float* fp = Fb + (size_t)ci * HW;
#pragma unroll
        for (int ky = 0; ky < 3; ky++) {
            int yy = y + ky - 1;
            if ((unsigned)yy >= 256u) continue;
#pragma unroll
            for (int kx = 0; kx < 3; kx++) {
                int xx = x + kx - 1;
                if ((unsigned)xx >= 256u) continue;
                acc = fmaf(ws[ci * 9 + ky * 3 + kx], __ldg(&fp[yy * 256 + xx]), acc);
            }
        }
    }
    g_SA[b * HW + p] = 1.f / (1.f + expf(-acc));
}

// ---------------- window MLP + gumbel hard mask ----------------
__global__ void mask_kernel(const float* __restrict__ gu,
                            const float* __restrict__ rm1_w, const float* __restrict__ rm1_b,
                            const float* __restrict__ rm2_w, const float* __restrict__ rm2_b) {
    __shared__ float m[256];
    __shared__ float h1s[16];
    int n = blockIdx.x, b = blockIdx.y;
    int t = threadIdx.x;
    int dh = t >> 4, dw = t & 15;
    int pix = ((n >> 4) * 16 + dh) * 256 + (n & 15) * 16 + dw;
    m[t] = g_FMC[b * HW + pix];
    __syncthreads();
    if (t < 16) {
        float s = __ldg(&rm1_b[t]);
        for (int e = 0; e < 256; e++) s = fmaf(__ldg(&rm1_w[t * 256 + e]), m[e], s);
        h1s[t] = leakyf(s);
    }
    __syncthreads();
    if (t == 0) {
        float z0 = __ldg(&rm2_b[0]), z1 = __ldg(&rm2_b[1]);
#pragma unroll
        for (int o = 0; o < 16; o++) {
            z0 = fmaf(__ldg(&rm2_w[o]), h1s[o], z0);
            z1 = fmaf(__ldg(&rm2_w[16 + o]), h1s[o], z1);
        }
        float mx = fmaxf(z0, z1);
        float e0 = expf(z0 - mx), e1 = expf(z1 - mx);
        float inv = 1.f / (e0 + e1);
        float p0 = e0 * inv, p1 = e1 * inv;
        float u0 = __ldg(&gu[(b * 256 + n) * 2 + 0]);
        float u1 = __ldg(&gu[(b * 256 + n) * 2 + 1]);
        float g0 = -logf(-logf(u0 + 1e-10f) + 1e-10f);
        float g1 = -logf(-logf(u1 + 1e-10f) + 1e-10f);
        g_MASK[b * 256 + n] = (p0 + g0 >= p1 + g1) ? 1.f : 0.f;
    }
}

// ---------------- window attention, 512 threads (16 warps) ----------------
// smem: S[64*257] f32 | red[512] | rmax[64] | rsum[64] | Qh/Ql [64*136] | KVh/KVl [9216] | Pth/Ptl [64*72]
#define SMEM_ATTN3 ((64*257 + 512 + 64 + 64) * 4 + 90112)
__global__ void __launch_bounds__(512, 1) attn_mma_kernel() {
    int n = blockIdx.x, b = blockIdx.y;
    int t = threadIdx.x;
    int py0 = (n >> 4) * 16, px0 = (n & 15) * 16;
    int cbase = b * CH * HW;
    if (g_MASK[b * 256 + n] == 0.f) {
        const float* sab = g_SA + (size_t)b * HW;
#pragma unroll 4
        for (int i = t; i < 8192; i += 512) {
            int ch = i >> 6, r4 = i & 63;
            int wrow = r4 >> 2, px4 = (r4 & 3) * 4;
            int pix = (py0 + wrow) * 256 + px0 + px4;
            float4 v = *(const float4*)(g_V + cbase + ch * HW + pix);
            float4 s = *(const float4*)(sab + pix);
            v.x *= s.x; v.y *= s.y; v.z *= s.z; v.w *= s.w;
            *(float4*)(g_OUT + cbase + ch * HW + pix) = v;
        }
        return;
    }
    extern __shared__ char smraw[];
    float* S = (float*)smraw;
    float* red = S + 64 * 257;        // 512
    float* rmax = red + 512;          // 64
    float* rsum = rmax + 64;          // 64
    __nv_bfloat16* Qh = (__nv_bfloat16*)(rsum + 64);
    __nv_bfloat16* Ql = Qh + 64 * 136;
    __nv_bfloat16* KVh = Ql + 64 * 136;
    __nv_bfloat16* KVl = KVh + 9216;
    __nv_bfloat16* Pth = KVl + 9216;
    __nv_bfloat16* Ptl = Pth + 64 * 72;

    const uint32_t* QhW = (const uint32_t*)Qh;
    const uint32_t* QlW = (const uint32_t*)Ql;
    const uint32_t* KVhW = (const uint32_t*)KVh;
    const uint32_t* KVlW = (const uint32_t*)KVl;
    const uint32_t* PthW = (const uint32_t*)Pth;
    const uint32_t* PtlW = (const uint32_t*)Ptl;

    int w = t >> 5, lane = t & 31;
    int gid = lane >> 2;
    int tig = lane & 3;

#pragma unroll 1
    for (int rc = 0; rc < 4; rc++) {
        int r0 = rc * 64;
        __syncthreads();
        // ---- stage Q chunk (64 px x 128 ch) hi/lo ----
#pragma unroll
        for (int j = 0; j < 8; j++) {
            int i = t + j * 512;
            int px = i & 63, cp = i >> 6;
            int p = r0 + px;
            int pix = (py0 + (p >> 4)) * 256 + px0 + (p & 15);
            float v0 = g_Qb[cbase + (2 * cp) * HW + pix];
            float v1 = g_Qb[cbase + (2 * cp + 1) * HW + pix];
            __nv_bfloat16 h0 = __float2bfloat16_rn(v0);
            __nv_bfloat16 h1 = __float2bfloat16_rn(v1);
            __nv_bfloat16 l0 = __float2bfloat16_rn(v0 - __bfloat162float(h0));
            __nv_bfloat16 l1 = __float2bfloat16_rn(v1 - __bfloat162float(h1));
            ((__nv_bfloat162*)(Qh + px * 136))[cp] = __nv_bfloat162(h0, h1);
            ((__nv_bfloat162*)(Ql + px * 136))[cp] = __nv_bfloat162(l0, l1);
        }

        // ---- S = Q K^T : 16 warps = 4(m) x 4(n); warp tile 16x16 per 64-col KV tile ----
        int mrowS = (w & 3) * 16, ncolS = (w >> 2) * 16;
#pragma unroll 1
        for (int kvt = 0; kvt < 4; kvt++) {
            __syncthreads();
#pragma unroll
            for (int j = 0; j < 8; j++) {
                int i = t + j * 512;
                int px = i & 63, cp = i >> 6;
                int p = kvt * 64 + px;
                int pix = (py0 + (p >> 4)) * 256 + px0 + (p & 15);
                float v0 = g_Kb[cbase + (2 * cp) * HW + pix];
                float v1 = g_Kb[cbase + (2 * cp + 1) * HW + pix];
                __nv_bfloat16 h0 = __float2bfloat16_rn(v0);
                __nv_bfloat16 h1 = __float2bfloat16_rn(v1);
                __nv_bfloat16 l0 = __float2bfloat16_rn(v0 - __bfloat162float(h0));
                __nv_bfloat16 l1 = __float2bfloat16_rn(v1 - __bfloat162float(h1));
                ((__nv_bfloat162*)(KVh + px * 136))[cp] = __nv_bfloat162(h0, h1);
                ((__nv_bfloat162*)(KVl + px * 136))[cp] = __nv_bfloat162(l0, l1);
            }
            __syncthreads();
            float acc[2][4];
#pragma unroll
            for (int i = 0; i < 2; i++)
#pragma unroll
                for (int j2 = 0; j2 < 4; j2++) acc[i][j2] = 0.f;
#pragma unroll
            for (int ks = 0; ks < 8; ks++) {
                int kw = ks * 8;
                uint32_t Ahf[4], Alf[4], Bhf[2][2], Blf[2][2];
                int ra = (mrowS + gid) * 68 + kw + tig;
                int ra8 = ra + 8 * 68;
                Ahf[0] = QhW[ra];     Ahf[1] = QhW[ra8];
                Ahf[2] = QhW[ra + 4]; Ahf[3] = QhW[ra8 + 4];
                Alf[0] = QlW[ra];     Alf[1] = QlW[ra8];
                Alf[2] = QlW[ra + 4]; Alf[3] = QlW[ra8 + 4];
#pragma unroll
                for (int nt = 0; nt < 2; nt++) {
                    int rr = (ncolS + nt * 8 + gid) * 68 + kw + tig;
                    Bhf[nt][0] = KVhW[rr]; Bhf[nt][1] = KVhW[rr + 4];
                    Blf[nt][0] = KVlW[rr]; Blf[nt][1] = KVlW[rr + 4];
                }
#pragma unroll
                for (int nt = 0; nt < 2; nt++) {
                    MMA_BF16(acc[nt], Ahf, Bhf[nt]);
                    MMA_BF16(acc[nt], Ahf, Blf[nt]);
                    MMA_BF16(acc[nt], Alf, Bhf[nt]);
                }
            }
#pragma unroll
            for (int nt = 0; nt < 2; nt++) {
                int col = kvt * 64 + ncolS + nt * 8 + tig * 2;
                S[(mrowS + gid) * 257 + col] = acc[nt][0];
                S[(mrowS + gid) * 257 + col + 1] = acc[nt][1];
                S[(mrowS + gid + 8) * 257 + col] = acc[nt][2];
                S[(mrowS + gid + 8) * 257 + col + 1] = acc[nt][3];
            }
        }
        __syncthreads();

        // ---- softmax: 8 segments x 32 cols, 512 threads ----
        {
            int r = t & 63, seg = t >> 6;   // seg 0..7
            float* srow = &S[r * 257 + seg * 32];
            float mx = -1e30f;
#pragma unroll 8
            for (int k = 0; k < 32; k++) mx = fmaxf(mx, srow[k]);
            red[seg * 64 + r] = mx;
            __syncthreads();
            if (t < 64) {
                float m0 = fmaxf(fmaxf(red[t], red[64 + t]), fmaxf(red[128 + t], red[192 + t]));
                float m1 = fmaxf(fmaxf(red[256 + t], red[320 + t]), fmaxf(red[384 + t], red[448 + t]));
                rmax[t] = fmaxf(m0, m1);
            }
            __syncthreads();
            float rm_ = rmax[r];
            float s = 0.f;
#pragma unroll 8
            for (int k = 0; k < 32; k++) {
                float e = __expf(srow[k] - rm_);
                srow[k] = e;
                s += e;
            }
            red[seg * 64 + r] = s;
            __syncthreads();
            if (t < 64)
                rsum[t] = (red[t] + red[64 + t] + red[128 + t] + red[192 + t]) +
                          (red[256 + t] + red[320 + t] + red[384 + t] + red[448 + t]);
            __syncthreads();
        }

        // ---- O = P V : 16 warps = 4(m) x 4(n); warp tile 16 rows x 32 ch ----
        int mrowO = (w & 3) * 16, ncolO = (w >> 2) * 32;
        float oacc[4][4];
#pragma unroll
        for (int i = 0; i < 4; i++)
#pragma unroll
            for (int j2 = 0; j2 < 4; j2++) oacc[i][j2] = 0.f;

#pragma unroll 1
        for (int kvt = 0; kvt < 4; kvt++) {
            __syncthreads();
#pragma unroll
            for (int j = 0; j < 8; j++) {
                int i = t + j * 512;
                int col = i & 63, row = i >> 6;
                float v = S[row * 257 + kvt * 64 + col];
                __nv_bfloat16 h = __float2bfloat16_rn(v);
                Pth[row * 72 + col] = h;
                Ptl[row * 72 + col] = __float2bfloat16_rn(v - __bfloat162float(h));
            }
#pragma unroll
            for (int j = 0; j < 16; j++) {
                int i = t + j * 512;
                int px = i & 63, ch = i >> 6;
                int p = kvt * 64 + px;
                int pix = (py0 + (p >> 4)) * 256 + px0 + (p & 15);
                float v = g_V[cbase + ch * HW + pix];
                __nv_bfloat16 h = __float2bfloat16_rn(v);
                KVh[ch * 72 + px] = h;
                KVl[ch * 72 + px] = __float2bfloat16_rn(v - __bfloat162float(h));
            }
            __syncthreads();
#pragma unroll
            for (int ks = 0; ks < 4; ks++) {
                int kw = ks * 8;
                uint32_t Ahf[4], Alf[4], Bhf[4][2], Blf[4][2];
                int ra = (mrowO + gid) * 36 + kw + tig;
                int ra8 = ra + 8 * 36;
                Ahf[0] = PthW[ra];     Ahf[1] = PthW[ra8];
                Ahf[2] = PthW[ra + 4]; Ahf[3] = PthW[ra8 + 4];
                Alf[0] = PtlW[ra];     Alf[1] = PtlW[ra8];
                Alf[2] = PtlW[ra + 4]; Alf[3] = PtlW[ra8 + 4];
#pragma unroll
                for (int nt = 0; nt < 4; nt++) {
                    int rr = (ncolO + nt * 8 + gid) * 36 + kw + tig;
                    Bhf[nt][0] = KVhW[rr]; Bhf[nt][1] = KVhW[rr + 4];
                    Blf[nt][0] = KVlW[rr]; Blf[nt][1] = KVlW[rr + 4];
                }
#pragma unroll
                for (int nt = 0; nt < 4; nt++) {
                    MMA_BF16(oacc[nt], Ahf, Bhf[nt]);
                    MMA_BF16(oacc[nt], Ahf, Blf[nt]);
                    MMA_BF16(oacc[nt], Alf, Bhf[nt]);
                }
            }
        }

        // ---- epilogue ----
        {
            int rowA = mrowO + gid, rowB = rowA + 8;
            float invA = 1.f / rsum[rowA];
            float invB = 1.f / rsum[rowB];
            int pA = r0 + rowA, pB = r0 + rowB;
            int pixA = (py0 + (pA >> 4)) * 256 + px0 + (pA & 15);
            int pixB = (py0 + (pB >> 4)) * 256 + px0 + (pB & 15);
#pragma unroll
            for (int nt = 0; nt < 4; nt++) {
                int ch = ncolO + nt * 8 + tig * 2;
                g_OUT[cbase + ch * HW + pixA] = oacc[nt][0] * invA;
                g_OUT[cbase + (ch + 1) * HW + pixA] = oacc[nt][1] * invA;
                g_OUT[cbase + ch * HW + pixB] = oacc[nt][2] * invB;
                g_OUT[cbase + (ch + 1) * HW + pixB] = oacc[nt][3] * invB;
            }
        }
    }
}

// ---------------- fused depthwise 5x5(d1) -> 5x5(d3) + gelu*ca + residual ----------------
__global__ void __launch_bounds__(256) dw5x2_kernel(
    const float* __restrict__ in, const float* __restrict__ w2, const float* __restrict__ b2,
    const float* __restrict__ w3, const float* __restrict__ b3, float* __restrict__ out) {
    __shared__ float sIn[48][81];
    __shared__ float sMid[44][77];
    __shared__ float wA[25], wB[25];
    int c = blockIdx.z & 127, b = blockIdx.z >> 7;
    int t = threadIdx.x;
    if (t < 25) wA[t] = w2[c * 25 + t];
    else if (t < 50) wB[t - 25] = w3[c * 25 + (t - 25)];
    int ox0 = blockIdx.x * 64, oy0 = blockIdx.y * 32;
    const float* ip = in + (size_t)(b * CH + c) * HW;

    for (int i = t; i < 48 * 80; i += 256) {
        int lx = i % 80, ly = i / 80;
        int gx = ox0 - 8 + lx, gy = oy0 - 8 + ly;
        float v = 0.f;
        if ((unsigned)gx < 256u && (unsigned)gy < 256u) v = __ldg(&ip[gy * 256 + gx]);
        sIn[ly][lx] = v;
    }
    __syncthreads();

    float b2v = __ldg(&b2[c]);
    for (int i = t; i < 44 * 76; i += 256) {
        int mx = i % 76, my = i / 76;
        int gx = ox0 - 6 + mx, gy = oy0 - 6 + my;
        float acc = 0.f;
        if ((unsigned)gx < 256u && (unsigned)gy < 256u) {
            acc = b2v;
#pragma unroll
            for (int ky = 0; ky < 5; ky++)
#pragma unroll
                for (int kx = 0; kx < 5; kx++)
                    acc = fmaf(wA[ky * 5 + kx], sIn[my + ky][mx + kx], acc);
        }
        sMid[my][mx] = acc;
    }
    __syncthreads();

    float b3v = __ldg(&b3[c]);
    float cav = g_CA[b * CH + c];
    size_t obase = (size_t)(b * CH + c) * HW;
    for (int i = t; i < 32 * 64; i += 256) {
        int x = i % 64, y = i / 64;
        float acc = b3v;
#pragma unroll
        for (int ky = 0; ky < 5; ky++)
#pragma unroll
            for (int kx = 0; kx < 5; kx++)
                acc = fmaf(wB[ky * 5 + kx], sMid[y + 3 * ky][x + 3 * kx], acc);
        float g = 0.5f * acc * (1.f + erff(acc * 0.7071067811865475f));
        size_t oidx = obase + (size_t)(oy0 + y) * 256 + ox0 + x;
        out[oidx] = g * cav + g_OUT[oidx];
    }
}

// ---------------- launch ----------------
extern "C" void kernel_launch(void* const* d_in, const int* in_sizes, int n_in,
                              void* d_out, int out_size) {
    const float* x      = (const float*)d_in[0];
    const float* cond_g = (const float*)d_in[1];
    const float* gu     = (const float*)d_in[2];
    const float* pv_w   = (const float*)d_in[3];
    const float* pv_b   = (const float*)d_in[4];
    const float* pq_w   = (const float*)d_in[5];
    const float* pq_b   = (const float*)d_in[6];
    const float* pk_w   = (const float*)d_in[7];
    const float* pk_b   = (const float*)d_in[8];
    const float* cs1_w  = (const float*)d_in[9];
    const float* cs1_b  = (const float*)d_in[10];
    const float* cs2_w  = (const float*)d_in[11];
    const float* cs2_b  = (const float*)d_in[12];
    const float* cs3_w  = (const float*)d_in[13];
    const float* cs3_b  = (const float*)d_in[14];
    const float* po_w   = (const float*)d_in[15];
    const float* po_b   = (const float*)d_in[16];
    const float* rin_w  = (const float*)d_in[17];
    const float* rin_b  = (const float*)d_in[18];
    const float* r1w    = (const float*)d_in[19];
    const float* r1b    = (const float*)d_in[20];
    const float* r2w    = (const float*)d_in[21];
    const float* r2b    = (const float*)d_in[22];
    const float* rm1_w  = (const float*)d_in[23];
    const float* rm1_b  = (const float*)d_in[24];
    const float* rm2_w  = (const float*)d_in[25];
    const float* rm2_b  = (const float*)d_in[26];
    const float* rca_w  = (const float*)d_in[27];
    const float* rca_b  = (const float*)d_in[28];
    const float* rsa_w  = (const float*)d_in[29];
    const float* rsa_b  = (const float*)d_in[30];

    float *pV, *pOUT, *pT1, *pT2;
    __nv_bfloat16* pWT;
    cudaGetSymbolAddress((void**)&pV, g_V);
    cudaGetSymbolAddress((void**)&pOUT, g_OUT);
    cudaGetSymbolAddress((void**)&pT1, g_T1);
    cudaGetSymbolAddress((void**)&pT2, g_T2);
    cudaGetSymbolAddress((void**)&pWT, g_WT);

    cudaFuncSetAttribute(attn_mma_kernel, cudaFuncAttributeMaxDynamicSharedMemorySize, SMEM_ATTN3);
    cudaFuncSetAttribute(conv1x1_mma, cudaFuncAttributeMaxDynamicSharedMemorySize, CV_SMEM_FULL);
    cudaFuncSetAttribute(convqk_mma, cudaFuncAttributeMaxDynamicSharedMemorySize, CV_SMEM_FULL);

    const int WSET = 2 * 128 * 136;

    prep_all_kernel<<<dim3(64, 5), 256>>>(pv_w, pq_w, pk_w, cs1_w, po_w);
    zero_fsum_kernel<<<1, 128>>>();
    conv1x1_mma<<<dim3(256, BB), 512, CV_SMEM_FULL>>>(x, pWT + 0 * WSET, pv_b, pV, 0);
    predictor_kernel<<<dim3(HW / 512, BB), 256>>>(cond_g, rin_w, rin_b, r1w, r1b, r2w, r2b);
    ca_kernel<<<BB, 128>>>(rca_w, rca_b);
    sa_kernel<<<dim3(HW / 256, BB), 256>>>(rsa_w, rsa_b);
    mask_kernel<<<dim3(256, BB), 256>>>(gu, rm1_w, rm1_b, rm2_w, rm2_b);
    convqk_mma<<<dim3(256, BB), 512, CV_SMEM_FULL>>>(x, pWT + 1 * WSET, pWT + 2 * WSET, pq_b, pk_b);
    attn_mma_kernel<<<dim3(256, BB), 512, SMEM_ATTN3>>>();
    conv1x1_mma<<<dim3(256, BB), 512, CV_SMEM_FULL>>>(pOUT, pWT + 3 * WSET, cs1_b, pT1, 0);
    dw5x2_kernel<<<dim3(4, 8, BB * CH), 256>>>(pT1, cs2_w, cs2_b, cs3_w, cs3_b, pT2);
    conv1x1_mma<<<dim3(256, BB), 512, CV_SMEM_FULL>>>(pT2, pWT + 4 * WSET, po_b, (float*)d_out, 0);
}

// round 12
// speedup vs baseline: 2.3294x; 1.0161x over previous
#include <cuda_runtime.h>
#include <cuda_bf16.h>
#include <stdint.h>
#include <math.h>

#define HW 65536
#define WIMG 256
#define CH 128
#define BB 4
#define ELT (BB*CH*HW)

// ---------------- scratch ----------------
__device__ float g_V[ELT];
__device__ float g_Qb[ELT];
__device__ float g_Kb[ELT];
__device__ float g_OUT[ELT];
__device__ float g_T1[ELT];
__device__ float g_T2[ELT];
__device__ float g_F[BB*32*HW];
__device__ float g_OFF[BB*2*HW];
__device__ float g_FMC[BB*HW];
__device__ float g_SA[BB*HW];
__device__ float g_FSUM[BB*32];
__device__ float g_CA[BB*CH];
__device__ float g_MASK[BB*256];
__device__ __align__(16) __nv_bfloat16 g_WT[5][2][128*136];

__device__ __forceinline__ float leakyf(float x) { return x > 0.f ? x : 0.2f * x; }

__global__ void zero_fsum_kernel() {
    g_FSUM[threadIdx.x] = 0.f;
}

// ---------------- weight prep ----------------
__global__ void prep_all_kernel(const float* __restrict__ w0, const float* __restrict__ w1,
                                const float* __restrict__ w2, const float* __restrict__ w3,
                                const float* __restrict__ w4) {
    int set = blockIdx.y;
    const float* w = (set == 0) ? w0 : (set == 1) ? w1 : (set == 2) ? w2 : (set == 3) ? w3 : w4;
    int i = blockIdx.x * 256 + threadIdx.x;
    int oc = i >> 7, ci = i & 127;
    float v = w[i];
    __nv_bfloat16 h = __float2bfloat16_rn(v);
    __nv_bfloat16 l = __float2bfloat16_rn(v - __bfloat162float(h));
    g_WT[set][0][oc * 136 + ci] = h;
    g_WT[set][1][oc * 136 + ci] = l;
}

// ---------------- HMMA m16n8k16 bf16 ----------------
#define MMA_BF16(d, a, b) \
    asm volatile("mma.sync.aligned.m16n8k16.row.col.f32.bf16.bf16.f32 " \
        "{%0,%1,%2,%3}, {%4,%5,%6,%7}, {%8,%9}, {%0,%1,%2,%3};" \
        : "+f"((d)[0]), "+f"((d)[1]), "+f"((d)[2]), "+f"((d)[3]) \
        : "r"((a)[0]), "r"((a)[1]), "r"((a)[2]), "r"((a)[3]), "r"((b)[0]), "r"((b)[1]))

// ---- shared GEMM body (proven): 8-warp slice over one 128px half ----
__device__ __forceinline__ void gemm_body_128(
    const uint32_t* WhW, const uint32_t* WlW,
    const uint32_t* XhW, const uint32_t* XlW,
    const float* __restrict__ bias, float* __restrict__ yb,
    int py0, int px0, int half, int w, int gid, int tig) {
    int oc0 = (w & 3) * 32;
    int n0 = (w >> 2) * 64;
    float acc[16][4];
#pragma unroll
    for (int i = 0; i < 16; i++)
#pragma unroll
        for (int j = 0; j < 4; j++) acc[i][j] = 0.f;
#pragma unroll 1
    for (int ks = 0; ks < 8; ks++) {
        int kw = ks * 8;
        uint32_t Ah[2][4], Al[2][4], Bh[8][2], Bl[8][2];
#pragma unroll
        for (int mt = 0; mt < 2; mt++) {
            int r0 = (oc0 + mt * 16 + gid) * 68 + kw + tig;
            int r8 = r0 + 8 * 68;
            Ah[mt][0] = WhW[r0];     Ah[mt][1] = WhW[r8];
            Ah[mt][2] = WhW[r0 + 4]; Ah[mt][3] = WhW[r8 + 4];
            Al[mt][0] = WlW[r0];     Al[mt][1] = WlW[r8];
            Al[mt][2] = WlW[r0 + 4]; Al[mt][3] = WlW[r8 + 4];
        }
#pragma unroll
        for (int nt = 0; nt < 8; nt++) {
            int rr = (n0 + nt * 8 + gid) * 68 + kw + tig;
            Bh[nt][0] = XhW[rr]; Bh[nt][1] = XhW[rr + 4];
            Bl[nt][0] = XlW[rr]; Bl[nt][1] = XlW[rr + 4];
        }
#pragma unroll
        for (int mt = 0; mt < 2; mt++)
#pragma unroll
            for (int nt = 0; nt < 8; nt++) {
                MMA_BF16(acc[mt * 8 + nt], Ah[mt], Bh[nt]);
                MMA_BF16(acc[mt * 8 + nt], Ah[mt], Bl[nt]);
                MMA_BF16(acc[mt * 8 + nt], Al[mt], Bh[nt]);
            }
    }
#pragma unroll
    for (int mt = 0; mt < 2; mt++) {
        int ocA = oc0 + mt * 16 + gid;
        int ocB = ocA + 8;
        float bvA = __ldg(&bias[ocA]);
        float bvB = __ldg(&bias[ocB]);
#pragma unroll
        for (int nt = 0; nt < 8; nt++) {
            int col = n0 + nt * 8 + tig * 2;
            int p = half * 128 + col;
            int pix = (py0 + (p >> 4)) * 256 + px0 + (p & 15);
            float2 v0 = make_float2(acc[mt * 8 + nt][0] + bvA, acc[mt * 8 + nt][1] + bvA);
            float2 v1 = make_float2(acc[mt * 8 + nt][2] + bvB, acc[mt * 8 + nt][3] + bvB);
            *(float2*)(yb + (size_t)ocA * HW + pix) = v0;
            *(float2*)(yb + (size_t)ocB * HW + pix) = v1;
        }
    }
}

// ---------------- conv1x1 GEMM, FULL window per block (512 thr) ----------------
#define CV_SMEM_FULL ((2 * 128 * 136 + 2 * 256 * 136) * 2)
__global__ void __launch_bounds__(512, 1)
conv1x1_mma(const float* __restrict__ xin, const __nv_bfloat16* __restrict__ wsp,
            const float* __restrict__ bias, float* __restrict__ yout, int bOff) {
    int n = blockIdx.x, b = blockIdx.y + bOff;
    extern __shared__ __nv_bfloat16 smb[];
    __nv_bfloat16* Wh = smb;
    __nv_bfloat16* Wl = Wh + 128 * 136;
    __nv_bfloat16* Xh = Wl + 128 * 136;
    __nv_bfloat16* Xl = Xh + 256 * 136;
    int t = threadIdx.x;

    {
        const uint4* src = (const uint4*)wsp;
        uint4* dst = (uint4*)smb;
#pragma unroll
        for (int i = 0; i < 9; i++) {
            int idx = t + i * 512;
            if (idx < 4352) dst[idx] = src[idx];
        }
    }

    int py0 = (n >> 4) * 16, px0 = (n & 15) * 16;
    const float* xb = xin + (size_t)b * CH * HW;
    {
        int px = t & 255;
        int pix = (py0 + (px >> 4)) * 256 + px0 + (px & 15);
        int cp0 = t >> 8;
#pragma unroll
        for (int j = 0; j < 32; j++) {
            int cp = cp0 + j * 2;
            float v0 = xb[(size_t)(2 * cp) * HW + pix];
            float v1 = xb[(size_t)(2 * cp + 1) * HW + pix];
            __nv_bfloat16 h0 = __float2bfloat16_rn(v0);
            __nv_bfloat16 h1 = __float2bfloat16_rn(v1);
            __nv_bfloat16 l0 = __float2bfloat16_rn(v0 - __bfloat162float(h0));
            __nv_bfloat16 l1 = __float2bfloat16_rn(v1 - __bfloat162float(h1));
            ((__nv_bfloat162*)(Xh + px * 136))[cp] = __nv_bfloat162(h0, h1);
            ((__nv_bfloat162*)(Xl + px * 136))[cp] = __nv_bfloat162(l0, l1);
        }
    }
    __syncthreads();

    int wfull = t >> 5, lane = t & 31;
    int half = wfull >> 3;
    int w = wfull & 7;
    int gid = lane >> 2, tig = lane & 3;
    gemm_body_128((const uint32_t*)Wh, (const uint32_t*)Wl,
                  (const uint32_t*)(Xh + half * 128 * 136), (const uint32_t*)(Xl + half * 128 * 136),
                  bias, yout + (size_t)b * CH * HW, py0, px0, half, w, gid, tig);
}

// ---------------- fused flow-warp + q/k projections, FULL window (512 thr) ----------------
__global__ void __launch_bounds__(512, 1)
convqk_mma(const float* __restrict__ xin,
           const __nv_bfloat16* __restrict__ wq, const __nv_bfloat16* __restrict__ wk,
           const float* __restrict__ qbias, const float* __restrict__ kbias) {
    int n = blockIdx.x, b = blockIdx.y;
    if (g_MASK[b * 256 + n] == 0.f) return;
    extern __shared__ __nv_bfloat16 smb[];
    __nv_bfloat16* Wh = smb;
    __nv_bfloat16* Wl = Wh + 128 * 136;
    __nv_bfloat16* Xh = Wl + 128 * 136;
    __nv_bfloat16* Xl = Xh + 256 * 136;
    int t = threadIdx.x;

    {
        const uint4* src = (const uint4*)wq;
        uint4* dst = (uint4*)smb;
#pragma unroll
        for (int i = 0; i < 9; i++) {
            int idx = t + i * 512;
            if (idx < 4352) dst[idx] = src[idx];
        }
    }

    int py0 = (n >> 4) * 16, px0 = (n & 15) * 16;
    {
        int px = t & 255;
        int gy = py0 + (px >> 4), gx = px0 + (px & 15);
        int pp = gy * 256 + gx;
        const float* OFb = g_OFF + (size_t)b * 2 * HW;
        float fx = OFb[pp];
        float fy = OFb[HW + pp];
        float sx = fminf(fmaxf((float)gx + fx, 0.f), 255.f);
        float sy = fminf(fmaxf((float)gy + fy, 0.f), 255.f);
        float x0f = floorf(sx), y0f = floorf(sy);
        float x1f = fminf(x0f + 1.f, 255.f), y1f = fminf(y0f + 1.f, 255.f);
        float wx = sx - x0f, wy = sy - y0f;
        int x0 = (int)x0f, x1 = (int)x1f, y0 = (int)y0f, y1 = (int)y1f;
        int iA = y0 * 256 + x0, iB = y0 * 256 + x1, iC = y1 * 256 + x0, iD = y1 * 256 + x1;
        float w00 = (1.f - wx) * (1.f - wy), w01 = wx * (1.f - wy);
        float w10 = (1.f - wx) * wy, w11 = wx * wy;
        const float* xb = xin + (size_t)b * CH * HW;
        int cp0 = t >> 8;
#pragma unroll 4
        for (int j = 0; j < 32; j++) {
            int cp = cp0 + j * 2;
            const float* xc0 = xb + (size_t)(2 * cp) * HW;
            const float* xc1 = xc0 + HW;
            float v0 = __ldg(&xc0[iA]) * w00 + __ldg(&xc0[iB]) * w01 +
                       __ldg(&xc0[iC]) * w10 + __ldg(&xc0[iD]) * w11;
            float v1 = __ldg(&xc1[iA]) * w00 + __ldg(&xc1[iB]) * w01 +
                       __ldg(&xc1[iC]) * w10 + __ldg(&xc1[iD]) * w11;
            __nv_bfloat16 h0 = __float2bfloat16_rn(v0);
            __nv_bfloat16 h1 = __float2bfloat16_rn(v1);
            __nv_bfloat16 l0 = __float2bfloat16_rn(v0 - __bfloat162float(h0));
            __nv_bfloat16 l1 = __float2bfloat16_rn(v1 - __bfloat162float(h1));
            ((__nv_bfloat162*)(Xh + px * 136))[cp] = __nv_bfloat162(h0, h1);
            ((__nv_bfloat162*)(Xl + px * 136))[cp] = __nv_bfloat162(l0, l1);
        }
    }
    __syncthreads();

    int wfull = t >> 5, lane = t & 31;
    int half = wfull >> 3;
    int w = wfull & 7;
    int gid = lane >> 2, tig = lane & 3;
    const uint32_t* XhW = (const uint32_t*)(Xh + half * 128 * 136);
    const uint32_t* XlW = (const uint32_t*)(Xl + half * 128 * 136);

    gemm_body_128((const uint32_t*)Wh, (const uint32_t*)Wl, XhW, XlW,
                  qbias, g_Qb + (size_t)b * CH * HW, py0, px0, half, w, gid, tig);
    __syncthreads();
    {
        const uint4* src = (const uint4*)wk;
        uint4* dst = (uint4*)smb;
#pragma unroll
        for (int i = 0; i < 9; i++) {
            int idx = t + i * 512;
            if (idx < 4352) dst[idx] = src[idx];
        }
    }
    __syncthreads();
    gemm_body_128((const uint32_t*)Wh, (const uint32_t*)Wl, XhW, XlW,
                  kbias, g_Kb + (size_t)b * CH * HW, py0, px0, half, w, gid, tig);
}

// ---------------- predictor v2: 8 outputs x 4 pixels per thread ----------------
// dyn smem: wr[32*131] | wr1[16*32] | wr2[32] | fsum_s[32] | fS[32*261]
#define PRED_SMEM ((32*131 + 16*32 + 32 + 32 + 32*261) * 4)
__global__ void __launch_bounds__(256, 1)
predictor_kernel(const float* __restrict__ cond_g,
                 const float* __restrict__ rin_w, const float* __restrict__ rin_b,
                 const float* __restrict__ r1w, const float* __restrict__ r1b,
                 const float* __restrict__ r2w, const float* __restrict__ r2b) {
    extern __shared__ float smf[];
    float* wr = smf;                 // 32*131
    float* wr1 = wr + 32 * 131;      // 16*32
    float* wr2 = wr1 + 16 * 32;      // 32
    float* fsum_s = wr2 + 32;        // 32
    float* fS = fsum_s + 32;         // 32*261

    int t = threadIdx.x;
    int b = blockIdx.y;
    for (int i = t; i < 32 * 131; i += 256) wr[i] = rin_w[i];
    for (int i = t; i < 16 * 32; i += 256) wr1[i] = r1w[i];
    if (t < 32) { wr2[t] = r2w[t]; fsum_s[t] = 0.f; }
    __syncthreads();

    int og = t & 3, pxg = t >> 2;
    int pbase = blockIdx.x * 256;
    int p0 = pbase + pxg * 4;

    float acc[8][4];
#pragma unroll
    for (int o = 0; o < 8; o++) {
        float bv = __ldg(&rin_b[og * 8 + o]);
#pragma unroll
        for (int i = 0; i < 4; i++) acc[o][i] = bv;
    }
    const float* vb = g_V + (size_t)b * CH * HW;
#pragma unroll 4
    for (int ci = 0; ci < 128; ci++) {
        float4 xv = *(const float4*)(vb + (size_t)ci * HW + p0);
#pragma unroll
        for (int o = 0; o < 8; o++) {
            float wv = wr[(og * 8 + o) * 131 + ci];
            acc[o][0] = fmaf(wv, xv.x, acc[o][0]);
            acc[o][1] = fmaf(wv, xv.y, acc[o][1]);
            acc[o][2] = fmaf(wv, xv.z, acc[o][2]);
            acc[o][3] = fmaf(wv, xv.w, acc[o][3]);
        }
    }
    // cond terms
    {
        float4 cg = *(const float4*)(cond_g + (size_t)b * HW + p0);
        float cgv[4] = {cg.x, cg.y, cg.z, cg.w};
        int y = p0 >> 8, x0p = p0 & 255;
        float ly = -1.f + (float)(y & 15) * (2.f / 15.f);
        float lxv[4];
#pragma unroll
        for (int i = 0; i < 4; i++) lxv[i] = -1.f + (float)((x0p & 15) + i) * (2.f / 15.f);
        float* Fb = g_F + (size_t)b * 32 * HW;
#pragma unroll
        for (int o = 0; o < 8; o++) {
            int oo = og * 8 + o;
            float w128 = wr[oo * 131 + 128], w129 = wr[oo * 131 + 129], w130 = wr[oo * 131 + 130];
#pragma unroll
            for (int i = 0; i < 4; i++) {
                float v = acc[o][i] + w128 * cgv[i] + w129 * ly + w130 * lxv[i];
                acc[o][i] = leakyf(v);
            }
            // store f: smem tile + global
            fS[oo * 261 + pxg * 4 + 0] = acc[o][0];
            fS[oo * 261 + pxg * 4 + 1] = acc[o][1];
            fS[oo * 261 + pxg * 4 + 2] = acc[o][2];
            fS[oo * 261 + pxg * 4 + 3] = acc[o][3];
            float4 fv = make_float4(acc[o][0], acc[o][1], acc[o][2], acc[o][3]);
            *(float4*)(Fb + (size_t)oo * HW + p0) = fv;
        }
    }
    // fsum partial: reduce over pxg lanes (lane bits 2-4)
    {
        int lane = t & 31;
#pragma unroll
        for (int o = 0; o < 8; o++) {
            float s = acc[o][0] + acc[o][1] + acc[o][2] + acc[o][3];
            s += __shfl_xor_sync(0xffffffff, s, 4);
            s += __shfl_xor_sync(0xffffffff, s, 8);
            s += __shfl_xor_sync(0xffffffff, s, 16);
            if (lane < 4) atomicAdd(&fsum_s[og * 8 + o], s);
        }
    }
    __syncthreads();

    // per-pixel: fmc + offsets
    {
        int px = t;
        int p = pbase + px;
        float fv[32];
        float fm = 0.f;
#pragma unroll
        for (int o = 0; o < 32; o++) {
            fv[o] = fS[o * 261 + px];
            fm += fv[o];
        }
        g_FMC[(size_t)b * HW + p] = fm * (1.f / 32.f);

        float h[16];
#pragma unroll
        for (int o2 = 0; o2 < 16; o2++) {
            float s = __ldg(&r1b[o2]);
#pragma unroll
            for (int o = 0; o < 32; o++) s = fmaf(wr1[o2 * 32 + o], fv[o], s);
            h[o2] = leakyf(s);
        }
        float ox = __ldg(&r2b[0]), oy = __ldg(&r2b[1]);
#pragma unroll
        for (int o2 = 0; o2 < 16; o2++) {
            ox = fmaf(wr2[o2], h[o2], ox);
            oy = fmaf(wr2[16 + o2], h[o2], oy);
        }
        float* OFb = g_OFF + (size_t)b * 2 * HW;
        OFb[p] = ox;
        OFb[HW + p] = oy;
    }
    __syncthreads();
    if (t < 32) atomicAdd(&g_FSUM[b * 32 + t], fsum_s[t]);
}

// ---------------- channel attention ca ----------------
__global__ void ca_kernel(const float* __restrict__ rca_w, const float* __restrict__ rca_b) {
    int c = threadIdx.x;
    int b = blockIdx.x;
    float s = __ldg(&rca_b[c]);
#pragma unroll
    for (int ci = 0; ci < 32; ci++)
        s = fmaf(__ldg(&rca_w[c * 32 + ci]), g_FSUM[b * 32 + ci] * (1.f / 65536.f), s);
    g_CA[b * CH + c] = 1.f / (1.f + expf(-s));
}

// ---------------- spatial attention sa: 2D-tiled (32x8 out tile, per-ci halo tile) ----------------
__global__ void __launch_bounds__(256) sa_kernel(const float* __restrict__ rsa_w,
                                                 const float* __restrict__ rsa_b) {
    __shared__ float ws[288];
    __shared__ float tile[10][36];
    int t = threadIdx.x;
    for (int i = t; i < 288; i += 256) ws[i] = rsa_w[i];
    int b = blockIdx.z;
    int tx0 = blockIdx.x * 32, ty0 = blockIdx.y * 8;
    int lx = t & 31, lyy = t >> 5;
    float acc = __ldg(&rsa_b[0]);
    const float* Fb = g_F + (size_t)b * 32 * HW;
#pragma unroll 1
    for (int ci = 0; ci < 32; ci++) {
        __syncthreads();
        for (int i = t; i < 340; i += 256) {
            int lyl = i / 34, lxl = i % 34;
            int gy = ty0 - 1 + lyl, gx = tx0 - 1 + lxl;
            float v = 0.f;
            if ((unsigned)gy < 256u && (unsigned)gx < 256u)
                v = __ldg(&Fb[(size_t)ci * HW + gy * 256 + gx]);
            tile[lyl][lxl] = v;
        }
        __syncthreads();
        const float* wc = ws + ci * 9;
#pragma unroll
        for (int ky = 0; ky < 3; ky++)
#pragma unroll
            for (int kx = 0; kx < 3; kx++)
                acc = fmaf(wc[ky * 3 + kx], tile[lyy + ky][lx + kx], acc);
    }
    g_SA[(size_t)b * HW + (ty0 + lyy) * 256 + tx0 + lx] = 1.f / (1.f + expf(-acc));
}

// ---------------- window MLP + gumbel hard mask ----------------
__global__ void mask_kernel(const float* __restrict__ gu,
                            const float* __restrict__ rm1_w, const float* __restrict__ rm1_b,
                            const float* __restrict__ rm2_w, const float* __restrict__ rm2_b) {
    __shared__ float m[256];
    __shared__ float h1s[16];
    int n = blockIdx.x, b = blockIdx.y;
    int t = threadIdx.x;
    int dh = t >> 4, dw = t & 15;
    int pix = ((n >> 4) * 16 + dh) * 256 + (n & 15) * 16 + dw;
    m[t] = g_FMC[b * HW + pix];
    __syncthreads();
    if (t < 16) {
        float s = __ldg(&rm1_b[t]);
        for (int e = 0; e < 256; e++) s = fmaf(__ldg(&rm1_w[t * 256 + e]), m[e], s);
        h1s[t] = leakyf(s);
    }
    __syncthreads();
    if (t == 0) {
        float z0 = __ldg(&rm2_b[0]), z1 = __ldg(&rm2_b[1]);
#pragma unroll
        for (int o = 0; o < 16; o++) {
            z0 = fmaf(__ldg(&rm2_w[o]), h1s[o], z0);
            z1 = fmaf(__ldg(&rm2_w[16 + o]), h1s[o], z1);
        }
        float mx = fmaxf(z0, z1);
        float e0 = expf(z0 - mx), e1 = expf(z1 - mx);
        float inv = 1.f / (e0 + e1);
        float p0 = e0 * inv, p1 = e1 * inv;
        float u0 = __ldg(&gu[(b * 256 + n) * 2 + 0]);
        float u1 = __ldg(&gu[(b * 256 + n) * 2 + 1]);
        float g0 = -logf(-logf(u0 + 1e-10f) + 1e-10f);
        float g1 = -logf(-logf(u1 + 1e-10f) + 1e-10f);
        g_MASK[b * 256 + n] = (p0 + g0 >= p1 + g1) ? 1.f : 0.f;
    }
}

// ---------------- window attention, 512 threads (16 warps) ----------------
#define SMEM_ATTN3 ((64*257 + 512 + 64 + 64) * 4 + 90112)
__global__ void __launch_bounds__(512, 1) attn_mma_kernel() {
    int n = blockIdx.x, b = blockIdx.y;
    int t = threadIdx.x;
    int py0 = (n >> 4) * 16, px0 = (n & 15) * 16;
    int cbase = b * CH * HW;
    if (g_MASK[b * 256 + n] == 0.f) {
        const float* sab = g_SA + (size_t)b * HW;
#pragma unroll 4
        for (int i = t; i < 8192; i += 512) {
            int ch = i >> 6, r4 = i & 63;
            int wrow = r4 >> 2, px4 = (r4 & 3) * 4;
            int pix = (py0 + wrow) * 256 + px0 + px4;
            float4 v = *(const float4*)(g_V + cbase + ch * HW + pix);
            float4 s = *(const float4*)(sab + pix);
            v.x *= s.x; v.y *= s.y; v.z *= s.z; v.w *= s.w;
            *(float4*)(g_OUT + cbase + ch * HW + pix) = v;
        }
        return;
    }
    extern __shared__ char smraw[];
    float* S = (float*)smraw;
    float* red = S + 64 * 257;
    float* rmax = red + 512;
    float* rsum = rmax + 64;
    __nv_bfloat16* Qh = (__nv_bfloat16*)(rsum + 64);
    __nv_bfloat16* Ql = Qh + 64 * 136;
    __nv_bfloat16* KVh = Ql + 64 * 136;
    __nv_bfloat16* KVl = KVh + 9216;
    __nv_bfloat16* Pth = KVl + 9216;
    __nv_bfloat16* Ptl = Pth + 64 * 72;

    const uint32_t* QhW = (const uint32_t*)Qh;
    const uint32_t* QlW = (const uint32_t*)Ql;
    const uint32_t* KVhW = (const uint32_t*)KVh;
    const uint32_t* KVlW = (const uint32_t*)KVl;
    const uint32_t* PthW = (const uint32_t*)Pth;
    const uint32_t* PtlW = (const uint32_t*)Ptl;

    int w = t >> 5, lane = t & 31;
    int gid = lane >> 2;
    int tig = lane & 3;

#pragma unroll 1
    for (int rc = 0; rc < 4; rc++) {
        int r0 = rc * 64;
        __syncthreads();
#pragma unroll
        for (int j = 0; j < 8; j++) {
            int i = t + j * 512;
            int px = i & 63, cp = i >> 6;
            int p = r0 + px;
            int pix = (py0 + (p >> 4)) * 256 + px0 + (p & 15);
            float v0 = g_Qb[cbase + (2 * cp) * HW + pix];
            float v1 = g_Qb[cbase + (2 * cp + 1) * HW + pix];
            __nv_bfloat16 h0 = __float2bfloat16_rn(v0);
            __nv_bfloat16 h1 = __float2bfloat16_rn(v1);
            __nv_bfloat16 l0 = __float2bfloat16_rn(v0 - __bfloat162float(h0));
            __nv_bfloat16 l1 = __float2bfloat16_rn(v1 - __bfloat162float(h1));
            ((__nv_bfloat162*)(Qh + px * 136))[cp] = __nv_bfloat162(h0, h1);
            ((__nv_bfloat162*)(Ql + px * 136))[cp] = __nv_bfloat162(l0, l1);
        }

        int mrowS = (w & 3) * 16, ncolS = (w >> 2) * 16;
#pragma unroll 1
        for (int kvt = 0; kvt < 4; kvt++) {
            __syncthreads();
#pragma unroll
            for (int j = 0; j < 8; j++) {
                int i = t + j * 512;
                int px = i & 63, cp = i >> 6;
                int p = kvt * 64 + px;
                int pix = (py0 + (p >> 4)) * 256 + px0 + (p & 15);
                float v0 = g_Kb[cbase + (2 * cp) * HW + pix];
                float v1 = g_Kb[cbase + (2 * cp + 1) * HW + pix];
                __nv_bfloat16 h0 = __float2bfloat16_rn(v0);
                __nv_bfloat16 h1 = __float2bfloat16_rn(v1);
                __nv_bfloat16 l0 = __float2bfloat16_rn(v0 - __bfloat162float(h0));
                __nv_bfloat16 l1 = __float2bfloat16_rn(v1 - __bfloat162float(h1));
                ((__nv_bfloat162*)(KVh + px * 136))[cp] = __nv_bfloat162(h0, h1);
                ((__nv_bfloat162*)(KVl + px * 136))[cp] = __nv_bfloat162(l0, l1);
            }
            __syncthreads();
            float acc[2][4];
#pragma unroll
            for (int i = 0; i < 2; i++)
#pragma unroll
                for (int j2 = 0; j2 < 4; j2++) acc[i][j2] = 0.f;
#pragma unroll
            for (int ks = 0; ks < 8; ks++) {
                int kw = ks * 8;
                uint32_t Ahf[4], Alf[4], Bhf[2][2], Blf[2][2];
                int ra = (mrowS + gid) * 68 + kw + tig;
                int ra8 = ra + 8 * 68;
                Ahf[0] = QhW[ra];     Ahf[1] = QhW[ra8];
                Ahf[2] = QhW[ra + 4]; Ahf[3] = QhW[ra8 + 4];
                Alf[0] = QlW[ra];     Alf[1] = QlW[ra8];
                Alf[2] = QlW[ra + 4]; Alf[3] = QlW[ra8 + 4];
#pragma unroll
                for (int nt = 0; nt < 2; nt++) {
                    int rr = (ncolS + nt * 8 + gid) * 68 + kw + tig;
                    Bhf[nt][0] = KVhW[rr]; Bhf[nt][1] = KVhW[rr + 4];
                    Blf[nt][0] = KVlW[rr]; Blf[nt][1] = KVlW[rr + 4];
                }
#pragma unroll
                for (int nt = 0; nt < 2; nt++) {
                    MMA_BF16(acc[nt], Ahf, Bhf[nt]);
                    MMA_BF16(acc[nt], Ahf, Blf[nt]);
                    MMA_BF16(acc[nt], Alf, Bhf[nt]);
                }
            }
#pragma unroll
            for (int nt = 0; nt < 2; nt++) {
                int col = kvt * 64 + ncolS + nt * 8 + tig * 2;
                S[(mrowS + gid) * 257 + col] = acc[nt][0];
                S[(mrowS + gid) * 257 + col + 1] = acc[nt][1];
                S[(mrowS + gid + 8) * 257 + col] = acc[nt][2];
                S[(mrowS + gid + 8) * 257 + col + 1] = acc[nt][3];
            }
        }
        __syncthreads();

        {
            int r = t & 63, seg = t >> 6;
            float* srow = &S[r * 257 + seg * 32];
            float mx = -1e30f;
#pragma unroll 8
            for (int k = 0; k < 32; k++) mx = fmaxf(mx, srow[k]);
            red[seg * 64 + r] = mx;
            __syncthreads();
            if (t < 64) {
                float m0 = fmaxf(fmaxf(red[t], red[64 + t]), fmaxf(red[128 + t], red[192 + t]));
                float m1 = fmaxf(fmaxf(red[256 + t], red[320 + t]), fmaxf(red[384 + t], red[448 + t]));
                rmax[t] = fmaxf(m0, m1);
            }
            __syncthreads();
            float rm_ = rmax[r];
            float s = 0.f;
#pragma unroll 8
            for (int k = 0; k < 32; k++) {
                float e = __expf(srow[k] - rm_);
                srow[k] = e;
                s += e;
            }
            red[seg * 64 + r] = s;
            __syncthreads();
            if (t < 64)
                rsum[t] = (red[t] + red[64 + t] + red[128 + t] + red[192 + t]) +
                          (red[256 + t] + red[320 + t] + red[384 + t] + red[448 + t]);
            __syncthreads();
        }

        int mrowO = (w & 3) * 16, ncolO = (w >> 2) * 32;
        float oacc[4][4];
#pragma unroll
        for (int i = 0; i < 4; i++)
#pragma unroll
            for (int j2 = 0; j2 < 4; j2++) oacc[i][j2] = 0.f;

#pragma unroll 1
        for (int kvt = 0; kvt < 4; kvt++) {
            __syncthreads();
#pragma unroll
            for (int j = 0; j < 8; j++) {
                int i = t + j * 512;
                int col = i & 63, row = i >> 6;
                float v = S[row * 257 + kvt * 64 + col];
                __nv_bfloat16 h = __float2bfloat16_rn(v);
                Pth[row * 72 + col] = h;
                Ptl[row * 72 + col] = __float2bfloat16_rn(v - __bfloat162float(h));
            }
#pragma unroll
            for (int j = 0; j < 16; j++) {
                int i = t + j * 512;
                int px = i & 63, ch = i >> 6;
                int p = kvt * 64 + px;
                int pix = (py0 + (p >> 4)) * 256 + px0 + (p & 15);
                float v = g_V[cbase + ch * HW + pix];
                __nv_bfloat16 h = __float2bfloat16_rn(v);
                KVh[ch * 72 + px] = h;
                KVl[ch * 72 + px] = __float2bfloat16_rn(v - __bfloat162float(h));
            }
            __syncthreads();
#pragma unroll
            for (int ks = 0; ks < 4; ks++) {
                int kw = ks * 8;
                uint32_t Ahf[4], Alf[4], Bhf[4][2], Blf[4][2];
                int ra = (mrowO + gid) * 36 + kw + tig;
                int ra8 = ra + 8 * 36;
                Ahf[0] = PthW[ra];     Ahf[1] = PthW[ra8];
                Ahf[2] = PthW[ra + 4]; Ahf[3] = PthW[ra8 + 4];
                Alf[0] = PtlW[ra];     Alf[1] = PtlW[ra8];
                Alf[2] = PtlW[ra + 4]; Alf[3] = PtlW[ra8 + 4];
#pragma unroll
                for (int nt = 0; nt < 4; nt++) {
                    int rr = (ncolO + nt * 8 + gid) * 36 + kw + tig;
                    Bhf[nt][0] = KVhW[rr]; Bhf[nt][1] = KVhW[rr + 4];
                    Blf[nt][0] = KVlW[rr]; Blf[nt][1] = KVlW[rr + 4];
                }
#pragma unroll
                for (int nt = 0; nt < 4; nt++) {
                    MMA_BF16(oacc[nt], Ahf, Bhf[nt]);
                    MMA_BF16(oacc[nt], Ahf, Blf[nt]);
                    MMA_BF16(oacc[nt], Alf, Bhf[nt]);
                }
            }
        }

        {
            int rowA = mrowO + gid, rowB = rowA + 8;
            float invA = 1.f / rsum[rowA];
            float invB = 1.f / rsum[rowB];
            int pA = r0 + rowA, pB = r0 + rowB;
            int pixA = (py0 + (pA >> 4)) * 256 + px0 + (pA & 15);
            int pixB = (py0 + (pB >> 4)) * 256 + px0 + (pB & 15);
#pragma unroll
            for (int nt = 0; nt < 4; nt++) {
                int ch = ncolO + nt * 8 + tig * 2;
                g_OUT[cbase + ch * HW + pixA] = oacc[nt][0] * invA;
                g_OUT[cbase + (ch + 1) * HW + pixA] = oacc[nt][1] * invA;
                g_OUT[cbase + ch * HW + pixB] = oacc[nt][2] * invB;
                g_OUT[cbase + (ch + 1) * HW + pixB] = oacc[nt][3] * invB;
            }
        }
    }
}

// ---------------- fused depthwise 5x5(d1) -> 5x5(d3) + gelu*ca + residual ----------------
__global__ void __launch_bounds__(256) dw5x2_kernel(
    const float* __restrict__ in, const float* __restrict__ w2, const float* __restrict__ b2,
    const float* __restrict__ w3, const float* __restrict__ b3, float* __restrict__ out) {
    __shared__ float sIn[48][81];
    __shared__ float sMid[44][77];
    __shared__ float wA[25], wB[25];
    int c = blockIdx.z & 127, b = blockIdx.z >> 7;
    int t = threadIdx.x;
    if (t < 25) wA[t] = w2[c * 25 + t];
    else if (t < 50) wB[t - 25] = w3[c * 25 + (t - 25)];
    int ox0 = blockIdx.x * 64, oy0 = blockIdx.y * 32;
    const float* ip = in + (size_t)(b * CH + c) * HW;

    for (int i = t; i < 48 * 80; i += 256) {
        int lx = i % 80, ly = i / 80;
        int gx = ox0 - 8 + lx, gy = oy0 - 8 + ly;
        float v = 0.f;
        if ((unsigned)gx < 256u && (unsigned)gy < 256u) v = __ldg(&ip[gy * 256 + gx]);
        sIn[ly][lx] = v;
    }
    __syncthreads();

    float b2v = __ldg(&b2[c]);
    for (int i = t; i < 44 * 76; i += 256) {
        int mx = i % 76, my = i / 76;
        int gx = ox0 - 6 + mx, gy = oy0 - 6 + my;
        float acc = 0.f;
        if ((unsigned)gx < 256u && (unsigned)gy < 256u) {
            acc = b2v;
#pragma unroll
            for (int ky = 0; ky < 5; ky++)
#pragma unroll
                for (int kx = 0; kx < 5; kx++)
                    acc = fmaf(wA[ky * 5 + kx], sIn[my + ky][mx + kx], acc);
        }
        sMid[my][mx] = acc;
    }
    __syncthreads();

    float b3v = __ldg(&b3[c]);
    float cav = g_CA[b * CH + c];
    size_t obase = (size_t)(b * CH + c) * HW;
    for (int i = t; i < 32 * 64; i += 256) {
        int x = i % 64, y = i / 64;
        float acc = b3v;
#pragma unroll
        for (int ky = 0; ky < 5; ky++)
#pragma unroll
            for (int kx = 0; kx < 5; kx++)
                acc = fmaf(wB[ky * 5 + kx], sMid[y + 3 * ky][x + 3 * kx], acc);
        float g = 0.5f * acc * (1.f + erff(acc * 0.7071067811865475f));
        size_t oidx = obase + (size_t)(oy0 + y) * 256 + ox0 + x;
        out[oidx] = g * cav + g_OUT[oidx];
    }
}

// ---------------- launch ----------------
extern "C" void kernel_launch(void* const* d_in, const int* in_sizes, int n_in,
                              void* d_out, int out_size) {
    const float* x      = (const float*)d_in[0];
    const float* cond_g = (const float*)d_in[1];
    const float* gu     = (const float*)d_in[2];
    const float* pv_w   = (const float*)d_in[3];
    const float* pv_b   = (const float*)d_in[4];
    const float* pq_w   = (const float*)d_in[5];
    const float* pq_b   = (const float*)d_in[6];
    const float* pk_w   = (const float*)d_in[7];
    const float* pk_b   = (const float*)d_in[8];
    const float* cs1_w  = (const float*)d_in[9];
    const float* cs1_b  = (const float*)d_in[10];
    const float* cs2_w  = (const float*)d_in[11];
    const float* cs2_b  = (const float*)d_in[12];
    const float* cs3_w  = (const float*)d_in[13];
    const float* cs3_b  = (const float*)d_in[14];
    const float* po_w   = (const float*)d_in[15];
    const float* po_b   = (const float*)d_in[16];
    const float* rin_w  = (const float*)d_in[17];
    const float* rin_b  = (const float*)d_in[18];
    const float* r1w    = (const float*)d_in[19];
    const float* r1b    = (const float*)d_in[20];
    const float* r2w    = (const float*)d_in[21];
    const float* r2b    = (const float*)d_in[22];
    const float* rm1_w  = (const float*)d_in[23];
    const float* rm1_b  = (const float*)d_in[24];
    const float* rm2_w  = (const float*)d_in[25];
    const float* rm2_b  = (const float*)d_in[26];
    const float* rca_w  = (const float*)d_in[27];
    const float* rca_b  = (const float*)d_in[28];
    const float* rsa_w  = (const float*)d_in[29];
    const float* rsa_b  = (const float*)d_in[30];

    float *pV, *pOUT, *pT1, *pT2;
    __nv_bfloat16* pWT;
    cudaGetSymbolAddress((void**)&pV, g_V);
    cudaGetSymbolAddress((void**)&pOUT, g_OUT);
    cudaGetSymbolAddress((void**)&pT1, g_T1);
    cudaGetSymbolAddress((void**)&pT2, g_T2);
    cudaGetSymbolAddress((void**)&pWT, g_WT);

    cudaFuncSetAttribute(attn_mma_kernel, cudaFuncAttributeMaxDynamicSharedMemorySize, SMEM_ATTN3);
    cudaFuncSetAttribute(conv1x1_mma, cudaFuncAttributeMaxDynamicSharedMemorySize, CV_SMEM_FULL);
    cudaFuncSetAttribute(convqk_mma, cudaFuncAttributeMaxDynamicSharedMemorySize, CV_SMEM_FULL);
    cudaFuncSetAttribute(predictor_kernel, cudaFuncAttributeMaxDynamicSharedMemorySize, PRED_SMEM);

    const int WSET = 2 * 128 * 136;

    prep_all_kernel<<<dim3(64, 5), 256>>>(pv_w, pq_w, pk_w, cs1_w, po_w);
    zero_fsum_kernel<<<1, 128>>>();
    conv1x1_mma<<<dim3(256, BB), 512, CV_SMEM_FULL>>>(x, pWT + 0 * WSET, pv_b, pV, 0);
    predictor_kernel<<<dim3(HW / 256, BB), 256, PRED_SMEM>>>(cond_g, rin_w, rin_b, r1w, r1b, r2w, r2b);
    ca_kernel<<<BB, 128>>>(rca_w, rca_b);
    sa_kernel<<<dim3(8, 32, BB), 256>>>(rsa_w, rsa_b);
    mask_kernel<<<dim3(256, BB), 256>>>(gu, rm1_w, rm1_b, rm2_w, rm2_b);
    convqk_mma<<<dim3(256, BB), 512, CV_SMEM_FULL>>>(x, pWT + 1 * WSET, pWT + 2 * WSET, pq_b, pk_b);
    attn_mma_kernel<<<dim3(256, BB), 512, SMEM_ATTN3>>>();
    conv1x1_mma<<<dim3(256, BB), 512, CV_SMEM_FULL>>>(pOUT, pWT + 3 * WSET, cs1_b, pT1, 0);
    dw5x2_kernel<<<dim3(4, 8, BB * CH), 256>>>(pT1, cs2_w, cs2_b, cs3_w, cs3_b, pT2);
    conv1x1_mma<<<dim3(256, BB), 512, CV_SMEM_FULL>>>(pT2, pWT + 4 * WSET, po_b, (float*)d_out, 0);
}

// round 14
// speedup vs baseline: 2.3924x; 1.0270x over previous
#include <cuda_runtime.h>
#include <cuda_bf16.h>
#include <stdint.h>
#include <math.h>

#define HW 65536
#define WIMG 256
#define CH 128
#define BB 4
#define ELT (BB*CH*HW)

// ---------------- scratch ----------------
__device__ float g_V[ELT];
__device__ float g_Qb[ELT];
__device__ float g_Kb[ELT];
__device__ float g_OUT[ELT];
__device__ float g_T1[ELT];
__device__ float g_T2[ELT];
__device__ float g_F[BB*32*HW];
__device__ float g_OFF[BB*2*HW];
__device__ float g_FMC[BB*HW];
__device__ float g_SA[BB*HW];
__device__ float g_FSUM[BB*32];
__device__ float g_CA[BB*CH];
__device__ float g_MASK[BB*256];
__device__ __align__(16) __nv_bfloat16 g_WT[5][2][128*136];
__device__ __align__(16) __nv_bfloat16 g_WRIN[2][32*136];

__device__ __forceinline__ float leakyf(float x) { return x > 0.f ? x : 0.2f * x; }

__global__ void zero_fsum_kernel() {
    g_FSUM[threadIdx.x] = 0.f;
}

// ---------------- weight prep ----------------
__global__ void prep_all_kernel(const float* __restrict__ w0, const float* __restrict__ w1,
                                const float* __restrict__ w2, const float* __restrict__ w3,
                                const float* __restrict__ w4) {
    int set = blockIdx.y;
    const float* w = (set == 0) ? w0 : (set == 1) ? w1 : (set == 2) ? w2 : (set == 3) ? w3 : w4;
    int i = blockIdx.x * 256 + threadIdx.x;
    int oc = i >> 7, ci = i & 127;
    float v = w[i];
    __nv_bfloat16 h = __float2bfloat16_rn(v);
    __nv_bfloat16 l = __float2bfloat16_rn(v - __bfloat162float(h));
    g_WT[set][0][oc * 136 + ci] = h;
    g_WT[set][1][oc * 136 + ci] = l;
}

// rin_w is 32 x 131; prep first 128 input channels into padded hi/lo
__global__ void prep_rin_kernel(const float* __restrict__ w) {
    int i = blockIdx.x * 256 + threadIdx.x;   // 4096
    int oc = i >> 7, ci = i & 127;
    float v = w[oc * 131 + ci];
    __nv_bfloat16 h = __float2bfloat16_rn(v);
    __nv_bfloat16 l = __float2bfloat16_rn(v - __bfloat162float(h));
    g_WRIN[0][oc * 136 + ci] = h;
    g_WRIN[1][oc * 136 + ci] = l;
}

// ---------------- HMMA m16n8k16 bf16 ----------------
#define MMA_BF16(d, a, b) \
    asm volatile("mma.sync.aligned.m16n8k16.row.col.f32.bf16.bf16.f32 " \
        "{%0,%1,%2,%3}, {%4,%5,%6,%7}, {%8,%9}, {%0,%1,%2,%3};" \
        : "+f"((d)[0]), "+f"((d)[1]), "+f"((d)[2]), "+f"((d)[3]) \
        : "r"((a)[0]), "r"((a)[1]), "r"((a)[2]), "r"((a)[3]), "r"((b)[0]), "r"((b)[1]))

// ---- shared GEMM body (proven): 8-warp slice over one 128px half ----
__device__ __forceinline__ void gemm_body_128(
    const uint32_t* WhW, const uint32_t* WlW,
    const uint32_t* XhW, const uint32_t* XlW,
    const float* __restrict__ bias, float* __restrict__ yb,
    int py0, int px0, int half, int w, int gid, int tig) {
    int oc0 = (w & 3) * 32;
    int n0 = (w >> 2) * 64;
    float acc[16][4];
#pragma unroll
    for (int i = 0; i < 16; i++)
#pragma unroll
        for (int j = 0; j < 4; j++) acc[i][j] = 0.f;
#pragma unroll 1
    for (int ks = 0; ks < 8; ks++) {
        int kw = ks * 8;
        uint32_t Ah[2][4], Al[2][4], Bh[8][2], Bl[8][2];
#pragma unroll
        for (int mt = 0; mt < 2; mt++) {
            int r0 = (oc0 + mt * 16 + gid) * 68 + kw + tig;
            int r8 = r0 + 8 * 68;
            Ah[mt][0] = WhW[r0];     Ah[mt][1] = WhW[r8];
            Ah[mt][2] = WhW[r0 + 4]; Ah[mt][3] = WhW[r8 + 4];
            Al[mt][0] = WlW[r0];     Al[mt][1] = WlW[r8];
            Al[mt][2] = WlW[r0 + 4]; Al[mt][3] = WlW[r8 + 4];
        }
#pragma unroll
        for (int nt = 0; nt < 8; nt++) {
            int rr = (n0 + nt * 8 + gid) * 68 + kw + tig;
            Bh[nt][0] = XhW[rr]; Bh[nt][1] = XhW[rr + 4];
            Bl[nt][0] = XlW[rr]; Bl[nt][1] = XlW[rr + 4];
        }
#pragma unroll
        for (int mt = 0; mt < 2; mt++)
#pragma unroll
            for (int nt = 0; nt < 8; nt++) {
                MMA_BF16(acc[mt * 8 + nt], Ah[mt], Bh[nt]);
                MMA_BF16(acc[mt * 8 + nt], Ah[mt], Bl[nt]);
                MMA_BF16(acc[mt * 8 + nt], Al[mt], Bh[nt]);
            }
    }
#pragma unroll
    for (int mt = 0; mt < 2; mt++) {
        int ocA = oc0 + mt * 16 + gid;
        int ocB = ocA + 8;
        float bvA = __ldg(&bias[ocA]);
        float bvB = __ldg(&bias[ocB]);
#pragma unroll
        for (int nt = 0; nt < 8; nt++) {
            int col = n0 + nt * 8 + tig * 2;
            int p = half * 128 + col;
            int pix = (py0 + (p >> 4)) * 256 + px0 + (p & 15);
            float2 v0 = make_float2(acc[mt * 8 + nt][0] + bvA, acc[mt * 8 + nt][1] + bvA);
            float2 v1 = make_float2(acc[mt * 8 + nt][2] + bvB, acc[mt * 8 + nt][3] + bvB);
            *(float2*)(yb + (size_t)ocA * HW + pix) = v0;
            *(float2*)(yb + (size_t)ocB * HW + pix) = v1;
        }
    }
}

// ---------------- conv1x1 GEMM, FULL window per block (512 thr) ----------------
#define CV_SMEM_FULL ((2 * 128 * 136 + 2 * 256 * 136) * 2)
__global__ void __launch_bounds__(512, 1)
conv1x1_mma(const float* __restrict__ xin, const __nv_bfloat16* __restrict__ wsp,
            const float* __restrict__ bias, float* __restrict__ yout, int bOff) {
    int n = blockIdx.x, b = blockIdx.y + bOff;
    extern __shared__ __nv_bfloat16 smb[];
    __nv_bfloat16* Wh = smb;
    __nv_bfloat16* Wl = Wh + 128 * 136;
    __nv_bfloat16* Xh = Wl + 128 * 136;
    __nv_bfloat16* Xl = Xh + 256 * 136;
    int t = threadIdx.x;

    {
        const uint4* src = (const uint4*)wsp;
        uint4* dst = (uint4*)smb;
#pragma unroll
        for (int i = 0; i < 9; i++) {
            int idx = t + i * 512;
            if (idx < 4352) dst[idx] = src[idx];
        }
    }

    int py0 = (n >> 4) * 16, px0 = (n & 15) * 16;
    const float* xb = xin + (size_t)b * CH * HW;
    {
        int px = t & 255;
        int pix = (py0 + (px >> 4)) * 256 + px0 + (px & 15);
        int cp0 = t >> 8;
#pragma unroll
        for (int j = 0; j < 32; j++) {
            int cp = cp0 + j * 2;
            float v0 = xb[(size_t)(2 * cp) * HW + pix];
            float v1 = xb[(size_t)(2 * cp + 1) * HW + pix];
            __nv_bfloat16 h0 = __float2bfloat16_rn(v0);
            __nv_bfloat16 h1 = __float2bfloat16_rn(v1);
            __nv_bfloat16 l0 = __float2bfloat16_rn(v0 - __bfloat162float(h0));
            __nv_bfloat16 l1 = __float2bfloat16_rn(v1 - __bfloat162float(h1));
            ((__nv_bfloat162*)(Xh + px * 136))[cp] = __nv_bfloat162(h0, h1);
            ((__nv_bfloat162*)(Xl + px * 136))[cp] = __nv_bfloat162(l0, l1);
        }
    }
    __syncthreads();

    int wfull = t >> 5, lane = t & 31;
    int half = wfull >> 3;
    int w = wfull & 7;
    int gid = lane >> 2, tig = lane & 3;
    gemm_body_128((const uint32_t*)Wh, (const uint32_t*)Wl,
                  (const uint32_t*)(Xh + half * 128 * 136), (const uint32_t*)(Xl + half * 128 * 136),
                  bias, yout + (size_t)b * CH * HW, py0, px0, half, w, gid, tig);
}

// ---------------- fused flow-warp + q/k projections, FULL window (512 thr) ----------------
__global__ void __launch_bounds__(512, 1)
convqk_mma(const float* __restrict__ xin,
           const __nv_bfloat16* __restrict__ wq, const __nv_bfloat16* __restrict__ wk,
           const float* __restrict__ qbias, const float* __restrict__ kbias) {
    int n = blockIdx.x, b = blockIdx.y;
    if (g_MASK[b * 256 + n] == 0.f) return;
    extern __shared__ __nv_bfloat16 smb[];
    __nv_bfloat16* Wh = smb;
    __nv_bfloat16* Wl = Wh + 128 * 136;
    __nv_bfloat16* Xh = Wl + 128 * 136;
    __nv_bfloat16* Xl = Xh + 256 * 136;
    int t = threadIdx.x;

    {
        const uint4* src = (const uint4*)wq;
        uint4* dst = (uint4*)smb;
#pragma unroll
        for (int i = 0; i < 9; i++) {
            int idx = t + i * 512;
            if (idx < 4352) dst[idx] = src[idx];
        }
    }

    int py0 = (n >> 4) * 16, px0 = (n & 15) * 16;
    {
        int px = t & 255;
        int gy = py0 + (px >> 4), gx = px0 + (px & 15);
        int pp = gy * 256 + gx;
        const float* OFb = g_OFF + (size_t)b * 2 * HW;
        float fx = OFb[pp];
        float fy = OFb[HW + pp];
        float sx = fminf(fmaxf((float)gx + fx, 0.f), 255.f);
        float sy = fminf(fmaxf((float)gy + fy, 0.f), 255.f);
        float x0f = floorf(sx), y0f = floorf(sy);
        float x1f = fminf(x0f + 1.f, 255.f), y1f = fminf(y0f + 1.f, 255.f);
        float wx = sx - x0f, wy = sy - y0f;
        int x0 = (int)x0f, x1 = (int)x1f, y0 = (int)y0f, y1 = (int)y1f;
        int iA = y0 * 256 + x0, iB = y0 * 256 + x1, iC = y1 * 256 + x0, iD = y1 * 256 + x1;
        float w00 = (1.f - wx) * (1.f - wy), w01 = wx * (1.f - wy);
        float w10 = (1.f - wx) * wy, w11 = wx * wy;
        const float* xb = xin + (size_t)b * CH * HW;
        int cp0 = t >> 8;
#pragma unroll 4
        for (int j = 0; j < 32; j++) {
            int cp = cp0 + j * 2;
            const float* xc0 = xb + (size_t)(2 * cp) * HW;
            const float* xc1 = xc0 + HW;
            float v0 = __ldg(&xc0[iA]) * w00 + __ldg(&xc0[iB]) * w01 +
                       __ldg(&xc0[iC]) * w10 + __ldg(&xc0[iD]) * w11;
            float v1 = __ldg(&xc1[iA]) * w00 + __ldg(&xc1[iB]) * w01 +
                       __ldg(&xc1[iC]) * w10 + __ldg(&xc1[iD]) * w11;
            __nv_bfloat16 h0 = __float2bfloat16_rn(v0);
            __nv_bfloat16 h1 = __float2bfloat16_rn(v1);
            __nv_bfloat16 l0 = __float2bfloat16_rn(v0 - __bfloat162float(h0));
            __nv_bfloat16 l1 = __float2bfloat16_rn(v1 - __bfloat162float(h1));
            ((__nv_bfloat162*)(Xh + px * 136))[cp] = __nv_bfloat162(h0, h1);
            ((__nv_bfloat162*)(Xl + px * 136))[cp] = __nv_bfloat162(l0, l1);
        }
    }
    __syncthreads();

    int wfull = t >> 5, lane = t & 31;
    int half = wfull >> 3;
    int w = wfull & 7;
    int gid = lane >> 2, tig = lane & 3;
    const uint32_t* XhW = (const uint32_t*)(Xh + half * 128 * 136);
    const uint32_t* XlW = (const uint32_t*)(Xl + half * 128 * 136);

    gemm_body_128((const uint32_t*)Wh, (const uint32_t*)Wl, XhW, XlW,
                  qbias, g_Qb + (size_t)b * CH * HW, py0, px0, half, w, gid, tig);
    __syncthreads();
    {
        const uint4* src = (const uint4*)wk;
        uint4* dst = (uint4*)smb;
#pragma unroll
        for (int i = 0; i < 9; i++) {
            int idx = t + i * 512;
            if (idx < 4352) dst[idx] = src[idx];
        }
    }
    __syncthreads();
    gemm_body_128((const uint32_t*)Wh, (const uint32_t*)Wl, XhW, XlW,
                  kbias, g_Kb + (size_t)b * CH * HW, py0, px0, half, w, gid, tig);
}

// ---------------- predictor v3: tensor-core phase-1, per-pixel phase-2 ----------------
// one block = one 16x16 window, 512 threads.
// smem: Xh|Xl [256*136] bf16, Wh|Wl [32*136] bf16, fS [32*261] f32,
//       wr1[16*32], wr2[32], cgS[256], fsum_s[32] f32
#define PRED2_SMEM (69632*2 + 8704*2 + 33408 + 2048 + 128 + 1024 + 128)
__global__ void __launch_bounds__(512, 1)
predictor_mma(const float* __restrict__ cond_g,
              const float* __restrict__ rin_w, const float* __restrict__ rin_b,
              const float* __restrict__ r1w, const float* __restrict__ r1b,
              const float* __restrict__ r2w, const float* __restrict__ r2b) {
    int n = blockIdx.x, b = blockIdx.y;
    extern __shared__ char smraw[];
    __nv_bfloat16* Xh = (__nv_bfloat16*)smraw;
    __nv_bfloat16* Xl = Xh + 256 * 136;
    __nv_bfloat16* Wh = Xl + 256 * 136;
    __nv_bfloat16* Wl = Wh + 32 * 136;
    float* fS = (float*)(Wl + 32 * 136);   // 32*261
    float* wr1 = fS + 32 * 261;            // 16*32
    float* wr2 = wr1 + 16 * 32;            // 32
    float* cgS = wr2 + 32;                 // 256
    float* fsum_s = cgS + 256;             // 32
    int t = threadIdx.x;

    // stage W (hi+lo: 17408 B = 1088 uint4)
    {
        const uint4* src = (const uint4*)g_WRIN;
        uint4* dst = (uint4*)Wh;
#pragma unroll
        for (int i = 0; i < 3; i++) {
            int idx = t + i * 512;
            if (idx < 1088) dst[idx] = src[idx];
        }
    }
    for (int i = t; i < 16 * 32; i += 512) wr1[i] = r1w[i];
    if (t < 32) { wr2[t] = r2w[t]; fsum_s[t] = 0.f; }

    int py0 = (n >> 4) * 16, px0 = (n & 15) * 16;
    if (t < 256) {
        int pix = (py0 + (t >> 4)) * 256 + px0 + (t & 15);
        cgS[t] = __ldg(&cond_g[(size_t)b * HW + pix]);
    }
    // stage X = V window hi/lo
    const float* xb = g_V + (size_t)b * CH * HW;
    {
        int px = t & 255;
        int pix = (py0 + (px >> 4)) * 256 + px0 + (px & 15);
        int cp0 = t >> 8;
#pragma unroll
        for (int j = 0; j < 32; j++) {
            int cp = cp0 + j * 2;
            float v0 = xb[(size_t)(2 * cp) * HW + pix];
            float v1 = xb[(size_t)(2 * cp + 1) * HW + pix];
            __nv_bfloat16 h0 = __float2bfloat16_rn(v0);
            __nv_bfloat16 h1 = __float2bfloat16_rn(v1);
            __nv_bfloat16 l0 = __float2bfloat16_rn(v0 - __bfloat162float(h0));
            __nv_bfloat16 l1 = __float2bfloat16_rn(v1 - __bfloat162float(h1));
            ((__nv_bfloat162*)(Xh + px * 136))[cp] = __nv_bfloat162(h0, h1);
            ((__nv_bfloat162*)(Xl + px * 136))[cp] = __nv_bfloat162(l0, l1);
        }
    }
    __syncthreads();

    // GEMM: 16 warps = 2(m16) x 8(n32); W 32 rows, X 256 rows
    int w = t >> 5, lane = t & 31;
    int gid = lane >> 2, tig = lane & 3;
    int mrow = (w & 1) * 16;
    int ncol = (w >> 1) * 32;
    const uint32_t* WhW = (const uint32_t*)Wh;
    const uint32_t* WlW = (const uint32_t*)Wl;
    const uint32_t* XhW = (const uint32_t*)Xh;
    const uint32_t* XlW = (const uint32_t*)Xl;

    float acc[4][4];
#pragma unroll
    for (int i = 0; i < 4; i++)
#pragma unroll
        for (int j = 0; j < 4; j++) acc[i][j] = 0.f;
#pragma unroll 1
    for (int ks = 0; ks < 8; ks++) {
        int kw = ks * 8;
        uint32_t Ah[4], Al[4], Bh[4][2], Bl[4][2];
        int ra = (mrow + gid) * 68 + kw + tig;
        int ra8 = ra + 8 * 68;
        Ah[0] = WhW[ra];     Ah[1] = WhW[ra8];
        Ah[2] = WhW[ra + 4]; Ah[3] = WhW[ra8 + 4];
        Al[0] = WlW[ra];     Al[1] = WlW[ra8];
        Al[2] = WlW[ra + 4]; Al[3] = WlW[ra8 + 4];
#pragma unroll
        for (int nt = 0; nt < 4; nt++) {
            int rr = (ncol + nt * 8 + gid) * 68 + kw + tig;
            Bh[nt][0] = XhW[rr]; Bh[nt][1] = XhW[rr + 4];
            Bl[nt][0] = XlW[rr]; Bl[nt][1] = XlW[rr + 4];
        }
#pragma unroll
        for (int nt = 0; nt < 4; nt++) {
            MMA_BF16(acc[nt], Ah, Bh[nt]);
            MMA_BF16(acc[nt], Ah, Bl[nt]);
            MMA_BF16(acc[nt], Al, Bh[nt]);
        }
    }

    // epilogue: +bias +cond terms, leaky, write fS + g_F, accumulate fsum
    {
        int ocA = mrow + gid, ocB = ocA + 8;
        float bA = __ldg(&rin_b[ocA]), bB = __ldg(&rin_b[ocB]);
        float wA128 = __ldg(&rin_w[ocA * 131 + 128]);
        float wA129 = __ldg(&rin_w[ocA * 131 + 129]);
        float wA130 = __ldg(&rin_w[ocA * 131 + 130]);
        float wB128 = __ldg(&rin_w[ocB * 131 + 128]);
        float wB129 = __ldg(&rin_w[ocB * 131 + 129]);
        float wB130 = __ldg(&rin_w[ocB * 131 + 130]);
        float* Fb = g_F + (size_t)b * 32 * HW;
        float sA = 0.f, sB = 0.f;
#pragma unroll
        for (int nt = 0; nt < 4; nt++) {
            int col = ncol + nt * 8 + tig * 2;
#pragma unroll
            for (int d = 0; d < 2; d++) {
                int px = col + d;
                float cg = cgS[px];
                float ly = -1.f + (float)(px >> 4) * (2.f / 15.f);
                float lx = -1.f + (float)(px & 15) * (2.f / 15.f);
                float vA = leakyf(acc[nt][d] + bA + wA128 * cg + wA129 * ly + wA130 * lx);
                float vB = leakyf(acc[nt][2 + d] + bB + wB128 * cg + wB129 * ly + wB130 * lx);
                fS[ocA * 261 + px] = vA;
                fS[ocB * 261 + px] = vB;
                sA += vA; sB += vB;
                int pix = (py0 + (px >> 4)) * 256 + px0 + (px & 15);
                Fb[(size_t)ocA * HW + pix] = vA;
                Fb[(size_t)ocB * HW + pix] = vB;
            }
        }
        atomicAdd(&fsum_s[ocA], sA);
        atomicAdd(&fsum_s[ocB], sB);
    }
    __syncthreads();

    // phase 2: per-pixel fmc + offsets (256 active threads)
    if (t < 256) {
        int px = t;
        float fv[32];
        float fm = 0.f;
#pragma unroll
        for (int o = 0; o < 32; o++) {
            fv[o] = fS[o * 261 + px];
            fm += fv[o];
        }
        int pix = (py0 + (px >> 4)) * 256 + px0 + (px & 15);
        g_FMC[(size_t)b * HW + pix] = fm * (1.f / 32.f);

        float h[16];
#pragma unroll
        for (int o2 = 0; o2 < 16; o2++) {
            float s = __ldg(&r1b[o2]);
#pragma unroll
            for (int o = 0; o < 32; o++) s = fmaf(wr1[o2 * 32 + o], fv[o], s);
            h[o2] = leakyf(s);
        }
        float ox = __ldg(&r2b[0]), oy = __ldg(&r2b[1]);
#pragma unroll
        for (int o2 = 0; o2 < 16; o2++) {
            ox = fmaf(wr2[o2], h[o2], ox);
            oy = fmaf(wr2[16 + o2], h[o2], oy);
        }
        float* OFb = g_OFF + (size_t)b * 2 * HW;
        OFb[pix] = ox;
        OFb[HW + pix] = oy;
    }
    __syncthreads();
    if (t < 32) atomicAdd(&g_FSUM[b * 32 + t], fsum_s[t]);
}

// ---------------- channel attention ca ----------------
__global__ void ca_kernel(const float* __restrict__ rca_w, const float* __restrict__ rca_b) {
    int c = threadIdx.x;
    int b = blockIdx.x;
    float s = __ldg(&rca_b[c]);
#pragma unroll
    for (int ci = 0; ci < 32; ci++)
        s = fmaf(__ldg(&rca_w[c * 32 + ci]), g_FSUM[b * 32 + ci] * (1.f / 65536.f), s);
    g_CA[b * CH + c] = 1.f / (1.f + expf(-s));
}

// ---------------- spatial attention sa: 2D-tiled ----------------
__global__ void __launch_bounds__(256) sa_kernel(const float* __restrict__ rsa_w,
                                                 const float* __restrict__ rsa_b) {
    __shared__ float ws[288];
    __shared__ float tile[10][36];
    int t = threadIdx.x;
    for (int i = t; i < 288; i += 256) ws[i] = rsa_w[i];
    int b = blockIdx.z;
    int tx0 = blockIdx.x * 32, ty0 = blockIdx.y * 8;
    int lx = t & 31, lyy = t >> 5;
    float acc = __ldg(&rsa_b[0]);
    const float* Fb = g_F + (size_t)b * 32 * HW;
#pragma unroll 1
    for (int ci = 0; ci < 32; ci++) {
        __syncthreads();
        for (int i = t; i < 340; i += 256) {
            int lyl = i / 34, lxl = i % 34;
            int gy = ty0 - 1 + lyl, gx = tx0 - 1 + lxl;
            float v = 0.f;
            if ((unsigned)gy < 256u && (unsigned)gx < 256u)
                v = __ldg(&Fb[(size_t)ci * HW + gy * 256 + gx]);
            tile[lyl][lxl] = v;
        }
        __syncthreads();
        const float* wc = ws + ci * 9;
#pragma unroll
        for (int ky = 0; ky < 3; ky++)
#pragma unroll
            for (int kx = 0; kx < 3; kx++)
                acc = fmaf(wc[ky * 3 + kx], tile[lyy + ky][lx + kx], acc);
    }
    g_SA[(size_t)b * HW + (ty0 + lyy) * 256 + tx0 + lx] = 1.f / (1.f + expf(-acc));
}

// ---------------- window MLP + gumbel hard mask ----------------
__global__ void mask_kernel(const float* __restrict__ gu,
                            const float* __restrict__ rm1_w, const float* __restrict__ rm1_b,
                            const float* __restrict__ rm2_w, const float* __restrict__ rm2_b) {
    __shared__ float m[256];
    __shared__ float h1s[16];
    int n = blockIdx.x, b = blockIdx.y;
    int t = threadIdx.x;
    int dh = t >> 4, dw = t & 15;
    int pix = ((n >> 4) * 16 + dh) * 256 + (n & 15) * 16 + dw;
    m[t] = g_FMC[b * HW + pix];
    __syncthreads();
    if (t < 16) {
        float s = __ldg(&rm1_b[t]);
        for (int e = 0; e < 256; e++) s = fmaf(__ldg(&rm1_w[t * 256 + e]), m[e], s);
        h1s[t] = leakyf(s);
    }
    __syncthreads();
    if (t == 0) {
        float z0 = __ldg(&rm2_b[0]), z1 = __ldg(&rm2_b[1]);
#pragma unroll
        for (int o = 0; o < 16; o++) {
            z0 = fmaf(__ldg(&rm2_w[o]), h1s[o], z0);
            z1 = fmaf(__ldg(&rm2_w[16 + o]), h1s[o], z1);
        }
        float mx = fmaxf(z0, z1);
        float e0 = expf(z0 - mx), e1 = expf(z1 - mx);
        float inv = 1.f / (e0 + e1);
        float p0 = e0 * inv, p1 = e1 * inv;
        float u0 = __ldg(&gu[(b * 256 + n) * 2 + 0]);
        float u1 = __ldg(&gu[(b * 256 + n) * 2 + 1]);
        float g0 = -logf(-logf(u0 + 1e-10f) + 1e-10f);
        float g1 = -logf(-logf(u1 + 1e-10f) + 1e-10f);
        g_MASK[b * 256 + n] = (p0 + g0 >= p1 + g1) ? 1.f : 0.f;
    }
}

// ---------------- window attention, 512 threads (16 warps) ----------------
#define SMEM_ATTN3 ((64*257 + 512 + 64 + 64) * 4 + 90112)
__global__ void __launch_bounds__(512, 1) attn_mma_kernel() {
    int n = blockIdx.x, b = blockIdx.y;
    int t = threadIdx.x;
    int py0 = (n >> 4) * 16, px0 = (n & 15) * 16;
    int cbase = b * CH * HW;
    if (g_MASK[b * 256 + n] == 0.f) {
        const float* sab = g_SA + (size_t)b * HW;
#pragma unroll 4
        for (int i = t; i < 8192; i += 512) {
            int ch = i >> 6, r4 = i & 63;
            int wrow = r4 >> 2, px4 = (r4 & 3) * 4;
            int pix = (py0 + wrow) * 256 + px0 + px4;
            float4 v = *(const float4*)(g_V + cbase + ch * HW + pix);
            float4 s = *(const float4*)(sab + pix);
            v.x *= s.x; v.y *= s.y; v.z *= s.z; v.w *= s.w;
            *(float4*)(g_OUT + cbase + ch * HW + pix) = v;
        }
        return;
    }
    extern __shared__ char smraw[];
    float* S = (float*)smraw;
    float* red = S + 64 * 257;
    float* rmax = red + 512;
    float* rsum = rmax + 64;
    __nv_bfloat16* Qh = (__nv_bfloat16*)(rsum + 64);
    __nv_bfloat16* Ql = Qh + 64 * 136;
    __nv_bfloat16* KVh = Ql + 64 * 136;
    __nv_bfloat16* KVl = KVh + 9216;
    __nv_bfloat16* Pth = KVl + 9216;
    __nv_bfloat16* Ptl = Pth + 64 * 72;

    const uint32_t* QhW = (const uint32_t*)Qh;
    const uint32_t* QlW = (const uint32_t*)Ql;
    const uint32_t* KVhW = (const uint32_t*)KVh;
    const uint32_t* KVlW = (const uint32_t*)KVl;
    const uint32_t* PthW = (const uint32_t*)Pth;
    const uint32_t* PtlW = (const uint32_t*)Ptl;

    int w = t >> 5, lane = t & 31;
    int gid = lane >> 2;
    int tig = lane & 3;

#pragma unroll 1
    for (int rc = 0; rc < 4; rc++) {
        int r0 = rc * 64;
        __syncthreads();
#pragma unroll
        for (int j = 0; j < 8; j++) {
            int i = t + j * 512;
            int px = i & 63, cp = i >> 6;
            int p = r0 + px;
            int pix = (py0 + (p >> 4)) * 256 + px0 + (p & 15);
            float v0 = g_Qb[cbase + (2 * cp) * HW + pix];
            float v1 = g_Qb[cbase + (2 * cp + 1) * HW + pix];
            __nv_bfloat16 h0 = __float2bfloat16_rn(v0);
            __nv_bfloat16 h1 = __float2bfloat16_rn(v1);
            __nv_bfloat16 l0 = __float2bfloat16_rn(v0 - __bfloat162float(h0));
            __nv_bfloat16 l1 = __float2bfloat16_rn(v1 - __bfloat162float(h1));
            ((__nv_bfloat162*)(Qh + px * 136))[cp] = __nv_bfloat162(h0, h1);
            ((__nv_bfloat162*)(Ql + px * 136))[cp] = __nv_bfloat162(l0, l1);
        }

        int mrowS = (w & 3) * 16, ncolS = (w >> 2) * 16;
#pragma unroll 1
        for (int kvt = 0; kvt < 4; kvt++) {
            __syncthreads();
#pragma unroll
            for (int j = 0; j < 8; j++) {
                int i = t + j * 512;
                int px = i & 63, cp = i >> 6;
                int p = kvt * 64 + px;
                int pix = (py0 + (p >> 4)) * 256 + px0 + (p & 15);
                float v0 = g_Kb[cbase + (2 * cp) * HW + pix];
                float v1 = g_Kb[cbase + (2 * cp + 1) * HW + pix];
                __nv_bfloat16 h0 = __float2bfloat16_rn(v0);
                __nv_bfloat16 h1 = __float2bfloat16_rn(v1);
                __nv_bfloat16 l0 = __float2bfloat16_rn(v0 - __bfloat162float(h0));
                __nv_bfloat16 l1 = __float2bfloat16_rn(v1 - __bfloat162float(h1));
                ((__nv_bfloat162*)(KVh + px * 136))[cp] = __nv_bfloat162(h0, h1);
                ((__nv_bfloat162*)(KVl + px * 136))[cp] = __nv_bfloat162(l0, l1);
            }
            __syncthreads();
            float acc[2][4];
#pragma unroll
            for (int i = 0; i < 2; i++)
#pragma unroll
                for (int j2 = 0; j2 < 4; j2++) acc[i][j2] = 0.f;
#pragma unroll
            for (int ks = 0; ks < 8; ks++) {
                int kw = ks * 8;
                uint32_t Ahf[4], Alf[4], Bhf[2][2], Blf[2][2];
                int ra = (mrowS + gid) * 68 + kw + tig;
                int ra8 = ra + 8 * 68;
                Ahf[0] = QhW[ra];     Ahf[1] = QhW[ra8];
                Ahf[2] = QhW[ra + 4]; Ahf[3] = QhW[ra8 + 4];
                Alf[0] = QlW[ra];     Alf[1] = QlW[ra8];
                Alf[2] = QlW[ra + 4]; Alf[3] = QlW[ra8 + 4];
#pragma unroll
                for (int nt = 0; nt < 2; nt++) {
                    int rr = (ncolS + nt * 8 + gid) * 68 + kw + tig;
                    Bhf[nt][0] = KVhW[rr]; Bhf[nt][1] = KVhW[rr + 4];
                    Blf[nt][0] = KVlW[rr]; Blf[nt][1] = KVlW[rr + 4];
                }
#pragma unroll
                for (int nt = 0; nt < 2; nt++) {
                    MMA_BF16(acc[nt], Ahf, Bhf[nt]);
                    MMA_BF16(acc[nt], Ahf, Blf[nt]);
                    MMA_BF16(acc[nt], Alf, Bhf[nt]);
                }
            }
#pragma unroll
            for (int nt = 0; nt < 2; nt++) {
                int col = kvt * 64 + ncolS + nt * 8 + tig * 2;
                S[(mrowS + gid) * 257 + col] = acc[nt][0];
                S[(mrowS + gid) * 257 + col + 1] = acc[nt][1];
                S[(mrowS + gid + 8) * 257 + col] = acc[nt][2];
                S[(mrowS + gid + 8) * 257 + col + 1] = acc[nt][3];
            }
        }
        __syncthreads();

        {
            int r = t & 63, seg = t >> 6;
            float* srow = &S[r * 257 + seg * 32];
            float mx = -1e30f;
#pragma unroll 8
            for (int k = 0; k < 32; k++) mx = fmaxf(mx, srow[k]);
            red[seg * 64 + r] = mx;
            __syncthreads();
            if (t < 64) {
                float m0 = fmaxf(fmaxf(red[t], red[64 + t]), fmaxf(red[128 + t], red[192 + t]));
                float m1 = fmaxf(fmaxf(red[256 + t], red[320 + t]), fmaxf(red[384 + t], red[448 + t]));
                rmax[t] = fmaxf(m0, m1);
            }
            __syncthreads();
            float rm_ = rmax[r];
            float s = 0.f;
#pragma unroll 8
            for (int k = 0; k < 32; k++) {
                float e = __expf(srow[k] - rm_);
                srow[k] = e;
                s += e;
            }
            red[seg * 64 + r] = s;
            __syncthreads();
            if (t < 64)
                rsum[t] = (red[t] + red[64 + t] + red[128 + t] + red[192 + t]) +
                          (red[256 + t] + red[320 + t] + red[384 + t] + red[448 + t]);
            __syncthreads();
        }

        int mrowO = (w & 3) * 16, ncolO = (w >> 2) * 32;
        float oacc[4][4];
#pragma unroll
        for (int i = 0; i < 4; i++)
#pragma unroll
            for (int j2 = 0; j2 < 4; j2++) oacc[i][j2] = 0.f;

#pragma unroll 1
        for (int kvt = 0; kvt < 4; kvt++) {
            __syncthreads();
#pragma unroll
            for (int j = 0; j < 8; j++) {
                int i = t + j * 512;
                int col = i & 63, row = i >> 6;
                float v = S[row * 257 + kvt * 64 + col];
                __nv_bfloat16 h = __float2bfloat16_rn(v);
                Pth[row * 72 + col] = h;
                Ptl[row * 72 + col] = __float2bfloat16_rn(v - __bfloat162float(h));
            }
#pragma unroll
            for (int j = 0; j < 16; j++) {
                int i = t + j * 512;
                int px = i & 63, ch = i >> 6;
                int p = kvt * 64 + px;
                int pix = (py0 + (p >> 4)) * 256 + px0 + (p & 15);
                float v = g_V[cbase + ch * HW + pix];
                __nv_bfloat16 h = __float2bfloat16_rn(v);
                KVh[ch * 72 + px] = h;
                KVl[ch * 72 + px] = __float2bfloat16_rn(v - __bfloat162float(h));
            }
            __syncthreads();
#pragma unroll
            for (int ks = 0; ks < 4; ks++) {
                int kw = ks * 8;
                uint32_t Ahf[4], Alf[4], Bhf[4][2], Blf[4][2];
                int ra = (mrowO + gid) * 36 + kw + tig;
                int ra8 = ra + 8 * 36;
                Ahf[0] = PthW[ra];     Ahf[1] = PthW[ra8];
                Ahf[2] = PthW[ra + 4]; Ahf[3] = PthW[ra8 + 4];
                Alf[0] = PtlW[ra];     Alf[1] = PtlW[ra8];
                Alf[2] = PtlW[ra + 4]; Alf[3] = PtlW[ra8 + 4];
#pragma unroll
                for (int nt = 0; nt < 4; nt++) {
                    int rr = (ncolO + nt * 8 + gid) * 36 + kw + tig;
                    Bhf[nt][0] = KVhW[rr]; Bhf[nt][1] = KVhW[rr + 4];
                    Blf[nt][0] = KVlW[rr]; Blf[nt][1] = KVlW[rr + 4];
                }
#pragma unroll
                for (int nt = 0; nt < 4; nt++) {
                    MMA_BF16(oacc[nt], Ahf, Bhf[nt]);
                    MMA_BF16(oacc[nt], Ahf, Blf[nt]);
                    MMA_BF16(oacc[nt], Alf, Bhf[nt]);
                }
            }
        }

        {
            int rowA = mrowO + gid, rowB = rowA + 8;
            float invA = 1.f / rsum[rowA];
            float invB = 1.f / rsum[rowB];
            int pA = r0 + rowA, pB = r0 + rowB;
            int pixA = (py0 + (pA >> 4)) * 256 + px0 + (pA & 15);
            int pixB = (py0 + (pB >> 4)) * 256 + px0 + (pB & 15);
#pragma unroll
            for (int nt = 0; nt < 4; nt++) {
                int ch = ncolO + nt * 8 + tig * 2;
                g_OUT[cbase + ch * HW + pixA] = oacc[nt][0] * invA;
                g_OUT[cbase + (ch + 1) * HW + pixA] = oacc[nt][1] * invA;
                g_OUT[cbase + ch * HW + pixB] = oacc[nt][2] * invB;
                g_OUT[cbase + (ch + 1) * HW + pixB] = oacc[nt][3] * invB;
            }
        }
    }
}

// ---------------- fused depthwise 5x5(d1) -> 5x5(d3) + gelu*ca + residual ----------------
__global__ void __launch_bounds__(256) dw5x2_kernel(
    const float* __restrict__ in, const float* __restrict__ w2, const float* __restrict__ b2,
    const float* __restrict__ w3, const float* __restrict__ b3, float* __restrict__ out) {
    __shared__ float sIn[48][81];
    __shared__ float sMid[44][77];
    __shared__ float wA[25], wB[25];
    int c = blockIdx.z & 127, b = blockIdx.z >> 7;
    int t = threadIdx.x;
    if (t < 25) wA[t] = w2[c * 25 + t];
    else if (t < 50) wB[t - 25] = w3[c * 25 + (t - 25)];
    int ox0 = blockIdx.x * 64, oy0 = blockIdx.y * 32;
    const float* ip = in + (size_t)(b * CH + c) * HW;

    for (int i = t; i < 48 * 80; i += 256) {
        int lx = i % 80, ly = i / 80;
        int gx = ox0 - 8 + lx, gy = oy0 - 8 + ly;
        float v = 0.f;
        if ((unsigned)gx < 256u && (unsigned)gy < 256u) v = __ldg(&ip[gy * 256 + gx]);
        sIn[ly][lx] = v;
    }
    __syncthreads();

    float b2v = __ldg(&b2[c]);
    for (int i = t; i < 44 * 76; i += 256) {
        int mx = i % 76, my = i / 76;
        int gx = ox0 - 6 + mx, gy = oy0 - 6 + my;
        float acc = 0.f;
        if ((unsigned)gx < 256u && (unsigned)gy < 256u) {
            acc = b2v;
#pragma unroll
            for (int ky = 0; ky < 5; ky++)
#pragma unroll
                for (int kx = 0; kx < 5; kx++)
                    acc = fmaf(wA[ky * 5 + kx], sIn[my + ky][mx + kx], acc);
        }
        sMid[my][mx] = acc;
    }
    __syncthreads();

    float b3v = __ldg(&b3[c]);
    float cav = g_CA[b * CH + c];
    size_t obase = (size_t)(b * CH + c) * HW;
    for (int i = t; i < 32 * 64; i += 256) {
        int x = i % 64, y = i / 64;
        float acc = b3v;
#pragma unroll
        for (int ky = 0; ky < 5; ky++)
#pragma unroll
            for (int kx = 0; kx < 5; kx++)
                acc = fmaf(wB[ky * 5 + kx], sMid[y + 3 * ky][x + 3 * kx], acc);
        float g = 0.5f * acc * (1.f + erff(acc * 0.7071067811865475f));
        size_t oidx = obase + (size_t)(oy0 + y) * 256 + ox0 + x;
        out[oidx] = g * cav + g_OUT[oidx];
    }
}

// ---------------- launch ----------------
extern "C" void kernel_launch(void* const* d_in, const int* in_sizes, int n_in,
                              void* d_out, int out_size) {
    const float* x      = (const float*)d_in[0];
    const float* cond_g = (const float*)d_in[1];
    const float* gu     = (const float*)d_in[2];
    const float* pv_w   = (const float*)d_in[3];
    const float* pv_b   = (const float*)d_in[4];
    const float* pq_w   = (const float*)d_in[5];
    const float* pq_b   = (const float*)d_in[6];
    const float* pk_w   = (const float*)d_in[7];
    const float* pk_b   = (const float*)d_in[8];
    const float* cs1_w  = (const float*)d_in[9];
    const float* cs1_b  = (const float*)d_in[10];
    const float* cs2_w  = (const float*)d_in[11];
    const float* cs2_b  = (const float*)d_in[12];
    const float* cs3_w  = (const float*)d_in[13];
    const float* cs3_b  = (const float*)d_in[14];
    const float* po_w   = (const float*)d_in[15];
    const float* po_b   = (const float*)d_in[16];
    const float* rin_w  = (const float*)d_in[17];
    const float* rin_b  = (const float*)d_in[18];
    const float* r1w    = (const float*)d_in[19];
    const float* r1b    = (const float*)d_in[20];
    const float* r2w    = (const float*)d_in[21];
    const float* r2b    = (const float*)d_in[22];
    const float* rm1_w  = (const float*)d_in[23];
    const float* rm1_b  = (const float*)d_in[24];
    const float* rm2_w  = (const float*)d_in[25];
    const float* rm2_b  = (const float*)d_in[26];
    const float* rca_w  = (const float*)d_in[27];
    const float* rca_b  = (const float*)d_in[28];
    const float* rsa_w  = (const float*)d_in[29];
    const float* rsa_b  = (const float*)d_in[30];

    float *pV, *pOUT, *pT1, *pT2;
    __nv_bfloat16* pWT;
    cudaGetSymbolAddress((void**)&pV, g_V);
    cudaGetSymbolAddress((void**)&pOUT, g_OUT);
    cudaGetSymbolAddress((void**)&pT1, g_T1);
    cudaGetSymbolAddress((void**)&pT2, g_T2);
    cudaGetSymbolAddress((void**)&pWT, g_WT);

    cudaFuncSetAttribute(attn_mma_kernel, cudaFuncAttributeMaxDynamicSharedMemorySize, SMEM_ATTN3);
    cudaFuncSetAttribute(conv1x1_mma, cudaFuncAttributeMaxDynamicSharedMemorySize, CV_SMEM_FULL);
    cudaFuncSetAttribute(convqk_mma, cudaFuncAttributeMaxDynamicSharedMemorySize, CV_SMEM_FULL);
    cudaFuncSetAttribute(predictor_mma, cudaFuncAttributeMaxDynamicSharedMemorySize, PRED2_SMEM);

    const int WSET = 2 * 128 * 136;

    prep_all_kernel<<<dim3(64, 5), 256>>>(pv_w, pq_w, pk_w, cs1_w, po_w);
    prep_rin_kernel<<<16, 256>>>(rin_w);
    zero_fsum_kernel<<<1, 128>>>();
    conv1x1_mma<<<dim3(256, BB), 512, CV_SMEM_FULL>>>(x, pWT + 0 * WSET, pv_b, pV, 0);
    predictor_mma<<<dim3(256, BB), 512, PRED2_SMEM>>>(cond_g, rin_w, rin_b, r1w, r1b, r2w, r2b);
    ca_kernel<<<BB, 128>>>(rca_w, rca_b);
    sa_kernel<<<dim3(8, 32, BB), 256>>>(rsa_w, rsa_b);
    mask_kernel<<<dim3(256, BB), 256>>>(gu, rm1_w, rm1_b, rm2_w, rm2_b);
    convqk_mma<<<dim3(256, BB), 512, CV_SMEM_FULL>>>(x, pWT + 1 * WSET, pWT + 2 * WSET, pq_b, pk_b);
    attn_mma_kernel<<<dim3(256, BB), 512, SMEM_ATTN3>>>();
    conv1x1_mma<<<dim3(256, BB), 512, CV_SMEM_FULL>>>(pOUT, pWT + 3 * WSET, cs1_b, pT1, 0);
    dw5x2_kernel<<<dim3(4, 8, BB * CH), 256>>>(pT1, cs2_w, cs2_b, cs3_w, cs3_b, pT2);
    conv1x1_mma<<<dim3(256, BB), 512, CV_SMEM_FULL>>>(pT2, pWT + 4 * WSET, po_b, (float*)d_out, 0);
}

// round 15
// speedup vs baseline: 2.4203x; 1.0117x over previous
#include <cuda_runtime.h>
#include <cuda_bf16.h>
#include <stdint.h>
#include <math.h>

#define HW 65536
#define WIMG 256
#define CH 128
#define BB 4
#define ELT (BB*CH*HW)

// ---------------- scratch ----------------
__device__ float g_V[ELT];
__device__ float g_Qb[ELT];
__device__ float g_Kb[ELT];
__device__ float g_OUT[ELT];
__device__ float g_T1[ELT];
__device__ float g_T2[ELT];
__device__ float g_F[BB*32*HW];
__device__ float g_OFF[BB*2*HW];
__device__ float g_FMC[BB*HW];
__device__ float g_SA[BB*HW];
__device__ float g_FSUM[BB*32];
__device__ float g_CA[BB*CH];
__device__ float g_MASK[BB*256];
__device__ __align__(16) __nv_bfloat16 g_WT[5][2][128*136];
__device__ __align__(16) __nv_bfloat16 g_WRIN[2][32*136];

__device__ __forceinline__ float leakyf(float x) { return x > 0.f ? x : 0.2f * x; }

__global__ void zero_fsum_kernel() {
    g_FSUM[threadIdx.x] = 0.f;
}

// ---------------- weight prep ----------------
__global__ void prep_all_kernel(const float* __restrict__ w0, const float* __restrict__ w1,
                                const float* __restrict__ w2, const float* __restrict__ w3,
                                const float* __restrict__ w4) {
    int set = blockIdx.y;
    const float* w = (set == 0) ? w0 : (set == 1) ? w1 : (set == 2) ? w2 : (set == 3) ? w3 : w4;
    int i = blockIdx.x * 256 + threadIdx.x;
    int oc = i >> 7, ci = i & 127;
    float v = w[i];
    __nv_bfloat16 h = __float2bfloat16_rn(v);
    __nv_bfloat16 l = __float2bfloat16_rn(v - __bfloat162float(h));
    g_WT[set][0][oc * 136 + ci] = h;
    g_WT[set][1][oc * 136 + ci] = l;
}

__global__ void prep_rin_kernel(const float* __restrict__ w) {
    int i = blockIdx.x * 256 + threadIdx.x;   // 4096
    int oc = i >> 7, ci = i & 127;
    float v = w[oc * 131 + ci];
    __nv_bfloat16 h = __float2bfloat16_rn(v);
    __nv_bfloat16 l = __float2bfloat16_rn(v - __bfloat162float(h));
    g_WRIN[0][oc * 136 + ci] = h;
    g_WRIN[1][oc * 136 + ci] = l;
}

// ---------------- HMMA m16n8k16 bf16 + ldmatrix ----------------
#define MMA_BF16(d, a, b) \
    asm volatile("mma.sync.aligned.m16n8k16.row.col.f32.bf16.bf16.f32 " \
        "{%0,%1,%2,%3}, {%4,%5,%6,%7}, {%8,%9}, {%0,%1,%2,%3};" \
        : "+f"((d)[0]), "+f"((d)[1]), "+f"((d)[2]), "+f"((d)[3]) \
        : "r"((a)[0]), "r"((a)[1]), "r"((a)[2]), "r"((a)[3]), "r"((b)[0]), "r"((b)[1]))

#define LDSM_X4(r, a) \
    asm volatile("ldmatrix.sync.aligned.m8n8.x4.shared.b16 {%0,%1,%2,%3}, [%4];" \
        : "=r"((r)[0]), "=r"((r)[1]), "=r"((r)[2]), "=r"((r)[3]) : "r"(a))

__device__ __forceinline__ uint32_t smaddr(const void* p) {
    return (uint32_t)__cvta_generic_to_shared(p);
}

// ---- shared GEMM body: 8-warp slice over one 128px half, ldmatrix fragments ----
// A rows stride 272B (136 bf16), B rows stride 272B.
__device__ __forceinline__ void gemm_body_128(
    const __nv_bfloat16* Wh, const __nv_bfloat16* Wl,
    const __nv_bfloat16* Xh, const __nv_bfloat16* Xl,
    const float* __restrict__ bias, float* __restrict__ yb,
    int py0, int px0, int half, int w, int lane) {
    int oc0 = (w & 3) * 32;
    int n0 = (w >> 2) * 64;
    int gid = lane >> 2, tig = lane & 3;
    int mm = lane >> 3, r8 = lane & 7;
    uint32_t aoff = (uint32_t)((oc0 + (mm & 1) * 8 + r8) * 272 + (mm >> 1) * 16);
    uint32_t aHi = smaddr(Wh) + aoff;
    uint32_t aLo = smaddr(Wl) + aoff;
    uint32_t boff = (uint32_t)((n0 + (mm >> 1) * 8 + r8) * 272 + (mm & 1) * 16);
    uint32_t bHi = smaddr(Xh) + boff;
    uint32_t bLo = smaddr(Xl) + boff;

    float acc[16][4];
#pragma unroll
    for (int i = 0; i < 16; i++)
#pragma unroll
        for (int j = 0; j < 4; j++) acc[i][j] = 0.f;

#pragma unroll 1
    for (int ks = 0; ks < 8; ks++) {
        uint32_t ko = ks * 32;
        uint32_t Ah[2][4], Al[2][4], Bh[4][4], Bl[4][4];
        LDSM_X4(Ah[0], aHi + ko);
        LDSM_X4(Ah[1], aHi + 16 * 272 + ko);
        LDSM_X4(Al[0], aLo + ko);
        LDSM_X4(Al[1], aLo + 16 * 272 + ko);
#pragma unroll
        for (int p = 0; p < 4; p++) {
            LDSM_X4(Bh[p], bHi + p * (16 * 272) + ko);
            LDSM_X4(Bl[p], bLo + p * (16 * 272) + ko);
        }
#pragma unroll
        for (int mt = 0; mt < 2; mt++)
#pragma unroll
            for (int nt = 0; nt < 8; nt++) {
                const uint32_t* bh = &Bh[nt >> 1][(nt & 1) * 2];
                const uint32_t* bl = &Bl[nt >> 1][(nt & 1) * 2];
                MMA_BF16(acc[mt * 8 + nt], Ah[mt], bh);
                MMA_BF16(acc[mt * 8 + nt], Ah[mt], bl);
                MMA_BF16(acc[mt * 8 + nt], Al[mt], bh);
            }
    }
#pragma unroll
    for (int mt = 0; mt < 2; mt++) {
        int ocA = oc0 + mt * 16 + gid;
        int ocB = ocA + 8;
        float bvA = __ldg(&bias[ocA]);
        float bvB = __ldg(&bias[ocB]);
#pragma unroll
        for (int nt = 0; nt < 8; nt++) {
            int col = n0 + nt * 8 + tig * 2;
            int p = half * 128 + col;
            int pix = (py0 + (p >> 4)) * 256 + px0 + (p & 15);
            float2 v0 = make_float2(acc[mt * 8 + nt][0] + bvA, acc[mt * 8 + nt][1] + bvA);
            float2 v1 = make_float2(acc[mt * 8 + nt][2] + bvB, acc[mt * 8 + nt][3] + bvB);
            *(float2*)(yb + (size_t)ocA * HW + pix) = v0;
            *(float2*)(yb + (size_t)ocB * HW + pix) = v1;
        }
    }
}

// ---------------- conv1x1 GEMM, FULL window per block (512 thr) ----------------
#define CV_SMEM_FULL ((2 * 128 * 136 + 2 * 256 * 136) * 2)
__global__ void __launch_bounds__(512, 1)
conv1x1_mma(const float* __restrict__ xin, const __nv_bfloat16* __restrict__ wsp,
            const float* __restrict__ bias, float* __restrict__ yout, int bOff) {
    int n = blockIdx.x, b = blockIdx.y + bOff;
    extern __shared__ __nv_bfloat16 smb[];
    __nv_bfloat16* Wh = smb;
    __nv_bfloat16* Wl = Wh + 128 * 136;
    __nv_bfloat16* Xh = Wl + 128 * 136;
    __nv_bfloat16* Xl = Xh + 256 * 136;
    int t = threadIdx.x;

    {
        const uint4* src = (const uint4*)wsp;
        uint4* dst = (uint4*)smb;
#pragma unroll
        for (int i = 0; i < 9; i++) {
            int idx = t + i * 512;
            if (idx < 4352) dst[idx] = src[idx];
        }
    }

    int py0 = (n >> 4) * 16, px0 = (n & 15) * 16;
    const float* xb = xin + (size_t)b * CH * HW;
    {
        int px = t & 255;
        int pix = (py0 + (px >> 4)) * 256 + px0 + (px & 15);
        int cp0 = t >> 8;
#pragma unroll
        for (int j = 0; j < 32; j++) {
            int cp = cp0 + j * 2;
            float v0 = xb[(size_t)(2 * cp) * HW + pix];
            float v1 = xb[(size_t)(2 * cp + 1) * HW + pix];
            __nv_bfloat16 h0 = __float2bfloat16_rn(v0);
            __nv_bfloat16 h1 = __float2bfloat16_rn(v1);
            __nv_bfloat16 l0 = __float2bfloat16_rn(v0 - __bfloat162float(h0));
            __nv_bfloat16 l1 = __float2bfloat16_rn(v1 - __bfloat162float(h1));
            ((__nv_bfloat162*)(Xh + px * 136))[cp] = __nv_bfloat162(h0, h1);
            ((__nv_bfloat162*)(Xl + px * 136))[cp] = __nv_bfloat162(l0, l1);
        }
    }
    __syncthreads();

    int wfull = t >> 5, lane = t & 31;
    int half = wfull >> 3;
    int w = wfull & 7;
    gemm_body_128(Wh, Wl, Xh + half * 128 * 136, Xl + half * 128 * 136,
                  bias, yout + (size_t)b * CH * HW, py0, px0, half, w, lane);
}

// ---------------- fused flow-warp + q/k projections, FULL window (512 thr) ----------------
__global__ void __launch_bounds__(512, 1)
convqk_mma(const float* __restrict__ xin,
           const __nv_bfloat16* __restrict__ wq, const __nv_bfloat16* __restrict__ wk,
           const float* __restrict__ qbias, const float* __restrict__ kbias) {
    int n = blockIdx.x, b = blockIdx.y;
    if (g_MASK[b * 256 + n] == 0.f) return;
    extern __shared__ __nv_bfloat16 smb[];
    __nv_bfloat16* Wh = smb;
    __nv_bfloat16* Wl = Wh + 128 * 136;
    __nv_bfloat16* Xh = Wl + 128 * 136;
    __nv_bfloat16* Xl = Xh + 256 * 136;
    int t = threadIdx.x;

    {
        const uint4* src = (const uint4*)wq;
        uint4* dst = (uint4*)smb;
#pragma unroll
        for (int i = 0; i < 9; i++) {
            int idx = t + i * 512;
            if (idx < 4352) dst[idx] = src[idx];
        }
    }

    int py0 = (n >> 4) * 16, px0 = (n & 15) * 16;
    {
        int px = t & 255;
        int gy = py0 + (px >> 4), gx = px0 + (px & 15);
        int pp = gy * 256 + gx;
        const float* OFb = g_OFF + (size_t)b * 2 * HW;
        float fx = OFb[pp];
        float fy = OFb[HW + pp];
        float sx = fminf(fmaxf((float)gx + fx, 0.f), 255.f);
        float sy = fminf(fmaxf((float)gy + fy, 0.f), 255.f);
        float x0f = floorf(sx), y0f = floorf(sy);
        float x1f = fminf(x0f + 1.f, 255.f), y1f = fminf(y0f + 1.f, 255.f);
        float wx = sx - x0f, wy = sy - y0f;
        int x0 = (int)x0f, x1 = (int)x1f, y0 = (int)y0f, y1 = (int)y1f;
        int iA = y0 * 256 + x0, iB = y0 * 256 + x1, iC = y1 * 256 + x0, iD = y1 * 256 + x1;
        float w00 = (1.f - wx) * (1.f - wy), w01 = wx * (1.f - wy);
        float w10 = (1.f - wx) * wy, w11 = wx * wy;
        const float* xb = xin + (size_t)b * CH * HW;
        int cp0 = t >> 8;
#pragma unroll 4
        for (int j = 0; j < 32; j++) {
            int cp = cp0 + j * 2;
            const float* xc0 = xb + (size_t)(2 * cp) * HW;
            const float* xc1 = xc0 + HW;
            float v0 = __ldg(&xc0[iA]) * w00 + __ldg(&xc0[iB]) * w01 +
                       __ldg(&xc0[iC]) * w10 + __ldg(&xc0[iD]) * w11;
            float v1 = __ldg(&xc1[iA]) * w00 + __ldg(&xc1[iB]) * w01 +
                       __ldg(&xc1[iC]) * w10 + __ldg(&xc1[iD]) * w11;
            __nv_bfloat16 h0 = __float2bfloat16_rn(v0);
            __nv_bfloat16 h1 = __float2bfloat16_rn(v1);
            __nv_bfloat16 l0 = __float2bfloat16_rn(v0 - __bfloat162float(h0));
            __nv_bfloat16 l1 = __float2bfloat16_rn(v1 - __bfloat162float(h1));
            ((__nv_bfloat162*)(Xh + px * 136))[cp] = __nv_bfloat162(h0, h1);
            ((__nv_bfloat162*)(Xl + px * 136))[cp] = __nv_bfloat162(l0, l1);
        }
    }
    __syncthreads();

    int wfull = t >> 5, lane = t & 31;
    int half = wfull >> 3;
    int w = wfull & 7;
    const __nv_bfloat16* XhH = Xh + half * 128 * 136;
    const __nv_bfloat16* XlH = Xl + half * 128 * 136;

    gemm_body_128(Wh, Wl, XhH, XlH, qbias, g_Qb + (size_t)b * CH * HW, py0, px0, half, w, lane);
    __syncthreads();
    {
        const uint4* src = (const uint4*)wk;
        uint4* dst = (uint4*)smb;
#pragma unroll
        for (int i = 0; i < 9; i++) {
            int idx = t + i * 512;
            if (idx < 4352) dst[idx] = src[idx];
        }
    }
    __syncthreads();
    gemm_body_128(Wh, Wl, XhH, XlH, kbias, g_Kb + (size_t)b * CH * HW, py0, px0, half, w, lane);
}

// ---------------- predictor: tensor-core phase-1, per-pixel phase-2 ----------------
#define PRED2_SMEM (69632*2 + 8704*2 + 33408 + 2048 + 128 + 1024 + 128)
__global__ void __launch_bounds__(512, 1)
predictor_mma(const float* __restrict__ cond_g,
              const float* __restrict__ rin_w, const float* __restrict__ rin_b,
              const float* __restrict__ r1w, const float* __restrict__ r1b,
              const float* __restrict__ r2w, const float* __restrict__ r2b) {
    int n = blockIdx.x, b = blockIdx.y;
    extern __shared__ char smraw[];
    __nv_bfloat16* Xh = (__nv_bfloat16*)smraw;
    __nv_bfloat16* Xl = Xh + 256 * 136;
    __nv_bfloat16* Wh = Xl + 256 * 136;
    __nv_bfloat16* Wl = Wh + 32 * 136;
    float* fS = (float*)(Wl + 32 * 136);   // 32*261
    float* wr1 = fS + 32 * 261;            // 16*32
    float* wr2 = wr1 + 16 * 32;            // 32
    float* cgS = wr2 + 32;                 // 256
    float* fsum_s = cgS + 256;             // 32
    int t = threadIdx.x;

    {
        const uint4* src = (const uint4*)g_WRIN;
        uint4* dst = (uint4*)Wh;
#pragma unroll
        for (int i = 0; i < 3; i++) {
            int idx = t + i * 512;
            if (idx < 1088) dst[idx] = src[idx];
        }
    }
    for (int i = t; i < 16 * 32; i += 512) wr1[i] = r1w[i];
    if (t < 32) { wr2[t] = r2w[t]; fsum_s[t] = 0.f; }

    int py0 = (n >> 4) * 16, px0 = (n & 15) * 16;
    if (t < 256) {
        int pix = (py0 + (t >> 4)) * 256 + px0 + (t & 15);
        cgS[t] = __ldg(&cond_g[(size_t)b * HW + pix]);
    }
    const float* xb = g_V + (size_t)b * CH * HW;
    {
        int px = t & 255;
        int pix = (py0 + (px >> 4)) * 256 + px0 + (px & 15);
        int cp0 = t >> 8;
#pragma unroll
        for (int j = 0; j < 32; j++) {
            int cp = cp0 + j * 2;
            float v0 = xb[(size_t)(2 * cp) * HW + pix];
            float v1 = xb[(size_t)(2 * cp + 1) * HW + pix];
            __nv_bfloat16 h0 = __float2bfloat16_rn(v0);
            __nv_bfloat16 h1 = __float2bfloat16_rn(v1);
            __nv_bfloat16 l0 = __float2bfloat16_rn(v0 - __bfloat162float(h0));
            __nv_bfloat16 l1 = __float2bfloat16_rn(v1 - __bfloat162float(h1));
            ((__nv_bfloat162*)(Xh + px * 136))[cp] = __nv_bfloat162(h0, h1);
            ((__nv_bfloat162*)(Xl + px * 136))[cp] = __nv_bfloat162(l0, l1);
        }
    }
    __syncthreads();

    // GEMM: 16 warps = 2(m16) x 8(n32)
    int w = t >> 5, lane = t & 31;
    int gid = lane >> 2, tig = lane & 3;
    int mm = lane >> 3, r8 = lane & 7;
    int mrow = (w & 1) * 16;
    int ncol = (w >> 1) * 32;
    uint32_t aoff = (uint32_t)((mrow + (mm & 1) * 8 + r8) * 272 + (mm >> 1) * 16);
    uint32_t aHi = smaddr(Wh) + aoff;
    uint32_t aLo = smaddr(Wl) + aoff;
    uint32_t boff = (uint32_t)((ncol + (mm >> 1) * 8 + r8) * 272 + (mm & 1) * 16);
    uint32_t bHi = smaddr(Xh) + boff;
    uint32_t bLo = smaddr(Xl) + boff;

    float acc[4][4];
#pragma unroll
    for (int i = 0; i < 4; i++)
#pragma unroll
        for (int j = 0; j < 4; j++) acc[i][j] = 0.f;
#pragma unroll 1
    for (int ks = 0; ks < 8; ks++) {
        uint32_t ko = ks * 32;
        uint32_t Ah[4], Al[4], Bh[2][4], Bl[2][4];
        LDSM_X4(Ah, aHi + ko);
        LDSM_X4(Al, aLo + ko);
        LDSM_X4(Bh[0], bHi + ko);
        LDSM_X4(Bl[0], bLo + ko);
        LDSM_X4(Bh[1], bHi + 16 * 272 + ko);
        LDSM_X4(Bl[1], bLo + 16 * 272 + ko);
#pragma unroll
        for (int nt = 0; nt < 4; nt++) {
            const uint32_t* bh = &Bh[nt >> 1][(nt & 1) * 2];
            const uint32_t* bl = &Bl[nt >> 1][(nt & 1) * 2];
            MMA_BF16(acc[nt], Ah, bh);
            MMA_BF16(acc[nt], Ah, bl);
            MMA_BF16(acc[nt], Al, bh);
        }
    }

    // epilogue: +bias +cond terms, leaky, write fS + g_F, accumulate fsum
    {
        int ocA = mrow + gid, ocB = ocA + 8;
        float bA = __ldg(&rin_b[ocA]), bB = __ldg(&rin_b[ocB]);
        float wA128 = __ldg(&rin_w[ocA * 131 + 128]);
        float wA129 = __ldg(&rin_w[ocA * 131 + 129]);
        float wA130 = __ldg(&rin_w[ocA * 131 + 130]);
        float wB128 = __ldg(&rin_w[ocB * 131 + 128]);
        float wB129 = __ldg(&rin_w[ocB * 131 + 129]);
        float wB130 = __ldg(&rin_w[ocB * 131 + 130]);
        float* Fb = g_F + (size_t)b * 32 * HW;
        float sA = 0.f, sB = 0.f;
#pragma unroll
        for (int nt = 0; nt < 4; nt++) {
            int col = ncol + nt * 8 + tig * 2;
#pragma unroll
            for (int d = 0; d < 2; d++) {
                int px = col + d;
                float cg = cgS[px];
                float ly = -1.f + (float)(px >> 4) * (2.f / 15.f);
                float lx = -1.f + (float)(px & 15) * (2.f / 15.f);
                float vA = leakyf(acc[nt][d] + bA + wA128 * cg + wA129 * ly + wA130 * lx);
                float vB = leakyf(acc[nt][2 + d] + bB + wB128 * cg + wB129 * ly + wB130 * lx);
                fS[ocA * 261 + px] = vA;
                fS[ocB * 261 + px] = vB;
                sA += vA; sB += vB;
                int pix = (py0 + (px >> 4)) * 256 + px0 + (px & 15);
                Fb[(size_t)ocA * HW + pix] = vA;
                Fb[(size_t)ocB * HW + pix] = vB;
            }
        }
        atomicAdd(&fsum_s[ocA], sA);
        atomicAdd(&fsum_s[ocB], sB);
    }
    __syncthreads();

    if (t < 256) {
        int px = t;
        float fv[32];
        float fm = 0.f;
#pragma unroll
        for (int o = 0; o < 32; o++) {
            fv[o] = fS[o * 261 + px];
            fm += fv[o];
        }
        int pix = (py0 + (px >> 4)) * 256 + px0 + (px & 15);
        g_FMC[(size_t)b * HW + pix] = fm * (1.f / 32.f);

        float h[16];
#pragma unroll
        for (int o2 = 0; o2 < 16; o2++) {
            float s = __ldg(&r1b[o2]);
#pragma unroll
            for (int o = 0; o < 32; o++) s = fmaf(wr1[o2 * 32 + o], fv[o], s);
            h[o2] = leakyf(s);
        }
        float ox = __ldg(&r2b[0]), oy = __ldg(&r2b[1]);
#pragma unroll
        for (int o2 = 0; o2 < 16; o2++) {
            ox = fmaf(wr2[o2], h[o2], ox);
            oy = fmaf(wr2[16 + o2], h[o2], oy);
        }
        float* OFb = g_OFF + (size_t)b * 2 * HW;
        OFb[pix] = ox;
        OFb[HW + pix] = oy;
    }
    __syncthreads();
    if (t < 32) atomicAdd(&g_FSUM[b * 32 + t], fsum_s[t]);
}

// ---------------- channel attention ca ----------------
__global__ void ca_kernel(const float* __restrict__ rca_w, const float* __restrict__ rca_b) {
    int c = threadIdx.x;
    int b = blockIdx.x;
    float s = __ldg(&rca_b[c]);
#pragma unroll
    for (int ci = 0; ci < 32; ci++)
        s = fmaf(__ldg(&rca_w[c * 32 + ci]), g_FSUM[b * 32 + ci] * (1.f / 65536.f), s);
    g_CA[b * CH + c] = 1.f / (1.f + expf(-s));
}

// ---------------- spatial attention sa: 2D-tiled ----------------
__global__ void __launch_bounds__(256) sa_kernel(const float* __restrict__ rsa_w,
                                                 const float* __restrict__ rsa_b) {
    __shared__ float ws[288];
    __shared__ float tile[10][36];
    int t = threadIdx.x;
    for (int i = t; i < 288; i += 256) ws[i] = rsa_w[i];
    int b = blockIdx.z;
    int tx0 = blockIdx.x * 32, ty0 = blockIdx.y * 8;
    int lx = t & 31, lyy = t >> 5;
    float acc = __ldg(&rsa_b[0]);
    const float* Fb = g_F + (size_t)b * 32 * HW;
#pragma unroll 1
    for (int ci = 0; ci < 32; ci++) {
        __syncthreads();
        for (int i = t; i < 340; i += 256) {
            int lyl = i / 34, lxl = i % 34;
            int gy = ty0 - 1 + lyl, gx = tx0 - 1 + lxl;
            float v = 0.f;
            if ((unsigned)gy < 256u && (unsigned)gx < 256u)
                v = __ldg(&Fb[(size_t)ci * HW + gy * 256 + gx]);
            tile[lyl][lxl] = v;
        }
        __syncthreads();
        const float* wc = ws + ci * 9;
#pragma unroll
        for (int ky = 0; ky < 3; ky++)
#pragma unroll
            for (int kx = 0; kx < 3; kx++)
                acc = fmaf(wc[ky * 3 + kx], tile[lyy + ky][lx + kx], acc);
    }
    g_SA[(size_t)b * HW + (ty0 + lyy) * 256 + tx0 + lx] = 1.f / (1.f + expf(-acc));
}

// ---------------- window MLP + gumbel hard mask ----------------
__global__ void mask_kernel(const float* __restrict__ gu,
                            const float* __restrict__ rm1_w, const float* __restrict__ rm1_b,
                            const float* __restrict__ rm2_w, const float* __restrict__ rm2_b) {
    __shared__ float m[256];
    __shared__ float h1s[16];
    int n = blockIdx.x, b = blockIdx.y;
    int t = threadIdx.x;
    int dh = t >> 4, dw = t & 15;
    int pix = ((n >> 4) * 16 + dh) * 256 + (n & 15) * 16 + dw;
    m[t] = g_FMC[b * HW + pix];
    __syncthreads();
    if (t < 16) {
        float s = __ldg(&rm1_b[t]);
        for (int e = 0; e < 256; e++) s = fmaf(__ldg(&rm1_w[t * 256 + e]), m[e], s);
        h1s[t] = leakyf(s);
    }
    __syncthreads();
    if (t == 0) {
        float z0 = __ldg(&rm2_b[0]), z1 = __ldg(&rm2_b[1]);
#pragma unroll
        for (int o = 0; o < 16; o++) {
            z0 = fmaf(__ldg(&rm2_w[o]), h1s[o], z0);
            z1 = fmaf(__ldg(&rm2_w[16 + o]), h1s[o], z1);
        }
        float mx = fmaxf(z0, z1);
        float e0 = expf(z0 - mx), e1 = expf(z1 - mx);
        float inv = 1.f / (e0 + e1);
        float p0 = e0 * inv, p1 = e1 * inv;
        float u0 = __ldg(&gu[(b * 256 + n) * 2 + 0]);
        float u1 = __ldg(&gu[(b * 256 + n) * 2 + 1]);
        float g0 = -logf(-logf(u0 + 1e-10f) + 1e-10f);
        float g1 = -logf(-logf(u1 + 1e-10f) + 1e-10f);
        g_MASK[b * 256 + n] = (p0 + g0 >= p1 + g1) ? 1.f : 0.f;
    }
}

// ---------------- window attention, 512 threads (16 warps), ldmatrix fragments ----------------
#define SMEM_ATTN3 ((64*257 + 512 + 64 + 64) * 4 + 90112)
__global__ void __launch_bounds__(512, 1) attn_mma_kernel() {
    int n = blockIdx.x, b = blockIdx.y;
    int t = threadIdx.x;
    int py0 = (n >> 4) * 16, px0 = (n & 15) * 16;
    int cbase = b * CH * HW;
    if (g_MASK[b * 256 + n] == 0.f) {
        const float* sab = g_SA + (size_t)b * HW;
#pragma unroll 4
        for (int i = t; i < 8192; i += 512) {
            int ch = i >> 6, r4 = i & 63;
            int wrow = r4 >> 2, px4 = (r4 & 3) * 4;
            int pix = (py0 + wrow) * 256 + px0 + px4;
            float4 v = *(const float4*)(g_V + cbase + ch * HW + pix);
            float4 s = *(const float4*)(sab + pix);
            v.x *= s.x; v.y *= s.y; v.z *= s.z; v.w *= s.w;
            *(float4*)(g_OUT + cbase + ch * HW + pix) = v;
        }
        return;
    }
    extern __shared__ char smraw[];
    float* S = (float*)smraw;
    float* red = S + 64 * 257;
    float* rmax = red + 512;
    float* rsum = rmax + 64;
    __nv_bfloat16* Qh = (__nv_bfloat16*)(rsum + 64);
    __nv_bfloat16* Ql = Qh + 64 * 136;
    __nv_bfloat16* KVh = Ql + 64 * 136;
    __nv_bfloat16* KVl = KVh + 9216;
    __nv_bfloat16* Pth = KVl + 9216;
    __nv_bfloat16* Ptl = Pth + 64 * 72;

    int w = t >> 5, lane = t & 31;
    int gid = lane >> 2;
    int tig = lane & 3;
    int mm = lane >> 3, r8 = lane & 7;

    // precomputed ldmatrix addresses (buffers are reused across iterations)
    int mrowS = (w & 3) * 16, ncolS = (w >> 2) * 16;
    uint32_t aoffS = (uint32_t)((mrowS + (mm & 1) * 8 + r8) * 272 + (mm >> 1) * 16);
    uint32_t aHiS = smaddr(Qh) + aoffS;
    uint32_t aLoS = smaddr(Ql) + aoffS;
    uint32_t boffS = (uint32_t)((ncolS + (mm >> 1) * 8 + r8) * 272 + (mm & 1) * 16);
    uint32_t bHiS = smaddr(KVh) + boffS;
    uint32_t bLoS = smaddr(KVl) + boffS;

    int mrowO = (w & 3) * 16, ncolO = (w >> 2) * 32;
    uint32_t aoffP = (uint32_t)((mrowO + (mm & 1) * 8 + r8) * 144 + (mm >> 1) * 16);
    uint32_t aHiP = smaddr(Pth) + aoffP;
    uint32_t aLoP = smaddr(Ptl) + aoffP;
    uint32_t boffP = (uint32_t)((ncolO + (mm >> 1) * 8 + r8) * 144 + (mm & 1) * 16);
    uint32_t bHiP = smaddr(KVh) + boffP;
    uint32_t bLoP = smaddr(KVl) + boffP;

#pragma unroll 1
    for (int rc = 0; rc < 4; rc++) {
        int r0 = rc * 64;
        __syncthreads();
#pragma unroll
        for (int j = 0; j < 8; j++) {
            int i = t + j * 512;
            int px = i & 63, cp = i >> 6;
            int p = r0 + px;
            int pix = (py0 + (p >> 4)) * 256 + px0 + (p & 15);
            float v0 = g_Qb[cbase + (2 * cp) * HW + pix];
            float v1 = g_Qb[cbase + (2 * cp + 1) * HW + pix];
            __nv_bfloat16 h0 = __float2bfloat16_rn(v0);
            __nv_bfloat16 h1 = __float2bfloat16_rn(v1);
            __nv_bfloat16 l0 = __float2bfloat16_rn(v0 - __bfloat162float(h0));
            __nv_bfloat16 l1 = __float2bfloat16_rn(v1 - __bfloat162float(h1));
            ((__nv_bfloat162*)(Qh + px * 136))[cp] = __nv_bfloat162(h0, h1);
            ((__nv_bfloat162*)(Ql + px * 136))[cp] = __nv_bfloat162(l0, l1);
        }

#pragma unroll 1
        for (int kvt = 0; kvt < 4; kvt++) {
            __syncthreads();
#pragma unroll
            for (int j = 0; j < 8; j++) {
                int i = t + j * 512;
                int px = i & 63, cp = i >> 6;
                int p = kvt * 64 + px;
                int pix = (py0 + (p >> 4)) * 256 + px0 + (p & 15);
                float v0 = g_Kb[cbase + (2 * cp) * HW + pix];
                float v1 = g_Kb[cbase + (2 * cp + 1) * HW + pix];
                __nv_bfloat16 h0 = __float2bfloat16_rn(v0);
                __nv_bfloat16 h1 = __float2bfloat16_rn(v1);
                __nv_bfloat16 l0 = __float2bfloat16_rn(v0 - __bfloat162float(h0));
                __nv_bfloat16 l1 = __float2bfloat16_rn(v1 - __bfloat162float(h1));
                ((__nv_bfloat162*)(KVh + px * 136))[cp] = __nv_bfloat162(h0, h1);
                ((__nv_bfloat162*)(KVl + px * 136))[cp] = __nv_bfloat162(l0, l1);
            }
            __syncthreads();
            float acc[2][4];
#pragma unroll
            for (int i = 0; i < 2; i++)
#pragma unroll
                for (int j2 = 0; j2 < 4; j2++) acc[i][j2] = 0.f;
#pragma unroll
            for (int ks = 0; ks < 8; ks++) {
                uint32_t ko = ks * 32;
                uint32_t Ahf[4], Alf[4], Bhf[4], Blf[4];
                LDSM_X4(Ahf, aHiS + ko);
                LDSM_X4(Alf, aLoS + ko);
                LDSM_X4(Bhf, bHiS + ko);
                LDSM_X4(Blf, bLoS + ko);
#pragma unroll
                for (int nt = 0; nt < 2; nt++) {
                    const uint32_t* bh = &Bhf[nt * 2];
                    const uint32_t* bl = &Blf[nt * 2];
                    MMA_BF16(acc[nt], Ahf, bh);
                    MMA_BF16(acc[nt], Ahf, bl);
                    MMA_BF16(acc[nt], Alf, bh);
                }
            }
#pragma unroll
            for (int nt = 0; nt < 2; nt++) {
                int col = kvt * 64 + ncolS + nt * 8 + tig * 2;
                S[(mrowS + gid) * 257 + col] = acc[nt][0];
                S[(mrowS + gid) * 257 + col + 1] = acc[nt][1];
                S[(mrowS + gid + 8) * 257 + col] = acc[nt][2];
                S[(mrowS + gid + 8) * 257 + col + 1] = acc[nt][3];
            }
        }
        __syncthreads();

        {
            int r = t & 63, seg = t >> 6;
            float* srow = &S[r * 257 + seg * 32];
            float mx = -1e30f;
#pragma unroll 8
            for (int k = 0; k < 32; k++) mx = fmaxf(mx, srow[k]);
            red[seg * 64 + r] = mx;
            __syncthreads();
            if (t < 64) {
                float m0 = fmaxf(fmaxf(red[t], red[64 + t]), fmaxf(red[128 + t], red[192 + t]));
                float m1 = fmaxf(fmaxf(red[256 + t], red[320 + t]), fmaxf(red[384 + t], red[448 + t]));
                rmax[t] = fmaxf(m0, m1);
            }
            __syncthreads();
            float rm_ = rmax[r];
            float s = 0.f;
#pragma unroll 8
            for (int k = 0; k < 32; k++) {
                float e = __expf(srow[k] - rm_);
                srow[k] = e;
                s += e;
            }
            red[seg * 64 + r] = s;
            __syncthreads();
            if (t < 64)
                rsum[t] = (red[t] + red[64 + t] + red[128 + t] + red[192 + t]) +
                          (red[256 + t] + red[320 + t] + red[384 + t] + red[448 + t]);
            __syncthreads();
        }

        float oacc[4][4];
#pragma unroll
        for (int i = 0; i < 4; i++)
#pragma unroll
            for (int j2 = 0; j2 < 4; j2++) oacc[i][j2] = 0.f;

#pragma unroll 1
        for (int kvt = 0; kvt < 4; kvt++) {
            __syncthreads();
#pragma unroll
            for (int j = 0; j < 8; j++) {
                int i = t + j * 512;
                int col = i & 63, row = i >> 6;
                float v = S[row * 257 + kvt * 64 + col];
                __nv_bfloat16 h = __float2bfloat16_rn(v);
                Pth[row * 72 + col] = h;
                Ptl[row * 72 + col] = __float2bfloat16_rn(v - __bfloat162float(h));
            }
#pragma unroll
            for (int j = 0; j < 16; j++) {
                int i = t + j * 512;
                int px = i & 63, ch = i >> 6;
                int p = kvt * 64 + px;
                int pix = (py0 + (p >> 4)) * 256 + px0 + (p & 15);
                float v = g_V[cbase + ch * HW + pix];
                __nv_bfloat16 h = __float2bfloat16_rn(v);
                KVh[ch * 72 + px] = h;
                KVl[ch * 72 + px] = __float2bfloat16_rn(v - __bfloat162float(h));
            }
            __syncthreads();
#pragma unroll
            for (int ks = 0; ks < 4; ks++) {
                uint32_t ko = ks * 32;
                uint32_t Ahf[4], Alf[4], Bhf[2][4], Blf[2][4];
                LDSM_X4(Ahf, aHiP + ko);
                LDSM_X4(Alf, aLoP + ko);
                LDSM_X4(Bhf[0], bHiP + ko);
                LDSM_X4(Blf[0], bLoP + ko);
                LDSM_X4(Bhf[1], bHiP + 16 * 144 + ko);
                LDSM_X4(Blf[1], bLoP + 16 * 144 + ko);
#pragma unroll
                for (int nt = 0; nt < 4; nt++) {
                    const uint32_t* bh = &Bhf[nt >> 1][(nt & 1) * 2];
                    const uint32_t* bl = &Blf[nt >> 1][(nt & 1) * 2];
                    MMA_BF16(oacc[nt], Ahf, bh);
                    MMA_BF16(oacc[nt], Ahf, bl);
                    MMA_BF16(oacc[nt], Alf, bh);
                }
            }
        }

        {
            int rowA = mrowO + gid, rowB = rowA + 8;
            float invA = 1.f / rsum[rowA];
            float invB = 1.f / rsum[rowB];
            int pA = r0 + rowA, pB = r0 + rowB;
            int pixA = (py0 + (pA >> 4)) * 256 + px0 + (pA & 15);
            int pixB = (py0 + (pB >> 4)) * 256 + px0 + (pB & 15);
#pragma unroll
            for (int nt = 0; nt < 4; nt++) {
                int ch = ncolO + nt * 8 + tig * 2;
                g_OUT[cbase + ch * HW + pixA] = oacc[nt][0] * invA;
                g_OUT[cbase + (ch + 1) * HW + pixA] = oacc[nt][1] * invA;
                g_OUT[cbase + ch * HW + pixB] = oacc[nt][2] * invB;
                g_OUT[cbase + (ch + 1) * HW + pixB] = oacc[nt][3] * invB;
            }
        }
    }
}

// ---------------- fused depthwise 5x5(d1) -> 5x5(d3) + gelu*ca + residual ----------------
__global__ void __launch_bounds__(256) dw5x2_kernel(
    const float* __restrict__ in, const float* __restrict__ w2, const float* __restrict__ b2,
    const float* __restrict__ w3, const float* __restrict__ b3, float* __restrict__ out) {
    __shared__ float sIn[48][81];
    __shared__ float sMid[44][77];
    __shared__ float wA[25], wB[25];
    int c = blockIdx.z & 127, b = blockIdx.z >> 7;
    int t = threadIdx.x;
    if (t < 25) wA[t] = w2[c * 25 + t];
    else if (t < 50) wB[t - 25] = w3[c * 25 + (t - 25)];
    int ox0 = blockIdx.x * 64, oy0 = blockIdx.y * 32;
    const float* ip = in + (size_t)(b * CH + c) * HW;

    for (int i = t; i < 48 * 80; i += 256) {
        int lx = i % 80, ly = i / 80;
        int gx = ox0 - 8 + lx, gy = oy0 - 8 + ly;
        float v = 0.f;
        if ((unsigned)gx < 256u && (unsigned)gy < 256u) v = __ldg(&ip[gy * 256 + gx]);
        sIn[ly][lx] = v;
    }
    __syncthreads();

    float b2v = __ldg(&b2[c]);
    for (int i = t; i < 44 * 76; i += 256) {
        int mx = i % 76, my = i / 76;
        int gx = ox0 - 6 + mx, gy = oy0 - 6 + my;
        float acc = 0.f;
        if ((unsigned)gx < 256u && (unsigned)gy < 256u) {
            acc = b2v;
#pragma unroll
            for (int ky = 0; ky < 5; ky++)
#pragma unroll
                for (int kx = 0; kx < 5; kx++)
                    acc = fmaf(wA[ky * 5 + kx], sIn[my + ky][mx + kx], acc);
        }
        sMid[my][mx] = acc;
    }
    __syncthreads();

    float b3v = __ldg(&b3[c]);
    float cav = g_CA[b * CH + c];
    size_t obase = (size_t)(b * CH + c) * HW;
    for (int i = t; i < 32 * 64; i += 256) {
        int x = i % 64, y = i / 64;
        float acc = b3v;
#pragma unroll
        for (int ky = 0; ky < 5; ky++)
#pragma unroll
            for (int kx = 0; kx < 5; kx++)
                acc = fmaf(wB[ky * 5 + kx], sMid[y + 3 * ky][x + 3 * kx], acc);
        float g = 0.5f * acc * (1.f + erff(acc * 0.7071067811865475f));
        size_t oidx = obase + (size_t)(oy0 + y) * 256 + ox0 + x;
        out[oidx] = g * cav + g_OUT[oidx];
    }
}

// ---------------- launch ----------------
extern "C" void kernel_launch(void* const* d_in, const int* in_sizes, int n_in,
                              void* d_out, int out_size) {
    const float* x      = (const float*)d_in[0];
    const float* cond_g = (const float*)d_in[1];
    const float* gu     = (const float*)d_in[2];
    const float* pv_w   = (const float*)d_in[3];
    const float* pv_b   = (const float*)d_in[4];
    const float* pq_w   = (const float*)d_in[5];
    const float* pq_b   = (const float*)d_in[6];
    const float* pk_w   = (const float*)d_in[7];
    const float* pk_b   = (const float*)d_in[8];
    const float* cs1_w  = (const float*)d_in[9];
    const float* cs1_b  = (const float*)d_in[10];
    const float* cs2_w  = (const float*)d_in[11];
    const float* cs2_b  = (const float*)d_in[12];
    const float* cs3_w  = (const float*)d_in[13];
    const float* cs3_b  = (const float*)d_in[14];
    const float* po_w   = (const float*)d_in[15];
    const float* po_b   = (const float*)d_in[16];
    const float* rin_w  = (const float*)d_in[17];
    const float* rin_b  = (const float*)d_in[18];
    const float* r1w    = (const float*)d_in[19];
    const float* r1b    = (const float*)d_in[20];
    const float* r2w    = (const float*)d_in[21];
    const float* r2b    = (const float*)d_in[22];
    const float* rm1_w  = (const float*)d_in[23];
    const float* rm1_b  = (const float*)d_in[24];
    const float* rm2_w  = (const float*)d_in[25];
    const float* rm2_b  = (const float*)d_in[26];
    const float* rca_w  = (const float*)d_in[27];
    const float* rca_b  = (const float*)d_in[28];
    const float* rsa_w  = (const float*)d_in[29];
    const float* rsa_b  = (const float*)d_in[30];

    float *pV, *pOUT, *pT1, *pT2;
    __nv_bfloat16* pWT;
    cudaGetSymbolAddress((void**)&pV, g_V);
    cudaGetSymbolAddress((void**)&pOUT, g_OUT);
    cudaGetSymbolAddress((void**)&pT1, g_T1);
    cudaGetSymbolAddress((void**)&pT2, g_T2);
    cudaGetSymbolAddress((void**)&pWT, g_WT);

    cudaFuncSetAttribute(attn_mma_kernel, cudaFuncAttributeMaxDynamicSharedMemorySize, SMEM_ATTN3);
    cudaFuncSetAttribute(conv1x1_mma, cudaFuncAttributeMaxDynamicSharedMemorySize, CV_SMEM_FULL);
    cudaFuncSetAttribute(convqk_mma, cudaFuncAttributeMaxDynamicSharedMemorySize, CV_SMEM_FULL);
    cudaFuncSetAttribute(predictor_mma, cudaFuncAttributeMaxDynamicSharedMemorySize, PRED2_SMEM);

    const int WSET = 2 * 128 * 136;

    prep_all_kernel<<<dim3(64, 5), 256>>>(pv_w, pq_w, pk_w, cs1_w, po_w);
    prep_rin_kernel<<<16, 256>>>(rin_w);
    zero_fsum_kernel<<<1, 128>>>();
    conv1x1_mma<<<dim3(256, BB), 512, CV_SMEM_FULL>>>(x, pWT + 0 * WSET, pv_b, pV, 0);
    predictor_mma<<<dim3(256, BB), 512, PRED2_SMEM>>>(cond_g, rin_w, rin_b, r1w, r1b, r2w, r2b);
    ca_kernel<<<BB, 128>>>(rca_w, rca_b);
    sa_kernel<<<dim3(8, 32, BB), 256>>>(rsa_w, rsa_b);
    mask_kernel<<<dim3(256, BB), 256>>>(gu, rm1_w, rm1_b, rm2_w, rm2_b);
    convqk_mma<<<dim3(256, BB), 512, CV_SMEM_FULL>>>(x, pWT + 1 * WSET, pWT + 2 * WSET, pq_b, pk_b);
    attn_mma_kernel<<<dim3(256, BB), 512, SMEM_ATTN3>>>();
    conv1x1_mma<<<dim3(256, BB), 512, CV_SMEM_FULL>>>(pOUT, pWT + 3 * WSET, cs1_b, pT1, 0);
    dw5x2_kernel<<<dim3(4, 8, BB * CH), 256>>>(pT1, cs2_w, cs2_b, cs3_w, cs3_b, pT2);
    conv1x1_mma<<<dim3(256, BB), 512, CV_SMEM_FULL>>>(pT2, pWT + 4 * WSET, po_b, (float*)d_out, 0);
}

// round 16
// speedup vs baseline: 2.4749x; 1.0226x over previous
#include <cuda_runtime.h>
#include <cuda_bf16.h>
#include <stdint.h>
#include <math.h>

#define HW 65536
#define WIMG 256
#define CH 128
#define BB 4
#define ELT (BB*CH*HW)

// ---------------- scratch ----------------
__device__ float g_V[ELT];
__device__ float g_Qb[ELT];
__device__ float g_Kb[ELT];
__device__ float g_OUT[ELT];
__device__ float g_T1[ELT];
__device__ float g_T2[ELT];
__device__ float g_F[BB*32*HW];
__device__ float g_OFF[BB*2*HW];
__device__ float g_FMC[BB*HW];
__device__ float g_SA[BB*HW];
__device__ float g_FSUM[BB*32];
__device__ float g_CA[BB*CH];
__device__ float g_MASK[BB*256];
__device__ __align__(16) __nv_bfloat16 g_WT[5][2][128*136];
__device__ __align__(16) __nv_bfloat16 g_WRIN[2][32*136];

__device__ __forceinline__ float leakyf(float x) { return x > 0.f ? x : 0.2f * x; }

__global__ void zero_fsum_kernel() {
    g_FSUM[threadIdx.x] = 0.f;
}

// ---------------- weight prep ----------------
__global__ void prep_all_kernel(const float* __restrict__ w0, const float* __restrict__ w1,
                                const float* __restrict__ w2, const float* __restrict__ w3,
                                const float* __restrict__ w4) {
    int set = blockIdx.y;
    const float* w = (set == 0) ? w0 : (set == 1) ? w1 : (set == 2) ? w2 : (set == 3) ? w3 : w4;
    int i = blockIdx.x * 256 + threadIdx.x;
    int oc = i >> 7, ci = i & 127;
    float v = w[i];
    __nv_bfloat16 h = __float2bfloat16_rn(v);
    __nv_bfloat16 l = __float2bfloat16_rn(v - __bfloat162float(h));
    g_WT[set][0][oc * 136 + ci] = h;
    g_WT[set][1][oc * 136 + ci] = l;
}

__global__ void prep_rin_kernel(const float* __restrict__ w) {
    int i = blockIdx.x * 256 + threadIdx.x;   // 4096
    int oc = i >> 7, ci = i & 127;
    float v = w[oc * 131 + ci];
    __nv_bfloat16 h = __float2bfloat16_rn(v);
    __nv_bfloat16 l = __float2bfloat16_rn(v - __bfloat162float(h));
    g_WRIN[0][oc * 136 + ci] = h;
    g_WRIN[1][oc * 136 + ci] = l;
}

// ---------------- HMMA m16n8k16 bf16 + ldmatrix ----------------
#define MMA_BF16(d, a, b) \
    asm volatile("mma.sync.aligned.m16n8k16.row.col.f32.bf16.bf16.f32 " \
        "{%0,%1,%2,%3}, {%4,%5,%6,%7}, {%8,%9}, {%0,%1,%2,%3};" \
        : "+f"((d)[0]), "+f"((d)[1]), "+f"((d)[2]), "+f"((d)[3]) \
        : "r"((a)[0]), "r"((a)[1]), "r"((a)[2]), "r"((a)[3]), "r"((b)[0]), "r"((b)[1]))

#define LDSM_X4(r, a) \
    asm volatile("ldmatrix.sync.aligned.m8n8.x4.shared.b16 {%0,%1,%2,%3}, [%4];" \
        : "=r"((r)[0]), "=r"((r)[1]), "=r"((r)[2]), "=r"((r)[3]) : "r"(a))

__device__ __forceinline__ uint32_t smaddr(const void* p) {
    return (uint32_t)__cvta_generic_to_shared(p);
}

// ---- GEMM body (half-window, 8-warp slice): used by convqk ----
__device__ __forceinline__ void gemm_body_128(
    const __nv_bfloat16* Wh, const __nv_bfloat16* Wl,
    const __nv_bfloat16* Xh, const __nv_bfloat16* Xl,
    const float* __restrict__ bias, float* __restrict__ yb,
    int py0, int px0, int half, int w, int lane) {
    int oc0 = (w & 3) * 32;
    int n0 = (w >> 2) * 64;
    int gid = lane >> 2, tig = lane & 3;
    int mm = lane >> 3, r8 = lane & 7;
    uint32_t aoff = (uint32_t)((oc0 + (mm & 1) * 8 + r8) * 272 + (mm >> 1) * 16);
    uint32_t aHi = smaddr(Wh) + aoff;
    uint32_t aLo = smaddr(Wl) + aoff;
    uint32_t boff = (uint32_t)((n0 + (mm >> 1) * 8 + r8) * 272 + (mm & 1) * 16);
    uint32_t bHi = smaddr(Xh) + boff;
    uint32_t bLo = smaddr(Xl) + boff;

    float acc[16][4];
#pragma unroll
    for (int i = 0; i < 16; i++)
#pragma unroll
        for (int j = 0; j < 4; j++) acc[i][j] = 0.f;

#pragma unroll 1
    for (int ks = 0; ks < 8; ks++) {
        uint32_t ko = ks * 32;
        uint32_t Ah[2][4], Al[2][4], Bh[4][4], Bl[4][4];
        LDSM_X4(Ah[0], aHi + ko);
        LDSM_X4(Ah[1], aHi + 16 * 272 + ko);
        LDSM_X4(Al[0], aLo + ko);
        LDSM_X4(Al[1], aLo + 16 * 272 + ko);
#pragma unroll
        for (int p = 0; p < 4; p++) {
            LDSM_X4(Bh[p], bHi + p * (16 * 272) + ko);
            LDSM_X4(Bl[p], bLo + p * (16 * 272) + ko);
        }
#pragma unroll
        for (int mt = 0; mt < 2; mt++)
#pragma unroll
            for (int nt = 0; nt < 8; nt++) {
                const uint32_t* bh = &Bh[nt >> 1][(nt & 1) * 2];
                const uint32_t* bl = &Bl[nt >> 1][(nt & 1) * 2];
                MMA_BF16(acc[mt * 8 + nt], Ah[mt], bh);
                MMA_BF16(acc[mt * 8 + nt], Ah[mt], bl);
                MMA_BF16(acc[mt * 8 + nt], Al[mt], bh);
            }
    }
#pragma unroll
    for (int mt = 0; mt < 2; mt++) {
        int ocA = oc0 + mt * 16 + gid;
        int ocB = ocA + 8;
        float bvA = __ldg(&bias[ocA]);
        float bvB = __ldg(&bias[ocB]);
#pragma unroll
        for (int nt = 0; nt < 8; nt++) {
            int col = n0 + nt * 8 + tig * 2;
            int p = half * 128 + col;
            int pix = (py0 + (p >> 4)) * 256 + px0 + (p & 15);
            float2 v0 = make_float2(acc[mt * 8 + nt][0] + bvA, acc[mt * 8 + nt][1] + bvA);
            float2 v1 = make_float2(acc[mt * 8 + nt][2] + bvB, acc[mt * 8 + nt][3] + bvB);
            *(float2*)(yb + (size_t)ocA * HW + pix) = v0;
            *(float2*)(yb + (size_t)ocB * HW + pix) = v1;
        }
    }
}

// ---------------- conv1x1 GEMM, QUARTER window per block (512 thr, 2 blocks/SM) ----------------
// smem: Wh|Wl (128*136 each) + Xh|Xl (64*136 each) = 104448 B
#define CV_SMEM_Q ((2 * 128 * 136 + 2 * 64 * 136) * 2)
__global__ void __launch_bounds__(512, 2)
conv1x1_mma(const float* __restrict__ xin, const __nv_bfloat16* __restrict__ wsp,
            const float* __restrict__ bias, float* __restrict__ yout, int bOff) {
    int bx = blockIdx.x;
    int n = bx >> 2, q = bx & 3;
    int b = blockIdx.y + bOff;
    extern __shared__ __nv_bfloat16 smb[];
    __nv_bfloat16* Wh = smb;
    __nv_bfloat16* Wl = Wh + 128 * 136;
    __nv_bfloat16* Xh = Wl + 128 * 136;
    __nv_bfloat16* Xl = Xh + 64 * 136;
    int t = threadIdx.x;

    // ---- copy W hi+lo (69632 B = 4352 uint4) ----
    {
        const uint4* src = (const uint4*)wsp;
        uint4* dst = (uint4*)smb;
#pragma unroll
        for (int i = 0; i < 9; i++) {
            int idx = t + i * 512;
            if (idx < 4352) dst[idx] = src[idx];
        }
    }

    // ---- stage X quarter (64 px) hi/lo ----
    int py0 = (n >> 4) * 16, px0 = (n & 15) * 16;
    const float* xb = xin + (size_t)b * CH * HW;
    {
        int px = t & 63;
        int p = q * 64 + px;
        int pix = (py0 + (p >> 4)) * 256 + px0 + (p & 15);
        int cp0 = t >> 6;   // 0..7
#pragma unroll
        for (int j = 0; j < 8; j++) {
            int cp = cp0 + j * 8;
            float v0 = xb[(size_t)(2 * cp) * HW + pix];
            float v1 = xb[(size_t)(2 * cp + 1) * HW + pix];
            __nv_bfloat16 h0 = __float2bfloat16_rn(v0);
            __nv_bfloat16 h1 = __float2bfloat16_rn(v1);
            __nv_bfloat16 l0 = __float2bfloat16_rn(v0 - __bfloat162float(h0));
            __nv_bfloat16 l1 = __float2bfloat16_rn(v1 - __bfloat162float(h1));
            ((__nv_bfloat162*)(Xh + px * 136))[cp] = __nv_bfloat162(h0, h1);
            ((__nv_bfloat162*)(Xl + px * 136))[cp] = __nv_bfloat162(l0, l1);
        }
    }
    __syncthreads();

    // ---- GEMM: 16 warps = 4(oc32) x 4(px16) ----
    int w = t >> 5, lane = t & 31;
    int oc0 = (w & 3) * 32;
    int npx = (w >> 2) * 16;
    int gid = lane >> 2, tig = lane & 3;
    int mm = lane >> 3, r8 = lane & 7;
    uint32_t aoff = (uint32_t)((oc0 + (mm & 1) * 8 + r8) * 272 + (mm >> 1) * 16);
    uint32_t aHi = smaddr(Wh) + aoff;
    uint32_t aLo = smaddr(Wl) + aoff;
    uint32_t boff = (uint32_t)((npx + (mm >> 1) * 8 + r8) * 272 + (mm & 1) * 16);
    uint32_t bHi = smaddr(Xh) + boff;
    uint32_t bLo = smaddr(Xl) + boff;

    float acc[4][4];
#pragma unroll
    for (int i = 0; i < 4; i++)
#pragma unroll
        for (int j = 0; j < 4; j++) acc[i][j] = 0.f;

#pragma unroll 1
    for (int ks = 0; ks < 8; ks++) {
        uint32_t ko = ks * 32;
        uint32_t Ah[2][4], Al[2][4], Bh[4], Bl[4];
        LDSM_X4(Ah[0], aHi + ko);
        LDSM_X4(Ah[1], aHi + 16 * 272 + ko);
        LDSM_X4(Al[0], aLo + ko);
        LDSM_X4(Al[1], aLo + 16 * 272 + ko);
        LDSM_X4(Bh, bHi + ko);
        LDSM_X4(Bl, bLo + ko);
#pragma unroll
        for (int mt = 0; mt < 2; mt++)
#pragma unroll
            for (int nt = 0; nt < 2; nt++) {
                const uint32_t* bh = &Bh[nt * 2];
                const uint32_t* bl = &Bl[nt * 2];
                MMA_BF16(acc[mt * 2 + nt], Ah[mt], bh);
                MMA_BF16(acc[mt * 2 + nt], Ah[mt], bl);
                MMA_BF16(acc[mt * 2 + nt], Al[mt], bh);
            }
    }

    // ---- epilogue ----
    float* yb = yout + (size_t)b * CH * HW;
#pragma unroll
    for (int mt = 0; mt < 2; mt++) {
        int ocA = oc0 + mt * 16 + gid;
        int ocB = ocA + 8;
        float bvA = __ldg(&bias[ocA]);
        float bvB = __ldg(&bias[ocB]);
#pragma unroll
        for (int nt = 0; nt < 2; nt++) {
            int col = npx + nt * 8 + tig * 2;
            int p = q * 64 + col;
            int pix = (py0 + (p >> 4)) * 256 + px0 + (p & 15);
            float2 v0 = make_float2(acc[mt * 2 + nt][0] + bvA, acc[mt * 2 + nt][1] + bvA);
            float2 v1 = make_float2(acc[mt * 2 + nt][2] + bvB, acc[mt * 2 + nt][3] + bvB);
            *(float2*)(yb + (size_t)ocA * HW + pix) = v0;
            *(float2*)(yb + (size_t)ocB * HW + pix) = v1;
        }
    }
}

// ---------------- fused flow-warp + q/k projections, FULL window (512 thr) ----------------
#define CV_SMEM_FULL ((2 * 128 * 136 + 2 * 256 * 136) * 2)
__global__ void __launch_bounds__(512, 1)
convqk_mma(const float* __restrict__ xin,
           const __nv_bfloat16* __restrict__ wq, const __nv_bfloat16* __restrict__ wk,
           const float* __restrict__ qbias, const float* __restrict__ kbias) {
    int n = blockIdx.x, b = blockIdx.y;
    if (g_MASK[b * 256 + n] == 0.f) return;
    extern __shared__ __nv_bfloat16 smb[];
    __nv_bfloat16* Wh = smb;
    __nv_bfloat16* Wl = Wh + 128 * 136;
    __nv_bfloat16* Xh = Wl + 128 * 136;
    __nv_bfloat16* Xl = Xh + 256 * 136;
    int t = threadIdx.x;

    {
        const uint4* src = (const uint4*)wq;
        uint4* dst = (uint4*)smb;
#pragma unroll
        for (int i = 0; i < 9; i++) {
            int idx = t + i * 512;
            if (idx < 4352) dst[idx] = src[idx];
        }
    }

    int py0 = (n >> 4) * 16, px0 = (n & 15) * 16;
    {
        int px = t & 255;
        int gy = py0 + (px >> 4), gx = px0 + (px & 15);
        int pp = gy * 256 + gx;
        const float* OFb = g_OFF + (size_t)b * 2 * HW;
        float fx = OFb[pp];
        float fy = OFb[HW + pp];
        float sx = fminf(fmaxf((float)gx + fx, 0.f), 255.f);
        float sy = fminf(fmaxf((float)gy + fy, 0.f), 255.f);
        float x0f = floorf(sx), y0f = floorf(sy);
        float x1f = fminf(x0f + 1.f, 255.f), y1f = fminf(y0f + 1.f, 255.f);
        float wx = sx - x0f, wy = sy - y0f;
        int x0 = (int)x0f, x1 = (int)x1f, y0 = (int)y0f, y1 = (int)y1f;
        int iA = y0 * 256 + x0, iB = y0 * 256 + x1, iC = y1 * 256 + x0, iD = y1 * 256 + x1;
        float w00 = (1.f - wx) * (1.f - wy), w01 = wx * (1.f - wy);
        float w10 = (1.f - wx) * wy, w11 = wx * wy;
        const float* xb = xin + (size_t)b * CH * HW;
        int cp0 = t >> 8;
#pragma unroll 4
        for (int j = 0; j < 32; j++) {
            int cp = cp0 + j * 2;
            const float* xc0 = xb + (size_t)(2 * cp) * HW;
            const float* xc1 = xc0 + HW;
            float v0 = __ldg(&xc0[iA]) * w00 + __ldg(&xc0[iB]) * w01 +
                       __ldg(&xc0[iC]) * w10 + __ldg(&xc0[iD]) * w11;
            float v1 = __ldg(&xc1[iA]) * w00 + __ldg(&xc1[iB]) * w01 +
                       __ldg(&xc1[iC]) * w10 + __ldg(&xc1[iD]) * w11;
            __nv_bfloat16 h0 = __float2bfloat16_rn(v0);
            __nv_bfloat16 h1 = __float2bfloat16_rn(v1);
            __nv_bfloat16 l0 = __float2bfloat16_rn(v0 - __bfloat162float(h0));
            __nv_bfloat16 l1 = __float2bfloat16_rn(v1 - __bfloat162float(h1));
            ((__nv_bfloat162*)(Xh + px * 136))[cp] = __nv_bfloat162(h0, h1);
            ((__nv_bfloat162*)(Xl + px * 136))[cp] = __nv_bfloat162(l0, l1);
        }
    }
    __syncthreads();

    int wfull = t >> 5, lane = t & 31;
    int half = wfull >> 3;
    int w = wfull & 7;
    const __nv_bfloat16* XhH = Xh + half * 128 * 136;
    const __nv_bfloat16* XlH = Xl + half * 128 * 136;

    gemm_body_128(Wh, Wl, XhH, XlH, qbias, g_Qb + (size_t)b * CH * HW, py0, px0, half, w, lane);
    __syncthreads();
    {
        const uint4* src = (const uint4*)wk;
        uint4* dst = (uint4*)smb;
#pragma unroll
        for (int i = 0; i < 9; i++) {
            int idx = t + i * 512;
            if (idx < 4352) dst[idx] = src[idx];
        }
    }
    __syncthreads();
    gemm_body_128(Wh, Wl, XhH, XlH, kbias, g_Kb + (size_t)b * CH * HW, py0, px0, half, w, lane);
}

// ---------------- predictor: tensor-core phase-1, per-pixel phase-2 ----------------
#define PRED2_SMEM (69632*2 + 8704*2 + 33408 + 2048 + 128 + 1024 + 128)
__global__ void __launch_bounds__(512, 1)
predictor_mma(const float* __restrict__ cond_g,
              const float* __restrict__ rin_w, const float* __restrict__ rin_b,
              const float* __restrict__ r1w, const float* __restrict__ r1b,
              const float* __restrict__ r2w, const float* __restrict__ r2b) {
    int n = blockIdx.x, b = blockIdx.y;
    extern __shared__ char smraw[];
    __nv_bfloat16* Xh = (__nv_bfloat16*)smraw;
    __nv_bfloat16* Xl = Xh + 256 * 136;
    __nv_bfloat16* Wh = Xl + 256 * 136;
    __nv_bfloat16* Wl = Wh + 32 * 136;
    float* fS = (float*)(Wl + 32 * 136);   // 32*261
    float* wr1 = fS + 32 * 261;            // 16*32
    float* wr2 = wr1 + 16 * 32;            // 32
    float* cgS = wr2 + 32;                 // 256
    float* fsum_s = cgS + 256;             // 32
    int t = threadIdx.x;

    {
        const uint4* src = (const uint4*)g_WRIN;
        uint4* dst = (uint4*)Wh;
#pragma unroll
        for (int i = 0; i < 3; i++) {
            int idx = t + i * 512;
            if (idx < 1088) dst[idx] = src[idx];
        }
    }
    for (int i = t; i < 16 * 32; i += 512) wr1[i] = r1w[i];
    if (t < 32) { wr2[t] = r2w[t]; fsum_s[t] = 0.f; }

    int py0 = (n >> 4) * 16, px0 = (n & 15) * 16;
    if (t < 256) {
        int pix = (py0 + (t >> 4)) * 256 + px0 + (t & 15);
        cgS[t] = __ldg(&cond_g[(size_t)b * HW + pix]);
    }
    const float* xb = g_V + (size_t)b * CH * HW;
    {
        int px = t & 255;
        int pix = (py0 + (px >> 4)) * 256 + px0 + (px & 15);
        int cp0 = t >> 8;
#pragma unroll
        for (int j = 0; j < 32; j++) {
            int cp = cp0 + j * 2;
            float v0 = xb[(size_t)(2 * cp) * HW + pix];
            float v1 = xb[(size_t)(2 * cp + 1) * HW + pix];
            __nv_bfloat16 h0 = __float2bfloat16_rn(v0);
            __nv_bfloat16 h1 = __float2bfloat16_rn(v1);
            __nv_bfloat16 l0 = __float2bfloat16_rn(v0 - __bfloat162float(h0));
            __nv_bfloat16 l1 = __float2bfloat16_rn(v1 - __bfloat162float(h1));
            ((__nv_bfloat162*)(Xh + px * 136))[cp] = __nv_bfloat162(h0, h1);
            ((__nv_bfloat162*)(Xl + px * 136))[cp] = __nv_bfloat162(l0, l1);
        }
    }
    __syncthreads();

    // GEMM: 16 warps = 2(m16) x 8(n32)
    int w = t >> 5, lane = t & 31;
    int gid = lane >> 2, tig = lane & 3;
    int mm = lane >> 3, r8 = lane & 7;
    int mrow = (w & 1) * 16;
    int ncol = (w >> 1) * 32;
    uint32_t aoff = (uint32_t)((mrow + (mm & 1) * 8 + r8) * 272 + (mm >> 1) * 16);
    uint32_t aHi = smaddr(Wh) + aoff;
    uint32_t aLo = smaddr(Wl) + aoff;
    uint32_t boff = (uint32_t)((ncol + (mm >> 1) * 8 + r8) * 272 + (mm & 1) * 16);
    uint32_t bHi = smaddr(Xh) + boff;
    uint32_t bLo = smaddr(Xl) + boff;

    float acc[4][4];
#pragma unroll
    for (int i = 0; i < 4; i++)
#pragma unroll
        for (int j = 0; j < 4; j++) acc[i][j] = 0.f;
#pragma unroll 1
    for (int ks = 0; ks < 8; ks++) {
        uint32_t ko = ks * 32;
        uint32_t Ah[4], Al[4], Bh[2][4], Bl[2][4];
        LDSM_X4(Ah, aHi + ko);
        LDSM_X4(Al, aLo + ko);
        LDSM_X4(Bh[0], bHi + ko);
        LDSM_X4(Bl[0], bLo + ko);
        LDSM_X4(Bh[1], bHi + 16 * 272 + ko);
        LDSM_X4(Bl[1], bLo + 16 * 272 + ko);
#pragma unroll
        for (int nt = 0; nt < 4; nt++) {
            const uint32_t* bh = &Bh[nt >> 1][(nt & 1) * 2];
            const uint32_t* bl = &Bl[nt >> 1][(nt & 1) * 2];
            MMA_BF16(acc[nt], Ah, bh);
            MMA_BF16(acc[nt], Ah, bl);
            MMA_BF16(acc[nt], Al, bh);
        }
    }

    {
        int ocA = mrow + gid, ocB = ocA + 8;
        float bA = __ldg(&rin_b[ocA]), bB = __ldg(&rin_b[ocB]);
        float wA128 = __ldg(&rin_w[ocA * 131 + 128]);
        float wA129 = __ldg(&rin_w[ocA * 131 + 129]);
        float wA130 = __ldg(&rin_w[ocA * 131 + 130]);
        float wB128 = __ldg(&rin_w[ocB * 131 + 128]);
        float wB129 = __ldg(&rin_w[ocB * 131 + 129]);
        float wB130 = __ldg(&rin_w[ocB * 131 + 130]);
        float* Fb = g_F + (size_t)b * 32 * HW;
        float sA = 0.f, sB = 0.f;
#pragma unroll
        for (int nt = 0; nt < 4; nt++) {
            int col = ncol + nt * 8 + tig * 2;
#pragma unroll
            for (int d = 0; d < 2; d++) {
                int px = col + d;
                float cg = cgS[px];
                float ly = -1.f + (float)(px >> 4) * (2.f / 15.f);
                float lx = -1.f + (float)(px & 15) * (2.f / 15.f);
                float vA = leakyf(acc[nt][d] + bA + wA128 * cg + wA129 * ly + wA130 * lx);
                float vB = leakyf(acc[nt][2 + d] + bB + wB128 * cg + wB129 * ly + wB130 * lx);
                fS[ocA * 261 + px] = vA;
                fS[ocB * 261 + px] = vB;
                sA += vA; sB += vB;
                int pix = (py0 + (px >> 4)) * 256 + px0 + (px & 15);
                Fb[(size_t)ocA * HW + pix] = vA;
                Fb[(size_t)ocB * HW + pix] = vB;
            }
        }
        atomicAdd(&fsum_s[ocA], sA);
        atomicAdd(&fsum_s[ocB], sB);
    }
    __syncthreads();

    if (t < 256) {
        int px = t;
        float fv[32];
        float fm = 0.f;
#pragma unroll
        for (int o = 0; o < 32; o++) {
            fv[o] = fS[o * 261 + px];
            fm += fv[o];
        }
        int pix = (py0 + (px >> 4)) * 256 + px0 + (px & 15);
        g_FMC[(size_t)b * HW + pix] = fm * (1.f / 32.f);

        float h[16];
#pragma unroll
        for (int o2 = 0; o2 < 16; o2++) {
            float s = __ldg(&r1b[o2]);
#pragma unroll
            for (int o = 0; o < 32; o++) s = fmaf(wr1[o2 * 32 + o], fv[o], s);
            h[o2] = leakyf(s);
        }
        float ox = __ldg(&r2b[0]), oy = __ldg(&r2b[1]);
#pragma unroll
        for (int o2 = 0; o2 < 16; o2++) {
            ox = fmaf(wr2[o2], h[o2], ox);
            oy = fmaf(wr2[16 + o2], h[o2], oy);
        }
        float* OFb = g_OFF + (size_t)b * 2 * HW;
        OFb[pix] = ox;
        OFb[HW + pix] = oy;
    }
    __syncthreads();
    if (t < 32) atomicAdd(&g_FSUM[b * 32 + t], fsum_s[t]);
}

// ---------------- channel attention ca ----------------
__global__ void ca_kernel(const float* __restrict__ rca_w, const float* __restrict__ rca_b) {
    int c = threadIdx.x;
    int b = blockIdx.x;
    float s = __ldg(&rca_b[c]);
#pragma unroll
    for (int ci = 0; ci < 32; ci++)
        s = fmaf(__ldg(&rca_w[c * 32 + ci]), g_FSUM[b * 32 + ci] * (1.f / 65536.f), s);
    g_CA[b * CH + c] = 1.f / (1.f + expf(-s));
}

// ---------------- spatial attention sa: 2D-tiled ----------------
__global__ void __launch_bounds__(256) sa_kernel(const float* __restrict__ rsa_w,
                                                 const float* __restrict__ rsa_b) {
    __shared__ float ws[288];
    __shared__ float tile[10][36];
    int t = threadIdx.x;
    for (int i = t; i < 288; i += 256) ws[i] = rsa_w[i];
    int b = blockIdx.z;
    int tx0 = blockIdx.x * 32, ty0 = blockIdx.y * 8;
    int lx = t & 31, lyy = t >> 5;
    float acc = __ldg(&rsa_b[0]);
    const float* Fb = g_F + (size_t)b * 32 * HW;
#pragma unroll 1
    for (int ci = 0; ci < 32; ci++) {
        __syncthreads();
        for (int i = t; i < 340; i += 256) {
            int lyl = i / 34, lxl = i % 34;
            int gy = ty0 - 1 + lyl, gx = tx0 - 1 + lxl;
            float v = 0.f;
            if ((unsigned)gy < 256u && (unsigned)gx < 256u)
                v = __ldg(&Fb[(size_t)ci * HW + gy * 256 + gx]);
            tile[lyl][lxl] = v;
        }
        __syncthreads();
        const float* wc = ws + ci * 9;
#pragma unroll
        for (int ky = 0; ky < 3; ky++)
#pragma unroll
            for (int kx = 0; kx < 3; kx++)
                acc = fmaf(wc[ky * 3 + kx], tile[lyy + ky][lx + kx], acc);
    }
    g_SA[(size_t)b * HW + (ty0 + lyy) * 256 + tx0 + lx] = 1.f / (1.f + expf(-acc));
}

// ---------------- window MLP + gumbel hard mask ----------------
__global__ void mask_kernel(const float* __restrict__ gu,
                            const float* __restrict__ rm1_w, const float* __restrict__ rm1_b,
                            const float* __restrict__ rm2_w, const float* __restrict__ rm2_b) {
    __shared__ float m[256];
    __shared__ float h1s[16];
    int n = blockIdx.x, b = blockIdx.y;
    int t = threadIdx.x;
    int dh = t >> 4, dw = t & 15;
    int pix = ((n >> 4) * 16 + dh) * 256 + (n & 15) * 16 + dw;
    m[t] = g_FMC[b * HW + pix];
    __syncthreads();
    if (t < 16) {
        float s = __ldg(&rm1_b[t]);
        for (int e = 0; e < 256; e++) s = fmaf(__ldg(&rm1_w[t * 256 + e]), m[e], s);
        h1s[t] = leakyf(s);
    }
    __syncthreads();
    if (t == 0) {
        float z0 = __ldg(&rm2_b[0]), z1 = __ldg(&rm2_b[1]);
#pragma unroll
        for (int o = 0; o < 16; o++) {
            z0 = fmaf(__ldg(&rm2_w[o]), h1s[o], z0);
            z1 = fmaf(__ldg(&rm2_w[16 + o]), h1s[o], z1);
        }
        float mx = fmaxf(z0, z1);
        float e0 = expf(z0 - mx), e1 = expf(z1 - mx);
        float inv = 1.f / (e0 + e1);
        float p0 = e0 * inv, p1 = e1 * inv;
        float u0 = __ldg(&gu[(b * 256 + n) * 2 + 0]);
        float u1 = __ldg(&gu[(b * 256 + n) * 2 + 1]);
        float g0 = -logf(-logf(u0 + 1e-10f) + 1e-10f);
        float g1 = -logf(-logf(u1 + 1e-10f) + 1e-10f);
        g_MASK[b * 256 + n] = (p0 + g0 >= p1 + g1) ? 1.f : 0.f;
    }
}

// ---------------- window attention, 512 threads (16 warps), ldmatrix fragments ----------------
#define SMEM_ATTN3 ((64*257 + 512 + 64 + 64) * 4 + 90112)
__global__ void __launch_bounds__(512, 1) attn_mma_kernel() {
    int n = blockIdx.x, b = blockIdx.y;
    int t = threadIdx.x;
    int py0 = (n >> 4) * 16, px0 = (n & 15) * 16;
    int cbase = b * CH * HW;
    if (g_MASK[b * 256 + n] == 0.f) {
        const float* sab = g_SA + (size_t)b * HW;
#pragma unroll 4
        for (int i = t; i < 8192; i += 512) {
            int ch = i >> 6, r4 = i & 63;
            int wrow = r4 >> 2, px4 = (r4 & 3) * 4;
            int pix = (py0 + wrow) * 256 + px0 + px4;
            float4 v = *(const float4*)(g_V + cbase + ch * HW + pix);
            float4 s = *(const float4*)(sab + pix);
            v.x *= s.x; v.y *= s.y; v.z *= s.z; v.w *= s.w;
            *(float4*)(g_OUT + cbase + ch * HW + pix) = v;
        }
        return;
    }
    extern __shared__ char smraw[];
    float* S = (float*)smraw;
    float* red = S + 64 * 257;
    float* rmax = red + 512;
    float* rsum = rmax + 64;
    __nv_bfloat16* Qh = (__nv_bfloat16*)(rsum + 64);
    __nv_bfloat16* Ql = Qh + 64 * 136;
    __nv_bfloat16* KVh = Ql + 64 * 136;
    __nv_bfloat16* KVl = KVh + 9216;
    __nv_bfloat16* Pth = KVl + 9216;
    __nv_bfloat16* Ptl = Pth + 64 * 72;

    int w = t >> 5, lane = t & 31;
    int gid = lane >> 2;
    int tig = lane & 3;
    int mm = lane >> 3, r8 = lane & 7;

    int mrowS = (w & 3) * 16, ncolS = (w >> 2) * 16;
    uint32_t aoffS = (uint32_t)((mrowS + (mm & 1) * 8 + r8) * 272 + (mm >> 1) * 16);
    uint32_t aHiS = smaddr(Qh) + aoffS;
    uint32_t aLoS = smaddr(Ql) + aoffS;
    uint32_t boffS = (uint32_t)((ncolS + (mm >> 1) * 8 + r8) * 272 + (mm & 1) * 16);
    uint32_t bHiS = smaddr(KVh) + boffS;
    uint32_t bLoS = smaddr(KVl) + boffS;

    int mrowO = (w & 3) * 16, ncolO = (w >> 2) * 32;
    uint32_t aoffP = (uint32_t)((mrowO + (mm & 1) * 8 + r8) * 144 + (mm >> 1) * 16);
    uint32_t aHiP = smaddr(Pth) + aoffP;
    uint32_t aLoP = smaddr(Ptl) + aoffP;
    uint32_t boffP = (uint32_t)((ncolO + (mm >> 1) * 8 + r8) * 144 + (mm & 1) * 16);
    uint32_t bHiP = smaddr(KVh) + boffP;
    uint32_t bLoP = smaddr(KVl) + boffP;

#pragma unroll 1
    for (int rc = 0; rc < 4; rc++) {
        int r0 = rc * 64;
        __syncthreads();
#pragma unroll
        for (int j = 0; j < 8; j++) {
            int i = t + j * 512;
            int px = i & 63, cp = i >> 6;
            int p = r0 + px;
            int pix = (py0 + (p >> 4)) * 256 + px0 + (p & 15);
            float v0 = g_Qb[cbase + (2 * cp) * HW + pix];
            float v1 = g_Qb[cbase + (2 * cp + 1) * HW + pix];
            __nv_bfloat16 h0 = __float2bfloat16_rn(v0);
            __nv_bfloat16 h1 = __float2bfloat16_rn(v1);
            __nv_bfloat16 l0 = __float2bfloat16_rn(v0 - __bfloat162float(h0));
            __nv_bfloat16 l1 = __float2bfloat16_rn(v1 - __bfloat162float(h1));
            ((__nv_bfloat162*)(Qh + px * 136))[cp] = __nv_bfloat162(h0, h1);
            ((__nv_bfloat162*)(Ql + px * 136))[cp] = __nv_bfloat162(l0, l1);
        }

#pragma unroll 1
        for (int kvt = 0; kvt < 4; kvt++) {
            __syncthreads();
#pragma unroll
            for (int j = 0; j < 8; j++) {
                int i = t + j * 512;
                int px = i & 63, cp = i >> 6;
                int p = kvt * 64 + px;
                int pix = (py0 + (p >> 4)) * 256 + px0 + (p & 15);
                float v0 = g_Kb[cbase + (2 * cp) * HW + pix];
                float v1 = g_Kb[cbase + (2 * cp + 1) * HW + pix];
                __nv_bfloat16 h0 = __float2bfloat16_rn(v0);
                __nv_bfloat16 h1 = __float2bfloat16_rn(v1);
                __nv_bfloat16 l0 = __float2bfloat16_rn(v0 - __bfloat162float(h0));
                __nv_bfloat16 l1 = __float2bfloat16_rn(v1 - __bfloat162float(h1));
                ((__nv_bfloat162*)(KVh + px * 136))[cp] = __nv_bfloat162(h0, h1);
                ((__nv_bfloat162*)(KVl + px * 136))[cp] = __nv_bfloat162(l0, l1);
            }
            __syncthreads();
            float acc[2][4];
#pragma unroll
            for (int i = 0; i < 2; i++)
#pragma unroll
                for (int j2 = 0; j2 < 4; j2++) acc[i][j2] = 0.f;
#pragma unroll
            for (int ks = 0; ks < 8; ks++) {
                uint32_t ko = ks * 32;
                uint32_t Ahf[4], Alf[4], Bhf[4], Blf[4];
                LDSM_X4(Ahf, aHiS + ko);
                LDSM_X4(Alf, aLoS + ko);
                LDSM_X4(Bhf, bHiS + ko);
                LDSM_X4(Blf, bLoS + ko);
#pragma unroll
                for (int nt = 0; nt < 2; nt++) {
                    const uint32_t* bh = &Bhf[nt * 2];
                    const uint32_t* bl = &Blf[nt * 2];
                    MMA_BF16(acc[nt], Ahf, bh);
                    MMA_BF16(acc[nt], Ahf, bl);
                    MMA_BF16(acc[nt], Alf, bh);
                }
            }
#pragma unroll
            for (int nt = 0; nt < 2; nt++) {
                int col = kvt * 64 + ncolS + nt * 8 + tig * 2;
                S[(mrowS + gid) * 257 + col] = acc[nt][0];
                S[(mrowS + gid) * 257 + col + 1] = acc[nt][1];
                S[(mrowS + gid + 8) * 257 + col] = acc[nt][2];
                S[(mrowS + gid + 8) * 257 + col + 1] = acc[nt][3];
            }
        }
        __syncthreads();

        {
            int r = t & 63, seg = t >> 6;
            float* srow = &S[r * 257 + seg * 32];
            float mx = -1e30f;
#pragma unroll 8
            for (int k = 0; k < 32; k++) mx = fmaxf(mx, srow[k]);
            red[seg * 64 + r] = mx;
            __syncthreads();
            if (t < 64) {
                float m0 = fmaxf(fmaxf(red[t], red[64 + t]), fmaxf(red[128 + t], red[192 + t]));
                float m1 = fmaxf(fmaxf(red[256 + t], red[320 + t]), fmaxf(red[384 + t], red[448 + t]));
                rmax[t] = fmaxf(m0, m1);
            }
            __syncthreads();
            float rm_ = rmax[r];
            float s = 0.f;
#pragma unroll 8
            for (int k = 0; k < 32; k++) {
                float e = __expf(srow[k] - rm_);
                srow[k] = e;
                s += e;
            }
            red[seg * 64 + r] = s;
            __syncthreads();
            if (t < 64)
                rsum[t] = (red[t] + red[64 + t] + red[128 + t] + red[192 + t]) +
                          (red[256 + t] + red[320 + t] + red[384 + t] + red[448 + t]);
            __syncthreads();
        }

        float oacc[4][4];
#pragma unroll
        for (int i = 0; i < 4; i++)
#pragma unroll
            for (int j2 = 0; j2 < 4; j2++) oacc[i][j2] = 0.f;

#pragma unroll 1
        for (int kvt = 0; kvt < 4; kvt++) {
            __syncthreads();
#pragma unroll
            for (int j = 0; j < 8; j++) {
                int i = t + j * 512;
                int col = i & 63, row = i >> 6;
                float v = S[row * 257 + kvt * 64 + col];
                __nv_bfloat16 h = __float2bfloat16_rn(v);
                Pth[row * 72 + col] = h;
                Ptl[row * 72 + col] = __float2bfloat16_rn(v - __bfloat162float(h));
            }
#pragma unroll
            for (int j = 0; j < 16; j++) {
                int i = t + j * 512;
                int px = i & 63, ch = i >> 6;
                int p = kvt * 64 + px;
                int pix = (py0 + (p >> 4)) * 256 + px0 + (p & 15);
                float v = g_V[cbase + ch * HW + pix];
                __nv_bfloat16 h = __float2bfloat16_rn(v);
                KVh[ch * 72 + px] = h;
                KVl[ch * 72 + px] = __float2bfloat16_rn(v - __bfloat162float(h));
            }
            __syncthreads();
#pragma unroll
            for (int ks = 0; ks < 4; ks++) {
                uint32_t ko = ks * 32;
                uint32_t Ahf[4], Alf[4], Bhf[2][4], Blf[2][4];
                LDSM_X4(Ahf, aHiP + ko);
                LDSM_X4(Alf, aLoP + ko);
                LDSM_X4(Bhf[0], bHiP + ko);
                LDSM_X4(Blf[0], bLoP + ko);
                LDSM_X4(Bhf[1], bHiP + 16 * 144 + ko);
                LDSM_X4(Blf[1], bLoP + 16 * 144 + ko);
#pragma unroll
                for (int nt = 0; nt < 4; nt++) {
                    const uint32_t* bh = &Bhf[nt >> 1][(nt & 1) * 2];
                    const uint32_t* bl = &Blf[nt >> 1][(nt & 1) * 2];
                    MMA_BF16(oacc[nt], Ahf, bh);
                    MMA_BF16(oacc[nt], Ahf, bl);
                    MMA_BF16(oacc[nt], Alf, bh);
                }
            }
        }

        {
            int rowA = mrowO + gid, rowB = rowA + 8;
            float invA = 1.f / rsum[rowA];
            float invB = 1.f / rsum[rowB];
            int pA = r0 + rowA, pB = r0 + rowB;
            int pixA = (py0 + (pA >> 4)) * 256 + px0 + (pA & 15);
            int pixB = (py0 + (pB >> 4)) * 256 + px0 + (pB & 15);
#pragma unroll
            for (int nt = 0; nt < 4; nt++) {
                int ch = ncolO + nt * 8 + tig * 2;
                g_OUT[cbase + ch * HW + pixA] = oacc[nt][0] * invA;
                g_OUT[cbase + (ch + 1) * HW + pixA] = oacc[nt][1] * invA;
                g_OUT[cbase + ch * HW + pixB] = oacc[nt][2] * invB;
                g_OUT[cbase + (ch + 1) * HW + pixB] = oacc[nt][3] * invB;
            }
        }
    }
}

// ---------------- fused depthwise 5x5(d1) -> 5x5(d3) + gelu*ca + residual ----------------
__global__ void __launch_bounds__(256) dw5x2_kernel(
    const float* __restrict__ in, const float* __restrict__ w2, const float* __restrict__ b2,
    const float* __restrict__ w3, const float* __restrict__ b3, float* __restrict__ out) {
    __shared__ float sIn[48][81];
    __shared__ float sMid[44][77];
    __shared__ float wA[25], wB[25];
    int c = blockIdx.z & 127, b = blockIdx.z >> 7;
    int t = threadIdx.x;
    if (t < 25) wA[t] = w2[c * 25 + t];
    else if (t < 50) wB[t - 25] = w3[c * 25 + (t - 25)];
    int ox0 = blockIdx.x * 64, oy0 = blockIdx.y * 32;
    const float* ip = in + (size_t)(b * CH + c) * HW;

    for (int i = t; i < 48 * 80; i += 256) {
        int lx = i % 80, ly = i / 80;
        int gx = ox0 - 8 + lx, gy = oy0 - 8 + ly;
        float v = 0.f;
        if ((unsigned)gx < 256u && (unsigned)gy < 256u) v = __ldg(&ip[gy * 256 + gx]);
        sIn[ly][lx] = v;
    }
    __syncthreads();

    float b2v = __ldg(&b2[c]);
    for (int i = t; i < 44 * 76; i += 256) {
        int mx = i % 76, my = i / 76;
        int gx = ox0 - 6 + mx, gy = oy0 - 6 + my;
        float acc = 0.f;
        if ((unsigned)gx < 256u && (unsigned)gy < 256u) {
            acc = b2v;
#pragma unroll
            for (int ky = 0; ky < 5; ky++)
#pragma unroll
                for (int kx = 0; kx < 5; kx++)
                    acc = fmaf(wA[ky * 5 + kx], sIn[my + ky][mx + kx], acc);
        }
        sMid[my][mx] = acc;
    }
    __syncthreads();

    float b3v = __ldg(&b3[c]);
    float cav = g_CA[b * CH + c];
    size_t obase = (size_t)(b * CH + c) * HW;
    for (int i = t; i < 32 * 64; i += 256) {
        int x = i % 64, y = i / 64;
        float acc = b3v;
#pragma unroll
        for (int ky = 0; ky < 5; ky++)
#pragma unroll
            for (int kx = 0; kx < 5; kx++)
                acc = fmaf(wB[ky * 5 + kx], sMid[y + 3 * ky][x + 3 * kx], acc);
        float g = 0.5f * acc * (1.f + erff(acc * 0.7071067811865475f));
        size_t oidx = obase + (size_t)(oy0 + y) * 256 + ox0 + x;
        out[oidx] = g * cav + g_OUT[oidx];
    }
}

// ---------------- launch ----------------
extern "C" void kernel_launch(void* const* d_in, const int* in_sizes, int n_in,
                              void* d_out, int out_size) {
    const float* x      = (const float*)d_in[0];
    const float* cond_g = (const float*)d_in[1];
    const float* gu     = (const float*)d_in[2];
    const float* pv_w   = (const float*)d_in[3];
    const float* pv_b   = (const float*)d_in[4];
    const float* pq_w   = (const float*)d_in[5];
    const float* pq_b   = (const float*)d_in[6];
    const float* pk_w   = (const float*)d_in[7];
    const float* pk_b   = (const float*)d_in[8];
    const float* cs1_w  = (const float*)d_in[9];
    const float* cs1_b  = (const float*)d_in[10];
    const float* cs2_w  = (const float*)d_in[11];
    const float* cs2_b  = (const float*)d_in[12];
    const float* cs3_w  = (const float*)d_in[13];
    const float* cs3_b  = (const float*)d_in[14];
    const float* po_w   = (const float*)d_in[15];
    const float* po_b   = (const float*)d_in[16];
    const float* rin_w  = (const float*)d_in[17];
    const float* rin_b  = (const float*)d_in[18];
    const float* r1w    = (const float*)d_in[19];
    const float* r1b    = (const float*)d_in[20];
    const float* r2w    = (const float*)d_in[21];
    const float* r2b    = (const float*)d_in[22];
    const float* rm1_w  = (const float*)d_in[23];
    const float* rm1_b  = (const float*)d_in[24];
    const float* rm2_w  = (const float*)d_in[25];
    const float* rm2_b  = (const float*)d_in[26];
    const float* rca_w  = (const float*)d_in[27];
    const float* rca_b  = (const float*)d_in[28];
    const float* rsa_w  = (const float*)d_in[29];
    const float* rsa_b  = (const float*)d_in[30];

    float *pV, *pOUT, *pT1, *pT2;
    __nv_bfloat16* pWT;
    cudaGetSymbolAddress((void**)&pV, g_V);
    cudaGetSymbolAddress((void**)&pOUT, g_OUT);
    cudaGetSymbolAddress((void**)&pT1, g_T1);
    cudaGetSymbolAddress((void**)&pT2, g_T2);
    cudaGetSymbolAddress((void**)&pWT, g_WT);

    cudaFuncSetAttribute(attn_mma_kernel, cudaFuncAttributeMaxDynamicSharedMemorySize, SMEM_ATTN3);
    cudaFuncSetAttribute(conv1x1_mma, cudaFuncAttributeMaxDynamicSharedMemorySize, CV_SMEM_Q);
    cudaFuncSetAttribute(convqk_mma, cudaFuncAttributeMaxDynamicSharedMemorySize, CV_SMEM_FULL);
    cudaFuncSetAttribute(predictor_mma, cudaFuncAttributeMaxDynamicSharedMemorySize, PRED2_SMEM);

    const int WSET = 2 * 128 * 136;

    prep_all_kernel<<<dim3(64, 5), 256>>>(pv_w, pq_w, pk_w, cs1_w, po_w);
    prep_rin_kernel<<<16, 256>>>(rin_w);
    zero_fsum_kernel<<<1, 128>>>();
    conv1x1_mma<<<dim3(1024, BB), 512, CV_SMEM_Q>>>(x, pWT + 0 * WSET, pv_b, pV, 0);
    predictor_mma<<<dim3(256, BB), 512, PRED2_SMEM>>>(cond_g, rin_w, rin_b, r1w, r1b, r2w, r2b);
    ca_kernel<<<BB, 128>>>(rca_w, rca_b);
    sa_kernel<<<dim3(8, 32, BB), 256>>>(rsa_w, rsa_b);
    mask_kernel<<<dim3(256, BB), 256>>>(gu, rm1_w, rm1_b, rm2_w, rm2_b);
    convqk_mma<<<dim3(256, BB), 512, CV_SMEM_FULL>>>(x, pWT + 1 * WSET, pWT + 2 * WSET, pq_b, pk_b);
    attn_mma_kernel<<<dim3(256, BB), 512, SMEM_ATTN3>>>();
    conv1x1_mma<<<dim3(1024, BB), 512, CV_SMEM_Q>>>(pOUT, pWT + 3 * WSET, cs1_b, pT1, 0);
    dw5x2_kernel<<<dim3(4, 8, BB * CH), 256>>>(pT1, cs2_w, cs2_b, cs3_w, cs3_b, pT2);
    conv1x1_mma<<<dim3(1024, BB), 512, CV_SMEM_Q>>>(pT2, pWT + 4 * WSET, po_b, (float*)d_out, 0);
}